// round 2
// baseline (speedup 1.0000x reference)
#include <cuda_runtime.h>
#include <cuda_bf16.h>
#include <math.h>

#define NBOX 2048
#define TPB  256

// shared arena offsets (floats)
#define OFF_CROP   0
#define OFF_P2     0
#define OFF_P1     6912
#define OFF_P3     6912
#define OFF_C4     7936
#define OFF_F5     9088
#define OFF_FC6    9344
#define OFF_W      24576
#define SMEM1_FLOATS 29736

__device__ float    g_score[NBOX];
__device__ float    g_box[NBOX * 4];
__device__ float    g_skey[NBOX];
__device__ int      g_sidx[NBOX];
__device__ float    g_sbox[NBOX * 4];
__device__ unsigned g_mask[NBOX * 64];

__global__ __launch_bounds__(TPB) void onet_cnn(
    const float* __restrict__ bboxes, const float* __restrict__ image,
    const float* __restrict__ c1w, const float* __restrict__ c1b, const float* __restrict__ p1a,
    const float* __restrict__ c2w, const float* __restrict__ c2b, const float* __restrict__ p2a,
    const float* __restrict__ c3w, const float* __restrict__ c3b, const float* __restrict__ p3a,
    const float* __restrict__ c4w, const float* __restrict__ c4b, const float* __restrict__ p4a,
    const float* __restrict__ f5w, const float* __restrict__ f5b, const float* __restrict__ p5a,
    const float* __restrict__ f6aw, const float* __restrict__ f6ab,
    const float* __restrict__ f6bw, const float* __restrict__ f6bb)
{
    extern __shared__ float sm[];
    const int t = threadIdx.x;
    const int b = blockIdx.x;

    float B0 = bboxes[b*4+0], B1 = bboxes[b*4+1], B2 = bboxes[b*4+2], B3 = bboxes[b*4+3];
    float bx1 = fmaxf(B0, 0.f), by1 = fmaxf(B1, 0.f);
    float bx2 = fminf(B2, 1024.f), by2 = fminf(B3, 1024.f);
    int ix1 = (int)bx1, iy1 = (int)by1, ix2 = (int)bx2, iy2 = (int)by2;
    int cw = max(ix2 - ix1, 1), ch = max(iy2 - iy1, 1);

    // ---- crop 48x48x3 HWC ----
    float* crop = sm + OFF_CROP;
    for (int i = t; i < 6912; i += TPB) {
        int c = i % 3; int xy = i / 3; int x = xy % 48; int y = xy / 48;
        int gx = ix1 + (x * cw) / 48;
        int gy = iy1 + (y * ch) / 48;
        crop[i] = (__ldg(&image[(gy * 1024 + gx) * 3 + c]) - 127.5f) * 0.0078125f;
    }

    // ---- conv1 weights ----
    float* w1s = sm + OFF_W; float* b1s = w1s + 864; float* a1s = w1s + 896;
    for (int i = t; i < 864; i += TPB) w1s[i] = c1w[i];
    if (t < 32) { b1s[t] = c1b[t]; a1s[t] = p1a[t]; }
    __syncthreads();

    // ===== stage 1: conv1 3x3x3->32 + prelu + pool(3,2,pad1) -> P1 [32][23][24] =====
    float* temp1 = sm + OFF_W + 928;           // 2ch x 46x46
    float* P1 = sm + OFF_P1;
    for (int g = 0; g < 16; ++g) {
        int ocl = t & 1;
        int oc = g * 2 + ocl;
        float wr[27];
        #pragma unroll
        for (int k = 0; k < 27; k++) wr[k] = w1s[k * 32 + oc];
        float bias = b1s[oc], alpha = a1s[oc];
        for (int task = t; task < 1104; task += TPB) {
            int tmp = task >> 1;
            int xg = tmp % 12; int cy = tmp / 12;
            int x0 = xg * 4;
            float a0 = bias, a1v = bias, a2 = bias, a3 = bias;
            #pragma unroll
            for (int ky = 0; ky < 3; ky++) {
                const float* row = crop + (cy + ky) * 144;
                float in[18];
                #pragma unroll
                for (int j = 0; j < 6; j++) {
                    int col = x0 + j; if (col > 47) col = 47;
                    in[j*3+0] = row[col*3+0];
                    in[j*3+1] = row[col*3+1];
                    in[j*3+2] = row[col*3+2];
                }
                #pragma unroll
                for (int kx = 0; kx < 3; kx++)
                    #pragma unroll
                    for (int ic = 0; ic < 3; ic++) {
                        float w = wr[(ky*3+kx)*3+ic];
                        a0  += in[(kx+0)*3+ic] * w;
                        a1v += in[(kx+1)*3+ic] * w;
                        a2  += in[(kx+2)*3+ic] * w;
                        a3  += in[(kx+3)*3+ic] * w;
                    }
            }
            a0  = a0  >= 0.f ? a0  : alpha * a0;
            a1v = a1v >= 0.f ? a1v : alpha * a1v;
            a2  = a2  >= 0.f ? a2  : alpha * a2;
            a3  = a3  >= 0.f ? a3  : alpha * a3;
            float* tp = temp1 + ocl * 2116 + cy * 46;
            tp[x0+0] = a0; tp[x0+1] = a1v;
            if (x0+2 < 46) tp[x0+2] = a2;
            if (x0+3 < 46) tp[x0+3] = a3;
        }
        __syncthreads();
        for (int i = t; i < 1058; i += TPB) {
            int c = i & 1; int pos = i >> 1; int px = pos % 23; int py = pos / 23;
            float m = -3.4e38f;
            #pragma unroll
            for (int dy = 0; dy < 3; dy++) {
                int cy2 = 2*py - 1 + dy; if (cy2 < 0 || cy2 >= 46) continue;
                #pragma unroll
                for (int dx = 0; dx < 3; dx++) {
                    int cx2 = 2*px - 1 + dx; if (cx2 < 0 || cx2 >= 46) continue;
                    m = fmaxf(m, temp1[c*2116 + cy2*46 + cx2]);
                }
            }
            P1[(g*2 + c) * 552 + py * 24 + px] = m;
        }
        __syncthreads();
    }

    // ===== stage 2: conv2 3x3x32->64 + prelu + pool(3,2) -> P2 [64][10][10] =====
    float* w2s = sm + OFF_W; float* b2s = w2s + 1152; float* a2s = b2s + 4;
    float* temp2 = sm + OFF_W + 1160;          // 4ch x 21x21
    float* P2 = sm + OFF_P2;
    for (int g = 0; g < 16; ++g) {
        __syncthreads();
        for (int i = t; i < 1152; i += TPB) {
            int c = i & 3; int kidx = i >> 2;
            w2s[i] = c2w[kidx * 64 + g*4 + c];
        }
        if (t < 4) { b2s[t] = c2b[g*4 + t]; a2s[t] = p2a[g*4 + t]; }
        __syncthreads();
        if (t < 252) {
            int xg = t % 3; int rem = t / 3; int c = rem & 3; int cy = rem >> 2;
            int x0 = xg * 7;
            float bias = b2s[c], alpha = a2s[c];
            float acc[7];
            #pragma unroll
            for (int j = 0; j < 7; j++) acc[j] = bias;
            #pragma unroll
            for (int ky = 0; ky < 3; ky++) {
                const float* inb = P1 + (cy + ky) * 24 + x0;
                const float* wb  = w2s + (ky * 3) * 128 + c;
                #pragma unroll 4
                for (int ic = 0; ic < 32; ic++) {
                    const float* in = inb + ic * 552;
                    float i0=in[0],i1=in[1],i2=in[2],i3=in[3],i4=in[4],i5=in[5],i6=in[6],i7=in[7],i8=in[8];
                    float w0 = wb[(0*32+ic)*4], w1 = wb[(1*32+ic)*4], w2v = wb[(2*32+ic)*4];
                    acc[0]+=i0*w0; acc[1]+=i1*w0; acc[2]+=i2*w0; acc[3]+=i3*w0; acc[4]+=i4*w0; acc[5]+=i5*w0; acc[6]+=i6*w0;
                    acc[0]+=i1*w1; acc[1]+=i2*w1; acc[2]+=i3*w1; acc[3]+=i4*w1; acc[4]+=i5*w1; acc[5]+=i6*w1; acc[6]+=i7*w1;
                    acc[0]+=i2*w2v;acc[1]+=i3*w2v;acc[2]+=i4*w2v;acc[3]+=i5*w2v;acc[4]+=i6*w2v;acc[5]+=i7*w2v;acc[6]+=i8*w2v;
                }
            }
            float* tp = temp2 + c * 441 + cy * 21 + x0;
            #pragma unroll
            for (int j = 0; j < 7; j++) {
                float v = acc[j];
                tp[j] = v >= 0.f ? v : alpha * v;
            }
        }
        __syncthreads();
        for (int i = t; i < 400; i += TPB) {
            int c = i & 3; int pos = i >> 2; int px = pos % 10; int py = pos / 10;
            const float* tp = temp2 + c * 441;
            float m = -3.4e38f;
            #pragma unroll
            for (int dy = 0; dy < 3; dy++)
                #pragma unroll
                for (int dx = 0; dx < 3; dx++)
                    m = fmaxf(m, tp[(2*py+dy)*21 + 2*px+dx]);
            P2[(g*4 + c) * 100 + py * 10 + px] = m;
        }
    }
    __syncthreads();

    // ===== stage 3: conv3 3x3x64->64 + prelu + pool(2,2) -> P3 [64][4][4] =====
    float* w3s = sm + OFF_W; float* b3s = w3s + 4608; float* a3s = b3s + 8;
    float* temp3 = sm + OFF_W + 4624;          // 8ch x 8x8
    float* P3 = sm + OFF_P3;
    for (int g = 0; g < 8; ++g) {
        __syncthreads();
        for (int i = t; i < 4608; i += TPB) { int c = i & 7; int kidx = i >> 3; w3s[i] = c3w[kidx*64 + g*8 + c]; }
        if (t < 8) { b3s[t] = c3b[g*8 + t]; a3s[t] = p3a[g*8 + t]; }
        __syncthreads();
        if (t < 128) {
            int xg = t & 1; int c = (t >> 1) & 7; int cy = t >> 4;
            int x0 = xg * 4;
            float bias = b3s[c], alpha = a3s[c];
            float a0 = bias, a1v = bias, a2 = bias, a3 = bias;
            #pragma unroll
            for (int ky = 0; ky < 3; ky++) {
                const float* inb = P2 + (cy + ky) * 10 + x0;
                const float* wb  = w3s + (ky * 3) * 512 + c;
                #pragma unroll 4
                for (int ic = 0; ic < 64; ic++) {
                    const float* in = inb + ic * 100;
                    float i0=in[0],i1=in[1],i2=in[2],i3=in[3],i4=in[4],i5=in[5];
                    float w0 = wb[(0*64+ic)*8], w1 = wb[(1*64+ic)*8], w2v = wb[(2*64+ic)*8];
                    a0+=i0*w0; a1v+=i1*w0; a2+=i2*w0; a3+=i3*w0;
                    a0+=i1*w1; a1v+=i2*w1; a2+=i3*w1; a3+=i4*w1;
                    a0+=i2*w2v;a1v+=i3*w2v;a2+=i4*w2v;a3+=i5*w2v;
                }
            }
            float* tp = temp3 + c * 64 + cy * 8 + x0;
            tp[0] = a0  >= 0.f ? a0  : alpha * a0;
            tp[1] = a1v >= 0.f ? a1v : alpha * a1v;
            tp[2] = a2  >= 0.f ? a2  : alpha * a2;
            tp[3] = a3  >= 0.f ? a3  : alpha * a3;
        }
        __syncthreads();
        if (t < 128) {
            int c = t & 7; int pos = t >> 3; int px = pos & 3; int py = pos >> 2;
            const float* tp = temp3 + c * 64;
            float m = fmaxf(fmaxf(tp[(2*py)*8 + 2*px], tp[(2*py)*8 + 2*px + 1]),
                            fmaxf(tp[(2*py+1)*8 + 2*px], tp[(2*py+1)*8 + 2*px + 1]));
            P3[(g*8 + c) * 16 + py * 4 + px] = m;
        }
    }
    __syncthreads();

    // ===== stage 4: conv4 2x2x64->128 + prelu -> C4 flat (c*9 + y*3 + x) =====
    float* w4s = sm + OFF_W; float* b4s = w4s + 4096; float* a4s = b4s + 16;
    float* C4 = sm + OFF_C4;
    for (int g = 0; g < 8; ++g) {
        __syncthreads();
        for (int i = t; i < 4096; i += TPB) { int c = i & 15; int kidx = i >> 4; w4s[i] = c4w[kidx*128 + g*16 + c]; }
        if (t < 16) { b4s[t] = c4b[g*16 + t]; a4s[t] = p4a[g*16 + t]; }
        __syncthreads();
        if (t < 144) {
            int c = t & 15; int pos = t >> 4; int y = pos / 3; int x = pos % 3;
            float acc = b4s[c];
            #pragma unroll
            for (int k = 0; k < 4; k++) {
                int ky = k >> 1, kx = k & 1;
                const float* inb = P3 + (y + ky) * 4 + (x + kx);
                const float* wb  = w4s + k * 1024 + c;
                #pragma unroll 4
                for (int ic = 0; ic < 64; ic++)
                    acc += inb[ic * 16] * wb[ic * 16];
            }
            float alpha = a4s[c];
            C4[(g*16 + c) * 9 + pos] = acc >= 0.f ? acc : alpha * acc;
        }
    }
    __syncthreads();

    // ===== fc5: 1152 -> 256 + prelu =====
    float* F5 = sm + OFF_F5;
    {
        int warp = t >> 5, lane = t & 31;
        for (int o = warp; o < 256; o += 8) {
            const float* wrow = f5w + o * 1152 + lane;
            float acc = 0.f;
            #pragma unroll 6
            for (int j = 0; j < 36; j++) acc += C4[lane + 32*j] * __ldg(&wrow[32*j]);
            #pragma unroll
            for (int s = 16; s; s >>= 1) acc += __shfl_xor_sync(0xFFFFFFFFu, acc, s);
            if (lane == 0) {
                float v = acc + f5b[o];
                float al = p5a[o];
                F5[o] = v >= 0.f ? v : al * v;
            }
        }
    }
    __syncthreads();

    // ===== fc6a (2) + fc6b (4) =====
    float* FC6 = sm + OFF_FC6;
    if (t < 192) {
        int o = t >> 5, lane = t & 31;
        const float* wrow = (o < 2) ? (f6aw + o * 256) : (f6bw + (o - 2) * 256);
        float acc = 0.f;
        #pragma unroll
        for (int j = 0; j < 8; j++) { int k = lane + 32*j; acc += F5[k] * __ldg(&wrow[k]); }
        #pragma unroll
        for (int s = 16; s; s >>= 1) acc += __shfl_xor_sync(0xFFFFFFFFu, acc, s);
        if (lane == 0) FC6[o] = acc + ((o < 2) ? f6ab[o] : f6bb[o - 2]);
    }
    __syncthreads();

    if (t == 0) {
        float l0 = FC6[0], l1 = FC6[1];
        float m = fmaxf(l0, l1);
        float e0 = expf(l0 - m), e1 = expf(l1 - m);
        float score = e1 / (e0 + e1);
        float w = bx2 - bx1, h = by2 - by1;
        g_score[b] = score;
        g_box[b*4+0] = bx1 + FC6[2] * w;
        g_box[b*4+1] = by1 + FC6[3] * h;
        g_box[b*4+2] = bx2 + FC6[4] * w;
        g_box[b*4+3] = by2 + FC6[5] * h;
    }
}

// ---------- NMS: bitonic sort by (score desc, idx asc) ----------
__device__ __forceinline__ bool nms_before(float ka, int ia, float kb, int ib) {
    return (ka > kb) || (ka == kb && ia < ib);
}

__global__ __launch_bounds__(1024) void nms_sort() {
    __shared__ float kk[NBOX];
    __shared__ int   id[NBOX];
    int t = threadIdx.x;
    kk[t] = g_score[t];         id[t] = t;
    kk[t+1024] = g_score[t+1024]; id[t+1024] = t + 1024;
    for (int k = 2; k <= NBOX; k <<= 1) {
        for (int j = k >> 1; j > 0; j >>= 1) {
            __syncthreads();
            #pragma unroll 2
            for (int i = t; i < NBOX; i += 1024) {
                int ixj = i ^ j;
                if (ixj > i) {
                    float ka = kk[i], kb = kk[ixj];
                    int ia = id[i], ib = id[ixj];
                    bool up = ((i & k) == 0);
                    bool bad = up ? nms_before(kb, ib, ka, ia) : nms_before(ka, ia, kb, ib);
                    if (bad) { kk[i] = kb; kk[ixj] = ka; id[i] = ib; id[ixj] = ia; }
                }
            }
        }
    }
    __syncthreads();
    #pragma unroll 2
    for (int i = t; i < NBOX; i += 1024) {
        g_skey[i] = kk[i];
        int o = id[i];
        g_sidx[i] = o;
        g_sbox[i*4+0] = g_box[o*4+0];
        g_sbox[i*4+1] = g_box[o*4+1];
        g_sbox[i*4+2] = g_box[o*4+2];
        g_sbox[i*4+3] = g_box[o*4+3];
    }
}

// ---------- NMS: IOU bitmask, mask[i*64 + bx] bit jj set if j=bx*32+jj > i and iou>thr ----------
__global__ __launch_bounds__(64) void nms_mask() {
    __shared__ float cb[32][4];
    int t = threadIdx.x;
    int j0 = blockIdx.x * 32;
    for (int i = t; i < 128; i += 64) cb[i >> 2][i & 3] = g_sbox[(j0 + (i >> 2)) * 4 + (i & 3)];
    __syncthreads();
    int i = blockIdx.y * 64 + t;
    float x1 = g_sbox[i*4+0], y1 = g_sbox[i*4+1], x2 = g_sbox[i*4+2], y2 = g_sbox[i*4+3];
    float area = (x2 - x1) * (y2 - y1);
    unsigned word = 0;
    #pragma unroll 8
    for (int jj = 0; jj < 32; jj++) {
        int j = j0 + jj;
        if (j > i) {
            float bx1v = cb[jj][0], by1v = cb[jj][1], bx2v = cb[jj][2], by2v = cb[jj][3];
            float xx1 = fmaxf(x1, bx1v), yy1 = fmaxf(y1, by1v);
            float xx2 = fminf(x2, bx2v), yy2 = fminf(y2, by2v);
            float inter = fmaxf(xx2 - xx1, 0.f) * fmaxf(yy2 - yy1, 0.f);
            float areab = (bx2v - bx1v) * (by2v - by1v);
            float iou = inter / (area + areab - inter + 1e-12f);
            if (iou > 0.5f) word |= (1u << jj);
        }
    }
    g_mask[i * 64 + blockIdx.x] = word;
}

// ---------- NMS: sequential scan (warp 0) + scatter ----------
__global__ __launch_bounds__(256) void nms_scan(float* __restrict__ out) {
    __shared__ unsigned rem[64];
    __shared__ unsigned keepw[64];
    int t = threadIdx.x;
    if (t < 64) { rem[t] = 0u; keepw[t] = 0u; }
    __syncthreads();
    if (t < 32) {
        for (int p = 0; p < NBOX; p++) {
            unsigned r = rem[p >> 5];
            bool keep = (g_skey[p] >= 0.5f) && !((r >> (p & 31)) & 1u);
            if (keep) {
                if (t == 0) keepw[p >> 5] |= (1u << (p & 31));
                rem[t]      |= g_mask[p * 64 + t];
                rem[t + 32] |= g_mask[p * 64 + t + 32];
            }
            __syncwarp();
        }
    }
    __syncthreads();
    for (int i = t; i < NBOX * 4; i += 256) out[i] = 0.f;
    __syncthreads();
    for (int p = t; p < NBOX; p += 256) {
        if ((keepw[p >> 5] >> (p & 31)) & 1u) {
            int o = g_sidx[p];
            out[o*4+0] = g_sbox[p*4+0];
            out[o*4+1] = g_sbox[p*4+1];
            out[o*4+2] = g_sbox[p*4+2];
            out[o*4+3] = g_sbox[p*4+3];
        }
    }
}

extern "C" void kernel_launch(void* const* d_in, const int* in_sizes, int n_in,
                              void* d_out, int out_size) {
    (void)in_sizes; (void)n_in; (void)out_size;
    cudaFuncSetAttribute(onet_cnn, cudaFuncAttributeMaxDynamicSharedMemorySize, SMEM1_FLOATS * 4);
    onet_cnn<<<NBOX, TPB, SMEM1_FLOATS * 4>>>(
        (const float*)d_in[0],  (const float*)d_in[1],
        (const float*)d_in[2],  (const float*)d_in[3],  (const float*)d_in[4],
        (const float*)d_in[5],  (const float*)d_in[6],  (const float*)d_in[7],
        (const float*)d_in[8],  (const float*)d_in[9],  (const float*)d_in[10],
        (const float*)d_in[11], (const float*)d_in[12], (const float*)d_in[13],
        (const float*)d_in[14], (const float*)d_in[15], (const float*)d_in[16],
        (const float*)d_in[17], (const float*)d_in[18],
        (const float*)d_in[19], (const float*)d_in[20]);
    nms_sort<<<1, 1024>>>();
    nms_mask<<<dim3(64, 32), 64>>>();
    nms_scan<<<1, 256>>>((float*)d_out);
}

// round 3
// speedup vs baseline: 1.4154x; 1.4154x over previous
#include <cuda_runtime.h>
#include <cuda_bf16.h>
#include <math.h>

#define NBOX 2048
#define TPB  256

// shared arena offsets (floats)
#define OFF_CROP   0        // 6912   (crop 48x48x3, dead after stage1) -> P2 [64][10][10]
#define OFF_P2     0
#define OFF_P1     6912     // 17664  (P1 [32][23][24], dead after stage2)
#define OFF_P3     6912     // 1024
#define OFF_C4     7936     // 1152
#define OFF_F5     9088     // 256
#define OFF_FC6    9344     // 8
#define OFF_W34    9472     // stage3/4 weights+temp (inside dead-P1 region)
#define OFF_W      24576    // stage1/2 weights+temp region (max 3044)
#define SMEM1_FLOATS 27620  // 110,480 bytes -> 2 CTAs/SM

__device__ float    g_score[NBOX];
__device__ float    g_box[NBOX * 4];
__device__ float    g_skey[NBOX];
__device__ int      g_sidx[NBOX];
__device__ float    g_sbox[NBOX * 4];
__device__ unsigned g_mask[NBOX * 64];

__global__ __launch_bounds__(TPB, 2) void onet_cnn(
    const float* __restrict__ bboxes, const float* __restrict__ image,
    const float* __restrict__ c1w, const float* __restrict__ c1b, const float* __restrict__ p1a,
    const float* __restrict__ c2w, const float* __restrict__ c2b, const float* __restrict__ p2a,
    const float* __restrict__ c3w, const float* __restrict__ c3b, const float* __restrict__ p3a,
    const float* __restrict__ c4w, const float* __restrict__ c4b, const float* __restrict__ p4a,
    const float* __restrict__ f5w, const float* __restrict__ f5b, const float* __restrict__ p5a,
    const float* __restrict__ f6aw, const float* __restrict__ f6ab,
    const float* __restrict__ f6bw, const float* __restrict__ f6bb)
{
    extern __shared__ float sm[];
    const int t = threadIdx.x;
    const int b = blockIdx.x;

    float B0 = bboxes[b*4+0], B1 = bboxes[b*4+1], B2 = bboxes[b*4+2], B3 = bboxes[b*4+3];
    float bx1 = fmaxf(B0, 0.f), by1 = fmaxf(B1, 0.f);
    float bx2 = fminf(B2, 1024.f), by2 = fminf(B3, 1024.f);
    int ix1 = (int)bx1, iy1 = (int)by1, ix2 = (int)bx2, iy2 = (int)by2;
    int cw = max(ix2 - ix1, 1), ch = max(iy2 - iy1, 1);

    // ---- crop 48x48x3 HWC ----
    float* crop = sm + OFF_CROP;
    for (int i = t; i < 6912; i += TPB) {
        int c = i % 3; int xy = i / 3; int x = xy % 48; int y = xy / 48;
        int gx = ix1 + (x * cw) / 48;
        int gy = iy1 + (y * ch) / 48;
        crop[i] = (__ldg(&image[(gy * 1024 + gx) * 3 + c]) - 127.5f) * 0.0078125f;
    }

    // ---- conv1 weights ----
    float* w1s = sm + OFF_W; float* b1s = w1s + 864; float* a1s = w1s + 896;
    for (int i = t; i < 864; i += TPB) w1s[i] = c1w[i];
    if (t < 32) { b1s[t] = c1b[t]; a1s[t] = p1a[t]; }
    __syncthreads();

    // ===== stage 1: conv1 3x3x3->32 + prelu + pool(3,2,pad1) -> P1 [32][23][24] =====
    // one out-channel per group (temp = 46x46)
    float* temp1 = sm + OFF_W + 928;
    float* P1 = sm + OFF_P1;
    for (int g = 0; g < 32; ++g) {
        float wr[27];
        #pragma unroll
        for (int k = 0; k < 27; k++) wr[k] = w1s[k * 32 + g];
        float bias = b1s[g], alpha = a1s[g];
        for (int task = t; task < 552; task += TPB) {
            int xg = task % 12; int cy = task / 12;
            int x0 = xg * 4;
            float a0 = bias, a1v = bias, a2 = bias, a3 = bias;
            #pragma unroll
            for (int ky = 0; ky < 3; ky++) {
                const float* row = crop + (cy + ky) * 144;
                float in[18];
                #pragma unroll
                for (int j = 0; j < 6; j++) {
                    int col = x0 + j; if (col > 47) col = 47;
                    in[j*3+0] = row[col*3+0];
                    in[j*3+1] = row[col*3+1];
                    in[j*3+2] = row[col*3+2];
                }
                #pragma unroll
                for (int kx = 0; kx < 3; kx++)
                    #pragma unroll
                    for (int ic = 0; ic < 3; ic++) {
                        float w = wr[(ky*3+kx)*3+ic];
                        a0  += in[(kx+0)*3+ic] * w;
                        a1v += in[(kx+1)*3+ic] * w;
                        a2  += in[(kx+2)*3+ic] * w;
                        a3  += in[(kx+3)*3+ic] * w;
                    }
            }
            a0  = a0  >= 0.f ? a0  : alpha * a0;
            a1v = a1v >= 0.f ? a1v : alpha * a1v;
            a2  = a2  >= 0.f ? a2  : alpha * a2;
            a3  = a3  >= 0.f ? a3  : alpha * a3;
            float* tp = temp1 + cy * 46;
            tp[x0+0] = a0; tp[x0+1] = a1v;
            if (x0+2 < 46) tp[x0+2] = a2;
            if (x0+3 < 46) tp[x0+3] = a3;
        }
        __syncthreads();
        for (int i = t; i < 529; i += TPB) {
            int px = i % 23; int py = i / 23;
            float m = -3.4e38f;
            #pragma unroll
            for (int dy = 0; dy < 3; dy++) {
                int cy2 = 2*py - 1 + dy; if (cy2 < 0 || cy2 >= 46) continue;
                #pragma unroll
                for (int dx = 0; dx < 3; dx++) {
                    int cx2 = 2*px - 1 + dx; if (cx2 < 0 || cx2 >= 46) continue;
                    m = fmaxf(m, temp1[cy2*46 + cx2]);
                }
            }
            P1[g * 552 + py * 24 + px] = m;
        }
        __syncthreads();
    }

    // ===== stage 2: conv2 3x3x32->64 + prelu + pool(3,2) -> P2 [64][10][10] =====
    float* w2s = sm + OFF_W; float* b2s = w2s + 1152; float* a2s = b2s + 4;
    float* temp2 = sm + OFF_W + 1160;          // 4ch x 21x21
    float* P2 = sm + OFF_P2;
    for (int g = 0; g < 16; ++g) {
        __syncthreads();
        for (int i = t; i < 1152; i += TPB) {
            int c = i & 3; int kidx = i >> 2;
            w2s[i] = c2w[kidx * 64 + g*4 + c];
        }
        if (t < 4) { b2s[t] = c2b[g*4 + t]; a2s[t] = p2a[g*4 + t]; }
        __syncthreads();
        if (t < 252) {
            int xg = t % 3; int rem = t / 3; int c = rem & 3; int cy = rem >> 2;
            int x0 = xg * 7;
            float bias = b2s[c], alpha = a2s[c];
            float acc[7];
            #pragma unroll
            for (int j = 0; j < 7; j++) acc[j] = bias;
            #pragma unroll
            for (int ky = 0; ky < 3; ky++) {
                const float* inb = P1 + (cy + ky) * 24 + x0;
                const float* wb  = w2s + (ky * 3) * 128 + c;
                #pragma unroll 4
                for (int ic = 0; ic < 32; ic++) {
                    const float* in = inb + ic * 552;
                    float i0=in[0],i1=in[1],i2=in[2],i3=in[3],i4=in[4],i5=in[5],i6=in[6],i7=in[7],i8=in[8];
                    float w0 = wb[(0*32+ic)*4], w1 = wb[(1*32+ic)*4], w2v = wb[(2*32+ic)*4];
                    acc[0]+=i0*w0; acc[1]+=i1*w0; acc[2]+=i2*w0; acc[3]+=i3*w0; acc[4]+=i4*w0; acc[5]+=i5*w0; acc[6]+=i6*w0;
                    acc[0]+=i1*w1; acc[1]+=i2*w1; acc[2]+=i3*w1; acc[3]+=i4*w1; acc[4]+=i5*w1; acc[5]+=i6*w1; acc[6]+=i7*w1;
                    acc[0]+=i2*w2v;acc[1]+=i3*w2v;acc[2]+=i4*w2v;acc[3]+=i5*w2v;acc[4]+=i6*w2v;acc[5]+=i7*w2v;acc[6]+=i8*w2v;
                }
            }
            float* tp = temp2 + c * 441 + cy * 21 + x0;
            #pragma unroll
            for (int j = 0; j < 7; j++) {
                float v = acc[j];
                tp[j] = v >= 0.f ? v : alpha * v;
            }
        }
        __syncthreads();
        for (int i = t; i < 400; i += TPB) {
            int c = i & 3; int pos = i >> 2; int px = pos % 10; int py = pos / 10;
            const float* tp = temp2 + c * 441;
            float m = -3.4e38f;
            #pragma unroll
            for (int dy = 0; dy < 3; dy++)
                #pragma unroll
                for (int dx = 0; dx < 3; dx++)
                    m = fmaxf(m, tp[(2*py+dy)*21 + 2*px+dx]);
            P2[(g*4 + c) * 100 + py * 10 + px] = m;
        }
    }
    __syncthreads();

    // ===== stage 3: conv3 3x3x64->64 + prelu + pool(2,2) -> P3 [64][4][4] =====
    float* w3s = sm + OFF_W34; float* b3s = w3s + 4608; float* a3s = b3s + 8;
    float* temp3 = sm + OFF_W34 + 4624;        // 8ch x 8x8
    float* P3 = sm + OFF_P3;
    for (int g = 0; g < 8; ++g) {
        __syncthreads();
        for (int i = t; i < 4608; i += TPB) { int c = i & 7; int kidx = i >> 3; w3s[i] = c3w[kidx*64 + g*8 + c]; }
        if (t < 8) { b3s[t] = c3b[g*8 + t]; a3s[t] = p3a[g*8 + t]; }
        __syncthreads();
        if (t < 128) {
            int xg = t & 1; int c = (t >> 1) & 7; int cy = t >> 4;
            int x0 = xg * 4;
            float bias = b3s[c], alpha = a3s[c];
            float a0 = bias, a1v = bias, a2 = bias, a3 = bias;
            #pragma unroll
            for (int ky = 0; ky < 3; ky++) {
                const float* inb = P2 + (cy + ky) * 10 + x0;
                const float* wb  = w3s + (ky * 3) * 512 + c;
                #pragma unroll 4
                for (int ic = 0; ic < 64; ic++) {
                    const float* in = inb + ic * 100;
                    float i0=in[0],i1=in[1],i2=in[2],i3=in[3],i4=in[4],i5=in[5];
                    float w0 = wb[(0*64+ic)*8], w1 = wb[(1*64+ic)*8], w2v = wb[(2*64+ic)*8];
                    a0+=i0*w0; a1v+=i1*w0; a2+=i2*w0; a3+=i3*w0;
                    a0+=i1*w1; a1v+=i2*w1; a2+=i3*w1; a3+=i4*w1;
                    a0+=i2*w2v;a1v+=i3*w2v;a2+=i4*w2v;a3+=i5*w2v;
                }
            }
            float* tp = temp3 + c * 64 + cy * 8 + x0;
            tp[0] = a0  >= 0.f ? a0  : alpha * a0;
            tp[1] = a1v >= 0.f ? a1v : alpha * a1v;
            tp[2] = a2  >= 0.f ? a2  : alpha * a2;
            tp[3] = a3  >= 0.f ? a3  : alpha * a3;
        }
        __syncthreads();
        if (t < 128) {
            int c = t & 7; int pos = t >> 3; int px = pos & 3; int py = pos >> 2;
            const float* tp = temp3 + c * 64;
            float m = fmaxf(fmaxf(tp[(2*py)*8 + 2*px], tp[(2*py)*8 + 2*px + 1]),
                            fmaxf(tp[(2*py+1)*8 + 2*px], tp[(2*py+1)*8 + 2*px + 1]));
            P3[(g*8 + c) * 16 + py * 4 + px] = m;
        }
    }
    __syncthreads();

    // ===== stage 4: conv4 2x2x64->128 + prelu -> C4 flat (c*9 + y*3 + x) =====
    float* w4s = sm + OFF_W34; float* b4s = w4s + 4096; float* a4s = b4s + 16;
    float* C4 = sm + OFF_C4;
    for (int g = 0; g < 8; ++g) {
        __syncthreads();
        for (int i = t; i < 4096; i += TPB) { int c = i & 15; int kidx = i >> 4; w4s[i] = c4w[kidx*128 + g*16 + c]; }
        if (t < 16) { b4s[t] = c4b[g*16 + t]; a4s[t] = p4a[g*16 + t]; }
        __syncthreads();
        if (t < 144) {
            int c = t & 15; int pos = t >> 4; int y = pos / 3; int x = pos % 3;
            float acc = b4s[c];
            #pragma unroll
            for (int k = 0; k < 4; k++) {
                int ky = k >> 1, kx = k & 1;
                const float* inb = P3 + (y + ky) * 4 + (x + kx);
                const float* wb  = w4s + k * 1024 + c;
                #pragma unroll 4
                for (int ic = 0; ic < 64; ic++)
                    acc += inb[ic * 16] * wb[ic * 16];
            }
            float alpha = a4s[c];
            C4[(g*16 + c) * 9 + pos] = acc >= 0.f ? acc : alpha * acc;
        }
    }
    __syncthreads();

    // ===== fc5: 1152 -> 256 + prelu =====
    float* F5 = sm + OFF_F5;
    {
        int warp = t >> 5, lane = t & 31;
        for (int o = warp; o < 256; o += 8) {
            const float* wrow = f5w + o * 1152 + lane;
            float acc = 0.f;
            #pragma unroll 6
            for (int j = 0; j < 36; j++) acc += C4[lane + 32*j] * __ldg(&wrow[32*j]);
            #pragma unroll
            for (int s = 16; s; s >>= 1) acc += __shfl_xor_sync(0xFFFFFFFFu, acc, s);
            if (lane == 0) {
                float v = acc + f5b[o];
                float al = p5a[o];
                F5[o] = v >= 0.f ? v : al * v;
            }
        }
    }
    __syncthreads();

    // ===== fc6a (2) + fc6b (4) =====
    float* FC6 = sm + OFF_FC6;
    if (t < 192) {
        int o = t >> 5, lane = t & 31;
        const float* wrow = (o < 2) ? (f6aw + o * 256) : (f6bw + (o - 2) * 256);
        float acc = 0.f;
        #pragma unroll
        for (int j = 0; j < 8; j++) { int k = lane + 32*j; acc += F5[k] * __ldg(&wrow[k]); }
        #pragma unroll
        for (int s = 16; s; s >>= 1) acc += __shfl_xor_sync(0xFFFFFFFFu, acc, s);
        if (lane == 0) FC6[o] = acc + ((o < 2) ? f6ab[o] : f6bb[o - 2]);
    }
    __syncthreads();

    if (t == 0) {
        float l0 = FC6[0], l1 = FC6[1];
        float m = fmaxf(l0, l1);
        float e0 = expf(l0 - m), e1 = expf(l1 - m);
        float score = e1 / (e0 + e1);
        float w = bx2 - bx1, h = by2 - by1;
        g_score[b] = score;
        g_box[b*4+0] = bx1 + FC6[2] * w;
        g_box[b*4+1] = by1 + FC6[3] * h;
        g_box[b*4+2] = bx2 + FC6[4] * w;
        g_box[b*4+3] = by2 + FC6[5] * h;
    }
}

// ---------- NMS: bitonic sort by (score desc, idx asc) ----------
__device__ __forceinline__ bool nms_before(float ka, int ia, float kb, int ib) {
    return (ka > kb) || (ka == kb && ia < ib);
}

__global__ __launch_bounds__(1024) void nms_sort() {
    __shared__ float kk[NBOX];
    __shared__ int   id[NBOX];
    int t = threadIdx.x;
    kk[t] = g_score[t];           id[t] = t;
    kk[t+1024] = g_score[t+1024]; id[t+1024] = t + 1024;
    for (int k = 2; k <= NBOX; k <<= 1) {
        for (int j = k >> 1; j > 0; j >>= 1) {
            __syncthreads();
            #pragma unroll 2
            for (int i = t; i < NBOX; i += 1024) {
                int ixj = i ^ j;
                if (ixj > i) {
                    float ka = kk[i], kb = kk[ixj];
                    int ia = id[i], ib = id[ixj];
                    bool up = ((i & k) == 0);
                    bool bad = up ? nms_before(kb, ib, ka, ia) : nms_before(ka, ia, kb, ib);
                    if (bad) { kk[i] = kb; kk[ixj] = ka; id[i] = ib; id[ixj] = ia; }
                }
            }
        }
    }
    __syncthreads();
    #pragma unroll 2
    for (int i = t; i < NBOX; i += 1024) {
        g_skey[i] = kk[i];
        int o = id[i];
        g_sidx[i] = o;
        g_sbox[i*4+0] = g_box[o*4+0];
        g_sbox[i*4+1] = g_box[o*4+1];
        g_sbox[i*4+2] = g_box[o*4+2];
        g_sbox[i*4+3] = g_box[o*4+3];
    }
}

// ---------- NMS: IOU bitmask ----------
__global__ __launch_bounds__(64) void nms_mask() {
    __shared__ float cb[32][4];
    int t = threadIdx.x;
    int j0 = blockIdx.x * 32;
    for (int i = t; i < 128; i += 64) cb[i >> 2][i & 3] = g_sbox[(j0 + (i >> 2)) * 4 + (i & 3)];
    __syncthreads();
    int i = blockIdx.y * 64 + t;
    float x1 = g_sbox[i*4+0], y1 = g_sbox[i*4+1], x2 = g_sbox[i*4+2], y2 = g_sbox[i*4+3];
    float area = (x2 - x1) * (y2 - y1);
    unsigned word = 0;
    #pragma unroll 8
    for (int jj = 0; jj < 32; jj++) {
        int j = j0 + jj;
        if (j > i) {
            float bx1v = cb[jj][0], by1v = cb[jj][1], bx2v = cb[jj][2], by2v = cb[jj][3];
            float xx1 = fmaxf(x1, bx1v), yy1 = fmaxf(y1, by1v);
            float xx2 = fminf(x2, bx2v), yy2 = fminf(y2, by2v);
            float inter = fmaxf(xx2 - xx1, 0.f) * fmaxf(yy2 - yy1, 0.f);
            float areab = (bx2v - bx1v) * (by2v - by1v);
            float iou = inter / (area + areab - inter + 1e-12f);
            if (iou > 0.5f) word |= (1u << jj);
        }
    }
    g_mask[i * 64 + blockIdx.x] = word;
}

// ---------- NMS: serial scan with register bitmap + block prefetch ----------
__global__ __launch_bounds__(256) void nms_scan(float* __restrict__ out) {
    __shared__ unsigned keepw[64];
    __shared__ int sV;
    int t = threadIdx.x;
    if (t < 64) keepw[t] = 0u;
    if (t == 0) sV = 0;
    __syncthreads();
    // count valid prefix length V (scores sorted desc)
    for (int p = t; p < NBOX; p += 256) {
        bool v = g_skey[p] >= 0.5f;
        unsigned bal = __ballot_sync(0xFFFFFFFFu, v);
        if ((t & 31) == 0) atomicAdd(&sV, __popc(bal));
    }
    __syncthreads();

    if (t < 32) {
        const int V = sV;
        unsigned r0 = 0u, r1 = 0u;           // lane t owns suppression words t and t+32
        unsigned cA[8], cB[8];
        #pragma unroll
        for (int j = 0; j < 8; j++) {
            if (j < V) { cA[j] = g_mask[j*64 + t]; cB[j] = g_mask[j*64 + 32 + t]; }
            else       { cA[j] = 0u; cB[j] = 0u; }
        }
        for (int base = 0; base < V; base += 8) {
            unsigned nA[8], nB[8];
            #pragma unroll
            for (int j = 0; j < 8; j++) {
                int p = base + 8 + j;
                if (p < V) { nA[j] = g_mask[p*64 + t]; nB[j] = g_mask[p*64 + 32 + t]; }
                else       { nA[j] = 0u; nB[j] = 0u; }
            }
            #pragma unroll
            for (int j = 0; j < 8; j++) {
                int p = base + j;
                if (p < V) {
                    int w = p >> 5;
                    unsigned word = __shfl_sync(0xFFFFFFFFu, (w < 32) ? r0 : r1, w & 31);
                    if (!((word >> (p & 31)) & 1u)) {
                        r0 |= cA[j]; r1 |= cB[j];
                        if (t == 0) keepw[w] |= 1u << (p & 31);
                    }
                }
            }
            #pragma unroll
            for (int j = 0; j < 8; j++) { cA[j] = nA[j]; cB[j] = nB[j]; }
        }
    }
    __syncthreads();
    for (int i = t; i < NBOX * 4; i += 256) out[i] = 0.f;
    __syncthreads();
    for (int p = t; p < NBOX; p += 256) {
        if ((keepw[p >> 5] >> (p & 31)) & 1u) {
            int o = g_sidx[p];
            out[o*4+0] = g_sbox[p*4+0];
            out[o*4+1] = g_sbox[p*4+1];
            out[o*4+2] = g_sbox[p*4+2];
            out[o*4+3] = g_sbox[p*4+3];
        }
    }
}

extern "C" void kernel_launch(void* const* d_in, const int* in_sizes, int n_in,
                              void* d_out, int out_size) {
    (void)in_sizes; (void)n_in; (void)out_size;
    cudaFuncSetAttribute(onet_cnn, cudaFuncAttributeMaxDynamicSharedMemorySize, SMEM1_FLOATS * 4);
    onet_cnn<<<NBOX, TPB, SMEM1_FLOATS * 4>>>(
        (const float*)d_in[0],  (const float*)d_in[1],
        (const float*)d_in[2],  (const float*)d_in[3],  (const float*)d_in[4],
        (const float*)d_in[5],  (const float*)d_in[6],  (const float*)d_in[7],
        (const float*)d_in[8],  (const float*)d_in[9],  (const float*)d_in[10],
        (const float*)d_in[11], (const float*)d_in[12], (const float*)d_in[13],
        (const float*)d_in[14], (const float*)d_in[15], (const float*)d_in[16],
        (const float*)d_in[17], (const float*)d_in[18],
        (const float*)d_in[19], (const float*)d_in[20]);
    nms_sort<<<1, 1024>>>();
    nms_mask<<<dim3(64, 32), 64>>>();
    nms_scan<<<1, 256>>>((float*)d_out);
}

// round 4
// speedup vs baseline: 1.4234x; 1.0057x over previous
#include <cuda_runtime.h>
#include <cuda_bf16.h>
#include <math.h>

#define NBOX 2048
#define TPB  256

// shared arena offsets (floats)
#define OFF_CROP   0        // 6912 (dead after stage1) -> P2 [64][10][10]
#define OFF_P2     0
#define OFF_P1     6912     // 17664 (dead after stage2)
#define OFF_P3     6912     // 1024
#define OFF_C4     7936     // 1152
#define OFF_F5     9088     // 256
#define OFF_FC6    9344     // 8
#define OFF_W34    9472     // stage3/4 weights+temp (inside dead-P1 region, 15104 avail)
#define OFF_W      24576    // stage1/2 weights+temp region (max 3044)
#define SMEM1_FLOATS 27620  // 110,480 bytes -> 2 CTAs/SM

__device__ float    g_score[NBOX];
__device__ float    g_box[NBOX * 4];
__device__ float    g_skey[NBOX];
__device__ int      g_sidx[NBOX];
__device__ float    g_sbox[NBOX * 4];
__device__ unsigned g_mask[NBOX * 64];

__global__ __launch_bounds__(TPB, 2) void onet_cnn(
    const float* __restrict__ bboxes, const float* __restrict__ image,
    const float* __restrict__ c1w, const float* __restrict__ c1b, const float* __restrict__ p1a,
    const float* __restrict__ c2w, const float* __restrict__ c2b, const float* __restrict__ p2a,
    const float* __restrict__ c3w, const float* __restrict__ c3b, const float* __restrict__ p3a,
    const float* __restrict__ c4w, const float* __restrict__ c4b, const float* __restrict__ p4a,
    const float* __restrict__ f5w, const float* __restrict__ f5b, const float* __restrict__ p5a,
    const float* __restrict__ f6aw, const float* __restrict__ f6ab,
    const float* __restrict__ f6bw, const float* __restrict__ f6bb)
{
    extern __shared__ float sm[];
    const int t = threadIdx.x;
    const int b = blockIdx.x;

    float B0 = bboxes[b*4+0], B1 = bboxes[b*4+1], B2 = bboxes[b*4+2], B3 = bboxes[b*4+3];
    float bx1 = fmaxf(B0, 0.f), by1 = fmaxf(B1, 0.f);
    float bx2 = fminf(B2, 1024.f), by2 = fminf(B3, 1024.f);
    int ix1 = (int)bx1, iy1 = (int)by1, ix2 = (int)bx2, iy2 = (int)by2;
    int cw = max(ix2 - ix1, 1), ch = max(iy2 - iy1, 1);

    // ---- crop 48x48x3 HWC ----
    float* crop = sm + OFF_CROP;
    for (int i = t; i < 6912; i += TPB) {
        int c = i % 3; int xy = i / 3; int x = xy % 48; int y = xy / 48;
        int gx = ix1 + (x * cw) / 48;
        int gy = iy1 + (y * ch) / 48;
        crop[i] = (__ldg(&image[(gy * 1024 + gx) * 3 + c]) - 127.5f) * 0.0078125f;
    }

    // ---- conv1 weights ----
    float* w1s = sm + OFF_W; float* b1s = w1s + 864; float* a1s = w1s + 896;
    for (int i = t; i < 864; i += TPB) w1s[i] = c1w[i];
    if (t < 32) { b1s[t] = c1b[t]; a1s[t] = p1a[t]; }
    __syncthreads();

    // ===== stage 1: conv1 3x3x3->32 + prelu + pool(3,2,pad1) -> P1 [32][23][24] =====
    float* temp1 = sm + OFF_W + 928;
    float* P1 = sm + OFF_P1;
    for (int g = 0; g < 32; ++g) {
        float wr[27];
        #pragma unroll
        for (int k = 0; k < 27; k++) wr[k] = w1s[k * 32 + g];
        float bias = b1s[g], alpha = a1s[g];
        for (int task = t; task < 552; task += TPB) {
            int xg = task % 12; int cy = task / 12;
            int x0 = xg * 4;
            float a0 = bias, a1v = bias, a2 = bias, a3 = bias;
            #pragma unroll
            for (int ky = 0; ky < 3; ky++) {
                const float* row = crop + (cy + ky) * 144;
                float in[18];
                #pragma unroll
                for (int j = 0; j < 6; j++) {
                    int col = x0 + j; if (col > 47) col = 47;
                    in[j*3+0] = row[col*3+0];
                    in[j*3+1] = row[col*3+1];
                    in[j*3+2] = row[col*3+2];
                }
                #pragma unroll
                for (int kx = 0; kx < 3; kx++)
                    #pragma unroll
                    for (int ic = 0; ic < 3; ic++) {
                        float w = wr[(ky*3+kx)*3+ic];
                        a0  += in[(kx+0)*3+ic] * w;
                        a1v += in[(kx+1)*3+ic] * w;
                        a2  += in[(kx+2)*3+ic] * w;
                        a3  += in[(kx+3)*3+ic] * w;
                    }
            }
            a0  = a0  >= 0.f ? a0  : alpha * a0;
            a1v = a1v >= 0.f ? a1v : alpha * a1v;
            a2  = a2  >= 0.f ? a2  : alpha * a2;
            a3  = a3  >= 0.f ? a3  : alpha * a3;
            float* tp = temp1 + cy * 46;
            tp[x0+0] = a0; tp[x0+1] = a1v;
            if (x0+2 < 46) tp[x0+2] = a2;
            if (x0+3 < 46) tp[x0+3] = a3;
        }
        __syncthreads();
        for (int i = t; i < 529; i += TPB) {
            int px = i % 23; int py = i / 23;
            float m = -3.4e38f;
            #pragma unroll
            for (int dy = 0; dy < 3; dy++) {
                int cy2 = 2*py - 1 + dy; if (cy2 < 0 || cy2 >= 46) continue;
                #pragma unroll
                for (int dx = 0; dx < 3; dx++) {
                    int cx2 = 2*px - 1 + dx; if (cx2 < 0 || cx2 >= 46) continue;
                    m = fmaxf(m, temp1[cy2*46 + cx2]);
                }
            }
            P1[g * 552 + py * 24 + px] = m;
        }
        __syncthreads();
    }

    // ===== stage 2: conv2 3x3x32->64 + prelu + pool(3,2) -> P2 [64][10][10] =====
    float* w2s = sm + OFF_W; float* b2s = w2s + 1152; float* a2s = b2s + 4;
    float* temp2 = sm + OFF_W + 1160;          // 4ch x 21x21
    float* P2 = sm + OFF_P2;
    for (int g = 0; g < 16; ++g) {
        __syncthreads();
        for (int i = t; i < 1152; i += TPB) {
            int c = i & 3; int kidx = i >> 2;
            w2s[i] = c2w[kidx * 64 + g*4 + c];
        }
        if (t < 4) { b2s[t] = c2b[g*4 + t]; a2s[t] = p2a[g*4 + t]; }
        __syncthreads();
        if (t < 252) {
            int xg = t % 3; int rem = t / 3; int c = rem & 3; int cy = rem >> 2;
            int x0 = xg * 7;
            float bias = b2s[c], alpha = a2s[c];
            float acc[7];
            #pragma unroll
            for (int j = 0; j < 7; j++) acc[j] = bias;
            #pragma unroll
            for (int ky = 0; ky < 3; ky++) {
                const float* inb = P1 + (cy + ky) * 24 + x0;
                const float* wb  = w2s + (ky * 3) * 128 + c;
                #pragma unroll 4
                for (int ic = 0; ic < 32; ic++) {
                    const float* in = inb + ic * 552;
                    float i0=in[0],i1=in[1],i2=in[2],i3=in[3],i4=in[4],i5=in[5],i6=in[6],i7=in[7],i8=in[8];
                    float w0 = wb[(0*32+ic)*4], w1 = wb[(1*32+ic)*4], w2v = wb[(2*32+ic)*4];
                    acc[0]+=i0*w0; acc[1]+=i1*w0; acc[2]+=i2*w0; acc[3]+=i3*w0; acc[4]+=i4*w0; acc[5]+=i5*w0; acc[6]+=i6*w0;
                    acc[0]+=i1*w1; acc[1]+=i2*w1; acc[2]+=i3*w1; acc[3]+=i4*w1; acc[4]+=i5*w1; acc[5]+=i6*w1; acc[6]+=i7*w1;
                    acc[0]+=i2*w2v;acc[1]+=i3*w2v;acc[2]+=i4*w2v;acc[3]+=i5*w2v;acc[4]+=i6*w2v;acc[5]+=i7*w2v;acc[6]+=i8*w2v;
                }
            }
            float* tp = temp2 + c * 441 + cy * 21 + x0;
            #pragma unroll
            for (int j = 0; j < 7; j++) {
                float v = acc[j];
                tp[j] = v >= 0.f ? v : alpha * v;
            }
        }
        __syncthreads();
        for (int i = t; i < 400; i += TPB) {
            int c = i & 3; int pos = i >> 2; int px = pos % 10; int py = pos / 10;
            const float* tp = temp2 + c * 441;
            float m = -3.4e38f;
            #pragma unroll
            for (int dy = 0; dy < 3; dy++)
                #pragma unroll
                for (int dx = 0; dx < 3; dx++)
                    m = fmaxf(m, tp[(2*py+dy)*21 + 2*px+dx]);
            P2[(g*4 + c) * 100 + py * 10 + px] = m;
        }
    }
    __syncthreads();

    // ===== stage 3: conv3 3x3x64->64 + prelu + pool(2,2) -> P3 [64][4][4] =====
    // 4 groups x 16 out-ch, 256 active threads
    float* w3s = sm + OFF_W34; float* b3s = w3s + 9216; float* a3s = b3s + 16;
    float* temp3 = sm + OFF_W34 + 9248;        // 16ch x 8x8
    float* P3 = sm + OFF_P3;
    for (int g = 0; g < 4; ++g) {
        __syncthreads();
        for (int i = t; i < 9216; i += TPB) { int c = i & 15; int kidx = i >> 4; w3s[i] = c3w[kidx*64 + g*16 + c]; }
        if (t < 16) { b3s[t] = c3b[g*16 + t]; a3s[t] = p3a[g*16 + t]; }
        __syncthreads();
        {
            int xg = t & 1; int c = (t >> 1) & 15; int cy = t >> 5;
            int x0 = xg * 4;
            float bias = b3s[c], alpha = a3s[c];
            float a0 = bias, a1v = bias, a2 = bias, a3 = bias;
            #pragma unroll
            for (int ky = 0; ky < 3; ky++) {
                const float* inb = P2 + (cy + ky) * 10 + x0;
                const float* wb  = w3s + (ky * 3) * 1024 + c;
                #pragma unroll 4
                for (int ic = 0; ic < 64; ic++) {
                    const float* in = inb + ic * 100;
                    float i0=in[0],i1=in[1],i2=in[2],i3=in[3],i4=in[4],i5=in[5];
                    float w0 = wb[(0*64+ic)*16], w1 = wb[(1*64+ic)*16], w2v = wb[(2*64+ic)*16];
                    a0+=i0*w0; a1v+=i1*w0; a2+=i2*w0; a3+=i3*w0;
                    a0+=i1*w1; a1v+=i2*w1; a2+=i3*w1; a3+=i4*w1;
                    a0+=i2*w2v;a1v+=i3*w2v;a2+=i4*w2v;a3+=i5*w2v;
                }
            }
            float* tp = temp3 + c * 64 + cy * 8 + x0;
            tp[0] = a0  >= 0.f ? a0  : alpha * a0;
            tp[1] = a1v >= 0.f ? a1v : alpha * a1v;
            tp[2] = a2  >= 0.f ? a2  : alpha * a2;
            tp[3] = a3  >= 0.f ? a3  : alpha * a3;
        }
        __syncthreads();
        {
            int c = t & 15; int pos = t >> 4; int px = pos & 3; int py = pos >> 2;
            const float* tp = temp3 + c * 64;
            float m = fmaxf(fmaxf(tp[(2*py)*8 + 2*px], tp[(2*py)*8 + 2*px + 1]),
                            fmaxf(tp[(2*py+1)*8 + 2*px], tp[(2*py+1)*8 + 2*px + 1]));
            P3[(g*16 + c) * 16 + py * 4 + px] = m;
        }
    }
    __syncthreads();

    // ===== stage 4: conv4 2x2x64->128 + prelu -> C4 flat (c*9 + y*3 + x) =====
    // 4 groups x 32 out-ch, 288 tasks over 256 threads
    float* w4s = sm + OFF_W34; float* b4s = w4s + 8192; float* a4s = b4s + 32;
    float* C4 = sm + OFF_C4;
    for (int g = 0; g < 4; ++g) {
        __syncthreads();
        for (int i = t; i < 8192; i += TPB) { int c = i & 31; int kidx = i >> 5; w4s[i] = c4w[kidx*128 + g*32 + c]; }
        if (t < 32) { b4s[t] = c4b[g*32 + t]; a4s[t] = p4a[g*32 + t]; }
        __syncthreads();
        for (int task = t; task < 288; task += TPB) {
            int c = task & 31; int pos = task >> 5; int y = pos / 3; int x = pos % 3;
            float acc = b4s[c];
            #pragma unroll
            for (int k = 0; k < 4; k++) {
                int ky = k >> 1, kx = k & 1;
                const float* inb = P3 + (y + ky) * 4 + (x + kx);
                const float* wb  = w4s + k * 2048 + c;
                #pragma unroll 4
                for (int ic = 0; ic < 64; ic++)
                    acc += inb[ic * 16] * wb[ic * 32];
            }
            float alpha = a4s[c];
            C4[(g*32 + c) * 9 + pos] = acc >= 0.f ? acc : alpha * acc;
        }
    }
    __syncthreads();

    // ===== fc5: 1152 -> 256 + prelu =====
    float* F5 = sm + OFF_F5;
    {
        int warp = t >> 5, lane = t & 31;
        for (int o = warp; o < 256; o += 8) {
            const float* wrow = f5w + o * 1152 + lane;
            float acc = 0.f;
            #pragma unroll 6
            for (int j = 0; j < 36; j++) acc += C4[lane + 32*j] * __ldg(&wrow[32*j]);
            #pragma unroll
            for (int s = 16; s; s >>= 1) acc += __shfl_xor_sync(0xFFFFFFFFu, acc, s);
            if (lane == 0) {
                float v = acc + f5b[o];
                float al = p5a[o];
                F5[o] = v >= 0.f ? v : al * v;
            }
        }
    }
    __syncthreads();

    // ===== fc6a (2) + fc6b (4) =====
    float* FC6 = sm + OFF_FC6;
    if (t < 192) {
        int o = t >> 5, lane = t & 31;
        const float* wrow = (o < 2) ? (f6aw + o * 256) : (f6bw + (o - 2) * 256);
        float acc = 0.f;
        #pragma unroll
        for (int j = 0; j < 8; j++) { int k = lane + 32*j; acc += F5[k] * __ldg(&wrow[k]); }
        #pragma unroll
        for (int s = 16; s; s >>= 1) acc += __shfl_xor_sync(0xFFFFFFFFu, acc, s);
        if (lane == 0) FC6[o] = acc + ((o < 2) ? f6ab[o] : f6bb[o - 2]);
    }
    __syncthreads();

    if (t == 0) {
        float l0 = FC6[0], l1 = FC6[1];
        float m = fmaxf(l0, l1);
        float e0 = expf(l0 - m), e1 = expf(l1 - m);
        float score = e1 / (e0 + e1);
        float w = bx2 - bx1, h = by2 - by1;
        g_score[b] = score;
        g_box[b*4+0] = bx1 + FC6[2] * w;
        g_box[b*4+1] = by1 + FC6[3] * h;
        g_box[b*4+2] = bx2 + FC6[4] * w;
        g_box[b*4+3] = by2 + FC6[5] * h;
    }
}

// ---------- NMS: bitonic sort by (score desc, idx asc) ----------
__device__ __forceinline__ bool nms_before(float ka, int ia, float kb, int ib) {
    return (ka > kb) || (ka == kb && ia < ib);
}

__global__ __launch_bounds__(1024) void nms_sort() {
    __shared__ float kk[NBOX];
    __shared__ int   id[NBOX];
    int t = threadIdx.x;
    kk[t] = g_score[t];           id[t] = t;
    kk[t+1024] = g_score[t+1024]; id[t+1024] = t + 1024;
    for (int k = 2; k <= NBOX; k <<= 1) {
        for (int j = k >> 1; j > 0; j >>= 1) {
            __syncthreads();
            #pragma unroll 2
            for (int i = t; i < NBOX; i += 1024) {
                int ixj = i ^ j;
                if (ixj > i) {
                    float ka = kk[i], kb = kk[ixj];
                    int ia = id[i], ib = id[ixj];
                    bool up = ((i & k) == 0);
                    bool bad = up ? nms_before(kb, ib, ka, ia) : nms_before(ka, ia, kb, ib);
                    if (bad) { kk[i] = kb; kk[ixj] = ka; id[i] = ib; id[ixj] = ia; }
                }
            }
        }
    }
    __syncthreads();
    #pragma unroll 2
    for (int i = t; i < NBOX; i += 1024) {
        g_skey[i] = kk[i];
        int o = id[i];
        g_sidx[i] = o;
        g_sbox[i*4+0] = g_box[o*4+0];
        g_sbox[i*4+1] = g_box[o*4+1];
        g_sbox[i*4+2] = g_box[o*4+2];
        g_sbox[i*4+3] = g_box[o*4+3];
    }
}

// ---------- NMS: IOU bitmask ----------
__global__ __launch_bounds__(64) void nms_mask() {
    __shared__ float cb[32][4];
    int t = threadIdx.x;
    int j0 = blockIdx.x * 32;
    for (int i = t; i < 128; i += 64) cb[i >> 2][i & 3] = g_sbox[(j0 + (i >> 2)) * 4 + (i & 3)];
    __syncthreads();
    int i = blockIdx.y * 64 + t;
    float x1 = g_sbox[i*4+0], y1 = g_sbox[i*4+1], x2 = g_sbox[i*4+2], y2 = g_sbox[i*4+3];
    float area = (x2 - x1) * (y2 - y1);
    unsigned word = 0;
    #pragma unroll 8
    for (int jj = 0; jj < 32; jj++) {
        int j = j0 + jj;
        if (j > i) {
            float bx1v = cb[jj][0], by1v = cb[jj][1], bx2v = cb[jj][2], by2v = cb[jj][3];
            float xx1 = fmaxf(x1, bx1v), yy1 = fmaxf(y1, by1v);
            float xx2 = fminf(x2, bx2v), yy2 = fminf(y2, by2v);
            float inter = fmaxf(xx2 - xx1, 0.f) * fmaxf(yy2 - yy1, 0.f);
            float areab = (bx2v - bx1v) * (by2v - by1v);
            float iou = inter / (area + areab - inter + 1e-12f);
            if (iou > 0.5f) word |= (1u << jj);
        }
    }
    g_mask[i * 64 + blockIdx.x] = word;
}

// ---------- NMS: serial scan, depth-6 (48-box) register pipeline ----------
__global__ __launch_bounds__(256) void nms_scan(float* __restrict__ out) {
    __shared__ unsigned keepw[64];
    __shared__ int sV;
    int t = threadIdx.x;
    if (t < 64) keepw[t] = 0u;
    if (t == 0) sV = 0;
    __syncthreads();
    for (int p = t; p < NBOX; p += 256) {
        bool v = g_skey[p] >= 0.5f;
        unsigned bal = __ballot_sync(0xFFFFFFFFu, v);
        if ((t & 31) == 0) atomicAdd(&sV, __popc(bal));
    }
    __syncthreads();

    if (t < 32) {
        const int V = sV;
        unsigned r0 = 0u, r1 = 0u;          // lane t owns suppression words t, t+32
        unsigned qA[48], qB[48];
        #pragma unroll
        for (int j = 0; j < 48; j++) {
            bool v = j < V;
            qA[j] = v ? g_mask[j*64 + t]      : 0u;
            qB[j] = v ? g_mask[j*64 + 32 + t] : 0u;
        }
        for (int base = 0; base < V; base += 48) {
            #pragma unroll
            for (int s = 0; s < 6; s++) {
                #pragma unroll
                for (int j = 0; j < 8; j++) {
                    int p = base + s*8 + j;
                    if (p < V) {
                        int w = p >> 5;
                        unsigned word = __shfl_sync(0xFFFFFFFFu, (w < 32) ? r0 : r1, w & 31);
                        if (!((word >> (p & 31)) & 1u)) {
                            r0 |= qA[s*8+j]; r1 |= qB[s*8+j];
                            if (t == 0) keepw[w] |= 1u << (p & 31);
                        }
                    }
                }
                #pragma unroll
                for (int j = 0; j < 8; j++) {
                    int p = base + 48 + s*8 + j;
                    bool v = p < V;
                    qA[s*8+j] = v ? g_mask[p*64 + t]      : 0u;
                    qB[s*8+j] = v ? g_mask[p*64 + 32 + t] : 0u;
                }
            }
        }
    }
    __syncthreads();
    for (int i = t; i < NBOX * 4; i += 256) out[i] = 0.f;
    __syncthreads();
    for (int p = t; p < NBOX; p += 256) {
        if ((keepw[p >> 5] >> (p & 31)) & 1u) {
            int o = g_sidx[p];
            out[o*4+0] = g_sbox[p*4+0];
            out[o*4+1] = g_sbox[p*4+1];
            out[o*4+2] = g_sbox[p*4+2];
            out[o*4+3] = g_sbox[p*4+3];
        }
    }
}

extern "C" void kernel_launch(void* const* d_in, const int* in_sizes, int n_in,
                              void* d_out, int out_size) {
    (void)in_sizes; (void)n_in; (void)out_size;
    cudaFuncSetAttribute(onet_cnn, cudaFuncAttributeMaxDynamicSharedMemorySize, SMEM1_FLOATS * 4);
    onet_cnn<<<NBOX, TPB, SMEM1_FLOATS * 4>>>(
        (const float*)d_in[0],  (const float*)d_in[1],
        (const float*)d_in[2],  (const float*)d_in[3],  (const float*)d_in[4],
        (const float*)d_in[5],  (const float*)d_in[6],  (const float*)d_in[7],
        (const float*)d_in[8],  (const float*)d_in[9],  (const float*)d_in[10],
        (const float*)d_in[11], (const float*)d_in[12], (const float*)d_in[13],
        (const float*)d_in[14], (const float*)d_in[15], (const float*)d_in[16],
        (const float*)d_in[17], (const float*)d_in[18],
        (const float*)d_in[19], (const float*)d_in[20]);
    nms_sort<<<1, 1024>>>();
    nms_mask<<<dim3(64, 32), 64>>>();
    nms_scan<<<1, 256>>>((float*)d_out);
}

// round 5
// speedup vs baseline: 1.6021x; 1.1255x over previous
#include <cuda_runtime.h>
#include <cuda_bf16.h>
#include <math.h>

#define NBOX 2048
#define TPB  256

// shared arena offsets (floats)
#define OFF_CROP   0        // 6912 (dead after stage1) -> P2 [64][10][10] (6400)
#define OFF_P2     0
#define OFF_P1     6912     // P1 [32][23][23] = 16928 (dead after stage2)
#define OFF_P3     6912     // 1024
#define OFF_C4     7936     // 1152
#define OFF_F5     9088     // 256
#define OFF_FC6    9344     // 8
#define OFF_W34    9472     // stage3/4 weights+temp (inside dead-P1 region)
#define OFF_W      23840    // stage1/2 staging region (4312 floats)
#define SMEM1_FLOATS 28152  // 112,608 bytes -> 2 CTAs/SM

__device__ float    g_score[NBOX];
__device__ float    g_box[NBOX * 4];
__device__ float    g_skey[NBOX];
__device__ int      g_sidx[NBOX];
__device__ float    g_sbox[NBOX * 4];
__device__ unsigned g_mask[NBOX * 64];

// packed dual fp32 FMA: c += a*b per lane (FFMA2)
__device__ __forceinline__ void dfma(float2& c, float2 a, float2 b) {
    asm("fma.rn.f32x2 %0, %1, %2, %0;"
        : "+l"(reinterpret_cast<unsigned long long&>(c))
        : "l"(reinterpret_cast<unsigned long long&>(a)),
          "l"(reinterpret_cast<unsigned long long&>(b)));
}
__device__ __forceinline__ float2 bcast2(float v) { return make_float2(v, v); }

__global__ __launch_bounds__(TPB, 2) void onet_cnn(
    const float* __restrict__ bboxes, const float* __restrict__ image,
    const float* __restrict__ c1w, const float* __restrict__ c1b, const float* __restrict__ p1a,
    const float* __restrict__ c2w, const float* __restrict__ c2b, const float* __restrict__ p2a,
    const float* __restrict__ c3w, const float* __restrict__ c3b, const float* __restrict__ p3a,
    const float* __restrict__ c4w, const float* __restrict__ c4b, const float* __restrict__ p4a,
    const float* __restrict__ f5w, const float* __restrict__ f5b, const float* __restrict__ p5a,
    const float* __restrict__ f6aw, const float* __restrict__ f6ab,
    const float* __restrict__ f6bw, const float* __restrict__ f6bb)
{
    extern __shared__ float sm[];
    const int t = threadIdx.x;
    const int b = blockIdx.x;

    float B0 = bboxes[b*4+0], B1 = bboxes[b*4+1], B2 = bboxes[b*4+2], B3 = bboxes[b*4+3];
    float bx1 = fmaxf(B0, 0.f), by1 = fmaxf(B1, 0.f);
    float bx2 = fminf(B2, 1024.f), by2 = fminf(B3, 1024.f);
    int ix1 = (int)bx1, iy1 = (int)by1, ix2 = (int)bx2, iy2 = (int)by2;
    int cw = max(ix2 - ix1, 1), ch = max(iy2 - iy1, 1);

    // ---- crop 48x48x3 HWC ----
    float* crop = sm + OFF_CROP;
    for (int i = t; i < 6912; i += TPB) {
        int c = i % 3; int xy = i / 3; int x = xy % 48; int y = xy / 48;
        int gx = ix1 + (x * cw) / 48;
        int gy = iy1 + (y * ch) / 48;
        crop[i] = (__ldg(&image[(gy * 1024 + gx) * 3 + c]) - 127.5f) * 0.0078125f;
    }

    // ---- conv1 weights ----
    float* w1s = sm + OFF_W; float* b1s = w1s + 864; float* a1s = w1s + 896;
    for (int i = t; i < 864; i += TPB) w1s[i] = c1w[i];
    if (t < 32) { b1s[t] = c1b[t]; a1s[t] = p1a[t]; }
    __syncthreads();

    // ===== stage 1: conv1 3x3x3->32 + prelu + pool(3,2,pad1) -> P1 [32][23][23] =====
    float* temp1 = sm + OFF_W + 928;           // 46x46
    float* P1 = sm + OFF_P1;                   // ch stride 529, row stride 23
    for (int g = 0; g < 32; ++g) {
        float wr[27];
        #pragma unroll
        for (int k = 0; k < 27; k++) wr[k] = w1s[k * 32 + g];
        float bias = b1s[g], alpha = a1s[g];
        for (int task = t; task < 552; task += TPB) {
            int xg = task % 12; int cy = task / 12;
            int x0 = xg * 4;
            float a0 = bias, a1v = bias, a2 = bias, a3 = bias;
            #pragma unroll
            for (int ky = 0; ky < 3; ky++) {
                const float* row = crop + (cy + ky) * 144;
                float in[18];
                #pragma unroll
                for (int j = 0; j < 6; j++) {
                    int col = x0 + j; if (col > 47) col = 47;
                    in[j*3+0] = row[col*3+0];
                    in[j*3+1] = row[col*3+1];
                    in[j*3+2] = row[col*3+2];
                }
                #pragma unroll
                for (int kx = 0; kx < 3; kx++)
                    #pragma unroll
                    for (int ic = 0; ic < 3; ic++) {
                        float w = wr[(ky*3+kx)*3+ic];
                        a0  += in[(kx+0)*3+ic] * w;
                        a1v += in[(kx+1)*3+ic] * w;
                        a2  += in[(kx+2)*3+ic] * w;
                        a3  += in[(kx+3)*3+ic] * w;
                    }
            }
            a0  = a0  >= 0.f ? a0  : alpha * a0;
            a1v = a1v >= 0.f ? a1v : alpha * a1v;
            a2  = a2  >= 0.f ? a2  : alpha * a2;
            a3  = a3  >= 0.f ? a3  : alpha * a3;
            float* tp = temp1 + cy * 46;
            tp[x0+0] = a0; tp[x0+1] = a1v;
            if (x0+2 < 46) tp[x0+2] = a2;
            if (x0+3 < 46) tp[x0+3] = a3;
        }
        __syncthreads();
        for (int i = t; i < 529; i += TPB) {
            int px = i % 23; int py = i / 23;
            float m = -3.4e38f;
            #pragma unroll
            for (int dy = 0; dy < 3; dy++) {
                int cy2 = 2*py - 1 + dy; if (cy2 < 0 || cy2 >= 46) continue;
                #pragma unroll
                for (int dx = 0; dx < 3; dx++) {
                    int cx2 = 2*px - 1 + dx; if (cx2 < 0 || cx2 >= 46) continue;
                    m = fmaxf(m, temp1[cy2*46 + cx2]);
                }
            }
            P1[g * 529 + py * 23 + px] = m;
        }
        __syncthreads();
    }

    // ===== stage 2: conv2 3x3x32->64 + prelu + pool(3,2) -> P2 [64][10][10] =====
    // 8 groups x 8 out-channels (4 channel-pairs), per-ky weight staging, packed FFMA2.
    // w2s layout per ky: [(kx*32+ic)*8 + c]
    float* w2s = sm + OFF_W; float* b2s = w2s + 768; float* a2s = b2s + 8;
    float* temp2 = sm + OFF_W + 784;           // 8ch x 21x21 = 3528
    float* P2 = sm + OFF_P2;
    for (int g = 0; g < 8; ++g) {
        if (t < 8) { b2s[t] = c2b[g*8 + t]; a2s[t] = p2a[g*8 + t]; }
        const int xg = t % 3; const int rem = t / 3;
        const int cp = rem & 3; const int cy = rem >> 2;
        const int x0 = xg * 7;
        float2 acc[7];
        #pragma unroll
        for (int j = 0; j < 7; j++) acc[j] = make_float2(0.f, 0.f);
        for (int ky = 0; ky < 3; ky++) {
            __syncthreads();
            for (int i = t; i < 768; i += TPB) {
                int c = i & 7; int kidx = i >> 3;   // kidx = kx*32+ic
                w2s[i] = c2w[((ky*3 + (kidx>>5))*32 + (kidx&31)) * 64 + g*8 + c];
            }
            __syncthreads();
            if (t < 252) {
                const float* inb = P1 + (cy + ky) * 23 + x0;
                const float* wb  = w2s + 2*cp;
                #pragma unroll 4
                for (int ic = 0; ic < 32; ic++) {
                    const float* in = inb + ic * 529;
                    float2 p0 = bcast2(in[0]), p1 = bcast2(in[1]), p2 = bcast2(in[2]);
                    float2 p3 = bcast2(in[3]), p4 = bcast2(in[4]), p5 = bcast2(in[5]);
                    float2 p6 = bcast2(in[6]), p7 = bcast2(in[7]), p8 = bcast2(in[8]);
                    float2 w0 = *(const float2*)&wb[(0*32+ic)*8];
                    float2 w1 = *(const float2*)&wb[(1*32+ic)*8];
                    float2 w2v = *(const float2*)&wb[(2*32+ic)*8];
                    dfma(acc[0],p0,w0); dfma(acc[1],p1,w0); dfma(acc[2],p2,w0); dfma(acc[3],p3,w0);
                    dfma(acc[4],p4,w0); dfma(acc[5],p5,w0); dfma(acc[6],p6,w0);
                    dfma(acc[0],p1,w1); dfma(acc[1],p2,w1); dfma(acc[2],p3,w1); dfma(acc[3],p4,w1);
                    dfma(acc[4],p5,w1); dfma(acc[5],p6,w1); dfma(acc[6],p7,w1);
                    dfma(acc[0],p2,w2v); dfma(acc[1],p3,w2v); dfma(acc[2],p4,w2v); dfma(acc[3],p5,w2v);
                    dfma(acc[4],p6,w2v); dfma(acc[5],p7,w2v); dfma(acc[6],p8,w2v);
                }
            }
        }
        if (t < 252) {
            float bias0 = b2s[2*cp], bias1 = b2s[2*cp+1];
            float al0 = a2s[2*cp], al1 = a2s[2*cp+1];
            float* tp0 = temp2 + (2*cp)   * 441 + cy * 21 + x0;
            float* tp1 = temp2 + (2*cp+1) * 441 + cy * 21 + x0;
            #pragma unroll
            for (int j = 0; j < 7; j++) {
                float v0 = acc[j].x + bias0;
                float v1 = acc[j].y + bias1;
                tp0[j] = v0 >= 0.f ? v0 : al0 * v0;
                tp1[j] = v1 >= 0.f ? v1 : al1 * v1;
            }
        }
        __syncthreads();
        for (int i = t; i < 800; i += TPB) {
            int c = i & 7; int pos = i >> 3; int px = pos % 10; int py = pos / 10;
            const float* tp = temp2 + c * 441;
            float m = -3.4e38f;
            #pragma unroll
            for (int dy = 0; dy < 3; dy++)
                #pragma unroll
                for (int dx = 0; dx < 3; dx++)
                    m = fmaxf(m, tp[(2*py+dy)*21 + 2*px+dx]);
            P2[(g*8 + c) * 100 + py * 10 + px] = m;
        }
        __syncthreads();
    }

    // ===== stage 3: conv3 3x3x64->64 + prelu + pool(2,2) -> P3 [64][4][4] =====
    // 4 groups x 16 out-ch (8 pairs), packed. 128 active threads.
    float* w3s = sm + OFF_W34; float* b3s = w3s + 9216; float* a3s = b3s + 16;
    float* temp3 = sm + OFF_W34 + 9248;        // 16ch x 8x8
    float* P3 = sm + OFF_P3;
    for (int g = 0; g < 4; ++g) {
        __syncthreads();
        for (int i = t; i < 9216; i += TPB) { int c = i & 15; int kidx = i >> 4; w3s[i] = c3w[kidx*64 + g*16 + c]; }
        if (t < 16) { b3s[t] = c3b[g*16 + t]; a3s[t] = p3a[g*16 + t]; }
        __syncthreads();
        if (t < 128) {
            int xg = t & 1; int cp = (t >> 1) & 7; int cy = t >> 4;
            int x0 = xg * 4;
            float2 a0 = make_float2(0.f,0.f), a1v = a0, a2 = a0, a3 = a0;
            #pragma unroll
            for (int ky = 0; ky < 3; ky++) {
                const float* inb = P2 + (cy + ky) * 10 + x0;
                const float* wb  = w3s + (ky * 3) * 1024 + 2*cp;
                #pragma unroll 4
                for (int ic = 0; ic < 64; ic++) {
                    const float* in = inb + ic * 100;
                    float2 p0 = bcast2(in[0]), p1 = bcast2(in[1]), p2 = bcast2(in[2]);
                    float2 p3 = bcast2(in[3]), p4 = bcast2(in[4]), p5 = bcast2(in[5]);
                    float2 w0 = *(const float2*)&wb[(0*64+ic)*16];
                    float2 w1 = *(const float2*)&wb[(1*64+ic)*16];
                    float2 w2v = *(const float2*)&wb[(2*64+ic)*16];
                    dfma(a0,p0,w0); dfma(a1v,p1,w0); dfma(a2,p2,w0); dfma(a3,p3,w0);
                    dfma(a0,p1,w1); dfma(a1v,p2,w1); dfma(a2,p3,w1); dfma(a3,p4,w1);
                    dfma(a0,p2,w2v); dfma(a1v,p3,w2v); dfma(a2,p4,w2v); dfma(a3,p5,w2v);
                }
            }
            float b0 = b3s[2*cp], b1 = b3s[2*cp+1];
            float al0 = a3s[2*cp], al1 = a3s[2*cp+1];
            float* tp0 = temp3 + (2*cp)   * 64 + cy * 8 + x0;
            float* tp1 = temp3 + (2*cp+1) * 64 + cy * 8 + x0;
            float v;
            v = a0.x + b0;  tp0[0] = v >= 0.f ? v : al0 * v;
            v = a1v.x + b0; tp0[1] = v >= 0.f ? v : al0 * v;
            v = a2.x + b0;  tp0[2] = v >= 0.f ? v : al0 * v;
            v = a3.x + b0;  tp0[3] = v >= 0.f ? v : al0 * v;
            v = a0.y + b1;  tp1[0] = v >= 0.f ? v : al1 * v;
            v = a1v.y + b1; tp1[1] = v >= 0.f ? v : al1 * v;
            v = a2.y + b1;  tp1[2] = v >= 0.f ? v : al1 * v;
            v = a3.y + b1;  tp1[3] = v >= 0.f ? v : al1 * v;
        }
        __syncthreads();
        for (int task = t; task < 256; task += TPB) {
            int c = task & 15; int pos = task >> 4; int px = pos & 3; int py = pos >> 2;
            const float* tp = temp3 + c * 64;
            float m = fmaxf(fmaxf(tp[(2*py)*8 + 2*px], tp[(2*py)*8 + 2*px + 1]),
                            fmaxf(tp[(2*py+1)*8 + 2*px], tp[(2*py+1)*8 + 2*px + 1]));
            P3[(g*16 + c) * 16 + py * 4 + px] = m;
        }
    }
    __syncthreads();

    // ===== stage 4: conv4 2x2x64->128 + prelu -> C4 flat (c*9 + y*3 + x) =====
    // 4 groups x 32 out-ch (16 pairs), packed. 144 active threads.
    float* w4s = sm + OFF_W34; float* b4s = w4s + 8192; float* a4s = b4s + 32;
    float* C4 = sm + OFF_C4;
    for (int g = 0; g < 4; ++g) {
        __syncthreads();
        for (int i = t; i < 8192; i += TPB) { int c = i & 31; int kidx = i >> 5; w4s[i] = c4w[kidx*128 + g*32 + c]; }
        if (t < 32) { b4s[t] = c4b[g*32 + t]; a4s[t] = p4a[g*32 + t]; }
        __syncthreads();
        if (t < 144) {
            int cp = t & 15; int pos = t >> 4; int y = pos / 3; int x = pos % 3;
            float2 acc = make_float2(0.f, 0.f);
            #pragma unroll
            for (int k = 0; k < 4; k++) {
                int ky = k >> 1, kx = k & 1;
                const float* inb = P3 + (y + ky) * 4 + (x + kx);
                const float* wb  = w4s + k * 2048 + 2*cp;
                #pragma unroll 4
                for (int ic = 0; ic < 64; ic++) {
                    float2 p = bcast2(inb[ic * 16]);
                    float2 w = *(const float2*)&wb[ic * 32];
                    dfma(acc, p, w);
                }
            }
            float v0 = acc.x + b4s[2*cp], v1 = acc.y + b4s[2*cp+1];
            float al0 = a4s[2*cp], al1 = a4s[2*cp+1];
            C4[(g*32 + 2*cp)   * 9 + pos] = v0 >= 0.f ? v0 : al0 * v0;
            C4[(g*32 + 2*cp+1) * 9 + pos] = v1 >= 0.f ? v1 : al1 * v1;
        }
    }
    __syncthreads();

    // ===== fc5: 1152 -> 256 + prelu (vectorized) =====
    float* F5 = sm + OFF_F5;
    {
        int warp = t >> 5, lane = t & 31;
        for (int o = warp; o < 256; o += 8) {
            const float4* wrow = (const float4*)(f5w + o * 1152);
            float acc = 0.f;
            #pragma unroll
            for (int j = 0; j < 9; j++) {
                float4 cv = *(const float4*)&C4[j*128 + lane*4];
                float4 wv = __ldg(&wrow[j*32 + lane]);
                acc += cv.x*wv.x + cv.y*wv.y + cv.z*wv.z + cv.w*wv.w;
            }
            #pragma unroll
            for (int s = 16; s; s >>= 1) acc += __shfl_xor_sync(0xFFFFFFFFu, acc, s);
            if (lane == 0) {
                float v = acc + f5b[o];
                float al = p5a[o];
                F5[o] = v >= 0.f ? v : al * v;
            }
        }
    }
    __syncthreads();

    // ===== fc6a (2) + fc6b (4) =====
    float* FC6 = sm + OFF_FC6;
    if (t < 192) {
        int o = t >> 5, lane = t & 31;
        const float* wrow = (o < 2) ? (f6aw + o * 256) : (f6bw + (o - 2) * 256);
        float acc = 0.f;
        #pragma unroll
        for (int j = 0; j < 8; j++) { int k = lane + 32*j; acc += F5[k] * __ldg(&wrow[k]); }
        #pragma unroll
        for (int s = 16; s; s >>= 1) acc += __shfl_xor_sync(0xFFFFFFFFu, acc, s);
        if (lane == 0) FC6[o] = acc + ((o < 2) ? f6ab[o] : f6bb[o - 2]);
    }
    __syncthreads();

    if (t == 0) {
        float l0 = FC6[0], l1 = FC6[1];
        float m = fmaxf(l0, l1);
        float e0 = expf(l0 - m), e1 = expf(l1 - m);
        float score = e1 / (e0 + e1);
        float w = bx2 - bx1, h = by2 - by1;
        g_score[b] = score;
        g_box[b*4+0] = bx1 + FC6[2] * w;
        g_box[b*4+1] = by1 + FC6[3] * h;
        g_box[b*4+2] = bx2 + FC6[4] * w;
        g_box[b*4+3] = by2 + FC6[5] * h;
    }
}

// ---------- NMS: bitonic sort by (score desc, idx asc) ----------
__device__ __forceinline__ bool nms_before(float ka, int ia, float kb, int ib) {
    return (ka > kb) || (ka == kb && ia < ib);
}

__global__ __launch_bounds__(1024) void nms_sort() {
    __shared__ float kk[NBOX];
    __shared__ int   id[NBOX];
    int t = threadIdx.x;
    kk[t] = g_score[t];           id[t] = t;
    kk[t+1024] = g_score[t+1024]; id[t+1024] = t + 1024;
    for (int k = 2; k <= NBOX; k <<= 1) {
        for (int j = k >> 1; j > 0; j >>= 1) {
            __syncthreads();
            #pragma unroll 2
            for (int i = t; i < NBOX; i += 1024) {
                int ixj = i ^ j;
                if (ixj > i) {
                    float ka = kk[i], kb = kk[ixj];
                    int ia = id[i], ib = id[ixj];
                    bool up = ((i & k) == 0);
                    bool bad = up ? nms_before(kb, ib, ka, ia) : nms_before(ka, ia, kb, ib);
                    if (bad) { kk[i] = kb; kk[ixj] = ka; id[i] = ib; id[ixj] = ia; }
                }
            }
        }
    }
    __syncthreads();
    #pragma unroll 2
    for (int i = t; i < NBOX; i += 1024) {
        g_skey[i] = kk[i];
        int o = id[i];
        g_sidx[i] = o;
        g_sbox[i*4+0] = g_box[o*4+0];
        g_sbox[i*4+1] = g_box[o*4+1];
        g_sbox[i*4+2] = g_box[o*4+2];
        g_sbox[i*4+3] = g_box[o*4+3];
    }
}

// ---------- NMS: IOU bitmask ----------
__global__ __launch_bounds__(64) void nms_mask() {
    __shared__ float cb[32][4];
    int t = threadIdx.x;
    int j0 = blockIdx.x * 32;
    for (int i = t; i < 128; i += 64) cb[i >> 2][i & 3] = g_sbox[(j0 + (i >> 2)) * 4 + (i & 3)];
    __syncthreads();
    int i = blockIdx.y * 64 + t;
    float x1 = g_sbox[i*4+0], y1 = g_sbox[i*4+1], x2 = g_sbox[i*4+2], y2 = g_sbox[i*4+3];
    float area = (x2 - x1) * (y2 - y1);
    unsigned word = 0;
    #pragma unroll 8
    for (int jj = 0; jj < 32; jj++) {
        int j = j0 + jj;
        if (j > i) {
            float bx1v = cb[jj][0], by1v = cb[jj][1], bx2v = cb[jj][2], by2v = cb[jj][3];
            float xx1 = fmaxf(x1, bx1v), yy1 = fmaxf(y1, by1v);
            float xx2 = fminf(x2, bx2v), yy2 = fminf(y2, by2v);
            float inter = fmaxf(xx2 - xx1, 0.f) * fmaxf(yy2 - yy1, 0.f);
            float areab = (bx2v - bx1v) * (by2v - by1v);
            float iou = inter / (area + areab - inter + 1e-12f);
            if (iou > 0.5f) word |= (1u << jj);
        }
    }
    g_mask[i * 64 + blockIdx.x] = word;
}

// ---------- NMS: serial scan; warps 1-7 double-buffer mask chunks into shared ----------
#define SCHUNK 88
__global__ __launch_bounds__(256) void nms_scan(float* __restrict__ out) {
    __shared__ unsigned buf[2][SCHUNK * 64];
    __shared__ unsigned keepw[64];
    __shared__ int sV;
    int t = threadIdx.x;
    if (t < 64) keepw[t] = 0u;
    if (t == 0) sV = 0;
    __syncthreads();
    for (int p = t; p < NBOX; p += 256) {
        bool v = g_skey[p] >= 0.5f;
        unsigned bal = __ballot_sync(0xFFFFFFFFu, v);
        if ((t & 31) == 0) atomicAdd(&sV, __popc(bal));
    }
    __syncthreads();
    const int V = sV;
    const int nch = (V + SCHUNK - 1) / SCHUNK;
    for (int i = t; i < SCHUNK * 64; i += 256) {
        int p = i >> 6;
        buf[0][i] = (p < V) ? g_mask[i] : 0u;
    }
    __syncthreads();
    unsigned r0 = 0u, r1 = 0u;   // warp0: lane t owns suppression words t, t+32
    for (int ci = 0; ci < nch; ci++) {
        if (t >= 32) {
            if (ci + 1 < nch) {
                unsigned* nb = buf[(ci + 1) & 1];
                int pb = (ci + 1) * SCHUNK;
                for (int i = t - 32; i < SCHUNK * 64; i += 224) {
                    int p = pb + (i >> 6);
                    nb[i] = (p < V) ? g_mask[p * 64 + (i & 63)] : 0u;
                }
            }
        } else {
            const unsigned* B = buf[ci & 1];
            int pb = ci * SCHUNK;
            int lim = min(SCHUNK, V - pb);
            for (int jb = 0; jb < lim; jb += 8) {
                unsigned qa[8], qb[8];
                #pragma unroll
                for (int j = 0; j < 8; j++) {
                    int jj = jb + j;
                    bool ok = jj < lim;
                    qa[j] = ok ? B[jj*64 + t]      : 0u;
                    qb[j] = ok ? B[jj*64 + 32 + t] : 0u;
                }
                #pragma unroll
                for (int j = 0; j < 8; j++) {
                    if (jb + j < lim) {
                        int p = pb + jb + j;
                        int w = p >> 5;
                        unsigned word = __shfl_sync(0xFFFFFFFFu, (w < 32) ? r0 : r1, w & 31);
                        if (!((word >> (p & 31)) & 1u)) {
                            r0 |= qa[j]; r1 |= qb[j];
                            if (t == 0) keepw[w] |= 1u << (p & 31);
                        }
                    }
                }
            }
        }
        __syncthreads();
    }
    for (int i = t; i < NBOX * 4; i += 256) out[i] = 0.f;
    __syncthreads();
    for (int p = t; p < NBOX; p += 256) {
        if ((keepw[p >> 5] >> (p & 31)) & 1u) {
            int o = g_sidx[p];
            out[o*4+0] = g_sbox[p*4+0];
            out[o*4+1] = g_sbox[p*4+1];
            out[o*4+2] = g_sbox[p*4+2];
            out[o*4+3] = g_sbox[p*4+3];
        }
    }
}

extern "C" void kernel_launch(void* const* d_in, const int* in_sizes, int n_in,
                              void* d_out, int out_size) {
    (void)in_sizes; (void)n_in; (void)out_size;
    cudaFuncSetAttribute(onet_cnn, cudaFuncAttributeMaxDynamicSharedMemorySize, SMEM1_FLOATS * 4);
    onet_cnn<<<NBOX, TPB, SMEM1_FLOATS * 4>>>(
        (const float*)d_in[0],  (const float*)d_in[1],
        (const float*)d_in[2],  (const float*)d_in[3],  (const float*)d_in[4],
        (const float*)d_in[5],  (const float*)d_in[6],  (const float*)d_in[7],
        (const float*)d_in[8],  (const float*)d_in[9],  (const float*)d_in[10],
        (const float*)d_in[11], (const float*)d_in[12], (const float*)d_in[13],
        (const float*)d_in[14], (const float*)d_in[15], (const float*)d_in[16],
        (const float*)d_in[17], (const float*)d_in[18],
        (const float*)d_in[19], (const float*)d_in[20]);
    nms_sort<<<1, 1024>>>();
    nms_mask<<<dim3(64, 32), 64>>>();
    nms_scan<<<1, 256>>>((float*)d_out);
}

// round 6
// speedup vs baseline: 1.7924x; 1.1188x over previous
#include <cuda_runtime.h>
#include <cuda_bf16.h>
#include <math.h>

#define NBOX 2048
#define TPB  256

// shared arena offsets (floats)
#define OFF_CROP   0        // 6912 (dead after stage1) -> P2 [64][10][10] (6400)
#define OFF_P2     0
#define OFF_P1     6912     // P1 [32][23][23] = 16928 (dead after stage2)
#define OFF_P3     6912     // 1024
#define OFF_C4     7936     // 1152
#define OFF_F5     9088     // 256
#define OFF_FC6    9344     // 8
#define OFF_W34    9472     // stage3/4 weights+temp (inside dead-P1 region)
#define OFF_W      23840    // stage1/2 staging region (4312 floats)
#define SMEM1_FLOATS 28152  // 112,608 bytes -> 2 CTAs/SM

__device__ float    g_score[NBOX];
__device__ float    g_box[NBOX * 4];
__device__ float    g_skey[NBOX];
__device__ int      g_sidx[NBOX];
__device__ float    g_sbox[NBOX * 4];
__device__ unsigned g_mask[NBOX * 64];

// packed dual fp32 FMA: c += a*b per lane (FFMA2)
__device__ __forceinline__ void dfma(float2& c, float2 a, float2 b) {
    asm("fma.rn.f32x2 %0, %1, %2, %0;"
        : "+l"(reinterpret_cast<unsigned long long&>(c))
        : "l"(reinterpret_cast<unsigned long long&>(a)),
          "l"(reinterpret_cast<unsigned long long&>(b)));
}
__device__ __forceinline__ float2 bcast2(float v) { return make_float2(v, v); }

__global__ __launch_bounds__(TPB, 2) void onet_cnn(
    const float* __restrict__ bboxes, const float* __restrict__ image,
    const float* __restrict__ c1w, const float* __restrict__ c1b, const float* __restrict__ p1a,
    const float* __restrict__ c2w, const float* __restrict__ c2b, const float* __restrict__ p2a,
    const float* __restrict__ c3w, const float* __restrict__ c3b, const float* __restrict__ p3a,
    const float* __restrict__ c4w, const float* __restrict__ c4b, const float* __restrict__ p4a,
    const float* __restrict__ f5w, const float* __restrict__ f5b, const float* __restrict__ p5a,
    const float* __restrict__ f6aw, const float* __restrict__ f6ab,
    const float* __restrict__ f6bw, const float* __restrict__ f6bb)
{
    extern __shared__ float sm[];
    const int t = threadIdx.x;
    const int b = blockIdx.x;

    float B0 = bboxes[b*4+0], B1 = bboxes[b*4+1], B2 = bboxes[b*4+2], B3 = bboxes[b*4+3];
    float bx1 = fmaxf(B0, 0.f), by1 = fmaxf(B1, 0.f);
    float bx2 = fminf(B2, 1024.f), by2 = fminf(B3, 1024.f);
    int ix1 = (int)bx1, iy1 = (int)by1, ix2 = (int)bx2, iy2 = (int)by2;
    int cw = max(ix2 - ix1, 1), ch = max(iy2 - iy1, 1);

    // ---- crop 48x48x3 HWC ----
    float* crop = sm + OFF_CROP;
    for (int i = t; i < 6912; i += TPB) {
        int c = i % 3; int xy = i / 3; int x = xy % 48; int y = xy / 48;
        int gx = ix1 + (x * cw) / 48;
        int gy = iy1 + (y * ch) / 48;
        crop[i] = (__ldg(&image[(gy * 1024 + gx) * 3 + c]) - 127.5f) * 0.0078125f;
    }
    __syncthreads();

    // ===== stage 1: conv1 3x3x3->32 + prelu + pool(3,2,pad1) -> P1 [32][23][23] =====
    // 16 groups x 2 out-channels (FFMA2 pair); weights hoisted to regs from gmem.
    // temp1: channel-interleaved float2 [46][46]
    float* temp1 = sm + OFF_W;                 // 4232 floats
    float* P1 = sm + OFF_P1;                   // ch stride 529, row stride 23
    for (int g = 0; g < 16; ++g) {
        float2 wr[27];
        #pragma unroll
        for (int k = 0; k < 27; k++) wr[k] = __ldg((const float2*)&c1w[k * 32 + 2*g]);
        float2 bias  = __ldg((const float2*)&c1b[2*g]);
        float2 alpha = __ldg((const float2*)&p1a[2*g]);
        for (int task = t; task < 552; task += TPB) {
            int xg = task % 12; int cy = task / 12;
            int x0 = xg * 4;
            float2 a0 = make_float2(0.f,0.f), a1v = a0, a2 = a0, a3 = a0;
            #pragma unroll
            for (int ky = 0; ky < 3; ky++) {
                const float* row = crop + (cy + ky) * 144;
                float in[18];
                #pragma unroll
                for (int j = 0; j < 6; j++) {
                    int col = x0 + j; if (col > 47) col = 47;
                    in[j*3+0] = row[col*3+0];
                    in[j*3+1] = row[col*3+1];
                    in[j*3+2] = row[col*3+2];
                }
                #pragma unroll
                for (int kx = 0; kx < 3; kx++)
                    #pragma unroll
                    for (int ic = 0; ic < 3; ic++) {
                        float2 w = wr[(ky*3+kx)*3+ic];
                        dfma(a0,  bcast2(in[(kx+0)*3+ic]), w);
                        dfma(a1v, bcast2(in[(kx+1)*3+ic]), w);
                        dfma(a2,  bcast2(in[(kx+2)*3+ic]), w);
                        dfma(a3,  bcast2(in[(kx+3)*3+ic]), w);
                    }
            }
            float2* tp = (float2*)temp1 + cy * 46;
            float2 o;
            o.x = a0.x + bias.x; o.y = a0.y + bias.y;
            o.x = o.x >= 0.f ? o.x : alpha.x * o.x; o.y = o.y >= 0.f ? o.y : alpha.y * o.y;
            tp[x0+0] = o;
            o.x = a1v.x + bias.x; o.y = a1v.y + bias.y;
            o.x = o.x >= 0.f ? o.x : alpha.x * o.x; o.y = o.y >= 0.f ? o.y : alpha.y * o.y;
            tp[x0+1] = o;
            if (x0+2 < 46) {
                o.x = a2.x + bias.x; o.y = a2.y + bias.y;
                o.x = o.x >= 0.f ? o.x : alpha.x * o.x; o.y = o.y >= 0.f ? o.y : alpha.y * o.y;
                tp[x0+2] = o;
            }
            if (x0+3 < 46) {
                o.x = a3.x + bias.x; o.y = a3.y + bias.y;
                o.x = o.x >= 0.f ? o.x : alpha.x * o.x; o.y = o.y >= 0.f ? o.y : alpha.y * o.y;
                tp[x0+3] = o;
            }
        }
        __syncthreads();
        for (int i = t; i < 1058; i += TPB) {
            int c = i & 1; int pos = i >> 1; int px = pos % 23; int py = pos / 23;
            float m = -3.4e38f;
            #pragma unroll
            for (int dy = 0; dy < 3; dy++) {
                int cy2 = 2*py - 1 + dy; if (cy2 < 0 || cy2 >= 46) continue;
                #pragma unroll
                for (int dx = 0; dx < 3; dx++) {
                    int cx2 = 2*px - 1 + dx; if (cx2 < 0 || cx2 >= 46) continue;
                    m = fmaxf(m, temp1[(cy2*46 + cx2)*2 + c]);
                }
            }
            P1[(g*2 + c) * 529 + py * 23 + px] = m;
        }
        __syncthreads();
    }

    // ===== stage 2: conv2 3x3x32->64 + prelu + pool(3,2) -> P2 [64][10][10] =====
    // 8 groups x 8 out-channels (4 pairs), per-ky weight staging, packed FFMA2.
    float* w2s = sm + OFF_W; float* b2s = w2s + 768; float* a2s = b2s + 8;
    float* temp2 = sm + OFF_W + 784;           // 8ch x 21x21 = 3528
    float* P2 = sm + OFF_P2;
    for (int g = 0; g < 8; ++g) {
        if (t < 8) { b2s[t] = c2b[g*8 + t]; a2s[t] = p2a[g*8 + t]; }
        const int xg = t % 3; const int rem = t / 3;
        const int cp = rem & 3; const int cy = rem >> 2;
        const int x0 = xg * 7;
        float2 acc[7];
        #pragma unroll
        for (int j = 0; j < 7; j++) acc[j] = make_float2(0.f, 0.f);
        for (int ky = 0; ky < 3; ky++) {
            __syncthreads();
            for (int i = t; i < 768; i += TPB) {
                int c = i & 7; int kidx = i >> 3;   // kidx = kx*32+ic
                w2s[i] = c2w[((ky*3 + (kidx>>5))*32 + (kidx&31)) * 64 + g*8 + c];
            }
            __syncthreads();
            if (t < 252) {
                const float* inb = P1 + (cy + ky) * 23 + x0;
                const float* wb  = w2s + 2*cp;
                #pragma unroll 4
                for (int ic = 0; ic < 32; ic++) {
                    const float* in = inb + ic * 529;
                    float2 p0 = bcast2(in[0]), p1 = bcast2(in[1]), p2 = bcast2(in[2]);
                    float2 p3 = bcast2(in[3]), p4 = bcast2(in[4]), p5 = bcast2(in[5]);
                    float2 p6 = bcast2(in[6]), p7 = bcast2(in[7]), p8 = bcast2(in[8]);
                    float2 w0 = *(const float2*)&wb[(0*32+ic)*8];
                    float2 w1 = *(const float2*)&wb[(1*32+ic)*8];
                    float2 w2v = *(const float2*)&wb[(2*32+ic)*8];
                    dfma(acc[0],p0,w0); dfma(acc[1],p1,w0); dfma(acc[2],p2,w0); dfma(acc[3],p3,w0);
                    dfma(acc[4],p4,w0); dfma(acc[5],p5,w0); dfma(acc[6],p6,w0);
                    dfma(acc[0],p1,w1); dfma(acc[1],p2,w1); dfma(acc[2],p3,w1); dfma(acc[3],p4,w1);
                    dfma(acc[4],p5,w1); dfma(acc[5],p6,w1); dfma(acc[6],p7,w1);
                    dfma(acc[0],p2,w2v); dfma(acc[1],p3,w2v); dfma(acc[2],p4,w2v); dfma(acc[3],p5,w2v);
                    dfma(acc[4],p6,w2v); dfma(acc[5],p7,w2v); dfma(acc[6],p8,w2v);
                }
            }
        }
        if (t < 252) {
            float bias0 = b2s[2*cp], bias1 = b2s[2*cp+1];
            float al0 = a2s[2*cp], al1 = a2s[2*cp+1];
            float* tp0 = temp2 + (2*cp)   * 441 + cy * 21 + x0;
            float* tp1 = temp2 + (2*cp+1) * 441 + cy * 21 + x0;
            #pragma unroll
            for (int j = 0; j < 7; j++) {
                float v0 = acc[j].x + bias0;
                float v1 = acc[j].y + bias1;
                tp0[j] = v0 >= 0.f ? v0 : al0 * v0;
                tp1[j] = v1 >= 0.f ? v1 : al1 * v1;
            }
        }
        __syncthreads();
        for (int i = t; i < 800; i += TPB) {
            int c = i & 7; int pos = i >> 3; int px = pos % 10; int py = pos / 10;
            const float* tp = temp2 + c * 441;
            float m = -3.4e38f;
            #pragma unroll
            for (int dy = 0; dy < 3; dy++)
                #pragma unroll
                for (int dx = 0; dx < 3; dx++)
                    m = fmaxf(m, tp[(2*py+dy)*21 + 2*px+dx]);
            P2[(g*8 + c) * 100 + py * 10 + px] = m;
        }
        __syncthreads();
    }

    // ===== stage 3: conv3 3x3x64->64 + prelu + pool(2,2) -> P3 [64][4][4] =====
    float* w3s = sm + OFF_W34; float* b3s = w3s + 9216; float* a3s = b3s + 16;
    float* temp3 = sm + OFF_W34 + 9248;        // 16ch x 8x8
    float* P3 = sm + OFF_P3;
    for (int g = 0; g < 4; ++g) {
        __syncthreads();
        for (int i = t; i < 9216; i += TPB) { int c = i & 15; int kidx = i >> 4; w3s[i] = c3w[kidx*64 + g*16 + c]; }
        if (t < 16) { b3s[t] = c3b[g*16 + t]; a3s[t] = p3a[g*16 + t]; }
        __syncthreads();
        if (t < 128) {
            int xg = t & 1; int cp = (t >> 1) & 7; int cy = t >> 4;
            int x0 = xg * 4;
            float2 a0 = make_float2(0.f,0.f), a1v = a0, a2 = a0, a3 = a0;
            #pragma unroll
            for (int ky = 0; ky < 3; ky++) {
                const float* inb = P2 + (cy + ky) * 10 + x0;
                const float* wb  = w3s + (ky * 3) * 1024 + 2*cp;
                #pragma unroll 4
                for (int ic = 0; ic < 64; ic++) {
                    const float* in = inb + ic * 100;
                    float2 p0 = bcast2(in[0]), p1 = bcast2(in[1]), p2 = bcast2(in[2]);
                    float2 p3 = bcast2(in[3]), p4 = bcast2(in[4]), p5 = bcast2(in[5]);
                    float2 w0 = *(const float2*)&wb[(0*64+ic)*16];
                    float2 w1 = *(const float2*)&wb[(1*64+ic)*16];
                    float2 w2v = *(const float2*)&wb[(2*64+ic)*16];
                    dfma(a0,p0,w0); dfma(a1v,p1,w0); dfma(a2,p2,w0); dfma(a3,p3,w0);
                    dfma(a0,p1,w1); dfma(a1v,p2,w1); dfma(a2,p3,w1); dfma(a3,p4,w1);
                    dfma(a0,p2,w2v); dfma(a1v,p3,w2v); dfma(a2,p4,w2v); dfma(a3,p5,w2v);
                }
            }
            float b0 = b3s[2*cp], b1 = b3s[2*cp+1];
            float al0 = a3s[2*cp], al1 = a3s[2*cp+1];
            float* tp0 = temp3 + (2*cp)   * 64 + cy * 8 + x0;
            float* tp1 = temp3 + (2*cp+1) * 64 + cy * 8 + x0;
            float v;
            v = a0.x + b0;  tp0[0] = v >= 0.f ? v : al0 * v;
            v = a1v.x + b0; tp0[1] = v >= 0.f ? v : al0 * v;
            v = a2.x + b0;  tp0[2] = v >= 0.f ? v : al0 * v;
            v = a3.x + b0;  tp0[3] = v >= 0.f ? v : al0 * v;
            v = a0.y + b1;  tp1[0] = v >= 0.f ? v : al1 * v;
            v = a1v.y + b1; tp1[1] = v >= 0.f ? v : al1 * v;
            v = a2.y + b1;  tp1[2] = v >= 0.f ? v : al1 * v;
            v = a3.y + b1;  tp1[3] = v >= 0.f ? v : al1 * v;
        }
        __syncthreads();
        for (int task = t; task < 256; task += TPB) {
            int c = task & 15; int pos = task >> 4; int px = pos & 3; int py = pos >> 2;
            const float* tp = temp3 + c * 64;
            float m = fmaxf(fmaxf(tp[(2*py)*8 + 2*px], tp[(2*py)*8 + 2*px + 1]),
                            fmaxf(tp[(2*py+1)*8 + 2*px], tp[(2*py+1)*8 + 2*px + 1]));
            P3[(g*16 + c) * 16 + py * 4 + px] = m;
        }
    }
    __syncthreads();

    // ===== stage 4: conv4 2x2x64->128 + prelu -> C4 flat (c*9 + y*3 + x) =====
    float* w4s = sm + OFF_W34; float* b4s = w4s + 8192; float* a4s = b4s + 32;
    float* C4 = sm + OFF_C4;
    for (int g = 0; g < 4; ++g) {
        __syncthreads();
        for (int i = t; i < 8192; i += TPB) { int c = i & 31; int kidx = i >> 5; w4s[i] = c4w[kidx*128 + g*32 + c]; }
        if (t < 32) { b4s[t] = c4b[g*32 + t]; a4s[t] = p4a[g*32 + t]; }
        __syncthreads();
        if (t < 144) {
            int cp = t & 15; int pos = t >> 4; int y = pos / 3; int x = pos % 3;
            float2 acc = make_float2(0.f, 0.f);
            #pragma unroll
            for (int k = 0; k < 4; k++) {
                int ky = k >> 1, kx = k & 1;
                const float* inb = P3 + (y + ky) * 4 + (x + kx);
                const float* wb  = w4s + k * 2048 + 2*cp;
                #pragma unroll 4
                for (int ic = 0; ic < 64; ic++) {
                    float2 p = bcast2(inb[ic * 16]);
                    float2 w = *(const float2*)&wb[ic * 32];
                    dfma(acc, p, w);
                }
            }
            float v0 = acc.x + b4s[2*cp], v1 = acc.y + b4s[2*cp+1];
            float al0 = a4s[2*cp], al1 = a4s[2*cp+1];
            C4[(g*32 + 2*cp)   * 9 + pos] = v0 >= 0.f ? v0 : al0 * v0;
            C4[(g*32 + 2*cp+1) * 9 + pos] = v1 >= 0.f ? v1 : al1 * v1;
        }
    }
    __syncthreads();

    // ===== fc5: 1152 -> 256 + prelu (vectorized) =====
    float* F5 = sm + OFF_F5;
    {
        int warp = t >> 5, lane = t & 31;
        for (int o = warp; o < 256; o += 8) {
            const float4* wrow = (const float4*)(f5w + o * 1152);
            float acc = 0.f;
            #pragma unroll
            for (int j = 0; j < 9; j++) {
                float4 cv = *(const float4*)&C4[j*128 + lane*4];
                float4 wv = __ldg(&wrow[j*32 + lane]);
                acc += cv.x*wv.x + cv.y*wv.y + cv.z*wv.z + cv.w*wv.w;
            }
            #pragma unroll
            for (int s = 16; s; s >>= 1) acc += __shfl_xor_sync(0xFFFFFFFFu, acc, s);
            if (lane == 0) {
                float v = acc + f5b[o];
                float al = p5a[o];
                F5[o] = v >= 0.f ? v : al * v;
            }
        }
    }
    __syncthreads();

    // ===== fc6a (2) + fc6b (4) =====
    float* FC6 = sm + OFF_FC6;
    if (t < 192) {
        int o = t >> 5, lane = t & 31;
        const float* wrow = (o < 2) ? (f6aw + o * 256) : (f6bw + (o - 2) * 256);
        float acc = 0.f;
        #pragma unroll
        for (int j = 0; j < 8; j++) { int k = lane + 32*j; acc += F5[k] * __ldg(&wrow[k]); }
        #pragma unroll
        for (int s = 16; s; s >>= 1) acc += __shfl_xor_sync(0xFFFFFFFFu, acc, s);
        if (lane == 0) FC6[o] = acc + ((o < 2) ? f6ab[o] : f6bb[o - 2]);
    }
    __syncthreads();

    if (t == 0) {
        float l0 = FC6[0], l1 = FC6[1];
        float m = fmaxf(l0, l1);
        float e0 = expf(l0 - m), e1 = expf(l1 - m);
        float score = e1 / (e0 + e1);
        float w = bx2 - bx1, h = by2 - by1;
        g_score[b] = score;
        g_box[b*4+0] = bx1 + FC6[2] * w;
        g_box[b*4+1] = by1 + FC6[3] * h;
        g_box[b*4+2] = bx2 + FC6[4] * w;
        g_box[b*4+3] = by2 + FC6[5] * h;
    }
}

// ---------- NMS: bitonic sort by (score desc, idx asc) ----------
__device__ __forceinline__ bool nms_before(float ka, int ia, float kb, int ib) {
    return (ka > kb) || (ka == kb && ia < ib);
}

__global__ __launch_bounds__(1024) void nms_sort() {
    __shared__ float kk[NBOX];
    __shared__ int   id[NBOX];
    int t = threadIdx.x;
    kk[t] = g_score[t];           id[t] = t;
    kk[t+1024] = g_score[t+1024]; id[t+1024] = t + 1024;
    for (int k = 2; k <= NBOX; k <<= 1) {
        for (int j = k >> 1; j > 0; j >>= 1) {
            __syncthreads();
            #pragma unroll 2
            for (int i = t; i < NBOX; i += 1024) {
                int ixj = i ^ j;
                if (ixj > i) {
                    float ka = kk[i], kb = kk[ixj];
                    int ia = id[i], ib = id[ixj];
                    bool up = ((i & k) == 0);
                    bool bad = up ? nms_before(kb, ib, ka, ia) : nms_before(ka, ia, kb, ib);
                    if (bad) { kk[i] = kb; kk[ixj] = ka; id[i] = ib; id[ixj] = ia; }
                }
            }
        }
    }
    __syncthreads();
    #pragma unroll 2
    for (int i = t; i < NBOX; i += 1024) {
        g_skey[i] = kk[i];
        int o = id[i];
        g_sidx[i] = o;
        g_sbox[i*4+0] = g_box[o*4+0];
        g_sbox[i*4+1] = g_box[o*4+1];
        g_sbox[i*4+2] = g_box[o*4+2];
        g_sbox[i*4+3] = g_box[o*4+3];
    }
}

// ---------- NMS: IOU bitmask ----------
__global__ __launch_bounds__(64) void nms_mask() {
    __shared__ float cb[32][4];
    int t = threadIdx.x;
    int j0 = blockIdx.x * 32;
    for (int i = t; i < 128; i += 64) cb[i >> 2][i & 3] = g_sbox[(j0 + (i >> 2)) * 4 + (i & 3)];
    __syncthreads();
    int i = blockIdx.y * 64 + t;
    float x1 = g_sbox[i*4+0], y1 = g_sbox[i*4+1], x2 = g_sbox[i*4+2], y2 = g_sbox[i*4+3];
    float area = (x2 - x1) * (y2 - y1);
    unsigned word = 0;
    #pragma unroll 8
    for (int jj = 0; jj < 32; jj++) {
        int j = j0 + jj;
        if (j > i) {
            float bx1v = cb[jj][0], by1v = cb[jj][1], bx2v = cb[jj][2], by2v = cb[jj][3];
            float xx1 = fmaxf(x1, bx1v), yy1 = fmaxf(y1, by1v);
            float xx2 = fminf(x2, bx2v), yy2 = fminf(y2, by2v);
            float inter = fmaxf(xx2 - xx1, 0.f) * fmaxf(yy2 - yy1, 0.f);
            float areab = (bx2v - bx1v) * (by2v - by1v);
            float iou = inter / (area + areab - inter + 1e-12f);
            if (iou > 0.5f) word |= (1u << jj);
        }
    }
    g_mask[i * 64 + blockIdx.x] = word;
}

// ---------- NMS: serial scan; register decision word, branchless chain ----------
#define SCHUNK 64   // 2 runs of 32 per chunk; smem buf = 32 KB
__global__ __launch_bounds__(256) void nms_scan(float* __restrict__ out) {
    __shared__ unsigned buf[2][SCHUNK * 64];
    __shared__ unsigned keepw[64];
    __shared__ int sV;
    int t = threadIdx.x;
    if (t < 64) keepw[t] = 0u;
    if (t == 0) sV = 0;
    __syncthreads();
    for (int p = t; p < NBOX; p += 256) {
        bool v = g_skey[p] >= 0.5f;
        unsigned bal = __ballot_sync(0xFFFFFFFFu, v);
        if ((t & 31) == 0) atomicAdd(&sV, __popc(bal));
    }
    __syncthreads();
    const int V = sV;
    const int nch = (V + SCHUNK - 1) / SCHUNK;
    for (int i = t; i < SCHUNK * 64; i += 256) {
        int p = i >> 6;
        buf[0][i] = (p < V) ? g_mask[i] : 0u;
    }
    __syncthreads();
    unsigned r0 = 0u, r1 = 0u;   // warp0: lane t owns suppression words t, t+32
    for (int ci = 0; ci < nch; ci++) {
        if (t >= 32) {
            if (ci + 1 < nch) {
                unsigned* nb = buf[(ci + 1) & 1];
                int pb = (ci + 1) * SCHUNK;
                for (int i = t - 32; i < SCHUNK * 64; i += 224) {
                    int p = pb + (i >> 6);
                    nb[i] = (p < V) ? g_mask[p * 64 + (i & 63)] : 0u;
                }
            }
        } else {
            const unsigned* B = buf[ci & 1];
            int pb = ci * SCHUNK;
            #pragma unroll
            for (int r = 0; r < 2; r++) {
                int rb = pb + r * 32;
                if (rb >= V) break;
                int w = rb >> 5;                 // global word index (0..63)
                int lim = min(32, V - rb);
                unsigned dw = (w < 32) ? __shfl_sync(0xFFFFFFFFu, r0, w)
                                       : __shfl_sync(0xFFFFFFFFu, r1, w - 32);
                for (int jb = 0; jb < lim; jb += 8) {
                    unsigned qa[8], qb[8], qw[8];
                    #pragma unroll
                    for (int j = 0; j < 8; j++) {
                        int jj = r * 32 + jb + j;
                        bool ok = (jb + j) < lim;
                        qa[j] = ok ? B[jj*64 + t]      : 0u;
                        qb[j] = ok ? B[jj*64 + 32 + t] : 0u;
                        qw[j] = ok ? B[jj*64 + w]      : 0u;
                    }
                    #pragma unroll
                    for (int j = 0; j < 8; j++) {
                        int bb = jb + j;
                        unsigned m = ((dw >> bb) & 1u) - 1u;  // keep -> 0xFFFFFFFF
                        dw |= qw[j] & m;
                        r0 |= qa[j] & m;
                        r1 |= qb[j] & m;
                    }
                }
                if (t == 0) {
                    unsigned vmask = (lim >= 32) ? 0xFFFFFFFFu : ((1u << lim) - 1u);
                    keepw[w] = (~dw) & vmask;
                }
            }
        }
        __syncthreads();
    }
    for (int i = t; i < NBOX * 4; i += 256) out[i] = 0.f;
    __syncthreads();
    for (int p = t; p < NBOX; p += 256) {
        if ((keepw[p >> 5] >> (p & 31)) & 1u) {
            int o = g_sidx[p];
            out[o*4+0] = g_sbox[p*4+0];
            out[o*4+1] = g_sbox[p*4+1];
            out[o*4+2] = g_sbox[p*4+2];
            out[o*4+3] = g_sbox[p*4+3];
        }
    }
}

extern "C" void kernel_launch(void* const* d_in, const int* in_sizes, int n_in,
                              void* d_out, int out_size) {
    (void)in_sizes; (void)n_in; (void)out_size;
    cudaFuncSetAttribute(onet_cnn, cudaFuncAttributeMaxDynamicSharedMemorySize, SMEM1_FLOATS * 4);
    onet_cnn<<<NBOX, TPB, SMEM1_FLOATS * 4>>>(
        (const float*)d_in[0],  (const float*)d_in[1],
        (const float*)d_in[2],  (const float*)d_in[3],  (const float*)d_in[4],
        (const float*)d_in[5],  (const float*)d_in[6],  (const float*)d_in[7],
        (const float*)d_in[8],  (const float*)d_in[9],  (const float*)d_in[10],
        (const float*)d_in[11], (const float*)d_in[12], (const float*)d_in[13],
        (const float*)d_in[14], (const float*)d_in[15], (const float*)d_in[16],
        (const float*)d_in[17], (const float*)d_in[18],
        (const float*)d_in[19], (const float*)d_in[20]);
    nms_sort<<<1, 1024>>>();
    nms_mask<<<dim3(64, 32), 64>>>();
    nms_scan<<<1, 256>>>((float*)d_out);
}

// round 8
// speedup vs baseline: 1.8372x; 1.0250x over previous
#include <cuda_runtime.h>
#include <cuda_bf16.h>
#include <math.h>

#define NBOX 2048
#define TPB  256

// shared arena offsets (floats)
#define OFF_CROP   0        // 6912 (dead after stage1) -> P2 [64][10][10] (6400)
#define OFF_P2     0
#define OFF_P1     6912     // P1 [32][23][23] = 16928 (dead after stage2)
#define OFF_P3     6912     // 1024
#define OFF_C4     7936     // 1152
#define OFF_F5     9088     // 256
#define OFF_FC6    9344     // 8
#define OFF_W34    9472     // stage3/4 weights+temp (inside dead-P1 region, 14368 avail)
#define OFF_W      23840    // stage1/2 staging region (4312 floats)
#define SMEM1_FLOATS 28152  // 112,608 bytes -> 2 CTAs/SM

__device__ float    g_score[NBOX];
__device__ float    g_box[NBOX * 4];
__device__ float    g_skey[NBOX];
__device__ int      g_sidx[NBOX];
__device__ float    g_sbox[NBOX * 4];
__device__ uint4    g_mask4[NBOX * 16];   // NBOX rows x 64 words (16B-aligned)

// packed dual fp32 FMA: c += a*b per lane (FFMA2)
__device__ __forceinline__ void dfma(float2& c, float2 a, float2 b) {
    asm("fma.rn.f32x2 %0, %1, %2, %0;"
        : "+l"(reinterpret_cast<unsigned long long&>(c))
        : "l"(reinterpret_cast<unsigned long long&>(a)),
          "l"(reinterpret_cast<unsigned long long&>(b)));
}
__device__ __forceinline__ float2 bcast2(float v) { return make_float2(v, v); }

__global__ __launch_bounds__(TPB, 2) void onet_cnn(
    const float* __restrict__ bboxes, const float* __restrict__ image,
    const float* __restrict__ c1w, const float* __restrict__ c1b, const float* __restrict__ p1a,
    const float* __restrict__ c2w, const float* __restrict__ c2b, const float* __restrict__ p2a,
    const float* __restrict__ c3w, const float* __restrict__ c3b, const float* __restrict__ p3a,
    const float* __restrict__ c4w, const float* __restrict__ c4b, const float* __restrict__ p4a,
    const float* __restrict__ f5w, const float* __restrict__ f5b, const float* __restrict__ p5a,
    const float* __restrict__ f6aw, const float* __restrict__ f6ab,
    const float* __restrict__ f6bw, const float* __restrict__ f6bb)
{
    extern __shared__ float sm[];
    const int t = threadIdx.x;
    const int b = blockIdx.x;

    float B0 = bboxes[b*4+0], B1 = bboxes[b*4+1], B2 = bboxes[b*4+2], B3 = bboxes[b*4+3];
    float bx1 = fmaxf(B0, 0.f), by1 = fmaxf(B1, 0.f);
    float bx2 = fminf(B2, 1024.f), by2 = fminf(B3, 1024.f);
    int ix1 = (int)bx1, iy1 = (int)by1, ix2 = (int)bx2, iy2 = (int)by2;
    int cw = max(ix2 - ix1, 1), ch = max(iy2 - iy1, 1);

    // ---- crop 48x48x3 HWC ----
    float* crop = sm + OFF_CROP;
    for (int i = t; i < 6912; i += TPB) {
        int c = i % 3; int xy = i / 3; int x = xy % 48; int y = xy / 48;
        int gx = ix1 + (x * cw) / 48;
        int gy = iy1 + (y * ch) / 48;
        crop[i] = (__ldg(&image[(gy * 1024 + gx) * 3 + c]) - 127.5f) * 0.0078125f;
    }
    __syncthreads();

    // ===== stage 1: conv1 3x3x3->32 + prelu + pool(3,2,pad1) -> P1 [32][23][23] =====
    float* temp1 = sm + OFF_W;                 // 4232 floats (float2-interleaved 46x46)
    float* P1 = sm + OFF_P1;                   // ch stride 529, row stride 23
    for (int g = 0; g < 16; ++g) {
        float2 wr[27];
        #pragma unroll
        for (int k = 0; k < 27; k++) wr[k] = __ldg((const float2*)&c1w[k * 32 + 2*g]);
        float2 bias  = __ldg((const float2*)&c1b[2*g]);
        float2 alpha = __ldg((const float2*)&p1a[2*g]);
        for (int task = t; task < 552; task += TPB) {
            int xg = task % 12; int cy = task / 12;
            int x0 = xg * 4;
            float2 a0 = make_float2(0.f,0.f), a1v = a0, a2 = a0, a3 = a0;
            #pragma unroll
            for (int ky = 0; ky < 3; ky++) {
                const float* row = crop + (cy + ky) * 144;
                float in[18];
                #pragma unroll
                for (int j = 0; j < 6; j++) {
                    int col = x0 + j; if (col > 47) col = 47;
                    in[j*3+0] = row[col*3+0];
                    in[j*3+1] = row[col*3+1];
                    in[j*3+2] = row[col*3+2];
                }
                #pragma unroll
                for (int kx = 0; kx < 3; kx++)
                    #pragma unroll
                    for (int ic = 0; ic < 3; ic++) {
                        float2 w = wr[(ky*3+kx)*3+ic];
                        dfma(a0,  bcast2(in[(kx+0)*3+ic]), w);
                        dfma(a1v, bcast2(in[(kx+1)*3+ic]), w);
                        dfma(a2,  bcast2(in[(kx+2)*3+ic]), w);
                        dfma(a3,  bcast2(in[(kx+3)*3+ic]), w);
                    }
            }
            float2* tp = (float2*)temp1 + cy * 46;
            float2 o;
            o.x = a0.x + bias.x; o.y = a0.y + bias.y;
            o.x = o.x >= 0.f ? o.x : alpha.x * o.x; o.y = o.y >= 0.f ? o.y : alpha.y * o.y;
            tp[x0+0] = o;
            o.x = a1v.x + bias.x; o.y = a1v.y + bias.y;
            o.x = o.x >= 0.f ? o.x : alpha.x * o.x; o.y = o.y >= 0.f ? o.y : alpha.y * o.y;
            tp[x0+1] = o;
            if (x0+2 < 46) {
                o.x = a2.x + bias.x; o.y = a2.y + bias.y;
                o.x = o.x >= 0.f ? o.x : alpha.x * o.x; o.y = o.y >= 0.f ? o.y : alpha.y * o.y;
                tp[x0+2] = o;
            }
            if (x0+3 < 46) {
                o.x = a3.x + bias.x; o.y = a3.y + bias.y;
                o.x = o.x >= 0.f ? o.x : alpha.x * o.x; o.y = o.y >= 0.f ? o.y : alpha.y * o.y;
                tp[x0+3] = o;
            }
        }
        __syncthreads();
        for (int i = t; i < 1058; i += TPB) {
            int c = i & 1; int pos = i >> 1; int px = pos % 23; int py = pos / 23;
            float m = -3.4e38f;
            #pragma unroll
            for (int dy = 0; dy < 3; dy++) {
                int cy2 = 2*py - 1 + dy; if (cy2 < 0 || cy2 >= 46) continue;
                #pragma unroll
                for (int dx = 0; dx < 3; dx++) {
                    int cx2 = 2*px - 1 + dx; if (cx2 < 0 || cx2 >= 46) continue;
                    m = fmaxf(m, temp1[(cy2*46 + cx2)*2 + c]);
                }
            }
            P1[(g*2 + c) * 529 + py * 23 + px] = m;
        }
        __syncthreads();
    }

    // ===== stage 2: conv2 3x3x32->64 + prelu + pool(3,2) -> P2 [64][10][10] =====
    float* w2s = sm + OFF_W; float* b2s = w2s + 768; float* a2s = b2s + 8;
    float* temp2 = sm + OFF_W + 784;           // 8ch x 21x21 = 3528
    float* P2 = sm + OFF_P2;
    for (int g = 0; g < 8; ++g) {
        if (t < 8) { b2s[t] = c2b[g*8 + t]; a2s[t] = p2a[g*8 + t]; }
        const int xg = t % 3; const int rem = t / 3;
        const int cp = rem & 3; const int cy = rem >> 2;
        const int x0 = xg * 7;
        float2 acc[7];
        #pragma unroll
        for (int j = 0; j < 7; j++) acc[j] = make_float2(0.f, 0.f);
        for (int ky = 0; ky < 3; ky++) {
            __syncthreads();
            for (int i = t; i < 768; i += TPB) {
                int c = i & 7; int kidx = i >> 3;   // kidx = kx*32+ic
                w2s[i] = c2w[((ky*3 + (kidx>>5))*32 + (kidx&31)) * 64 + g*8 + c];
            }
            __syncthreads();
            if (t < 252) {
                const float* inb = P1 + (cy + ky) * 23 + x0;
                const float* wb  = w2s + 2*cp;
                #pragma unroll 4
                for (int ic = 0; ic < 32; ic++) {
                    const float* in = inb + ic * 529;
                    float2 p0 = bcast2(in[0]), p1 = bcast2(in[1]), p2 = bcast2(in[2]);
                    float2 p3 = bcast2(in[3]), p4 = bcast2(in[4]), p5 = bcast2(in[5]);
                    float2 p6 = bcast2(in[6]), p7 = bcast2(in[7]), p8 = bcast2(in[8]);
                    float2 w0 = *(const float2*)&wb[(0*32+ic)*8];
                    float2 w1 = *(const float2*)&wb[(1*32+ic)*8];
                    float2 w2v = *(const float2*)&wb[(2*32+ic)*8];
                    dfma(acc[0],p0,w0); dfma(acc[1],p1,w0); dfma(acc[2],p2,w0); dfma(acc[3],p3,w0);
                    dfma(acc[4],p4,w0); dfma(acc[5],p5,w0); dfma(acc[6],p6,w0);
                    dfma(acc[0],p1,w1); dfma(acc[1],p2,w1); dfma(acc[2],p3,w1); dfma(acc[3],p4,w1);
                    dfma(acc[4],p5,w1); dfma(acc[5],p6,w1); dfma(acc[6],p7,w1);
                    dfma(acc[0],p2,w2v); dfma(acc[1],p3,w2v); dfma(acc[2],p4,w2v); dfma(acc[3],p5,w2v);
                    dfma(acc[4],p6,w2v); dfma(acc[5],p7,w2v); dfma(acc[6],p8,w2v);
                }
            }
        }
        if (t < 252) {
            float bias0 = b2s[2*cp], bias1 = b2s[2*cp+1];
            float al0 = a2s[2*cp], al1 = a2s[2*cp+1];
            float* tp0 = temp2 + (2*cp)   * 441 + cy * 21 + x0;
            float* tp1 = temp2 + (2*cp+1) * 441 + cy * 21 + x0;
            #pragma unroll
            for (int j = 0; j < 7; j++) {
                float v0 = acc[j].x + bias0;
                float v1 = acc[j].y + bias1;
                tp0[j] = v0 >= 0.f ? v0 : al0 * v0;
                tp1[j] = v1 >= 0.f ? v1 : al1 * v1;
            }
        }
        __syncthreads();
        for (int i = t; i < 800; i += TPB) {
            int c = i & 7; int pos = i >> 3; int px = pos % 10; int py = pos / 10;
            const float* tp = temp2 + c * 441;
            float m = -3.4e38f;
            #pragma unroll
            for (int dy = 0; dy < 3; dy++)
                #pragma unroll
                for (int dx = 0; dx < 3; dx++)
                    m = fmaxf(m, tp[(2*py+dy)*21 + 2*px+dx]);
            P2[(g*8 + c) * 100 + py * 10 + px] = m;
        }
        __syncthreads();
    }

    // ===== stage 3: conv3 3x3x64->64 + prelu + pool(2,2) -> P3 [64][4][4] =====
    // 2 groups x 32 out-ch (16 pairs), per-ky weight staging, 256 active threads.
    float* w3s = sm + OFF_W34; float* b3s = w3s + 6144; float* a3s = b3s + 32;
    float* temp3 = sm + OFF_W34 + 6208;        // 32ch x 8x8 = 2048
    float* P3 = sm + OFF_P3;
    for (int g = 0; g < 2; ++g) {
        if (t < 32) { b3s[t] = c3b[g*32 + t]; a3s[t] = p3a[g*32 + t]; }
        const int pr = t & 15; const int pos = t >> 4;
        const int xg = pos & 1; const int cy = pos >> 1;
        const int x0 = xg * 4;
        float2 a0 = make_float2(0.f,0.f), a1v = a0, a2 = a0, a3 = a0;
        for (int ky = 0; ky < 3; ky++) {
            __syncthreads();
            for (int i = t; i < 6144; i += TPB) {
                int c = i & 31; int kidx = i >> 5;   // kidx = kx*64+ic
                w3s[i] = c3w[((ky*3 + (kidx>>6))*64 + (kidx&63)) * 64 + g*32 + c];
            }
            __syncthreads();
            const float* inb = P2 + (cy + ky) * 10 + x0;
            const float* wb  = w3s + 2*pr;
            #pragma unroll 4
            for (int ic = 0; ic < 64; ic++) {
                const float* in = inb + ic * 100;
                float2 p0 = bcast2(in[0]), p1 = bcast2(in[1]), p2 = bcast2(in[2]);
                float2 p3 = bcast2(in[3]), p4 = bcast2(in[4]), p5 = bcast2(in[5]);
                float2 w0 = *(const float2*)&wb[(0*64+ic)*32];
                float2 w1 = *(const float2*)&wb[(1*64+ic)*32];
                float2 w2v = *(const float2*)&wb[(2*64+ic)*32];
                dfma(a0,p0,w0); dfma(a1v,p1,w0); dfma(a2,p2,w0); dfma(a3,p3,w0);
                dfma(a0,p1,w1); dfma(a1v,p2,w1); dfma(a2,p3,w1); dfma(a3,p4,w1);
                dfma(a0,p2,w2v); dfma(a1v,p3,w2v); dfma(a2,p4,w2v); dfma(a3,p5,w2v);
            }
        }
        {
            float b0 = b3s[2*pr], b1 = b3s[2*pr+1];
            float al0 = a3s[2*pr], al1 = a3s[2*pr+1];
            float* tp0 = temp3 + (2*pr)   * 64 + cy * 8 + x0;
            float* tp1 = temp3 + (2*pr+1) * 64 + cy * 8 + x0;
            float v;
            v = a0.x + b0;  tp0[0] = v >= 0.f ? v : al0 * v;
            v = a1v.x + b0; tp0[1] = v >= 0.f ? v : al0 * v;
            v = a2.x + b0;  tp0[2] = v >= 0.f ? v : al0 * v;
            v = a3.x + b0;  tp0[3] = v >= 0.f ? v : al0 * v;
            v = a0.y + b1;  tp1[0] = v >= 0.f ? v : al1 * v;
            v = a1v.y + b1; tp1[1] = v >= 0.f ? v : al1 * v;
            v = a2.y + b1;  tp1[2] = v >= 0.f ? v : al1 * v;
            v = a3.y + b1;  tp1[3] = v >= 0.f ? v : al1 * v;
        }
        __syncthreads();
        for (int task = t; task < 512; task += TPB) {
            int c = task & 31; int pos2 = task >> 5; int px = pos2 & 3; int py = pos2 >> 2;
            const float* tp = temp3 + c * 64;
            float m = fmaxf(fmaxf(tp[(2*py)*8 + 2*px], tp[(2*py)*8 + 2*px + 1]),
                            fmaxf(tp[(2*py+1)*8 + 2*px], tp[(2*py+1)*8 + 2*px + 1]));
            P3[(g*32 + c) * 16 + py * 4 + px] = m;
        }
        __syncthreads();
    }

    // ===== stage 4: conv4 2x2x64->128 + prelu -> C4 flat (c*9 + y*3 + x) =====
    // 2 groups x 64 out-ch; per-k staging; thread does 4 channels (2 pairs). 144 active.
    float* w4s = sm + OFF_W34; float* b4s = w4s + 4096; float* a4s = b4s + 64;
    float* C4 = sm + OFF_C4;
    for (int g = 0; g < 2; ++g) {
        if (t < 64) { b4s[t] = c4b[g*64 + t]; a4s[t] = p4a[g*64 + t]; }
        const int cq = t & 15; const int pos = t >> 4;   // t<144: pos 0..8
        const int y = pos / 3, x = pos % 3;
        float2 accA = make_float2(0.f,0.f), accB = accA;
        for (int k = 0; k < 4; k++) {
            __syncthreads();
            for (int i = t; i < 4096; i += TPB) {
                int c = i & 63; int ic = i >> 6;
                w4s[i] = c4w[(k*64 + ic)*128 + g*64 + c];
            }
            __syncthreads();
            if (t < 144) {
                int ky = k >> 1, kx = k & 1;
                const float* inb = P3 + (y + ky) * 4 + (x + kx);
                const float* wb  = w4s + 4*cq;
                #pragma unroll 4
                for (int ic = 0; ic < 64; ic++) {
                    float2 p = bcast2(inb[ic * 16]);
                    float2 wA = *(const float2*)&wb[ic * 64];
                    float2 wB = *(const float2*)&wb[ic * 64 + 2];
                    dfma(accA, p, wA); dfma(accB, p, wB);
                }
            }
        }
        if (t < 144) {
            int c0 = g*64 + 4*cq;
            float v0 = accA.x + b4s[4*cq+0], v1 = accA.y + b4s[4*cq+1];
            float v2 = accB.x + b4s[4*cq+2], v3 = accB.y + b4s[4*cq+3];
            float l0 = a4s[4*cq+0], l1 = a4s[4*cq+1], l2 = a4s[4*cq+2], l3 = a4s[4*cq+3];
            C4[(c0+0)*9 + pos] = v0 >= 0.f ? v0 : l0 * v0;
            C4[(c0+1)*9 + pos] = v1 >= 0.f ? v1 : l1 * v1;
            C4[(c0+2)*9 + pos] = v2 >= 0.f ? v2 : l2 * v2;
            C4[(c0+3)*9 + pos] = v3 >= 0.f ? v3 : l3 * v3;
        }
        __syncthreads();   // protect b4s/a4s from next group's overwrite (R6 race fix)
    }

    // ===== fc5: 1152 -> 256 + prelu (vectorized) =====
    float* F5 = sm + OFF_F5;
    {
        int warp = t >> 5, lane = t & 31;
        for (int o = warp; o < 256; o += 8) {
            const float4* wrow = (const float4*)(f5w + o * 1152);
            float acc = 0.f;
            #pragma unroll
            for (int j = 0; j < 9; j++) {
                float4 cv = *(const float4*)&C4[j*128 + lane*4];
                float4 wv = __ldg(&wrow[j*32 + lane]);
                acc += cv.x*wv.x + cv.y*wv.y + cv.z*wv.z + cv.w*wv.w;
            }
            #pragma unroll
            for (int s = 16; s; s >>= 1) acc += __shfl_xor_sync(0xFFFFFFFFu, acc, s);
            if (lane == 0) {
                float v = acc + f5b[o];
                float al = p5a[o];
                F5[o] = v >= 0.f ? v : al * v;
            }
        }
    }
    __syncthreads();

    // ===== fc6a (2) + fc6b (4) =====
    float* FC6 = sm + OFF_FC6;
    if (t < 192) {
        int o = t >> 5, lane = t & 31;
        const float* wrow = (o < 2) ? (f6aw + o * 256) : (f6bw + (o - 2) * 256);
        float acc = 0.f;
        #pragma unroll
        for (int j = 0; j < 8; j++) { int k = lane + 32*j; acc += F5[k] * __ldg(&wrow[k]); }
        #pragma unroll
        for (int s = 16; s; s >>= 1) acc += __shfl_xor_sync(0xFFFFFFFFu, acc, s);
        if (lane == 0) FC6[o] = acc + ((o < 2) ? f6ab[o] : f6bb[o - 2]);
    }
    __syncthreads();

    if (t == 0) {
        float l0 = FC6[0], l1 = FC6[1];
        float m = fmaxf(l0, l1);
        float e0 = expf(l0 - m), e1 = expf(l1 - m);
        float score = e1 / (e0 + e1);
        float w = bx2 - bx1, h = by2 - by1;
        g_score[b] = score;
        g_box[b*4+0] = bx1 + FC6[2] * w;
        g_box[b*4+1] = by1 + FC6[3] * h;
        g_box[b*4+2] = bx2 + FC6[4] * w;
        g_box[b*4+3] = by2 + FC6[5] * h;
    }
}

// ---------- NMS: bitonic sort by (score desc, idx asc) ----------
__device__ __forceinline__ bool nms_before(float ka, int ia, float kb, int ib) {
    return (ka > kb) || (ka == kb && ia < ib);
}

__global__ __launch_bounds__(1024) void nms_sort() {
    __shared__ float kk[NBOX];
    __shared__ int   id[NBOX];
    int t = threadIdx.x;
    kk[t] = g_score[t];           id[t] = t;
    kk[t+1024] = g_score[t+1024]; id[t+1024] = t + 1024;
    for (int k = 2; k <= NBOX; k <<= 1) {
        for (int j = k >> 1; j > 0; j >>= 1) {
            __syncthreads();
            #pragma unroll 2
            for (int i = t; i < NBOX; i += 1024) {
                int ixj = i ^ j;
                if (ixj > i) {
                    float ka = kk[i], kb = kk[ixj];
                    int ia = id[i], ib = id[ixj];
                    bool up = ((i & k) == 0);
                    bool bad = up ? nms_before(kb, ib, ka, ia) : nms_before(ka, ia, kb, ib);
                    if (bad) { kk[i] = kb; kk[ixj] = ka; id[i] = ib; id[ixj] = ia; }
                }
            }
        }
    }
    __syncthreads();
    #pragma unroll 2
    for (int i = t; i < NBOX; i += 1024) {
        g_skey[i] = kk[i];
        int o = id[i];
        g_sidx[i] = o;
        g_sbox[i*4+0] = g_box[o*4+0];
        g_sbox[i*4+1] = g_box[o*4+1];
        g_sbox[i*4+2] = g_box[o*4+2];
        g_sbox[i*4+3] = g_box[o*4+3];
    }
}

// ---------- NMS: IOU bitmask ----------
__global__ __launch_bounds__(64) void nms_mask() {
    __shared__ float cb[32][4];
    int t = threadIdx.x;
    int j0 = blockIdx.x * 32;
    for (int i = t; i < 128; i += 64) cb[i >> 2][i & 3] = g_sbox[(j0 + (i >> 2)) * 4 + (i & 3)];
    __syncthreads();
    int i = blockIdx.y * 64 + t;
    float x1 = g_sbox[i*4+0], y1 = g_sbox[i*4+1], x2 = g_sbox[i*4+2], y2 = g_sbox[i*4+3];
    float area = (x2 - x1) * (y2 - y1);
    unsigned word = 0;
    #pragma unroll 8
    for (int jj = 0; jj < 32; jj++) {
        int j = j0 + jj;
        if (j > i) {
            float bx1v = cb[jj][0], by1v = cb[jj][1], bx2v = cb[jj][2], by2v = cb[jj][3];
            float xx1 = fmaxf(x1, bx1v), yy1 = fmaxf(y1, by1v);
            float xx2 = fminf(x2, bx2v), yy2 = fminf(y2, by2v);
            float inter = fmaxf(xx2 - xx1, 0.f) * fmaxf(yy2 - yy1, 0.f);
            float areab = (bx2v - bx1v) * (by2v - by1v);
            float iou = inter / (area + areab - inter + 1e-12f);
            if (iou > 0.5f) word |= (1u << jj);
        }
    }
    ((unsigned*)g_mask4)[i * 64 + blockIdx.x] = word;
}

// ---------- NMS: serial scan; uint4 streaming producers + register decision word ----------
#define SCHUNK 64           // boxes per chunk; 64*16 uint4 = 4 KB words -> buf 32 KB
#define SNT    512
__global__ __launch_bounds__(SNT) void nms_scan(float* __restrict__ out) {
    __shared__ uint4 buf4[2][SCHUNK * 16];
    __shared__ unsigned keepw[64];
    __shared__ int sV;
    int t = threadIdx.x;
    if (t < 64) keepw[t] = 0u;
    if (t == 0) sV = 0;
    __syncthreads();
    for (int p = t; p < NBOX; p += SNT) {
        bool v = g_skey[p] >= 0.5f;
        unsigned bal = __ballot_sync(0xFFFFFFFFu, v);
        if ((t & 31) == 0) atomicAdd(&sV, __popc(bal));
    }
    __syncthreads();
    const int V = sV;
    const int nch = (V + SCHUNK - 1) / SCHUNK;
    const uint4 z4 = make_uint4(0u,0u,0u,0u);
    for (int i = t; i < SCHUNK * 16; i += SNT) {
        int p = i >> 4;
        buf4[0][i] = (p < V) ? g_mask4[i] : z4;
    }
    __syncthreads();
    unsigned r0 = 0u, r1 = 0u;   // warp0: lane t owns suppression words t, t+32
    for (int ci = 0; ci < nch; ci++) {
        if (t >= 32) {
            if (ci + 1 < nch) {
                uint4* nb = buf4[(ci + 1) & 1];
                int pb = (ci + 1) * SCHUNK;
                for (int i = t - 32; i < SCHUNK * 16; i += (SNT - 32)) {
                    int p = pb + (i >> 4);
                    nb[i] = (p < V) ? g_mask4[p * 16 + (i & 15)] : z4;
                }
            }
        } else {
            const unsigned* B = (const unsigned*)buf4[ci & 1];
            int pb = ci * SCHUNK;
            #pragma unroll
            for (int r = 0; r < 2; r++) {
                int rb = pb + r * 32;
                if (rb >= V) break;
                int w = rb >> 5;                 // global word index (0..63)
                int lim = min(32, V - rb);
                unsigned dw = (w < 32) ? __shfl_sync(0xFFFFFFFFu, r0, w)
                                       : __shfl_sync(0xFFFFFFFFu, r1, w - 32);
                for (int jb = 0; jb < lim; jb += 8) {
                    unsigned qa[8], qb[8], qw[8];
                    #pragma unroll
                    for (int j = 0; j < 8; j++) {
                        int jj = r * 32 + jb + j;
                        bool ok = (jb + j) < lim;
                        qa[j] = ok ? B[jj*64 + t]      : 0u;
                        qb[j] = ok ? B[jj*64 + 32 + t] : 0u;
                        qw[j] = ok ? B[jj*64 + w]      : 0u;
                    }
                    #pragma unroll
                    for (int j = 0; j < 8; j++) {
                        int bb = jb + j;
                        unsigned m = ((dw >> bb) & 1u) - 1u;  // keep -> 0xFFFFFFFF
                        dw |= qw[j] & m;
                        r0 |= qa[j] & m;
                        r1 |= qb[j] & m;
                    }
                }
                if (t == 0) {
                    unsigned vmask = (lim >= 32) ? 0xFFFFFFFFu : ((1u << lim) - 1u);
                    keepw[w] = (~dw) & vmask;
                }
            }
        }
        __syncthreads();
    }
    for (int i = t; i < NBOX * 4; i += SNT) out[i] = 0.f;
    __syncthreads();
    for (int p = t; p < NBOX; p += SNT) {
        if ((keepw[p >> 5] >> (p & 31)) & 1u) {
            int o = g_sidx[p];
            out[o*4+0] = g_sbox[p*4+0];
            out[o*4+1] = g_sbox[p*4+1];
            out[o*4+2] = g_sbox[p*4+2];
            out[o*4+3] = g_sbox[p*4+3];
        }
    }
}

extern "C" void kernel_launch(void* const* d_in, const int* in_sizes, int n_in,
                              void* d_out, int out_size) {
    (void)in_sizes; (void)n_in; (void)out_size;
    cudaFuncSetAttribute(onet_cnn, cudaFuncAttributeMaxDynamicSharedMemorySize, SMEM1_FLOATS * 4);
    onet_cnn<<<NBOX, TPB, SMEM1_FLOATS * 4>>>(
        (const float*)d_in[0],  (const float*)d_in[1],
        (const float*)d_in[2],  (const float*)d_in[3],  (const float*)d_in[4],
        (const float*)d_in[5],  (const float*)d_in[6],  (const float*)d_in[7],
        (const float*)d_in[8],  (const float*)d_in[9],  (const float*)d_in[10],
        (const float*)d_in[11], (const float*)d_in[12], (const float*)d_in[13],
        (const float*)d_in[14], (const float*)d_in[15], (const float*)d_in[16],
        (const float*)d_in[17], (const float*)d_in[18],
        (const float*)d_in[19], (const float*)d_in[20]);
    nms_sort<<<1, 1024>>>();
    nms_mask<<<dim3(64, 32), 64>>>();
    nms_scan<<<1, SNT>>>((float*)d_out);
}

// round 9
// speedup vs baseline: 2.1552x; 1.1731x over previous
#include <cuda_runtime.h>
#include <cuda_bf16.h>
#include <math.h>

#define NBOX 2048
#define TPB  256

// shared arena offsets (floats)
#define OFF_CROP   0        // 6912 (dead after stage1) -> P2 [64][10][10] (6400)
#define OFF_P2     0
#define OFF_GAP    6400     // 512-float gap (conv2 biases)
#define OFF_P1     6912     // P1 [32][23][23] = 16928 (dead after stage2)
#define OFF_P3     6912     // 1024
#define OFF_C4     7936     // 1152
#define OFF_F5     9088     // 256
#define OFF_FC6    9344     // 8
#define OFF_W34    9472     // stage3/4 weights+temp (inside dead-P1 region, 14368 avail)
#define OFF_W      23840    // stage1/2 staging region (4312 floats)
#define SMEM1_FLOATS 28152  // 112,608 bytes -> 2 CTAs/SM

__device__ float    g_score[NBOX];
__device__ float    g_box[NBOX * 4];
__device__ float    g_skey[NBOX];
__device__ int      g_sidx[NBOX];
__device__ float    g_sbox[NBOX * 4];
__device__ uint4    g_mask4[NBOX * 16];   // NBOX rows x 64 words (16B-aligned)

// packed dual fp32 FMA: c += a*b per lane (FFMA2)
__device__ __forceinline__ void dfma(float2& c, float2 a, float2 b) {
    asm("fma.rn.f32x2 %0, %1, %2, %0;"
        : "+l"(reinterpret_cast<unsigned long long&>(c))
        : "l"(reinterpret_cast<unsigned long long&>(a)),
          "l"(reinterpret_cast<unsigned long long&>(b)));
}
__device__ __forceinline__ float2 bcast2(float v) { return make_float2(v, v); }

__global__ __launch_bounds__(TPB, 2) void onet_cnn(
    const float* __restrict__ bboxes, const float* __restrict__ image,
    const float* __restrict__ c1w, const float* __restrict__ c1b, const float* __restrict__ p1a,
    const float* __restrict__ c2w, const float* __restrict__ c2b, const float* __restrict__ p2a,
    const float* __restrict__ c3w, const float* __restrict__ c3b, const float* __restrict__ p3a,
    const float* __restrict__ c4w, const float* __restrict__ c4b, const float* __restrict__ p4a,
    const float* __restrict__ f5w, const float* __restrict__ f5b, const float* __restrict__ p5a,
    const float* __restrict__ f6aw, const float* __restrict__ f6ab,
    const float* __restrict__ f6bw, const float* __restrict__ f6bb)
{
    extern __shared__ float sm[];
    const int t = threadIdx.x;
    const int b = blockIdx.x;

    float B0 = bboxes[b*4+0], B1 = bboxes[b*4+1], B2 = bboxes[b*4+2], B3 = bboxes[b*4+3];
    float bx1 = fmaxf(B0, 0.f), by1 = fmaxf(B1, 0.f);
    float bx2 = fminf(B2, 1024.f), by2 = fminf(B3, 1024.f);
    int ix1 = (int)bx1, iy1 = (int)by1, ix2 = (int)bx2, iy2 = (int)by2;
    int cw = max(ix2 - ix1, 1), ch = max(iy2 - iy1, 1);

    // ---- crop 48x48x3 HWC ----
    float* crop = sm + OFF_CROP;
    for (int i = t; i < 6912; i += TPB) {
        int c = i % 3; int xy = i / 3; int x = xy % 48; int y = xy / 48;
        int gx = ix1 + (x * cw) / 48;
        int gy = iy1 + (y * ch) / 48;
        crop[i] = (__ldg(&image[(gy * 1024 + gx) * 3 + c]) - 127.5f) * 0.0078125f;
    }
    __syncthreads();

    // ===== stage 1: conv1 3x3x3->32 + prelu + pool(3,2,pad1) -> P1 [32][23][23] =====
    float* temp1 = sm + OFF_W;                 // 4232 floats (float2-interleaved 46x46)
    float* P1 = sm + OFF_P1;                   // ch stride 529, row stride 23
    for (int g = 0; g < 16; ++g) {
        float2 wr[27];
        #pragma unroll
        for (int k = 0; k < 27; k++) wr[k] = __ldg((const float2*)&c1w[k * 32 + 2*g]);
        float2 bias  = __ldg((const float2*)&c1b[2*g]);
        float2 alpha = __ldg((const float2*)&p1a[2*g]);
        for (int task = t; task < 552; task += TPB) {
            int xg = task % 12; int cy = task / 12;
            int x0 = xg * 4;
            float2 a0 = make_float2(0.f,0.f), a1v = a0, a2 = a0, a3 = a0;
            #pragma unroll
            for (int ky = 0; ky < 3; ky++) {
                const float* row = crop + (cy + ky) * 144;
                float in[18];
                #pragma unroll
                for (int j = 0; j < 6; j++) {
                    int col = x0 + j; if (col > 47) col = 47;
                    in[j*3+0] = row[col*3+0];
                    in[j*3+1] = row[col*3+1];
                    in[j*3+2] = row[col*3+2];
                }
                #pragma unroll
                for (int kx = 0; kx < 3; kx++)
                    #pragma unroll
                    for (int ic = 0; ic < 3; ic++) {
                        float2 w = wr[(ky*3+kx)*3+ic];
                        dfma(a0,  bcast2(in[(kx+0)*3+ic]), w);
                        dfma(a1v, bcast2(in[(kx+1)*3+ic]), w);
                        dfma(a2,  bcast2(in[(kx+2)*3+ic]), w);
                        dfma(a3,  bcast2(in[(kx+3)*3+ic]), w);
                    }
            }
            float2* tp = (float2*)temp1 + cy * 46;
            float2 o;
            o.x = a0.x + bias.x; o.y = a0.y + bias.y;
            o.x = o.x >= 0.f ? o.x : alpha.x * o.x; o.y = o.y >= 0.f ? o.y : alpha.y * o.y;
            tp[x0+0] = o;
            o.x = a1v.x + bias.x; o.y = a1v.y + bias.y;
            o.x = o.x >= 0.f ? o.x : alpha.x * o.x; o.y = o.y >= 0.f ? o.y : alpha.y * o.y;
            tp[x0+1] = o;
            if (x0+2 < 46) {
                o.x = a2.x + bias.x; o.y = a2.y + bias.y;
                o.x = o.x >= 0.f ? o.x : alpha.x * o.x; o.y = o.y >= 0.f ? o.y : alpha.y * o.y;
                tp[x0+2] = o;
            }
            if (x0+3 < 46) {
                o.x = a3.x + bias.x; o.y = a3.y + bias.y;
                o.x = o.x >= 0.f ? o.x : alpha.x * o.x; o.y = o.y >= 0.f ? o.y : alpha.y * o.y;
                tp[x0+3] = o;
            }
        }
        __syncthreads();
        for (int i = t; i < 1058; i += TPB) {
            int c = i & 1; int pos = i >> 1; int px = pos % 23; int py = pos / 23;
            float m = -3.4e38f;
            #pragma unroll
            for (int dy = 0; dy < 3; dy++) {
                int cy2 = 2*py - 1 + dy; if (cy2 < 0 || cy2 >= 46) continue;
                #pragma unroll
                for (int dx = 0; dx < 3; dx++) {
                    int cx2 = 2*px - 1 + dx; if (cx2 < 0 || cx2 >= 46) continue;
                    m = fmaxf(m, temp1[(cy2*46 + cx2)*2 + c]);
                }
            }
            P1[(g*2 + c) * 529 + py * 23 + px] = m;
        }
        __syncthreads();
    }

    // ===== stage 2: conv2 3x3x32->64 + prelu + pool(3,2) -> P2 [64][10][10] =====
    // 4 groups x 16 out-channels; thread owns a channel QUAD (2 FFMA2 pairs) x 7 x.
    // Weight staging per (ky, ic-half): w2s[(kx*16+icl)*16 + c], 768 floats.
    float* w2s = sm + OFF_W;
    float* temp2 = sm + OFF_W + 768;           // 8ch x 21x21 = 3528 (written in 2 halves)
    float* b2s = sm + OFF_GAP; float* a2s = b2s + 16;  // 32 floats in gap
    float* P2 = sm + OFF_P2;
    for (int g = 0; g < 4; ++g) {
        if (t < 16) { b2s[t] = c2b[g*16 + t]; a2s[t] = p2a[g*16 + t]; }
        const int xg = t % 3; const int rem = t / 3;       // t<252: rem 0..83
        const int cq = rem & 3; const int cy = rem >> 2;   // quad 0..3, cy 0..20
        const int x0 = xg * 7;
        float2 acc[2][7];
        #pragma unroll
        for (int p = 0; p < 2; p++)
            #pragma unroll
            for (int j = 0; j < 7; j++) acc[p][j] = make_float2(0.f, 0.f);
        for (int ky = 0; ky < 3; ky++) {
            for (int ih = 0; ih < 2; ih++) {
                __syncthreads();
                for (int i = t; i < 768; i += TPB) {
                    int c = i & 15; int rest = i >> 4;
                    int icl = rest & 15; int kx = rest >> 4;
                    w2s[i] = c2w[((ky*3 + kx)*32 + ih*16 + icl) * 64 + g*16 + c];
                }
                __syncthreads();
                if (t < 252) {
                    const float* inb = P1 + (ih*16)*529 + (cy + ky) * 23 + x0;
                    const float* wb  = w2s + 4*cq;
                    #pragma unroll 4
                    for (int icl = 0; icl < 16; icl++) {
                        const float* in = inb + icl * 529;
                        float2 p0 = bcast2(in[0]), p1 = bcast2(in[1]), p2 = bcast2(in[2]);
                        float2 p3 = bcast2(in[3]), p4 = bcast2(in[4]), p5 = bcast2(in[5]);
                        float2 p6 = bcast2(in[6]), p7 = bcast2(in[7]), p8 = bcast2(in[8]);
                        float2 wA0 = *(const float2*)&wb[(0*16+icl)*16];
                        float2 wB0 = *(const float2*)&wb[(0*16+icl)*16 + 2];
                        float2 wA1 = *(const float2*)&wb[(1*16+icl)*16];
                        float2 wB1 = *(const float2*)&wb[(1*16+icl)*16 + 2];
                        float2 wA2 = *(const float2*)&wb[(2*16+icl)*16];
                        float2 wB2 = *(const float2*)&wb[(2*16+icl)*16 + 2];
                        dfma(acc[0][0],p0,wA0); dfma(acc[0][1],p1,wA0); dfma(acc[0][2],p2,wA0);
                        dfma(acc[0][3],p3,wA0); dfma(acc[0][4],p4,wA0); dfma(acc[0][5],p5,wA0); dfma(acc[0][6],p6,wA0);
                        dfma(acc[1][0],p0,wB0); dfma(acc[1][1],p1,wB0); dfma(acc[1][2],p2,wB0);
                        dfma(acc[1][3],p3,wB0); dfma(acc[1][4],p4,wB0); dfma(acc[1][5],p5,wB0); dfma(acc[1][6],p6,wB0);
                        dfma(acc[0][0],p1,wA1); dfma(acc[0][1],p2,wA1); dfma(acc[0][2],p3,wA1);
                        dfma(acc[0][3],p4,wA1); dfma(acc[0][4],p5,wA1); dfma(acc[0][5],p6,wA1); dfma(acc[0][6],p7,wA1);
                        dfma(acc[1][0],p1,wB1); dfma(acc[1][1],p2,wB1); dfma(acc[1][2],p3,wB1);
                        dfma(acc[1][3],p4,wB1); dfma(acc[1][4],p5,wB1); dfma(acc[1][5],p6,wB1); dfma(acc[1][6],p7,wB1);
                        dfma(acc[0][0],p2,wA2); dfma(acc[0][1],p3,wA2); dfma(acc[0][2],p4,wA2);
                        dfma(acc[0][3],p5,wA2); dfma(acc[0][4],p6,wA2); dfma(acc[0][5],p7,wA2); dfma(acc[0][6],p8,wA2);
                        dfma(acc[1][0],p2,wB2); dfma(acc[1][1],p3,wB2); dfma(acc[1][2],p4,wB2);
                        dfma(acc[1][3],p5,wB2); dfma(acc[1][4],p6,wB2); dfma(acc[1][5],p7,wB2); dfma(acc[1][6],p8,wB2);
                    }
                }
            }
        }
        // bias + prelu in regs
        float vb[4], va[4];
        if (t < 252) {
            #pragma unroll
            for (int k = 0; k < 4; k++) { vb[k] = b2s[4*cq + k]; va[k] = a2s[4*cq + k]; }
        }
        // half 0: quads 0,1 (local channels 0..7)
        if (t < 252 && cq < 2) {
            #pragma unroll
            for (int p = 0; p < 2; p++) {
                float* t0 = temp2 + (4*cq + 2*p)     * 441 + cy * 21 + x0;
                float* t1 = temp2 + (4*cq + 2*p + 1) * 441 + cy * 21 + x0;
                #pragma unroll
                for (int j = 0; j < 7; j++) {
                    float v0 = acc[p][j].x + vb[2*p];
                    float v1 = acc[p][j].y + vb[2*p+1];
                    t0[j] = v0 >= 0.f ? v0 : va[2*p] * v0;
                    t1[j] = v1 >= 0.f ? v1 : va[2*p+1] * v1;
                }
            }
        }
        __syncthreads();
        for (int i = t; i < 800; i += TPB) {
            int c = i & 7; int pos = i >> 3; int px = pos % 10; int py = pos / 10;
            const float* tp = temp2 + c * 441;
            float m = -3.4e38f;
            #pragma unroll
            for (int dy = 0; dy < 3; dy++)
                #pragma unroll
                for (int dx = 0; dx < 3; dx++)
                    m = fmaxf(m, tp[(2*py+dy)*21 + 2*px+dx]);
            P2[(g*16 + c) * 100 + py * 10 + px] = m;
        }
        __syncthreads();
        // half 1: quads 2,3 (local channels 8..15)
        if (t < 252 && cq >= 2) {
            #pragma unroll
            for (int p = 0; p < 2; p++) {
                float* t0 = temp2 + (4*(cq-2) + 2*p)     * 441 + cy * 21 + x0;
                float* t1 = temp2 + (4*(cq-2) + 2*p + 1) * 441 + cy * 21 + x0;
                #pragma unroll
                for (int j = 0; j < 7; j++) {
                    float v0 = acc[p][j].x + vb[2*p];
                    float v1 = acc[p][j].y + vb[2*p+1];
                    t0[j] = v0 >= 0.f ? v0 : va[2*p] * v0;
                    t1[j] = v1 >= 0.f ? v1 : va[2*p+1] * v1;
                }
            }
        }
        __syncthreads();
        for (int i = t; i < 800; i += TPB) {
            int c = i & 7; int pos = i >> 3; int px = pos % 10; int py = pos / 10;
            const float* tp = temp2 + c * 441;
            float m = -3.4e38f;
            #pragma unroll
            for (int dy = 0; dy < 3; dy++)
                #pragma unroll
                for (int dx = 0; dx < 3; dx++)
                    m = fmaxf(m, tp[(2*py+dy)*21 + 2*px+dx]);
            P2[(g*16 + 8 + c) * 100 + py * 10 + px] = m;
        }
        __syncthreads();
    }

    // ===== stage 3: conv3 3x3x64->64 + prelu + pool(2,2) -> P3 [64][4][4] =====
    // 2 groups x 32 out-ch; thread owns channel QUAD x 4 x. 128 active threads.
    float* w3s = sm + OFF_W34; float* b3s = w3s + 6144; float* a3s = b3s + 32;
    float* temp3 = sm + OFF_W34 + 6208;        // 32ch x 8x8 = 2048
    float* P3 = sm + OFF_P3;
    for (int g = 0; g < 2; ++g) {
        if (t < 32) { b3s[t] = c3b[g*32 + t]; a3s[t] = p3a[g*32 + t]; }
        const int cq = t & 7; const int pos = t >> 3;   // t<128: pos 0..15
        const int xg = pos & 1; const int cy = pos >> 1;
        const int x0 = xg * 4;
        float2 acc[2][4];
        #pragma unroll
        for (int p = 0; p < 2; p++)
            #pragma unroll
            for (int j = 0; j < 4; j++) acc[p][j] = make_float2(0.f, 0.f);
        for (int ky = 0; ky < 3; ky++) {
            __syncthreads();
            for (int i = t; i < 6144; i += TPB) {
                int c = i & 31; int kidx = i >> 5;   // kidx = kx*64+ic
                w3s[i] = c3w[((ky*3 + (kidx>>6))*64 + (kidx&63)) * 64 + g*32 + c];
            }
            __syncthreads();
            if (t < 128) {
                const float* inb = P2 + (cy + ky) * 10 + x0;
                const float* wb  = w3s + 4*cq;
                #pragma unroll 4
                for (int ic = 0; ic < 64; ic++) {
                    const float* in = inb + ic * 100;
                    float2 p0 = bcast2(in[0]), p1 = bcast2(in[1]), p2 = bcast2(in[2]);
                    float2 p3 = bcast2(in[3]), p4 = bcast2(in[4]), p5 = bcast2(in[5]);
                    float2 wA0 = *(const float2*)&wb[(0*64+ic)*32];
                    float2 wB0 = *(const float2*)&wb[(0*64+ic)*32 + 2];
                    float2 wA1 = *(const float2*)&wb[(1*64+ic)*32];
                    float2 wB1 = *(const float2*)&wb[(1*64+ic)*32 + 2];
                    float2 wA2 = *(const float2*)&wb[(2*64+ic)*32];
                    float2 wB2 = *(const float2*)&wb[(2*64+ic)*32 + 2];
                    dfma(acc[0][0],p0,wA0); dfma(acc[0][1],p1,wA0); dfma(acc[0][2],p2,wA0); dfma(acc[0][3],p3,wA0);
                    dfma(acc[1][0],p0,wB0); dfma(acc[1][1],p1,wB0); dfma(acc[1][2],p2,wB0); dfma(acc[1][3],p3,wB0);
                    dfma(acc[0][0],p1,wA1); dfma(acc[0][1],p2,wA1); dfma(acc[0][2],p3,wA1); dfma(acc[0][3],p4,wA1);
                    dfma(acc[1][0],p1,wB1); dfma(acc[1][1],p2,wB1); dfma(acc[1][2],p3,wB1); dfma(acc[1][3],p4,wB1);
                    dfma(acc[0][0],p2,wA2); dfma(acc[0][1],p3,wA2); dfma(acc[0][2],p4,wA2); dfma(acc[0][3],p5,wA2);
                    dfma(acc[1][0],p2,wB2); dfma(acc[1][1],p3,wB2); dfma(acc[1][2],p4,wB2); dfma(acc[1][3],p5,wB2);
                }
            }
        }
        if (t < 128) {
            #pragma unroll
            for (int p = 0; p < 2; p++) {
                float b0 = b3s[4*cq + 2*p],  b1 = b3s[4*cq + 2*p + 1];
                float l0 = a3s[4*cq + 2*p],  l1 = a3s[4*cq + 2*p + 1];
                float* t0 = temp3 + (4*cq + 2*p)     * 64 + cy * 8 + x0;
                float* t1 = temp3 + (4*cq + 2*p + 1) * 64 + cy * 8 + x0;
                #pragma unroll
                for (int j = 0; j < 4; j++) {
                    float v0 = acc[p][j].x + b0;
                    float v1 = acc[p][j].y + b1;
                    t0[j] = v0 >= 0.f ? v0 : l0 * v0;
                    t1[j] = v1 >= 0.f ? v1 : l1 * v1;
                }
            }
        }
        __syncthreads();
        for (int task = t; task < 512; task += TPB) {
            int c = task & 31; int pos2 = task >> 5; int px = pos2 & 3; int py = pos2 >> 2;
            const float* tp = temp3 + c * 64;
            float m = fmaxf(fmaxf(tp[(2*py)*8 + 2*px], tp[(2*py)*8 + 2*px + 1]),
                            fmaxf(tp[(2*py+1)*8 + 2*px], tp[(2*py+1)*8 + 2*px + 1]));
            P3[(g*32 + c) * 16 + py * 4 + px] = m;
        }
        __syncthreads();
    }

    // ===== stage 4: conv4 2x2x64->128 + prelu -> C4 flat (c*9 + y*3 + x) =====
    float* w4s = sm + OFF_W34; float* b4s = w4s + 4096; float* a4s = b4s + 64;
    float* C4 = sm + OFF_C4;
    for (int g = 0; g < 2; ++g) {
        if (t < 64) { b4s[t] = c4b[g*64 + t]; a4s[t] = p4a[g*64 + t]; }
        const int cq = t & 15; const int pos = t >> 4;   // t<144: pos 0..8
        const int y = pos / 3, x = pos % 3;
        float2 accA = make_float2(0.f,0.f), accB = accA;
        for (int k = 0; k < 4; k++) {
            __syncthreads();
            for (int i = t; i < 4096; i += TPB) {
                int c = i & 63; int ic = i >> 6;
                w4s[i] = c4w[(k*64 + ic)*128 + g*64 + c];
            }
            __syncthreads();
            if (t < 144) {
                int ky = k >> 1, kx = k & 1;
                const float* inb = P3 + (y + ky) * 4 + (x + kx);
                const float* wb  = w4s + 4*cq;
                #pragma unroll 4
                for (int ic = 0; ic < 64; ic++) {
                    float2 p = bcast2(inb[ic * 16]);
                    float2 wA = *(const float2*)&wb[ic * 64];
                    float2 wB = *(const float2*)&wb[ic * 64 + 2];
                    dfma(accA, p, wA); dfma(accB, p, wB);
                }
            }
        }
        if (t < 144) {
            int c0 = g*64 + 4*cq;
            float v0 = accA.x + b4s[4*cq+0], v1 = accA.y + b4s[4*cq+1];
            float v2 = accB.x + b4s[4*cq+2], v3 = accB.y + b4s[4*cq+3];
            float l0 = a4s[4*cq+0], l1 = a4s[4*cq+1], l2 = a4s[4*cq+2], l3 = a4s[4*cq+3];
            C4[(c0+0)*9 + pos] = v0 >= 0.f ? v0 : l0 * v0;
            C4[(c0+1)*9 + pos] = v1 >= 0.f ? v1 : l1 * v1;
            C4[(c0+2)*9 + pos] = v2 >= 0.f ? v2 : l2 * v2;
            C4[(c0+3)*9 + pos] = v3 >= 0.f ? v3 : l3 * v3;
        }
        __syncthreads();   // protect b4s/a4s from next group's overwrite
    }

    // ===== fc5: 1152 -> 256 + prelu (vectorized) =====
    float* F5 = sm + OFF_F5;
    {
        int warp = t >> 5, lane = t & 31;
        for (int o = warp; o < 256; o += 8) {
            const float4* wrow = (const float4*)(f5w + o * 1152);
            float acc = 0.f;
            #pragma unroll
            for (int j = 0; j < 9; j++) {
                float4 cv = *(const float4*)&C4[j*128 + lane*4];
                float4 wv = __ldg(&wrow[j*32 + lane]);
                acc += cv.x*wv.x + cv.y*wv.y + cv.z*wv.z + cv.w*wv.w;
            }
            #pragma unroll
            for (int s = 16; s; s >>= 1) acc += __shfl_xor_sync(0xFFFFFFFFu, acc, s);
            if (lane == 0) {
                float v = acc + f5b[o];
                float al = p5a[o];
                F5[o] = v >= 0.f ? v : al * v;
            }
        }
    }
    __syncthreads();

    // ===== fc6a (2) + fc6b (4) =====
    float* FC6 = sm + OFF_FC6;
    if (t < 192) {
        int o = t >> 5, lane = t & 31;
        const float* wrow = (o < 2) ? (f6aw + o * 256) : (f6bw + (o - 2) * 256);
        float acc = 0.f;
        #pragma unroll
        for (int j = 0; j < 8; j++) { int k = lane + 32*j; acc += F5[k] * __ldg(&wrow[k]); }
        #pragma unroll
        for (int s = 16; s; s >>= 1) acc += __shfl_xor_sync(0xFFFFFFFFu, acc, s);
        if (lane == 0) FC6[o] = acc + ((o < 2) ? f6ab[o] : f6bb[o - 2]);
    }
    __syncthreads();

    if (t == 0) {
        float l0 = FC6[0], l1 = FC6[1];
        float m = fmaxf(l0, l1);
        float e0 = expf(l0 - m), e1 = expf(l1 - m);
        float score = e1 / (e0 + e1);
        float w = bx2 - bx1, h = by2 - by1;
        g_score[b] = score;
        g_box[b*4+0] = bx1 + FC6[2] * w;
        g_box[b*4+1] = by1 + FC6[3] * h;
        g_box[b*4+2] = bx2 + FC6[4] * w;
        g_box[b*4+3] = by2 + FC6[5] * h;
    }
}

// ---------- NMS: bitonic sort by (score desc, idx asc) ----------
__device__ __forceinline__ bool nms_before(float ka, int ia, float kb, int ib) {
    return (ka > kb) || (ka == kb && ia < ib);
}

__global__ __launch_bounds__(1024) void nms_sort() {
    __shared__ float kk[NBOX];
    __shared__ int   id[NBOX];
    int t = threadIdx.x;
    kk[t] = g_score[t];           id[t] = t;
    kk[t+1024] = g_score[t+1024]; id[t+1024] = t + 1024;
    for (int k = 2; k <= NBOX; k <<= 1) {
        for (int j = k >> 1; j > 0; j >>= 1) {
            __syncthreads();
            #pragma unroll 2
            for (int i = t; i < NBOX; i += 1024) {
                int ixj = i ^ j;
                if (ixj > i) {
                    float ka = kk[i], kb = kk[ixj];
                    int ia = id[i], ib = id[ixj];
                    bool up = ((i & k) == 0);
                    bool bad = up ? nms_before(kb, ib, ka, ia) : nms_before(ka, ia, kb, ib);
                    if (bad) { kk[i] = kb; kk[ixj] = ka; id[i] = ib; id[ixj] = ia; }
                }
            }
        }
    }
    __syncthreads();
    #pragma unroll 2
    for (int i = t; i < NBOX; i += 1024) {
        g_skey[i] = kk[i];
        int o = id[i];
        g_sidx[i] = o;
        g_sbox[i*4+0] = g_box[o*4+0];
        g_sbox[i*4+1] = g_box[o*4+1];
        g_sbox[i*4+2] = g_box[o*4+2];
        g_sbox[i*4+3] = g_box[o*4+3];
    }
}

// ---------- NMS: IOU bitmask ----------
__global__ __launch_bounds__(64) void nms_mask() {
    __shared__ float cb[32][4];
    int t = threadIdx.x;
    int j0 = blockIdx.x * 32;
    for (int i = t; i < 128; i += 64) cb[i >> 2][i & 3] = g_sbox[(j0 + (i >> 2)) * 4 + (i & 3)];
    __syncthreads();
    int i = blockIdx.y * 64 + t;
    float x1 = g_sbox[i*4+0], y1 = g_sbox[i*4+1], x2 = g_sbox[i*4+2], y2 = g_sbox[i*4+3];
    float area = (x2 - x1) * (y2 - y1);
    unsigned word = 0;
    #pragma unroll 8
    for (int jj = 0; jj < 32; jj++) {
        int j = j0 + jj;
        if (j > i) {
            float bx1v = cb[jj][0], by1v = cb[jj][1], bx2v = cb[jj][2], by2v = cb[jj][3];
            float xx1 = fmaxf(x1, bx1v), yy1 = fmaxf(y1, by1v);
            float xx2 = fminf(x2, bx2v), yy2 = fminf(y2, by2v);
            float inter = fmaxf(xx2 - xx1, 0.f) * fmaxf(yy2 - yy1, 0.f);
            float areab = (bx2v - bx1v) * (by2v - by1v);
            float iou = inter / (area + areab - inter + 1e-12f);
            if (iou > 0.5f) word |= (1u << jj);
        }
    }
    ((unsigned*)g_mask4)[i * 64 + blockIdx.x] = word;
}

// ---------- NMS: serial scan; uint4 streaming producers + register decision word ----------
#define SCHUNK 64           // boxes per chunk; 64*16 uint4 = 4 KB words -> buf 32 KB
#define SNT    512
__global__ __launch_bounds__(SNT) void nms_scan(float* __restrict__ out) {
    __shared__ uint4 buf4[2][SCHUNK * 16];
    __shared__ unsigned keepw[64];
    __shared__ int sV;
    int t = threadIdx.x;
    if (t < 64) keepw[t] = 0u;
    if (t == 0) sV = 0;
    __syncthreads();
    for (int p = t; p < NBOX; p += SNT) {
        bool v = g_skey[p] >= 0.5f;
        unsigned bal = __ballot_sync(0xFFFFFFFFu, v);
        if ((t & 31) == 0) atomicAdd(&sV, __popc(bal));
    }
    __syncthreads();
    const int V = sV;
    const int nch = (V + SCHUNK - 1) / SCHUNK;
    const uint4 z4 = make_uint4(0u,0u,0u,0u);
    for (int i = t; i < SCHUNK * 16; i += SNT) {
        int p = i >> 4;
        buf4[0][i] = (p < V) ? g_mask4[i] : z4;
    }
    __syncthreads();
    unsigned r0 = 0u, r1 = 0u;   // warp0: lane t owns suppression words t, t+32
    for (int ci = 0; ci < nch; ci++) {
        if (t >= 32) {
            if (ci + 1 < nch) {
                uint4* nb = buf4[(ci + 1) & 1];
                int pb = (ci + 1) * SCHUNK;
                for (int i = t - 32; i < SCHUNK * 16; i += (SNT - 32)) {
                    int p = pb + (i >> 4);
                    nb[i] = (p < V) ? g_mask4[p * 16 + (i & 15)] : z4;
                }
            }
        } else {
            const unsigned* B = (const unsigned*)buf4[ci & 1];
            int pb = ci * SCHUNK;
            #pragma unroll
            for (int r = 0; r < 2; r++) {
                int rb = pb + r * 32;
                if (rb >= V) break;
                int w = rb >> 5;                 // global word index (0..63)
                int lim = min(32, V - rb);
                unsigned dw = (w < 32) ? __shfl_sync(0xFFFFFFFFu, r0, w)
                                       : __shfl_sync(0xFFFFFFFFu, r1, w - 32);
                for (int jb = 0; jb < lim; jb += 8) {
                    unsigned qa[8], qb[8], qw[8];
                    #pragma unroll
                    for (int j = 0; j < 8; j++) {
                        int jj = r * 32 + jb + j;
                        bool ok = (jb + j) < lim;
                        qa[j] = ok ? B[jj*64 + t]      : 0u;
                        qb[j] = ok ? B[jj*64 + 32 + t] : 0u;
                        qw[j] = ok ? B[jj*64 + w]      : 0u;
                    }
                    #pragma unroll
                    for (int j = 0; j < 8; j++) {
                        int bb = jb + j;
                        unsigned m = ((dw >> bb) & 1u) - 1u;  // keep -> 0xFFFFFFFF
                        dw |= qw[j] & m;
                        r0 |= qa[j] & m;
                        r1 |= qb[j] & m;
                    }
                }
                if (t == 0) {
                    unsigned vmask = (lim >= 32) ? 0xFFFFFFFFu : ((1u << lim) - 1u);
                    keepw[w] = (~dw) & vmask;
                }
            }
        }
        __syncthreads();
    }
    for (int i = t; i < NBOX * 4; i += SNT) out[i] = 0.f;
    __syncthreads();
    for (int p = t; p < NBOX; p += SNT) {
        if ((keepw[p >> 5] >> (p & 31)) & 1u) {
            int o = g_sidx[p];
            out[o*4+0] = g_sbox[p*4+0];
            out[o*4+1] = g_sbox[p*4+1];
            out[o*4+2] = g_sbox[p*4+2];
            out[o*4+3] = g_sbox[p*4+3];
        }
    }
}

extern "C" void kernel_launch(void* const* d_in, const int* in_sizes, int n_in,
                              void* d_out, int out_size) {
    (void)in_sizes; (void)n_in; (void)out_size;
    cudaFuncSetAttribute(onet_cnn, cudaFuncAttributeMaxDynamicSharedMemorySize, SMEM1_FLOATS * 4);
    onet_cnn<<<NBOX, TPB, SMEM1_FLOATS * 4>>>(
        (const float*)d_in[0],  (const float*)d_in[1],
        (const float*)d_in[2],  (const float*)d_in[3],  (const float*)d_in[4],
        (const float*)d_in[5],  (const float*)d_in[6],  (const float*)d_in[7],
        (const float*)d_in[8],  (const float*)d_in[9],  (const float*)d_in[10],
        (const float*)d_in[11], (const float*)d_in[12], (const float*)d_in[13],
        (const float*)d_in[14], (const float*)d_in[15], (const float*)d_in[16],
        (const float*)d_in[17], (const float*)d_in[18],
        (const float*)d_in[19], (const float*)d_in[20]);
    nms_sort<<<1, 1024>>>();
    nms_mask<<<dim3(64, 32), 64>>>();
    nms_scan<<<1, SNT>>>((float*)d_out);
}

// round 10
// speedup vs baseline: 2.1805x; 1.0117x over previous
#include <cuda_runtime.h>
#include <cuda_bf16.h>
#include <math.h>

#define NBOX 2048
#define TPB  256

// shared arena offsets (floats)
#define OFF_CROP   0        // 6912 (dead after stage1) -> P2 [64][10][10] (6400)
#define OFF_P2     0
#define OFF_GAP    6400     // 512-float gap (conv2 biases)
#define OFF_P1     6912     // P1 [32][23][23] = 16928 (dead after stage2)
#define OFF_P3     6912     // 1024
#define OFF_C4     7936     // 1152
#define OFF_F5     9088     // 256
#define OFF_FC6    9344     // 8
#define OFF_W34    9472     // stage3/4 weights+temp (inside dead-P1 region, 14368 avail)
#define OFF_W      23840    // stage1/2 staging region (4312 floats)
#define SMEM1_FLOATS 28152  // 112,608 bytes -> 2 CTAs/SM

__device__ float    g_score[NBOX];
__device__ float    g_box[NBOX * 4];
__device__ float    g_skey[NBOX];
__device__ int      g_sidx[NBOX];
__device__ float    g_sbox[NBOX * 4];
__device__ uint4    g_mask4[NBOX * 16];   // NBOX rows x 64 words (16B-aligned)

// packed dual fp32 FMA: c += a*b per lane (FFMA2)
__device__ __forceinline__ void dfma(float2& c, float2 a, float2 b) {
    asm("fma.rn.f32x2 %0, %1, %2, %0;"
        : "+l"(reinterpret_cast<unsigned long long&>(c))
        : "l"(reinterpret_cast<unsigned long long&>(a)),
          "l"(reinterpret_cast<unsigned long long&>(b)));
}
__device__ __forceinline__ float2 bcast2(float v) { return make_float2(v, v); }

__global__ __launch_bounds__(TPB, 2) void onet_cnn(
    const float* __restrict__ bboxes, const float* __restrict__ image,
    const float* __restrict__ c1w, const float* __restrict__ c1b, const float* __restrict__ p1a,
    const float* __restrict__ c2w, const float* __restrict__ c2b, const float* __restrict__ p2a,
    const float* __restrict__ c3w, const float* __restrict__ c3b, const float* __restrict__ p3a,
    const float* __restrict__ c4w, const float* __restrict__ c4b, const float* __restrict__ p4a,
    const float* __restrict__ f5w, const float* __restrict__ f5b, const float* __restrict__ p5a,
    const float* __restrict__ f6aw, const float* __restrict__ f6ab,
    const float* __restrict__ f6bw, const float* __restrict__ f6bb)
{
    extern __shared__ float sm[];
    const int t = threadIdx.x;
    const int b = blockIdx.x;

    float B0 = bboxes[b*4+0], B1 = bboxes[b*4+1], B2 = bboxes[b*4+2], B3 = bboxes[b*4+3];
    float bx1 = fmaxf(B0, 0.f), by1 = fmaxf(B1, 0.f);
    float bx2 = fminf(B2, 1024.f), by2 = fminf(B3, 1024.f);
    int ix1 = (int)bx1, iy1 = (int)by1, ix2 = (int)bx2, iy2 = (int)by2;
    int cw = max(ix2 - ix1, 1), ch = max(iy2 - iy1, 1);

    // ---- crop 48x48x3 HWC (one index computation per pixel) ----
    float* crop = sm + OFF_CROP;
    for (int i = t; i < 2304; i += TPB) {
        int x = i % 48; int y = i / 48;
        int gx = ix1 + (x * cw) / 48;
        int gy = iy1 + (y * ch) / 48;
        const float* src = image + (gy * 1024 + gx) * 3;
        float* dst = crop + i * 3;
        dst[0] = (__ldg(&src[0]) - 127.5f) * 0.0078125f;
        dst[1] = (__ldg(&src[1]) - 127.5f) * 0.0078125f;
        dst[2] = (__ldg(&src[2]) - 127.5f) * 0.0078125f;
    }
    __syncthreads();

    // ===== stage 1: conv1 3x3x3->32 + prelu + pool(3,2,pad1) -> P1 [32][23][23] =====
    float* temp1 = sm + OFF_W;                 // 4232 floats (float2-interleaved 46x46)
    float* P1 = sm + OFF_P1;                   // ch stride 529, row stride 23
    for (int g = 0; g < 16; ++g) {
        float2 wr[27];
        #pragma unroll
        for (int k = 0; k < 27; k++) wr[k] = __ldg((const float2*)&c1w[k * 32 + 2*g]);
        float2 bias  = __ldg((const float2*)&c1b[2*g]);
        float2 alpha = __ldg((const float2*)&p1a[2*g]);
        for (int task = t; task < 552; task += TPB) {
            int xg = task % 12; int cy = task / 12;
            int x0 = xg * 4;
            float2 a0 = make_float2(0.f,0.f), a1v = a0, a2 = a0, a3 = a0;
            #pragma unroll
            for (int ky = 0; ky < 3; ky++) {
                const float* row = crop + (cy + ky) * 144;
                float in[18];
                #pragma unroll
                for (int j = 0; j < 6; j++) {
                    int col = x0 + j; if (col > 47) col = 47;
                    in[j*3+0] = row[col*3+0];
                    in[j*3+1] = row[col*3+1];
                    in[j*3+2] = row[col*3+2];
                }
                #pragma unroll
                for (int kx = 0; kx < 3; kx++)
                    #pragma unroll
                    for (int ic = 0; ic < 3; ic++) {
                        float2 w = wr[(ky*3+kx)*3+ic];
                        dfma(a0,  bcast2(in[(kx+0)*3+ic]), w);
                        dfma(a1v, bcast2(in[(kx+1)*3+ic]), w);
                        dfma(a2,  bcast2(in[(kx+2)*3+ic]), w);
                        dfma(a3,  bcast2(in[(kx+3)*3+ic]), w);
                    }
            }
            float2* tp = (float2*)temp1 + cy * 46;
            float2 o;
            o.x = a0.x + bias.x; o.y = a0.y + bias.y;
            o.x = o.x >= 0.f ? o.x : alpha.x * o.x; o.y = o.y >= 0.f ? o.y : alpha.y * o.y;
            tp[x0+0] = o;
            o.x = a1v.x + bias.x; o.y = a1v.y + bias.y;
            o.x = o.x >= 0.f ? o.x : alpha.x * o.x; o.y = o.y >= 0.f ? o.y : alpha.y * o.y;
            tp[x0+1] = o;
            if (x0+2 < 46) {
                o.x = a2.x + bias.x; o.y = a2.y + bias.y;
                o.x = o.x >= 0.f ? o.x : alpha.x * o.x; o.y = o.y >= 0.f ? o.y : alpha.y * o.y;
                tp[x0+2] = o;
            }
            if (x0+3 < 46) {
                o.x = a3.x + bias.x; o.y = a3.y + bias.y;
                o.x = o.x >= 0.f ? o.x : alpha.x * o.x; o.y = o.y >= 0.f ? o.y : alpha.y * o.y;
                tp[x0+3] = o;
            }
        }
        __syncthreads();
        for (int i = t; i < 1058; i += TPB) {
            int c = i & 1; int pos = i >> 1; int px = pos % 23; int py = pos / 23;
            float m = -3.4e38f;
            #pragma unroll
            for (int dy = 0; dy < 3; dy++) {
                int cy2 = 2*py - 1 + dy; if (cy2 < 0 || cy2 >= 46) continue;
                #pragma unroll
                for (int dx = 0; dx < 3; dx++) {
                    int cx2 = 2*px - 1 + dx; if (cx2 < 0 || cx2 >= 46) continue;
                    m = fmaxf(m, temp1[(cy2*46 + cx2)*2 + c]);
                }
            }
            P1[(g*2 + c) * 529 + py * 23 + px] = m;
        }
        __syncthreads();
    }

    // ===== stage 2: conv2 3x3x32->64 + prelu + pool(3,2) -> P2 [64][10][10] =====
    // 4 groups x 16 out-channels; thread owns a channel QUAD (2 FFMA2 pairs) x 7 x.
    float* w2s = sm + OFF_W;
    float* temp2 = sm + OFF_W + 768;           // 8ch x 21x21 = 3528 (written in 2 halves)
    float* b2s = sm + OFF_GAP; float* a2s = b2s + 16;  // 32 floats in gap
    float* P2 = sm + OFF_P2;
    for (int g = 0; g < 4; ++g) {
        if (t < 16) { b2s[t] = c2b[g*16 + t]; a2s[t] = p2a[g*16 + t]; }
        const int xg = t % 3; const int rem = t / 3;       // t<252: rem 0..83
        const int cq = rem & 3; const int cy = rem >> 2;   // quad 0..3, cy 0..20
        const int x0 = xg * 7;
        float2 acc[2][7];
        #pragma unroll
        for (int p = 0; p < 2; p++)
            #pragma unroll
            for (int j = 0; j < 7; j++) acc[p][j] = make_float2(0.f, 0.f);
        for (int ky = 0; ky < 3; ky++) {
            for (int ih = 0; ih < 2; ih++) {
                __syncthreads();
                for (int i = t; i < 768; i += TPB) {
                    int c = i & 15; int rest = i >> 4;
                    int icl = rest & 15; int kx = rest >> 4;
                    w2s[i] = c2w[((ky*3 + kx)*32 + ih*16 + icl) * 64 + g*16 + c];
                }
                __syncthreads();
                if (t < 252) {
                    const float* inb = P1 + (ih*16)*529 + (cy + ky) * 23 + x0;
                    const float* wb  = w2s + 4*cq;
                    #pragma unroll 4
                    for (int icl = 0; icl < 16; icl++) {
                        const float* in = inb + icl * 529;
                        float2 p0 = bcast2(in[0]), p1 = bcast2(in[1]), p2 = bcast2(in[2]);
                        float2 p3 = bcast2(in[3]), p4 = bcast2(in[4]), p5 = bcast2(in[5]);
                        float2 p6 = bcast2(in[6]), p7 = bcast2(in[7]), p8 = bcast2(in[8]);
                        float2 wA0 = *(const float2*)&w2s[(0*16+icl)*16 + 4*cq];
                        float2 wB0 = *(const float2*)&w2s[(0*16+icl)*16 + 4*cq + 2];
                        float2 wA1 = *(const float2*)&w2s[(1*16+icl)*16 + 4*cq];
                        float2 wB1 = *(const float2*)&w2s[(1*16+icl)*16 + 4*cq + 2];
                        float2 wA2 = *(const float2*)&w2s[(2*16+icl)*16 + 4*cq];
                        float2 wB2 = *(const float2*)&w2s[(2*16+icl)*16 + 4*cq + 2];
                        dfma(acc[0][0],p0,wA0); dfma(acc[0][1],p1,wA0); dfma(acc[0][2],p2,wA0);
                        dfma(acc[0][3],p3,wA0); dfma(acc[0][4],p4,wA0); dfma(acc[0][5],p5,wA0); dfma(acc[0][6],p6,wA0);
                        dfma(acc[1][0],p0,wB0); dfma(acc[1][1],p1,wB0); dfma(acc[1][2],p2,wB0);
                        dfma(acc[1][3],p3,wB0); dfma(acc[1][4],p4,wB0); dfma(acc[1][5],p5,wB0); dfma(acc[1][6],p6,wB0);
                        dfma(acc[0][0],p1,wA1); dfma(acc[0][1],p2,wA1); dfma(acc[0][2],p3,wA1);
                        dfma(acc[0][3],p4,wA1); dfma(acc[0][4],p5,wA1); dfma(acc[0][5],p6,wA1); dfma(acc[0][6],p7,wA1);
                        dfma(acc[1][0],p1,wB1); dfma(acc[1][1],p2,wB1); dfma(acc[1][2],p3,wB1);
                        dfma(acc[1][3],p4,wB1); dfma(acc[1][4],p5,wB1); dfma(acc[1][5],p6,wB1); dfma(acc[1][6],p7,wB1);
                        dfma(acc[0][0],p2,wA2); dfma(acc[0][1],p3,wA2); dfma(acc[0][2],p4,wA2);
                        dfma(acc[0][3],p5,wA2); dfma(acc[0][4],p6,wA2); dfma(acc[0][5],p7,wA2); dfma(acc[0][6],p8,wA2);
                        dfma(acc[1][0],p2,wB2); dfma(acc[1][1],p3,wB2); dfma(acc[1][2],p4,wB2);
                        dfma(acc[1][3],p5,wB2); dfma(acc[1][4],p6,wB2); dfma(acc[1][5],p7,wB2); dfma(acc[1][6],p8,wB2);
                    }
                }
            }
        }
        float vb[4], va[4];
        if (t < 252) {
            #pragma unroll
            for (int k = 0; k < 4; k++) { vb[k] = b2s[4*cq + k]; va[k] = a2s[4*cq + k]; }
        }
        if (t < 252 && cq < 2) {
            #pragma unroll
            for (int p = 0; p < 2; p++) {
                float* t0 = temp2 + (4*cq + 2*p)     * 441 + cy * 21 + x0;
                float* t1 = temp2 + (4*cq + 2*p + 1) * 441 + cy * 21 + x0;
                #pragma unroll
                for (int j = 0; j < 7; j++) {
                    float v0 = acc[p][j].x + vb[2*p];
                    float v1 = acc[p][j].y + vb[2*p+1];
                    t0[j] = v0 >= 0.f ? v0 : va[2*p] * v0;
                    t1[j] = v1 >= 0.f ? v1 : va[2*p+1] * v1;
                }
            }
        }
        __syncthreads();
        for (int i = t; i < 800; i += TPB) {
            int c = i & 7; int pos = i >> 3; int px = pos % 10; int py = pos / 10;
            const float* tp = temp2 + c * 441;
            float m = -3.4e38f;
            #pragma unroll
            for (int dy = 0; dy < 3; dy++)
                #pragma unroll
                for (int dx = 0; dx < 3; dx++)
                    m = fmaxf(m, tp[(2*py+dy)*21 + 2*px+dx]);
            P2[(g*16 + c) * 100 + py * 10 + px] = m;
        }
        __syncthreads();
        if (t < 252 && cq >= 2) {
            #pragma unroll
            for (int p = 0; p < 2; p++) {
                float* t0 = temp2 + (4*(cq-2) + 2*p)     * 441 + cy * 21 + x0;
                float* t1 = temp2 + (4*(cq-2) + 2*p + 1) * 441 + cy * 21 + x0;
                #pragma unroll
                for (int j = 0; j < 7; j++) {
                    float v0 = acc[p][j].x + vb[2*p];
                    float v1 = acc[p][j].y + vb[2*p+1];
                    t0[j] = v0 >= 0.f ? v0 : va[2*p] * v0;
                    t1[j] = v1 >= 0.f ? v1 : va[2*p+1] * v1;
                }
            }
        }
        __syncthreads();
        for (int i = t; i < 800; i += TPB) {
            int c = i & 7; int pos = i >> 3; int px = pos % 10; int py = pos / 10;
            const float* tp = temp2 + c * 441;
            float m = -3.4e38f;
            #pragma unroll
            for (int dy = 0; dy < 3; dy++)
                #pragma unroll
                for (int dx = 0; dx < 3; dx++)
                    m = fmaxf(m, tp[(2*py+dy)*21 + 2*px+dx]);
            P2[(g*16 + 8 + c) * 100 + py * 10 + px] = m;
        }
        __syncthreads();
    }

    // ===== stage 3: conv3 3x3x64->64 + prelu + pool(2,2) -> P3 [64][4][4] =====
    // SINGLE group of 64 out-ch; 16 quads x 16 positions = 256 active threads.
    // Weights staged per (ky, ic-half): w3s[(kx*32+icl)*64 + c], 6144 floats.
    float* w3s = sm + OFF_W34; float* b3s = w3s + 6144; float* a3s = b3s + 64;
    float* temp3 = sm + OFF_W34 + 6272;        // 32ch x 8x8 = 2048 (two halves)
    float* P3 = sm + OFF_P3;
    {
        if (t < 64) { b3s[t] = c3b[t]; a3s[t] = p3a[t]; }
        const int cq = t & 15; const int pos = t >> 4;   // pos 0..15
        const int xg = pos & 1; const int cy = pos >> 1;
        const int x0 = xg * 4;
        float2 acc[2][4];
        #pragma unroll
        for (int p = 0; p < 2; p++)
            #pragma unroll
            for (int j = 0; j < 4; j++) acc[p][j] = make_float2(0.f, 0.f);
        for (int ky = 0; ky < 3; ky++) {
            for (int ih = 0; ih < 2; ih++) {
                __syncthreads();
                for (int i = t; i < 6144; i += TPB) {
                    int c = i & 63; int rest = i >> 6;
                    int icl = rest & 31; int kx = rest >> 5;
                    w3s[i] = c3w[((ky*3 + kx)*64 + ih*32 + icl) * 64 + c];
                }
                __syncthreads();
                const float* inb = P2 + (ih*32)*100 + (cy + ky) * 10 + x0;
                #pragma unroll 4
                for (int icl = 0; icl < 32; icl++) {
                    const float* in = inb + icl * 100;
                    float2 p0 = bcast2(in[0]), p1 = bcast2(in[1]), p2 = bcast2(in[2]);
                    float2 p3 = bcast2(in[3]), p4 = bcast2(in[4]), p5 = bcast2(in[5]);
                    float2 wA0 = *(const float2*)&w3s[(0*32+icl)*64 + 4*cq];
                    float2 wB0 = *(const float2*)&w3s[(0*32+icl)*64 + 4*cq + 2];
                    float2 wA1 = *(const float2*)&w3s[(1*32+icl)*64 + 4*cq];
                    float2 wB1 = *(const float2*)&w3s[(1*32+icl)*64 + 4*cq + 2];
                    float2 wA2 = *(const float2*)&w3s[(2*32+icl)*64 + 4*cq];
                    float2 wB2 = *(const float2*)&w3s[(2*32+icl)*64 + 4*cq + 2];
                    dfma(acc[0][0],p0,wA0); dfma(acc[0][1],p1,wA0); dfma(acc[0][2],p2,wA0); dfma(acc[0][3],p3,wA0);
                    dfma(acc[1][0],p0,wB0); dfma(acc[1][1],p1,wB0); dfma(acc[1][2],p2,wB0); dfma(acc[1][3],p3,wB0);
                    dfma(acc[0][0],p1,wA1); dfma(acc[0][1],p2,wA1); dfma(acc[0][2],p3,wA1); dfma(acc[0][3],p4,wA1);
                    dfma(acc[1][0],p1,wB1); dfma(acc[1][1],p2,wB1); dfma(acc[1][2],p3,wB1); dfma(acc[1][3],p4,wB1);
                    dfma(acc[0][0],p2,wA2); dfma(acc[0][1],p3,wA2); dfma(acc[0][2],p4,wA2); dfma(acc[0][3],p5,wA2);
                    dfma(acc[1][0],p2,wB2); dfma(acc[1][1],p3,wB2); dfma(acc[1][2],p4,wB2); dfma(acc[1][3],p5,wB2);
                }
            }
        }
        float vb[4], va[4];
        #pragma unroll
        for (int k = 0; k < 4; k++) { vb[k] = b3s[4*cq + k]; va[k] = a3s[4*cq + k]; }
        // half 0: quads 0..7 (channels 0..31)
        if (cq < 8) {
            #pragma unroll
            for (int p = 0; p < 2; p++) {
                float* t0 = temp3 + (4*cq + 2*p)     * 64 + cy * 8 + x0;
                float* t1 = temp3 + (4*cq + 2*p + 1) * 64 + cy * 8 + x0;
                #pragma unroll
                for (int j = 0; j < 4; j++) {
                    float v0 = acc[p][j].x + vb[2*p];
                    float v1 = acc[p][j].y + vb[2*p+1];
                    t0[j] = v0 >= 0.f ? v0 : va[2*p] * v0;
                    t1[j] = v1 >= 0.f ? v1 : va[2*p+1] * v1;
                }
            }
        }
        __syncthreads();
        for (int task = t; task < 512; task += TPB) {
            int c = task & 31; int pos2 = task >> 5; int px = pos2 & 3; int py = pos2 >> 2;
            const float* tp = temp3 + c * 64;
            float m = fmaxf(fmaxf(tp[(2*py)*8 + 2*px], tp[(2*py)*8 + 2*px + 1]),
                            fmaxf(tp[(2*py+1)*8 + 2*px], tp[(2*py+1)*8 + 2*px + 1]));
            P3[c * 16 + py * 4 + px] = m;
        }
        __syncthreads();
        // half 1: quads 8..15 (channels 32..63)
        if (cq >= 8) {
            #pragma unroll
            for (int p = 0; p < 2; p++) {
                float* t0 = temp3 + (4*(cq-8) + 2*p)     * 64 + cy * 8 + x0;
                float* t1 = temp3 + (4*(cq-8) + 2*p + 1) * 64 + cy * 8 + x0;
                #pragma unroll
                for (int j = 0; j < 4; j++) {
                    float v0 = acc[p][j].x + vb[2*p];
                    float v1 = acc[p][j].y + vb[2*p+1];
                    t0[j] = v0 >= 0.f ? v0 : va[2*p] * v0;
                    t1[j] = v1 >= 0.f ? v1 : va[2*p+1] * v1;
                }
            }
        }
        __syncthreads();
        for (int task = t; task < 512; task += TPB) {
            int c = task & 31; int pos2 = task >> 5; int px = pos2 & 3; int py = pos2 >> 2;
            const float* tp = temp3 + c * 64;
            float m = fmaxf(fmaxf(tp[(2*py)*8 + 2*px], tp[(2*py)*8 + 2*px + 1]),
                            fmaxf(tp[(2*py+1)*8 + 2*px], tp[(2*py+1)*8 + 2*px + 1]));
            P3[(32 + c) * 16 + py * 4 + px] = m;
        }
        __syncthreads();
    }

    // ===== stage 4: conv4 2x2x64->128 + prelu -> C4 flat (c*9 + y*3 + x) =====
    float* w4s = sm + OFF_W34; float* b4s = w4s + 4096; float* a4s = b4s + 64;
    float* C4 = sm + OFF_C4;
    for (int g = 0; g < 2; ++g) {
        if (t < 64) { b4s[t] = c4b[g*64 + t]; a4s[t] = p4a[g*64 + t]; }
        const int cq = t & 15; const int pos = t >> 4;   // t<144: pos 0..8
        const int y = pos / 3, x = pos % 3;
        float2 accA = make_float2(0.f,0.f), accB = accA;
        for (int k = 0; k < 4; k++) {
            __syncthreads();
            for (int i = t; i < 4096; i += TPB) {
                int c = i & 63; int ic = i >> 6;
                w4s[i] = c4w[(k*64 + ic)*128 + g*64 + c];
            }
            __syncthreads();
            if (t < 144) {
                int ky = k >> 1, kx = k & 1;
                const float* inb = P3 + (y + ky) * 4 + (x + kx);
                const float* wb  = w4s + 4*cq;
                #pragma unroll 4
                for (int ic = 0; ic < 64; ic++) {
                    float2 p = bcast2(inb[ic * 16]);
                    float2 wA = *(const float2*)&wb[ic * 64];
                    float2 wB = *(const float2*)&wb[ic * 64 + 2];
                    dfma(accA, p, wA); dfma(accB, p, wB);
                }
            }
        }
        if (t < 144) {
            int c0 = g*64 + 4*cq;
            float v0 = accA.x + b4s[4*cq+0], v1 = accA.y + b4s[4*cq+1];
            float v2 = accB.x + b4s[4*cq+2], v3 = accB.y + b4s[4*cq+3];
            float l0 = a4s[4*cq+0], l1 = a4s[4*cq+1], l2 = a4s[4*cq+2], l3 = a4s[4*cq+3];
            C4[(c0+0)*9 + pos] = v0 >= 0.f ? v0 : l0 * v0;
            C4[(c0+1)*9 + pos] = v1 >= 0.f ? v1 : l1 * v1;
            C4[(c0+2)*9 + pos] = v2 >= 0.f ? v2 : l2 * v2;
            C4[(c0+3)*9 + pos] = v3 >= 0.f ? v3 : l3 * v3;
        }
        __syncthreads();   // protect b4s/a4s from next group's overwrite
    }

    // ===== fc5: 1152 -> 256 + prelu (vectorized) =====
    float* F5 = sm + OFF_F5;
    {
        int warp = t >> 5, lane = t & 31;
        for (int o = warp; o < 256; o += 8) {
            const float4* wrow = (const float4*)(f5w + o * 1152);
            float acc = 0.f;
            #pragma unroll
            for (int j = 0; j < 9; j++) {
                float4 cv = *(const float4*)&C4[j*128 + lane*4];
                float4 wv = __ldg(&wrow[j*32 + lane]);
                acc += cv.x*wv.x + cv.y*wv.y + cv.z*wv.z + cv.w*wv.w;
            }
            #pragma unroll
            for (int s = 16; s; s >>= 1) acc += __shfl_xor_sync(0xFFFFFFFFu, acc, s);
            if (lane == 0) {
                float v = acc + f5b[o];
                float al = p5a[o];
                F5[o] = v >= 0.f ? v : al * v;
            }
        }
    }
    __syncthreads();

    // ===== fc6a (2) + fc6b (4) =====
    float* FC6 = sm + OFF_FC6;
    if (t < 192) {
        int o = t >> 5, lane = t & 31;
        const float* wrow = (o < 2) ? (f6aw + o * 256) : (f6bw + (o - 2) * 256);
        float acc = 0.f;
        #pragma unroll
        for (int j = 0; j < 8; j++) { int k = lane + 32*j; acc += F5[k] * __ldg(&wrow[k]); }
        #pragma unroll
        for (int s = 16; s; s >>= 1) acc += __shfl_xor_sync(0xFFFFFFFFu, acc, s);
        if (lane == 0) FC6[o] = acc + ((o < 2) ? f6ab[o] : f6bb[o - 2]);
    }
    __syncthreads();

    if (t == 0) {
        float l0 = FC6[0], l1 = FC6[1];
        float m = fmaxf(l0, l1);
        float e0 = expf(l0 - m), e1 = expf(l1 - m);
        float score = e1 / (e0 + e1);
        float w = bx2 - bx1, h = by2 - by1;
        g_score[b] = score;
        g_box[b*4+0] = bx1 + FC6[2] * w;
        g_box[b*4+1] = by1 + FC6[3] * h;
        g_box[b*4+2] = bx2 + FC6[4] * w;
        g_box[b*4+3] = by2 + FC6[5] * h;
    }
}

// ---------- NMS: bitonic sort by (score desc, idx asc) ----------
__device__ __forceinline__ bool nms_before(float ka, int ia, float kb, int ib) {
    return (ka > kb) || (ka == kb && ia < ib);
}

__global__ __launch_bounds__(1024) void nms_sort() {
    __shared__ float kk[NBOX];
    __shared__ int   id[NBOX];
    int t = threadIdx.x;
    kk[t] = g_score[t];           id[t] = t;
    kk[t+1024] = g_score[t+1024]; id[t+1024] = t + 1024;
    for (int k = 2; k <= NBOX; k <<= 1) {
        for (int j = k >> 1; j > 0; j >>= 1) {
            __syncthreads();
            #pragma unroll 2
            for (int i = t; i < NBOX; i += 1024) {
                int ixj = i ^ j;
                if (ixj > i) {
                    float ka = kk[i], kb = kk[ixj];
                    int ia = id[i], ib = id[ixj];
                    bool up = ((i & k) == 0);
                    bool bad = up ? nms_before(kb, ib, ka, ia) : nms_before(ka, ia, kb, ib);
                    if (bad) { kk[i] = kb; kk[ixj] = ka; id[i] = ib; id[ixj] = ia; }
                }
            }
        }
    }
    __syncthreads();
    #pragma unroll 2
    for (int i = t; i < NBOX; i += 1024) {
        g_skey[i] = kk[i];
        int o = id[i];
        g_sidx[i] = o;
        g_sbox[i*4+0] = g_box[o*4+0];
        g_sbox[i*4+1] = g_box[o*4+1];
        g_sbox[i*4+2] = g_box[o*4+2];
        g_sbox[i*4+3] = g_box[o*4+3];
    }
}

// ---------- NMS: IOU bitmask ----------
__global__ __launch_bounds__(64) void nms_mask() {
    __shared__ float cb[32][4];
    int t = threadIdx.x;
    int j0 = blockIdx.x * 32;
    for (int i = t; i < 128; i += 64) cb[i >> 2][i & 3] = g_sbox[(j0 + (i >> 2)) * 4 + (i & 3)];
    __syncthreads();
    int i = blockIdx.y * 64 + t;
    float x1 = g_sbox[i*4+0], y1 = g_sbox[i*4+1], x2 = g_sbox[i*4+2], y2 = g_sbox[i*4+3];
    float area = (x2 - x1) * (y2 - y1);
    unsigned word = 0;
    #pragma unroll 8
    for (int jj = 0; jj < 32; jj++) {
        int j = j0 + jj;
        if (j > i) {
            float bx1v = cb[jj][0], by1v = cb[jj][1], bx2v = cb[jj][2], by2v = cb[jj][3];
            float xx1 = fmaxf(x1, bx1v), yy1 = fmaxf(y1, by1v);
            float xx2 = fminf(x2, bx2v), yy2 = fminf(y2, by2v);
            float inter = fmaxf(xx2 - xx1, 0.f) * fmaxf(yy2 - yy1, 0.f);
            float areab = (bx2v - bx1v) * (by2v - by1v);
            float iou = inter / (area + areab - inter + 1e-12f);
            if (iou > 0.5f) word |= (1u << jj);
        }
    }
    ((unsigned*)g_mask4)[i * 64 + blockIdx.x] = word;
}

// ---------- NMS: serial scan; uint4 streaming producers + register decision word ----------
#define SCHUNK 64           // boxes per chunk; 64*16 uint4 = 4 KB words -> buf 32 KB
#define SNT    512
__global__ __launch_bounds__(SNT) void nms_scan(float* __restrict__ out) {
    __shared__ uint4 buf4[2][SCHUNK * 16];
    __shared__ unsigned keepw[64];
    __shared__ int sV;
    int t = threadIdx.x;
    if (t < 64) keepw[t] = 0u;
    if (t == 0) sV = 0;
    __syncthreads();
    for (int p = t; p < NBOX; p += SNT) {
        bool v = g_skey[p] >= 0.5f;
        unsigned bal = __ballot_sync(0xFFFFFFFFu, v);
        if ((t & 31) == 0) atomicAdd(&sV, __popc(bal));
    }
    __syncthreads();
    const int V = sV;
    const int nch = (V + SCHUNK - 1) / SCHUNK;
    const uint4 z4 = make_uint4(0u,0u,0u,0u);
    for (int i = t; i < SCHUNK * 16; i += SNT) {
        int p = i >> 4;
        buf4[0][i] = (p < V) ? g_mask4[i] : z4;
    }
    __syncthreads();
    unsigned r0 = 0u, r1 = 0u;   // warp0: lane t owns suppression words t, t+32
    for (int ci = 0; ci < nch; ci++) {
        if (t >= 32) {
            if (ci + 1 < nch) {
                uint4* nb = buf4[(ci + 1) & 1];
                int pb = (ci + 1) * SCHUNK;
                for (int i = t - 32; i < SCHUNK * 16; i += (SNT - 32)) {
                    int p = pb + (i >> 4);
                    nb[i] = (p < V) ? g_mask4[p * 16 + (i & 15)] : z4;
                }
            }
        } else {
            const unsigned* B = (const unsigned*)buf4[ci & 1];
            int pb = ci * SCHUNK;
            #pragma unroll
            for (int r = 0; r < 2; r++) {
                int rb = pb + r * 32;
                if (rb >= V) break;
                int w = rb >> 5;                 // global word index (0..63)
                int lim = min(32, V - rb);
                unsigned dw = (w < 32) ? __shfl_sync(0xFFFFFFFFu, r0, w)
                                       : __shfl_sync(0xFFFFFFFFu, r1, w - 32);
                for (int jb = 0; jb < lim; jb += 8) {
                    unsigned qa[8], qb[8], qw[8];
                    #pragma unroll
                    for (int j = 0; j < 8; j++) {
                        int jj = r * 32 + jb + j;
                        bool ok = (jb + j) < lim;
                        qa[j] = ok ? B[jj*64 + t]      : 0u;
                        qb[j] = ok ? B[jj*64 + 32 + t] : 0u;
                        qw[j] = ok ? B[jj*64 + w]      : 0u;
                    }
                    #pragma unroll
                    for (int j = 0; j < 8; j++) {
                        int bb = jb + j;
                        unsigned m = ((dw >> bb) & 1u) - 1u;  // keep -> 0xFFFFFFFF
                        dw |= qw[j] & m;
                        r0 |= qa[j] & m;
                        r1 |= qb[j] & m;
                    }
                }
                if (t == 0) {
                    unsigned vmask = (lim >= 32) ? 0xFFFFFFFFu : ((1u << lim) - 1u);
                    keepw[w] = (~dw) & vmask;
                }
            }
        }
        __syncthreads();
    }
    for (int i = t; i < NBOX * 4; i += SNT) out[i] = 0.f;
    __syncthreads();
    for (int p = t; p < NBOX; p += SNT) {
        if ((keepw[p >> 5] >> (p & 31)) & 1u) {
            int o = g_sidx[p];
            out[o*4+0] = g_sbox[p*4+0];
            out[o*4+1] = g_sbox[p*4+1];
            out[o*4+2] = g_sbox[p*4+2];
            out[o*4+3] = g_sbox[p*4+3];
        }
    }
}

extern "C" void kernel_launch(void* const* d_in, const int* in_sizes, int n_in,
                              void* d_out, int out_size) {
    (void)in_sizes; (void)n_in; (void)out_size;
    cudaFuncSetAttribute(onet_cnn, cudaFuncAttributeMaxDynamicSharedMemorySize, SMEM1_FLOATS * 4);
    onet_cnn<<<NBOX, TPB, SMEM1_FLOATS * 4>>>(
        (const float*)d_in[0],  (const float*)d_in[1],
        (const float*)d_in[2],  (const float*)d_in[3],  (const float*)d_in[4],
        (const float*)d_in[5],  (const float*)d_in[6],  (const float*)d_in[7],
        (const float*)d_in[8],  (const float*)d_in[9],  (const float*)d_in[10],
        (const float*)d_in[11], (const float*)d_in[12], (const float*)d_in[13],
        (const float*)d_in[14], (const float*)d_in[15], (const float*)d_in[16],
        (const float*)d_in[17], (const float*)d_in[18],
        (const float*)d_in[19], (const float*)d_in[20]);
    nms_sort<<<1, 1024>>>();
    nms_mask<<<dim3(64, 32), 64>>>();
    nms_scan<<<1, SNT>>>((float*)d_out);
}

// round 12
// speedup vs baseline: 2.1847x; 1.0019x over previous
#include <cuda_runtime.h>
#include <cuda_bf16.h>
#include <math.h>

#define NBOX 2048
#define TPB  256

// shared arena offsets (floats) — liveness: crop/P2 @0 (crop s1; P2 s3+),
// P1 @6912 live s1-s2 (dead s3+ -> P3/C4/F5/FC6/W34), small scratch @23840 always free.
#define OFF_CROP   0
#define OFF_P2     0
#define OFF_GAP    6400     // 512-float gap (conv2 biases)
#define OFF_P1     6912
#define OFF_P3     6912
#define OFF_C4     7936
#define OFF_F5     9088
#define OFF_FC6    9344
#define OFF_W34    9472     // stage3/4 ONLY (inside dead-P1 region)
#define OFF_W      23840    // stage1/2/3 small scratch (4312 floats)
#define SMEM1_FLOATS 28152  // 112,608 bytes -> 2 CTAs/SM

__device__ float    g_score[NBOX];
__device__ float    g_box[NBOX * 4];
__device__ float    g_skey[NBOX];
__device__ int      g_sidx[NBOX];
__device__ float    g_sbox[NBOX * 4];
__device__ uint4    g_mask4[NBOX * 16];

// packed dual fp32 FMA: c += a*b per lane (FFMA2)
__device__ __forceinline__ void dfma(float2& c, float2 a, float2 b) {
    asm("fma.rn.f32x2 %0, %1, %2, %0;"
        : "+l"(reinterpret_cast<unsigned long long&>(c))
        : "l"(reinterpret_cast<unsigned long long&>(a)),
          "l"(reinterpret_cast<unsigned long long&>(b)));
}
__device__ __forceinline__ float2 bcast2(float v) { return make_float2(v, v); }

__global__ __launch_bounds__(TPB, 2) void onet_cnn(
    const float* __restrict__ bboxes, const float* __restrict__ image,
    const float* __restrict__ c1w, const float* __restrict__ c1b, const float* __restrict__ p1a,
    const float* __restrict__ c2w, const float* __restrict__ c2b, const float* __restrict__ p2a,
    const float* __restrict__ c3w, const float* __restrict__ c3b, const float* __restrict__ p3a,
    const float* __restrict__ c4w, const float* __restrict__ c4b, const float* __restrict__ p4a,
    const float* __restrict__ f5w, const float* __restrict__ f5b, const float* __restrict__ p5a,
    const float* __restrict__ f6aw, const float* __restrict__ f6ab,
    const float* __restrict__ f6bw, const float* __restrict__ f6bb)
{
    extern __shared__ float sm[];
    const int t = threadIdx.x;
    const int b = blockIdx.x;

    float B0 = bboxes[b*4+0], B1 = bboxes[b*4+1], B2 = bboxes[b*4+2], B3 = bboxes[b*4+3];
    float bx1 = fmaxf(B0, 0.f), by1 = fmaxf(B1, 0.f);
    float bx2 = fminf(B2, 1024.f), by2 = fminf(B3, 1024.f);
    int ix1 = (int)bx1, iy1 = (int)by1, ix2 = (int)bx2, iy2 = (int)by2;
    int cw = max(ix2 - ix1, 1), ch = max(iy2 - iy1, 1);

    // ---- crop 48x48x3 HWC ----
    float* crop = sm + OFF_CROP;
    for (int i = t; i < 2304; i += TPB) {
        int x = i % 48; int y = i / 48;
        int gx = ix1 + (x * cw) / 48;
        int gy = iy1 + (y * ch) / 48;
        const float* src = image + (gy * 1024 + gx) * 3;
        float* dst = crop + i * 3;
        dst[0] = (__ldg(&src[0]) - 127.5f) * 0.0078125f;
        dst[1] = (__ldg(&src[1]) - 127.5f) * 0.0078125f;
        dst[2] = (__ldg(&src[2]) - 127.5f) * 0.0078125f;
    }
    __syncthreads();

    // ===== stage 1: conv1 3x3x3->32 + prelu + pool(3,2,pad1) -> P1 [32][23][23] =====
    float* temp1 = sm + OFF_W;                 // 4232 floats (float2-interleaved 46x46)
    float* P1 = sm + OFF_P1;
    for (int g = 0; g < 16; ++g) {
        float2 wr[27];
        #pragma unroll
        for (int k = 0; k < 27; k++) wr[k] = __ldg((const float2*)&c1w[k * 32 + 2*g]);
        float2 bias  = __ldg((const float2*)&c1b[2*g]);
        float2 alpha = __ldg((const float2*)&p1a[2*g]);
        for (int task = t; task < 552; task += TPB) {
            int xg = task % 12; int cy = task / 12;
            int x0 = xg * 4;
            float2 a0 = make_float2(0.f,0.f), a1v = a0, a2 = a0, a3 = a0;
            #pragma unroll
            for (int ky = 0; ky < 3; ky++) {
                const float* row = crop + (cy + ky) * 144;
                float in[18];
                #pragma unroll
                for (int j = 0; j < 6; j++) {
                    int col = x0 + j; if (col > 47) col = 47;
                    in[j*3+0] = row[col*3+0];
                    in[j*3+1] = row[col*3+1];
                    in[j*3+2] = row[col*3+2];
                }
                #pragma unroll
                for (int kx = 0; kx < 3; kx++)
                    #pragma unroll
                    for (int ic = 0; ic < 3; ic++) {
                        float2 w = wr[(ky*3+kx)*3+ic];
                        dfma(a0,  bcast2(in[(kx+0)*3+ic]), w);
                        dfma(a1v, bcast2(in[(kx+1)*3+ic]), w);
                        dfma(a2,  bcast2(in[(kx+2)*3+ic]), w);
                        dfma(a3,  bcast2(in[(kx+3)*3+ic]), w);
                    }
            }
            float2* tp = (float2*)temp1 + cy * 46;
            float2 o;
            o.x = a0.x + bias.x; o.y = a0.y + bias.y;
            o.x = o.x >= 0.f ? o.x : alpha.x * o.x; o.y = o.y >= 0.f ? o.y : alpha.y * o.y;
            tp[x0+0] = o;
            o.x = a1v.x + bias.x; o.y = a1v.y + bias.y;
            o.x = o.x >= 0.f ? o.x : alpha.x * o.x; o.y = o.y >= 0.f ? o.y : alpha.y * o.y;
            tp[x0+1] = o;
            if (x0+2 < 46) {
                o.x = a2.x + bias.x; o.y = a2.y + bias.y;
                o.x = o.x >= 0.f ? o.x : alpha.x * o.x; o.y = o.y >= 0.f ? o.y : alpha.y * o.y;
                tp[x0+2] = o;
            }
            if (x0+3 < 46) {
                o.x = a3.x + bias.x; o.y = a3.y + bias.y;
                o.x = o.x >= 0.f ? o.x : alpha.x * o.x; o.y = o.y >= 0.f ? o.y : alpha.y * o.y;
                tp[x0+3] = o;
            }
        }
        __syncthreads();
        for (int i = t; i < 1058; i += TPB) {
            int c = i & 1; int pos = i >> 1; int px = pos % 23; int py = pos / 23;
            float m = -3.4e38f;
            #pragma unroll
            for (int dy = 0; dy < 3; dy++) {
                int cy2 = 2*py - 1 + dy; if (cy2 < 0 || cy2 >= 46) continue;
                #pragma unroll
                for (int dx = 0; dx < 3; dx++) {
                    int cx2 = 2*px - 1 + dx; if (cx2 < 0 || cx2 >= 46) continue;
                    m = fmaxf(m, temp1[(cy2*46 + cx2)*2 + c]);
                }
            }
            P1[(g*2 + c) * 529 + py * 23 + px] = m;
        }
        __syncthreads();
    }

    // ===== stage 2: conv2 3x3x32->64 + prelu + pool(3,2) -> P2 [64][10][10] =====
    // 4 groups x 16 out-ch (quad/thread), per-(ky,ic-half) staging (R9 layout, legal).
    float* w2s = sm + OFF_W;
    float* temp2 = sm + OFF_W + 768;           // 8ch x 21x21 = 3528 (two halves)
    float* b2s = sm + OFF_GAP; float* a2s = b2s + 16;
    float* P2 = sm + OFF_P2;
    for (int g = 0; g < 4; ++g) {
        if (t < 16) { b2s[t] = c2b[g*16 + t]; a2s[t] = p2a[g*16 + t]; }
        const int xg = t % 3; const int rem = t / 3;
        const int cq = rem & 3; const int cy = rem >> 2;
        const int x0 = xg * 7;
        float2 acc[2][7];
        #pragma unroll
        for (int p = 0; p < 2; p++)
            #pragma unroll
            for (int j = 0; j < 7; j++) acc[p][j] = make_float2(0.f, 0.f);
        for (int ky = 0; ky < 3; ky++) {
            for (int ih = 0; ih < 2; ih++) {
                __syncthreads();
                for (int i = t; i < 768; i += TPB) {
                    int c = i & 15; int rest = i >> 4;
                    int icl = rest & 15; int kx = rest >> 4;
                    w2s[i] = c2w[((ky*3 + kx)*32 + ih*16 + icl) * 64 + g*16 + c];
                }
                __syncthreads();
                if (t < 252) {
                    const float* inb = P1 + (ih*16)*529 + (cy + ky) * 23 + x0;
                    #pragma unroll 4
                    for (int icl = 0; icl < 16; icl++) {
                        const float* in = inb + icl * 529;
                        float2 p0 = bcast2(in[0]), p1 = bcast2(in[1]), p2 = bcast2(in[2]);
                        float2 p3 = bcast2(in[3]), p4 = bcast2(in[4]), p5 = bcast2(in[5]);
                        float2 p6 = bcast2(in[6]), p7 = bcast2(in[7]), p8 = bcast2(in[8]);
                        float2 wA0 = *(const float2*)&w2s[(0*16+icl)*16 + 4*cq];
                        float2 wB0 = *(const float2*)&w2s[(0*16+icl)*16 + 4*cq + 2];
                        float2 wA1 = *(const float2*)&w2s[(1*16+icl)*16 + 4*cq];
                        float2 wB1 = *(const float2*)&w2s[(1*16+icl)*16 + 4*cq + 2];
                        float2 wA2 = *(const float2*)&w2s[(2*16+icl)*16 + 4*cq];
                        float2 wB2 = *(const float2*)&w2s[(2*16+icl)*16 + 4*cq + 2];
                        dfma(acc[0][0],p0,wA0); dfma(acc[0][1],p1,wA0); dfma(acc[0][2],p2,wA0);
                        dfma(acc[0][3],p3,wA0); dfma(acc[0][4],p4,wA0); dfma(acc[0][5],p5,wA0); dfma(acc[0][6],p6,wA0);
                        dfma(acc[1][0],p0,wB0); dfma(acc[1][1],p1,wB0); dfma(acc[1][2],p2,wB0);
                        dfma(acc[1][3],p3,wB0); dfma(acc[1][4],p4,wB0); dfma(acc[1][5],p5,wB0); dfma(acc[1][6],p6,wB0);
                        dfma(acc[0][0],p1,wA1); dfma(acc[0][1],p2,wA1); dfma(acc[0][2],p3,wA1);
                        dfma(acc[0][3],p4,wA1); dfma(acc[0][4],p5,wA1); dfma(acc[0][5],p6,wA1); dfma(acc[0][6],p7,wA1);
                        dfma(acc[1][0],p1,wB1); dfma(acc[1][1],p2,wB1); dfma(acc[1][2],p3,wB1);
                        dfma(acc[1][3],p4,wB1); dfma(acc[1][4],p5,wB1); dfma(acc[1][5],p6,wB1); dfma(acc[1][6],p7,wB1);
                        dfma(acc[0][0],p2,wA2); dfma(acc[0][1],p3,wA2); dfma(acc[0][2],p4,wA2);
                        dfma(acc[0][3],p5,wA2); dfma(acc[0][4],p6,wA2); dfma(acc[0][5],p7,wA2); dfma(acc[0][6],p8,wA2);
                        dfma(acc[1][0],p2,wB2); dfma(acc[1][1],p3,wB2); dfma(acc[1][2],p4,wB2);
                        dfma(acc[1][3],p5,wB2); dfma(acc[1][4],p6,wB2); dfma(acc[1][5],p7,wB2); dfma(acc[1][6],p8,wB2);
                    }
                }
            }
        }
        float vb[4], va[4];
        if (t < 252) {
            #pragma unroll
            for (int k = 0; k < 4; k++) { vb[k] = b2s[4*cq + k]; va[k] = a2s[4*cq + k]; }
        }
        if (t < 252 && cq < 2) {
            #pragma unroll
            for (int p = 0; p < 2; p++) {
                float* t0 = temp2 + (4*cq + 2*p)     * 441 + cy * 21 + x0;
                float* t1 = temp2 + (4*cq + 2*p + 1) * 441 + cy * 21 + x0;
                #pragma unroll
                for (int j = 0; j < 7; j++) {
                    float v0 = acc[p][j].x + vb[2*p];
                    float v1 = acc[p][j].y + vb[2*p+1];
                    t0[j] = v0 >= 0.f ? v0 : va[2*p] * v0;
                    t1[j] = v1 >= 0.f ? v1 : va[2*p+1] * v1;
                }
            }
        }
        __syncthreads();
        for (int i = t; i < 800; i += TPB) {
            int c = i & 7; int pos = i >> 3; int px = pos % 10; int py = pos / 10;
            const float* tp = temp2 + c * 441;
            float m = -3.4e38f;
            #pragma unroll
            for (int dy = 0; dy < 3; dy++)
                #pragma unroll
                for (int dx = 0; dx < 3; dx++)
                    m = fmaxf(m, tp[(2*py+dy)*21 + 2*px+dx]);
            P2[(g*16 + c) * 100 + py * 10 + px] = m;
        }
        __syncthreads();
        if (t < 252 && cq >= 2) {
            #pragma unroll
            for (int p = 0; p < 2; p++) {
                float* t0 = temp2 + (4*(cq-2) + 2*p)     * 441 + cy * 21 + x0;
                float* t1 = temp2 + (4*(cq-2) + 2*p + 1) * 441 + cy * 21 + x0;
                #pragma unroll
                for (int j = 0; j < 7; j++) {
                    float v0 = acc[p][j].x + vb[2*p];
                    float v1 = acc[p][j].y + vb[2*p+1];
                    t0[j] = v0 >= 0.f ? v0 : va[2*p] * v0;
                    t1[j] = v1 >= 0.f ? v1 : va[2*p+1] * v1;
                }
            }
        }
        __syncthreads();
        for (int i = t; i < 800; i += TPB) {
            int c = i & 7; int pos = i >> 3; int px = pos % 10; int py = pos / 10;
            const float* tp = temp2 + c * 441;
            float m = -3.4e38f;
            #pragma unroll
            for (int dy = 0; dy < 3; dy++)
                #pragma unroll
                for (int dx = 0; dx < 3; dx++)
                    m = fmaxf(m, tp[(2*py+dy)*21 + 2*px+dx]);
            P2[(g*16 + 8 + c) * 100 + py * 10 + px] = m;
        }
        __syncthreads();
    }

    // ===== stage 3: conv3 3x3x64->64 + prelu + pool(2,2) -> P3 [64][4][4] =====
    // P1 dead -> W34 legal. Staging: all ky x ic-QUARTER: w3s 9216 floats; 4 stagings.
    float* w3s = sm + OFF_W34; float* b3s = w3s + 9216; float* a3s = b3s + 64;
    float* temp3 = sm + OFF_W;                 // 32ch x 8x8 = 2048 (two halves)
    float* P3 = sm + OFF_P3;
    {
        if (t < 64) { b3s[t] = c3b[t]; a3s[t] = p3a[t]; }
        const int cq = t & 15; const int pos = t >> 4;
        const int xg = pos & 1; const int cy = pos >> 1;
        const int x0 = xg * 4;
        float2 acc[2][4];
        #pragma unroll
        for (int p = 0; p < 2; p++)
            #pragma unroll
            for (int j = 0; j < 4; j++) acc[p][j] = make_float2(0.f, 0.f);
        for (int q = 0; q < 4; q++) {
            __syncthreads();
            for (int i = t; i < 9216; i += TPB) {
                int c = i & 63; int kidx = i >> 6;   // kidx = kk*16+icl
                int icl = kidx & 15; int kk = kidx >> 4;
                w3s[i] = c3w[(kk*64 + q*16 + icl) * 64 + c];
            }
            __syncthreads();
            #pragma unroll
            for (int ky = 0; ky < 3; ky++) {
                const float* inb = P2 + (q*16)*100 + (cy + ky) * 10 + x0;
                const float* wk = w3s + (ky*3)*1024;
                #pragma unroll 4
                for (int icl = 0; icl < 16; icl++) {
                    const float* in = inb + icl * 100;
                    float2 p0 = bcast2(in[0]), p1 = bcast2(in[1]), p2 = bcast2(in[2]);
                    float2 p3 = bcast2(in[3]), p4 = bcast2(in[4]), p5 = bcast2(in[5]);
                    float2 wA0 = *(const float2*)&wk[(0*16+icl)*64 + 4*cq];
                    float2 wB0 = *(const float2*)&wk[(0*16+icl)*64 + 4*cq + 2];
                    float2 wA1 = *(const float2*)&wk[(1*16+icl)*64 + 4*cq];
                    float2 wB1 = *(const float2*)&wk[(1*16+icl)*64 + 4*cq + 2];
                    float2 wA2 = *(const float2*)&wk[(2*16+icl)*64 + 4*cq];
                    float2 wB2 = *(const float2*)&wk[(2*16+icl)*64 + 4*cq + 2];
                    dfma(acc[0][0],p0,wA0); dfma(acc[0][1],p1,wA0); dfma(acc[0][2],p2,wA0); dfma(acc[0][3],p3,wA0);
                    dfma(acc[1][0],p0,wB0); dfma(acc[1][1],p1,wB0); dfma(acc[1][2],p2,wB0); dfma(acc[1][3],p3,wB0);
                    dfma(acc[0][0],p1,wA1); dfma(acc[0][1],p2,wA1); dfma(acc[0][2],p3,wA1); dfma(acc[0][3],p4,wA1);
                    dfma(acc[1][0],p1,wB1); dfma(acc[1][1],p2,wB1); dfma(acc[1][2],p3,wB1); dfma(acc[1][3],p4,wB1);
                    dfma(acc[0][0],p2,wA2); dfma(acc[0][1],p3,wA2); dfma(acc[0][2],p4,wA2); dfma(acc[0][3],p5,wA2);
                    dfma(acc[1][0],p2,wB2); dfma(acc[1][1],p3,wB2); dfma(acc[1][2],p4,wB2); dfma(acc[1][3],p5,wB2);
                }
            }
        }
        float vb[4], va[4];
        #pragma unroll
        for (int k = 0; k < 4; k++) { vb[k] = b3s[4*cq + k]; va[k] = a3s[4*cq + k]; }
        if (cq < 8) {
            #pragma unroll
            for (int p = 0; p < 2; p++) {
                float* t0 = temp3 + (4*cq + 2*p)     * 64 + cy * 8 + x0;
                float* t1 = temp3 + (4*cq + 2*p + 1) * 64 + cy * 8 + x0;
                #pragma unroll
                for (int j = 0; j < 4; j++) {
                    float v0 = acc[p][j].x + vb[2*p];
                    float v1 = acc[p][j].y + vb[2*p+1];
                    t0[j] = v0 >= 0.f ? v0 : va[2*p] * v0;
                    t1[j] = v1 >= 0.f ? v1 : va[2*p+1] * v1;
                }
            }
        }
        __syncthreads();
        for (int task = t; task < 512; task += TPB) {
            int c = task & 31; int pos2 = task >> 5; int px = pos2 & 3; int py = pos2 >> 2;
            const float* tp = temp3 + c * 64;
            float m = fmaxf(fmaxf(tp[(2*py)*8 + 2*px], tp[(2*py)*8 + 2*px + 1]),
                            fmaxf(tp[(2*py+1)*8 + 2*px], tp[(2*py+1)*8 + 2*px + 1]));
            P3[c * 16 + py * 4 + px] = m;
        }
        __syncthreads();
        if (cq >= 8) {
            #pragma unroll
            for (int p = 0; p < 2; p++) {
                float* t0 = temp3 + (4*(cq-8) + 2*p)     * 64 + cy * 8 + x0;
                float* t1 = temp3 + (4*(cq-8) + 2*p + 1) * 64 + cy * 8 + x0;
                #pragma unroll
                for (int j = 0; j < 4; j++) {
                    float v0 = acc[p][j].x + vb[2*p];
                    float v1 = acc[p][j].y + vb[2*p+1];
                    t0[j] = v0 >= 0.f ? v0 : va[2*p] * v0;
                    t1[j] = v1 >= 0.f ? v1 : va[2*p+1] * v1;
                }
            }
        }
        __syncthreads();
        for (int task = t; task < 512; task += TPB) {
            int c = task & 31; int pos2 = task >> 5; int px = pos2 & 3; int py = pos2 >> 2;
            const float* tp = temp3 + c * 64;
            float m = fmaxf(fmaxf(tp[(2*py)*8 + 2*px], tp[(2*py)*8 + 2*px + 1]),
                            fmaxf(tp[(2*py+1)*8 + 2*px], tp[(2*py+1)*8 + 2*px + 1]));
            P3[(32 + c) * 16 + py * 4 + px] = m;
        }
        __syncthreads();
    }

    // ===== stage 4: conv4 2x2x64->128 + prelu -> C4 flat (c*9 + y*3 + x) =====
    float* w4s = sm + OFF_W34; float* b4s = w4s + 4096; float* a4s = b4s + 64;
    float* C4 = sm + OFF_C4;
    for (int g = 0; g < 2; ++g) {
        if (t < 64) { b4s[t] = c4b[g*64 + t]; a4s[t] = p4a[g*64 + t]; }
        const int cq = t & 15; const int pos = t >> 4;
        const int y = pos / 3, x = pos % 3;
        float2 accA = make_float2(0.f,0.f), accB = accA;
        for (int k = 0; k < 4; k++) {
            __syncthreads();
            for (int i = t; i < 4096; i += TPB) {
                int c = i & 63; int ic = i >> 6;
                w4s[i] = c4w[(k*64 + ic)*128 + g*64 + c];
            }
            __syncthreads();
            if (t < 144) {
                int ky = k >> 1, kx = k & 1;
                const float* inb = P3 + (y + ky) * 4 + (x + kx);
                const float* wb  = w4s + 4*cq;
                #pragma unroll 4
                for (int ic = 0; ic < 64; ic++) {
                    float2 p = bcast2(inb[ic * 16]);
                    float2 wA = *(const float2*)&wb[ic * 64];
                    float2 wB = *(const float2*)&wb[ic * 64 + 2];
                    dfma(accA, p, wA); dfma(accB, p, wB);
                }
            }
        }
        if (t < 144) {
            int c0 = g*64 + 4*cq;
            float v0 = accA.x + b4s[4*cq+0], v1 = accA.y + b4s[4*cq+1];
            float v2 = accB.x + b4s[4*cq+2], v3 = accB.y + b4s[4*cq+3];
            float l0 = a4s[4*cq+0], l1 = a4s[4*cq+1], l2 = a4s[4*cq+2], l3 = a4s[4*cq+3];
            C4[(c0+0)*9 + pos] = v0 >= 0.f ? v0 : l0 * v0;
            C4[(c0+1)*9 + pos] = v1 >= 0.f ? v1 : l1 * v1;
            C4[(c0+2)*9 + pos] = v2 >= 0.f ? v2 : l2 * v2;
            C4[(c0+3)*9 + pos] = v3 >= 0.f ? v3 : l3 * v3;
        }
        __syncthreads();
    }

    // ===== fc5: 1152 -> 256 + prelu =====
    float* F5 = sm + OFF_F5;
    {
        int warp = t >> 5, lane = t & 31;
        for (int o = warp; o < 256; o += 8) {
            const float4* wrow = (const float4*)(f5w + o * 1152);
            float acc = 0.f;
            #pragma unroll
            for (int j = 0; j < 9; j++) {
                float4 cv = *(const float4*)&C4[j*128 + lane*4];
                float4 wv = __ldg(&wrow[j*32 + lane]);
                acc += cv.x*wv.x + cv.y*wv.y + cv.z*wv.z + cv.w*wv.w;
            }
            #pragma unroll
            for (int s = 16; s; s >>= 1) acc += __shfl_xor_sync(0xFFFFFFFFu, acc, s);
            if (lane == 0) {
                float v = acc + f5b[o];
                float al = p5a[o];
                F5[o] = v >= 0.f ? v : al * v;
            }
        }
    }
    __syncthreads();

    // ===== fc6a (2) + fc6b (4) =====
    float* FC6 = sm + OFF_FC6;
    if (t < 192) {
        int o = t >> 5, lane = t & 31;
        const float* wrow = (o < 2) ? (f6aw + o * 256) : (f6bw + (o - 2) * 256);
        float acc = 0.f;
        #pragma unroll
        for (int j = 0; j < 8; j++) { int k = lane + 32*j; acc += F5[k] * __ldg(&wrow[k]); }
        #pragma unroll
        for (int s = 16; s; s >>= 1) acc += __shfl_xor_sync(0xFFFFFFFFu, acc, s);
        if (lane == 0) FC6[o] = acc + ((o < 2) ? f6ab[o] : f6bb[o - 2]);
    }
    __syncthreads();

    if (t == 0) {
        float l0 = FC6[0], l1 = FC6[1];
        float m = fmaxf(l0, l1);
        float e0 = expf(l0 - m), e1 = expf(l1 - m);
        float score = e1 / (e0 + e1);
        float w = bx2 - bx1, h = by2 - by1;
        g_score[b] = score;
        g_box[b*4+0] = bx1 + FC6[2] * w;
        g_box[b*4+1] = by1 + FC6[3] * h;
        g_box[b*4+2] = bx2 + FC6[4] * w;
        g_box[b*4+3] = by2 + FC6[5] * h;
    }
}

// ---------- NMS: bitonic sort by (score desc, idx asc) ----------
__device__ __forceinline__ bool nms_before(float ka, int ia, float kb, int ib) {
    return (ka > kb) || (ka == kb && ia < ib);
}

__global__ __launch_bounds__(1024) void nms_sort() {
    __shared__ float kk[NBOX];
    __shared__ int   id[NBOX];
    int t = threadIdx.x;
    kk[t] = g_score[t];           id[t] = t;
    kk[t+1024] = g_score[t+1024]; id[t+1024] = t + 1024;
    for (int k = 2; k <= NBOX; k <<= 1) {
        for (int j = k >> 1; j > 0; j >>= 1) {
            __syncthreads();
            #pragma unroll 2
            for (int i = t; i < NBOX; i += 1024) {
                int ixj = i ^ j;
                if (ixj > i) {
                    float ka = kk[i], kb = kk[ixj];
                    int ia = id[i], ib = id[ixj];
                    bool up = ((i & k) == 0);
                    bool bad = up ? nms_before(kb, ib, ka, ia) : nms_before(ka, ia, kb, ib);
                    if (bad) { kk[i] = kb; kk[ixj] = ka; id[i] = ib; id[ixj] = ia; }
                }
            }
        }
    }
    __syncthreads();
    #pragma unroll 2
    for (int i = t; i < NBOX; i += 1024) {
        g_skey[i] = kk[i];
        int o = id[i];
        g_sidx[i] = o;
        g_sbox[i*4+0] = g_box[o*4+0];
        g_sbox[i*4+1] = g_box[o*4+1];
        g_sbox[i*4+2] = g_box[o*4+2];
        g_sbox[i*4+3] = g_box[o*4+3];
    }
}

// ---------- NMS: IOU bitmask ----------
__global__ __launch_bounds__(64) void nms_mask() {
    __shared__ float cb[32][4];
    int t = threadIdx.x;
    int j0 = blockIdx.x * 32;
    for (int i = t; i < 128; i += 64) cb[i >> 2][i & 3] = g_sbox[(j0 + (i >> 2)) * 4 + (i & 3)];
    __syncthreads();
    int i = blockIdx.y * 64 + t;
    float x1 = g_sbox[i*4+0], y1 = g_sbox[i*4+1], x2 = g_sbox[i*4+2], y2 = g_sbox[i*4+3];
    float area = (x2 - x1) * (y2 - y1);
    unsigned word = 0;
    #pragma unroll 8
    for (int jj = 0; jj < 32; jj++) {
        int j = j0 + jj;
        if (j > i) {
            float bx1v = cb[jj][0], by1v = cb[jj][1], bx2v = cb[jj][2], by2v = cb[jj][3];
            float xx1 = fmaxf(x1, bx1v), yy1 = fmaxf(y1, by1v);
            float xx2 = fminf(x2, bx2v), yy2 = fminf(y2, by2v);
            float inter = fmaxf(xx2 - xx1, 0.f) * fmaxf(yy2 - yy1, 0.f);
            float areab = (bx2v - bx1v) * (by2v - by1v);
            float iou = inter / (area + areab - inter + 1e-12f);
            if (iou > 0.5f) word |= (1u << jj);
        }
    }
    ((unsigned*)g_mask4)[i * 64 + blockIdx.x] = word;
}

// ---------- NMS: serial scan; uint4 streaming producers + register decision word ----------
#define SCHUNK 64
#define SNT    512
__global__ __launch_bounds__(SNT) void nms_scan(float* __restrict__ out) {
    __shared__ uint4 buf4[2][SCHUNK * 16];
    __shared__ unsigned keepw[64];
    __shared__ int sV;
    int t = threadIdx.x;
    if (t < 64) keepw[t] = 0u;
    if (t == 0) sV = 0;
    __syncthreads();
    for (int p = t; p < NBOX; p += SNT) {
        bool v = g_skey[p] >= 0.5f;
        unsigned bal = __ballot_sync(0xFFFFFFFFu, v);
        if ((t & 31) == 0) atomicAdd(&sV, __popc(bal));
    }
    __syncthreads();
    const int V = sV;
    const int nch = (V + SCHUNK - 1) / SCHUNK;
    const uint4 z4 = make_uint4(0u,0u,0u,0u);
    for (int i = t; i < SCHUNK * 16; i += SNT) {
        int p = i >> 4;
        buf4[0][i] = (p < V) ? g_mask4[i] : z4;
    }
    __syncthreads();
    unsigned r0 = 0u, r1 = 0u;
    for (int ci = 0; ci < nch; ci++) {
        if (t >= 32) {
            if (ci + 1 < nch) {
                uint4* nb = buf4[(ci + 1) & 1];
                int pb = (ci + 1) * SCHUNK;
                for (int i = t - 32; i < SCHUNK * 16; i += (SNT - 32)) {
                    int p = pb + (i >> 4);
                    nb[i] = (p < V) ? g_mask4[p * 16 + (i & 15)] : z4;
                }
            }
        } else {
            const unsigned* B = (const unsigned*)buf4[ci & 1];
            int pb = ci * SCHUNK;
            #pragma unroll
            for (int r = 0; r < 2; r++) {
                int rb = pb + r * 32;
                if (rb >= V) break;
                int w = rb >> 5;
                int lim = min(32, V - rb);
                unsigned dw = (w < 32) ? __shfl_sync(0xFFFFFFFFu, r0, w)
                                       : __shfl_sync(0xFFFFFFFFu, r1, w - 32);
                for (int jb = 0; jb < lim; jb += 8) {
                    unsigned qa[8], qb[8], qw[8];
                    #pragma unroll
                    for (int j = 0; j < 8; j++) {
                        int jj = r * 32 + jb + j;
                        bool ok = (jb + j) < lim;
                        qa[j] = ok ? B[jj*64 + t]      : 0u;
                        qb[j] = ok ? B[jj*64 + 32 + t] : 0u;
                        qw[j] = ok ? B[jj*64 + w]      : 0u;
                    }
                    #pragma unroll
                    for (int j = 0; j < 8; j++) {
                        int bb = jb + j;
                        unsigned m = ((dw >> bb) & 1u) - 1u;
                        dw |= qw[j] & m;
                        r0 |= qa[j] & m;
                        r1 |= qb[j] & m;
                    }
                }
                if (t == 0) {
                    unsigned vmask = (lim >= 32) ? 0xFFFFFFFFu : ((1u << lim) - 1u);
                    keepw[w] = (~dw) & vmask;
                }
            }
        }
        __syncthreads();
    }
    for (int i = t; i < NBOX * 4; i += SNT) out[i] = 0.f;
    __syncthreads();
    for (int p = t; p < NBOX; p += SNT) {
        if ((keepw[p >> 5] >> (p & 31)) & 1u) {
            int o = g_sidx[p];
            out[o*4+0] = g_sbox[p*4+0];
            out[o*4+1] = g_sbox[p*4+1];
            out[o*4+2] = g_sbox[p*4+2];
            out[o*4+3] = g_sbox[p*4+3];
        }
    }
}

extern "C" void kernel_launch(void* const* d_in, const int* in_sizes, int n_in,
                              void* d_out, int out_size) {
    (void)in_sizes; (void)n_in; (void)out_size;
    cudaFuncSetAttribute(onet_cnn, cudaFuncAttributeMaxDynamicSharedMemorySize, SMEM1_FLOATS * 4);
    onet_cnn<<<NBOX, TPB, SMEM1_FLOATS * 4>>>(
        (const float*)d_in[0],  (const float*)d_in[1],
        (const float*)d_in[2],  (const float*)d_in[3],  (const float*)d_in[4],
        (const float*)d_in[5],  (const float*)d_in[6],  (const float*)d_in[7],
        (const float*)d_in[8],  (const float*)d_in[9],  (const float*)d_in[10],
        (const float*)d_in[11], (const float*)d_in[12], (const float*)d_in[13],
        (const float*)d_in[14], (const float*)d_in[15], (const float*)d_in[16],
        (const float*)d_in[17], (const float*)d_in[18],
        (const float*)d_in[19], (const float*)d_in[20]);
    nms_sort<<<1, 1024>>>();
    nms_mask<<<dim3(64, 32), 64>>>();
    nms_scan<<<1, SNT>>>((float*)d_out);
}

// round 13
// speedup vs baseline: 2.1922x; 1.0034x over previous
#include <cuda_runtime.h>
#include <cuda_bf16.h>
#include <math.h>

#define NBOX 2048
#define TPB  256

// shared arena offsets (floats) — liveness: crop/P2 @0 (crop s1; P2 s3+),
// P1 @6912 live s1-s2 (dead s3+ -> P3/C4/F5/FC6/W34), small scratch @23840 always free.
#define OFF_CROP   0
#define OFF_P2     0
#define OFF_GAP    6400
#define OFF_P1     6912
#define OFF_P3     6912
#define OFF_C4     7936
#define OFF_F5     9088
#define OFF_FC6    9344
#define OFF_W34    9472     // stage3/4 ONLY (inside dead-P1 region)
#define OFF_W      23840    // stage1/2/3 small scratch (4312 floats)
#define SMEM1_FLOATS 28152  // 112,608 bytes -> 2 CTAs/SM

__device__ float    g_score[NBOX];
__device__ float    g_box[NBOX * 4];
__device__ float    g_skey[NBOX];
__device__ int      g_sidx[NBOX];
__device__ float    g_sbox[NBOX * 4];
__device__ uint4    g_mask4[NBOX * 16];

// packed dual fp32 FMA: c += a*b per lane (FFMA2)
__device__ __forceinline__ void dfma(float2& c, float2 a, float2 b) {
    asm("fma.rn.f32x2 %0, %1, %2, %0;"
        : "+l"(reinterpret_cast<unsigned long long&>(c))
        : "l"(reinterpret_cast<unsigned long long&>(a)),
          "l"(reinterpret_cast<unsigned long long&>(b)));
}
__device__ __forceinline__ float2 bcast2(float v) { return make_float2(v, v); }

__global__ __launch_bounds__(TPB, 2) void onet_cnn(
    const float* __restrict__ bboxes, const float* __restrict__ image,
    const float* __restrict__ c1w, const float* __restrict__ c1b, const float* __restrict__ p1a,
    const float* __restrict__ c2w, const float* __restrict__ c2b, const float* __restrict__ p2a,
    const float* __restrict__ c3w, const float* __restrict__ c3b, const float* __restrict__ p3a,
    const float* __restrict__ c4w, const float* __restrict__ c4b, const float* __restrict__ p4a,
    const float* __restrict__ f5w, const float* __restrict__ f5b, const float* __restrict__ p5a,
    const float* __restrict__ f6aw, const float* __restrict__ f6ab,
    const float* __restrict__ f6bw, const float* __restrict__ f6bb)
{
    extern __shared__ float sm[];
    const int t = threadIdx.x;
    const int b = blockIdx.x;

    float B0 = bboxes[b*4+0], B1 = bboxes[b*4+1], B2 = bboxes[b*4+2], B3 = bboxes[b*4+3];
    float bx1 = fmaxf(B0, 0.f), by1 = fmaxf(B1, 0.f);
    float bx2 = fminf(B2, 1024.f), by2 = fminf(B3, 1024.f);
    int ix1 = (int)bx1, iy1 = (int)by1, ix2 = (int)bx2, iy2 = (int)by2;
    int cw = max(ix2 - ix1, 1), ch = max(iy2 - iy1, 1);

    // ---- crop 48x48x3 HWC ----
    float* crop = sm + OFF_CROP;
    for (int i = t; i < 2304; i += TPB) {
        int x = i % 48; int y = i / 48;
        int gx = ix1 + (x * cw) / 48;
        int gy = iy1 + (y * ch) / 48;
        const float* src = image + (gy * 1024 + gx) * 3;
        float* dst = crop + i * 3;
        dst[0] = (__ldg(&src[0]) - 127.5f) * 0.0078125f;
        dst[1] = (__ldg(&src[1]) - 127.5f) * 0.0078125f;
        dst[2] = (__ldg(&src[2]) - 127.5f) * 0.0078125f;
    }
    __syncthreads();

    // ===== stage 1: conv1 3x3x3->32 + prelu + pool(3,2,pad1) -> P1 [32][23][23] =====
    float* temp1 = sm + OFF_W;                 // 4232 floats (float2-interleaved 46x46)
    float* P1 = sm + OFF_P1;
    for (int g = 0; g < 16; ++g) {
        float2 wr[27];
        #pragma unroll
        for (int k = 0; k < 27; k++) wr[k] = __ldg((const float2*)&c1w[k * 32 + 2*g]);
        float2 bias  = __ldg((const float2*)&c1b[2*g]);
        float2 alpha = __ldg((const float2*)&p1a[2*g]);
        for (int task = t; task < 552; task += TPB) {
            int xg = task % 12; int cy = task / 12;
            int x0 = xg * 4;
            float2 a0 = make_float2(0.f,0.f), a1v = a0, a2 = a0, a3 = a0;
            #pragma unroll
            for (int ky = 0; ky < 3; ky++) {
                const float* row = crop + (cy + ky) * 144;
                float in[18];
                #pragma unroll
                for (int j = 0; j < 6; j++) {
                    int col = x0 + j; if (col > 47) col = 47;
                    in[j*3+0] = row[col*3+0];
                    in[j*3+1] = row[col*3+1];
                    in[j*3+2] = row[col*3+2];
                }
                #pragma unroll
                for (int kx = 0; kx < 3; kx++)
                    #pragma unroll
                    for (int ic = 0; ic < 3; ic++) {
                        float2 w = wr[(ky*3+kx)*3+ic];
                        dfma(a0,  bcast2(in[(kx+0)*3+ic]), w);
                        dfma(a1v, bcast2(in[(kx+1)*3+ic]), w);
                        dfma(a2,  bcast2(in[(kx+2)*3+ic]), w);
                        dfma(a3,  bcast2(in[(kx+3)*3+ic]), w);
                    }
            }
            float2* tp = (float2*)temp1 + cy * 46;
            float2 o;
            o.x = a0.x + bias.x; o.y = a0.y + bias.y;
            o.x = o.x >= 0.f ? o.x : alpha.x * o.x; o.y = o.y >= 0.f ? o.y : alpha.y * o.y;
            tp[x0+0] = o;
            o.x = a1v.x + bias.x; o.y = a1v.y + bias.y;
            o.x = o.x >= 0.f ? o.x : alpha.x * o.x; o.y = o.y >= 0.f ? o.y : alpha.y * o.y;
            tp[x0+1] = o;
            if (x0+2 < 46) {
                o.x = a2.x + bias.x; o.y = a2.y + bias.y;
                o.x = o.x >= 0.f ? o.x : alpha.x * o.x; o.y = o.y >= 0.f ? o.y : alpha.y * o.y;
                tp[x0+2] = o;
            }
            if (x0+3 < 46) {
                o.x = a3.x + bias.x; o.y = a3.y + bias.y;
                o.x = o.x >= 0.f ? o.x : alpha.x * o.x; o.y = o.y >= 0.f ? o.y : alpha.y * o.y;
                tp[x0+3] = o;
            }
        }
        __syncthreads();
        for (int i = t; i < 1058; i += TPB) {
            int c = i & 1; int pos = i >> 1; int px = pos % 23; int py = pos / 23;
            float m = -3.4e38f;
            #pragma unroll
            for (int dy = 0; dy < 3; dy++) {
                int cy2 = 2*py - 1 + dy; if (cy2 < 0 || cy2 >= 46) continue;
                #pragma unroll
                for (int dx = 0; dx < 3; dx++) {
                    int cx2 = 2*px - 1 + dx; if (cx2 < 0 || cx2 >= 46) continue;
                    m = fmaxf(m, temp1[(cy2*46 + cx2)*2 + c]);
                }
            }
            P1[(g*2 + c) * 529 + py * 23 + px] = m;
        }
        __syncthreads();
    }

    // ===== stage 2: conv2 3x3x32->64 + prelu + pool(3,2) -> P2 [64][10][10] =====
    float* w2s = sm + OFF_W;
    float* temp2 = sm + OFF_W + 768;           // 8ch x 21x21 = 3528 (two halves)
    float* b2s = sm + OFF_GAP; float* a2s = b2s + 16;
    float* P2 = sm + OFF_P2;
    for (int g = 0; g < 4; ++g) {
        if (t < 16) { b2s[t] = c2b[g*16 + t]; a2s[t] = p2a[g*16 + t]; }
        const int xg = t % 3; const int rem = t / 3;
        const int cq = rem & 3; const int cy = rem >> 2;
        const int x0 = xg * 7;
        float2 acc[2][7];
        #pragma unroll
        for (int p = 0; p < 2; p++)
            #pragma unroll
            for (int j = 0; j < 7; j++) acc[p][j] = make_float2(0.f, 0.f);
        for (int ky = 0; ky < 3; ky++) {
            for (int ih = 0; ih < 2; ih++) {
                __syncthreads();
                for (int i = t; i < 768; i += TPB) {
                    int c = i & 15; int rest = i >> 4;
                    int icl = rest & 15; int kx = rest >> 4;
                    w2s[i] = c2w[((ky*3 + kx)*32 + ih*16 + icl) * 64 + g*16 + c];
                }
                __syncthreads();
                if (t < 252) {
                    const float* inb = P1 + (ih*16)*529 + (cy + ky) * 23 + x0;
                    const float* wb = w2s + 4*cq;
                    #pragma unroll
                    for (int icl = 0; icl < 16; icl++) {
                        const float* in = inb + icl * 529;
                        float2 p0 = bcast2(in[0]), p1 = bcast2(in[1]), p2 = bcast2(in[2]);
                        float2 p3 = bcast2(in[3]), p4 = bcast2(in[4]), p5 = bcast2(in[5]);
                        float2 p6 = bcast2(in[6]), p7 = bcast2(in[7]), p8 = bcast2(in[8]);
                        float2 wA0 = *(const float2*)&wb[(0*16+icl)*16];
                        float2 wB0 = *(const float2*)&wb[(0*16+icl)*16 + 2];
                        float2 wA1 = *(const float2*)&wb[(1*16+icl)*16];
                        float2 wB1 = *(const float2*)&wb[(1*16+icl)*16 + 2];
                        float2 wA2 = *(const float2*)&wb[(2*16+icl)*16];
                        float2 wB2 = *(const float2*)&wb[(2*16+icl)*16 + 2];
                        dfma(acc[0][0],p0,wA0); dfma(acc[0][1],p1,wA0); dfma(acc[0][2],p2,wA0);
                        dfma(acc[0][3],p3,wA0); dfma(acc[0][4],p4,wA0); dfma(acc[0][5],p5,wA0); dfma(acc[0][6],p6,wA0);
                        dfma(acc[1][0],p0,wB0); dfma(acc[1][1],p1,wB0); dfma(acc[1][2],p2,wB0);
                        dfma(acc[1][3],p3,wB0); dfma(acc[1][4],p4,wB0); dfma(acc[1][5],p5,wB0); dfma(acc[1][6],p6,wB0);
                        dfma(acc[0][0],p1,wA1); dfma(acc[0][1],p2,wA1); dfma(acc[0][2],p3,wA1);
                        dfma(acc[0][3],p4,wA1); dfma(acc[0][4],p5,wA1); dfma(acc[0][5],p6,wA1); dfma(acc[0][6],p7,wA1);
                        dfma(acc[1][0],p1,wB1); dfma(acc[1][1],p2,wB1); dfma(acc[1][2],p3,wB1);
                        dfma(acc[1][3],p4,wB1); dfma(acc[1][4],p5,wB1); dfma(acc[1][5],p6,wB1); dfma(acc[1][6],p7,wB1);
                        dfma(acc[0][0],p2,wA2); dfma(acc[0][1],p3,wA2); dfma(acc[0][2],p4,wA2);
                        dfma(acc[0][3],p5,wA2); dfma(acc[0][4],p6,wA2); dfma(acc[0][5],p7,wA2); dfma(acc[0][6],p8,wA2);
                        dfma(acc[1][0],p2,wB2); dfma(acc[1][1],p3,wB2); dfma(acc[1][2],p4,wB2);
                        dfma(acc[1][3],p5,wB2); dfma(acc[1][4],p6,wB2); dfma(acc[1][5],p7,wB2); dfma(acc[1][6],p8,wB2);
                    }
                }
            }
        }
        float vb[4], va[4];
        if (t < 252) {
            #pragma unroll
            for (int k = 0; k < 4; k++) { vb[k] = b2s[4*cq + k]; va[k] = a2s[4*cq + k]; }
        }
        if (t < 252 && cq < 2) {
            #pragma unroll
            for (int p = 0; p < 2; p++) {
                float* t0 = temp2 + (4*cq + 2*p)     * 441 + cy * 21 + x0;
                float* t1 = temp2 + (4*cq + 2*p + 1) * 441 + cy * 21 + x0;
                #pragma unroll
                for (int j = 0; j < 7; j++) {
                    float v0 = acc[p][j].x + vb[2*p];
                    float v1 = acc[p][j].y + vb[2*p+1];
                    t0[j] = v0 >= 0.f ? v0 : va[2*p] * v0;
                    t1[j] = v1 >= 0.f ? v1 : va[2*p+1] * v1;
                }
            }
        }
        __syncthreads();
        for (int i = t; i < 800; i += TPB) {
            int c = i & 7; int pos = i >> 3; int px = pos % 10; int py = pos / 10;
            const float* tp = temp2 + c * 441;
            float m = -3.4e38f;
            #pragma unroll
            for (int dy = 0; dy < 3; dy++)
                #pragma unroll
                for (int dx = 0; dx < 3; dx++)
                    m = fmaxf(m, tp[(2*py+dy)*21 + 2*px+dx]);
            P2[(g*16 + c) * 100 + py * 10 + px] = m;
        }
        __syncthreads();
        if (t < 252 && cq >= 2) {
            #pragma unroll
            for (int p = 0; p < 2; p++) {
                float* t0 = temp2 + (4*(cq-2) + 2*p)     * 441 + cy * 21 + x0;
                float* t1 = temp2 + (4*(cq-2) + 2*p + 1) * 441 + cy * 21 + x0;
                #pragma unroll
                for (int j = 0; j < 7; j++) {
                    float v0 = acc[p][j].x + vb[2*p];
                    float v1 = acc[p][j].y + vb[2*p+1];
                    t0[j] = v0 >= 0.f ? v0 : va[2*p] * v0;
                    t1[j] = v1 >= 0.f ? v1 : va[2*p+1] * v1;
                }
            }
        }
        __syncthreads();
        for (int i = t; i < 800; i += TPB) {
            int c = i & 7; int pos = i >> 3; int px = pos % 10; int py = pos / 10;
            const float* tp = temp2 + c * 441;
            float m = -3.4e38f;
            #pragma unroll
            for (int dy = 0; dy < 3; dy++)
                #pragma unroll
                for (int dx = 0; dx < 3; dx++)
                    m = fmaxf(m, tp[(2*py+dy)*21 + 2*px+dx]);
            P2[(g*16 + 8 + c) * 100 + py * 10 + px] = m;
        }
        __syncthreads();
    }

    // ===== stage 3: conv3 3x3x64->64 + prelu + pool(2,2) -> P3 [64][4][4] =====
    float* w3s = sm + OFF_W34; float* b3s = w3s + 9216; float* a3s = b3s + 64;
    float* temp3 = sm + OFF_W;                 // 32ch x 8x8 = 2048 (two halves)
    float* P3 = sm + OFF_P3;
    {
        if (t < 64) { b3s[t] = c3b[t]; a3s[t] = p3a[t]; }
        const int cq = t & 15; const int pos = t >> 4;
        const int xg = pos & 1; const int cy = pos >> 1;
        const int x0 = xg * 4;
        float2 acc[2][4];
        #pragma unroll
        for (int p = 0; p < 2; p++)
            #pragma unroll
            for (int j = 0; j < 4; j++) acc[p][j] = make_float2(0.f, 0.f);
        for (int q = 0; q < 4; q++) {
            __syncthreads();
            for (int i = t; i < 9216; i += TPB) {
                int c = i & 63; int kidx = i >> 6;
                int icl = kidx & 15; int kk = kidx >> 4;
                w3s[i] = c3w[(kk*64 + q*16 + icl) * 64 + c];
            }
            __syncthreads();
            #pragma unroll
            for (int ky = 0; ky < 3; ky++) {
                const float* inb = P2 + (q*16)*100 + (cy + ky) * 10 + x0;
                const float* wk = w3s + (ky*3)*1024 + 4*cq;
                #pragma unroll
                for (int icl = 0; icl < 16; icl++) {
                    const float* in = inb + icl * 100;
                    float2 p0 = bcast2(in[0]), p1 = bcast2(in[1]), p2 = bcast2(in[2]);
                    float2 p3 = bcast2(in[3]), p4 = bcast2(in[4]), p5 = bcast2(in[5]);
                    float2 wA0 = *(const float2*)&wk[(0*16+icl)*64];
                    float2 wB0 = *(const float2*)&wk[(0*16+icl)*64 + 2];
                    float2 wA1 = *(const float2*)&wk[(1*16+icl)*64];
                    float2 wB1 = *(const float2*)&wk[(1*16+icl)*64 + 2];
                    float2 wA2 = *(const float2*)&wk[(2*16+icl)*64];
                    float2 wB2 = *(const float2*)&wk[(2*16+icl)*64 + 2];
                    dfma(acc[0][0],p0,wA0); dfma(acc[0][1],p1,wA0); dfma(acc[0][2],p2,wA0); dfma(acc[0][3],p3,wA0);
                    dfma(acc[1][0],p0,wB0); dfma(acc[1][1],p1,wB0); dfma(acc[1][2],p2,wB0); dfma(acc[1][3],p3,wB0);
                    dfma(acc[0][0],p1,wA1); dfma(acc[0][1],p2,wA1); dfma(acc[0][2],p3,wA1); dfma(acc[0][3],p4,wA1);
                    dfma(acc[1][0],p1,wB1); dfma(acc[1][1],p2,wB1); dfma(acc[1][2],p3,wB1); dfma(acc[1][3],p4,wB1);
                    dfma(acc[0][0],p2,wA2); dfma(acc[0][1],p3,wA2); dfma(acc[0][2],p4,wA2); dfma(acc[0][3],p5,wA2);
                    dfma(acc[1][0],p2,wB2); dfma(acc[1][1],p3,wB2); dfma(acc[1][2],p4,wB2); dfma(acc[1][3],p5,wB2);
                }
            }
        }
        float vb[4], va[4];
        #pragma unroll
        for (int k = 0; k < 4; k++) { vb[k] = b3s[4*cq + k]; va[k] = a3s[4*cq + k]; }
        if (cq < 8) {
            #pragma unroll
            for (int p = 0; p < 2; p++) {
                float* t0 = temp3 + (4*cq + 2*p)     * 64 + cy * 8 + x0;
                float* t1 = temp3 + (4*cq + 2*p + 1) * 64 + cy * 8 + x0;
                #pragma unroll
                for (int j = 0; j < 4; j++) {
                    float v0 = acc[p][j].x + vb[2*p];
                    float v1 = acc[p][j].y + vb[2*p+1];
                    t0[j] = v0 >= 0.f ? v0 : va[2*p] * v0;
                    t1[j] = v1 >= 0.f ? v1 : va[2*p+1] * v1;
                }
            }
        }
        __syncthreads();
        for (int task = t; task < 512; task += TPB) {
            int c = task & 31; int pos2 = task >> 5; int px = pos2 & 3; int py = pos2 >> 2;
            const float* tp = temp3 + c * 64;
            float m = fmaxf(fmaxf(tp[(2*py)*8 + 2*px], tp[(2*py)*8 + 2*px + 1]),
                            fmaxf(tp[(2*py+1)*8 + 2*px], tp[(2*py+1)*8 + 2*px + 1]));
            P3[c * 16 + py * 4 + px] = m;
        }
        __syncthreads();
        if (cq >= 8) {
            #pragma unroll
            for (int p = 0; p < 2; p++) {
                float* t0 = temp3 + (4*(cq-8) + 2*p)     * 64 + cy * 8 + x0;
                float* t1 = temp3 + (4*(cq-8) + 2*p + 1) * 64 + cy * 8 + x0;
                #pragma unroll
                for (int j = 0; j < 4; j++) {
                    float v0 = acc[p][j].x + vb[2*p];
                    float v1 = acc[p][j].y + vb[2*p+1];
                    t0[j] = v0 >= 0.f ? v0 : va[2*p] * v0;
                    t1[j] = v1 >= 0.f ? v1 : va[2*p+1] * v1;
                }
            }
        }
        __syncthreads();
        for (int task = t; task < 512; task += TPB) {
            int c = task & 31; int pos2 = task >> 5; int px = pos2 & 3; int py = pos2 >> 2;
            const float* tp = temp3 + c * 64;
            float m = fmaxf(fmaxf(tp[(2*py)*8 + 2*px], tp[(2*py)*8 + 2*px + 1]),
                            fmaxf(tp[(2*py+1)*8 + 2*px], tp[(2*py+1)*8 + 2*px + 1]));
            P3[(32 + c) * 16 + py * 4 + px] = m;
        }
        __syncthreads();
    }

    // ===== stage 4: conv4 2x2x64->128 + prelu -> C4 flat (c*9 + y*3 + x) =====
    float* w4s = sm + OFF_W34; float* b4s = w4s + 4096; float* a4s = b4s + 64;
    float* C4 = sm + OFF_C4;
    for (int g = 0; g < 2; ++g) {
        if (t < 64) { b4s[t] = c4b[g*64 + t]; a4s[t] = p4a[g*64 + t]; }
        const int cq = t & 15; const int pos = t >> 4;
        const int y = pos / 3, x = pos % 3;
        float2 accA = make_float2(0.f,0.f), accB = accA;
        for (int k = 0; k < 4; k++) {
            __syncthreads();
            for (int i = t; i < 4096; i += TPB) {
                int c = i & 63; int ic = i >> 6;
                w4s[i] = c4w[(k*64 + ic)*128 + g*64 + c];
            }
            __syncthreads();
            if (t < 144) {
                int ky = k >> 1, kx = k & 1;
                const float* inb = P3 + (y + ky) * 4 + (x + kx);
                const float* wb  = w4s + 4*cq;
                #pragma unroll
                for (int ic = 0; ic < 64; ic++) {
                    float2 p = bcast2(inb[ic * 16]);
                    float2 wA = *(const float2*)&wb[ic * 64];
                    float2 wB = *(const float2*)&wb[ic * 64 + 2];
                    dfma(accA, p, wA); dfma(accB, p, wB);
                }
            }
        }
        if (t < 144) {
            int c0 = g*64 + 4*cq;
            float v0 = accA.x + b4s[4*cq+0], v1 = accA.y + b4s[4*cq+1];
            float v2 = accB.x + b4s[4*cq+2], v3 = accB.y + b4s[4*cq+3];
            float l0 = a4s[4*cq+0], l1 = a4s[4*cq+1], l2 = a4s[4*cq+2], l3 = a4s[4*cq+3];
            C4[(c0+0)*9 + pos] = v0 >= 0.f ? v0 : l0 * v0;
            C4[(c0+1)*9 + pos] = v1 >= 0.f ? v1 : l1 * v1;
            C4[(c0+2)*9 + pos] = v2 >= 0.f ? v2 : l2 * v2;
            C4[(c0+3)*9 + pos] = v3 >= 0.f ? v3 : l3 * v3;
        }
        __syncthreads();
    }

    // ===== fc5: 1152 -> 256 + prelu =====
    float* F5 = sm + OFF_F5;
    {
        int warp = t >> 5, lane = t & 31;
        for (int o = warp; o < 256; o += 8) {
            const float4* wrow = (const float4*)(f5w + o * 1152);
            float acc = 0.f;
            #pragma unroll
            for (int j = 0; j < 9; j++) {
                float4 cv = *(const float4*)&C4[j*128 + lane*4];
                float4 wv = __ldg(&wrow[j*32 + lane]);
                acc += cv.x*wv.x + cv.y*wv.y + cv.z*wv.z + cv.w*wv.w;
            }
            #pragma unroll
            for (int s = 16; s; s >>= 1) acc += __shfl_xor_sync(0xFFFFFFFFu, acc, s);
            if (lane == 0) {
                float v = acc + f5b[o];
                float al = p5a[o];
                F5[o] = v >= 0.f ? v : al * v;
            }
        }
    }
    __syncthreads();

    // ===== fc6a (2) + fc6b (4) =====
    float* FC6 = sm + OFF_FC6;
    if (t < 192) {
        int o = t >> 5, lane = t & 31;
        const float* wrow = (o < 2) ? (f6aw + o * 256) : (f6bw + (o - 2) * 256);
        float acc = 0.f;
        #pragma unroll
        for (int j = 0; j < 8; j++) { int k = lane + 32*j; acc += F5[k] * __ldg(&wrow[k]); }
        #pragma unroll
        for (int s = 16; s; s >>= 1) acc += __shfl_xor_sync(0xFFFFFFFFu, acc, s);
        if (lane == 0) FC6[o] = acc + ((o < 2) ? f6ab[o] : f6bb[o - 2]);
    }
    __syncthreads();

    if (t == 0) {
        float l0 = FC6[0], l1 = FC6[1];
        float m = fmaxf(l0, l1);
        float e0 = expf(l0 - m), e1 = expf(l1 - m);
        float score = e1 / (e0 + e1);
        float w = bx2 - bx1, h = by2 - by1;
        g_score[b] = score;
        g_box[b*4+0] = bx1 + FC6[2] * w;
        g_box[b*4+1] = by1 + FC6[3] * h;
        g_box[b*4+2] = bx2 + FC6[4] * w;
        g_box[b*4+3] = by2 + FC6[5] * h;
    }
}

// ---------- NMS: bitonic sort by (score desc, idx asc) ----------
__device__ __forceinline__ bool nms_before(float ka, int ia, float kb, int ib) {
    return (ka > kb) || (ka == kb && ia < ib);
}

__global__ __launch_bounds__(1024) void nms_sort() {
    __shared__ float kk[NBOX];
    __shared__ int   id[NBOX];
    int t = threadIdx.x;
    kk[t] = g_score[t];           id[t] = t;
    kk[t+1024] = g_score[t+1024]; id[t+1024] = t + 1024;
    for (int k = 2; k <= NBOX; k <<= 1) {
        for (int j = k >> 1; j > 0; j >>= 1) {
            __syncthreads();
            #pragma unroll 2
            for (int i = t; i < NBOX; i += 1024) {
                int ixj = i ^ j;
                if (ixj > i) {
                    float ka = kk[i], kb = kk[ixj];
                    int ia = id[i], ib = id[ixj];
                    bool up = ((i & k) == 0);
                    bool bad = up ? nms_before(kb, ib, ka, ia) : nms_before(ka, ia, kb, ib);
                    if (bad) { kk[i] = kb; kk[ixj] = ka; id[i] = ib; id[ixj] = ia; }
                }
            }
        }
    }
    __syncthreads();
    #pragma unroll 2
    for (int i = t; i < NBOX; i += 1024) {
        g_skey[i] = kk[i];
        int o = id[i];
        g_sidx[i] = o;
        g_sbox[i*4+0] = g_box[o*4+0];
        g_sbox[i*4+1] = g_box[o*4+1];
        g_sbox[i*4+2] = g_box[o*4+2];
        g_sbox[i*4+3] = g_box[o*4+3];
    }
}

// ---------- NMS: IOU bitmask ----------
__global__ __launch_bounds__(64) void nms_mask() {
    __shared__ float cb[32][4];
    int t = threadIdx.x;
    int j0 = blockIdx.x * 32;
    for (int i = t; i < 128; i += 64) cb[i >> 2][i & 3] = g_sbox[(j0 + (i >> 2)) * 4 + (i & 3)];
    __syncthreads();
    int i = blockIdx.y * 64 + t;
    float x1 = g_sbox[i*4+0], y1 = g_sbox[i*4+1], x2 = g_sbox[i*4+2], y2 = g_sbox[i*4+3];
    float area = (x2 - x1) * (y2 - y1);
    unsigned word = 0;
    #pragma unroll 8
    for (int jj = 0; jj < 32; jj++) {
        int j = j0 + jj;
        if (j > i) {
            float bx1v = cb[jj][0], by1v = cb[jj][1], bx2v = cb[jj][2], by2v = cb[jj][3];
            float xx1 = fmaxf(x1, bx1v), yy1 = fmaxf(y1, by1v);
            float xx2 = fminf(x2, bx2v), yy2 = fminf(y2, by2v);
            float inter = fmaxf(xx2 - xx1, 0.f) * fmaxf(yy2 - yy1, 0.f);
            float areab = (bx2v - bx1v) * (by2v - by1v);
            float iou = inter / (area + areab - inter + 1e-12f);
            if (iou > 0.5f) word |= (1u << jj);
        }
    }
    ((unsigned*)g_mask4)[i * 64 + blockIdx.x] = word;
}

// ---------- NMS: serial scan; uint4 streaming producers + register decision word ----------
#define SCHUNK 64
#define SNT    512
__global__ __launch_bounds__(SNT) void nms_scan(float* __restrict__ out) {
    __shared__ uint4 buf4[2][SCHUNK * 16];
    __shared__ unsigned keepw[64];
    __shared__ int sV;
    int t = threadIdx.x;
    if (t < 64) keepw[t] = 0u;
    if (t == 0) sV = 0;
    __syncthreads();
    for (int p = t; p < NBOX; p += SNT) {
        bool v = g_skey[p] >= 0.5f;
        unsigned bal = __ballot_sync(0xFFFFFFFFu, v);
        if ((t & 31) == 0) atomicAdd(&sV, __popc(bal));
    }
    __syncthreads();
    const int V = sV;
    const int nch = (V + SCHUNK - 1) / SCHUNK;
    const uint4 z4 = make_uint4(0u,0u,0u,0u);
    for (int i = t; i < SCHUNK * 16; i += SNT) {
        int p = i >> 4;
        buf4[0][i] = (p < V) ? g_mask4[i] : z4;
    }
    __syncthreads();
    unsigned r0 = 0u, r1 = 0u;
    for (int ci = 0; ci < nch; ci++) {
        if (t >= 32) {
            if (ci + 1 < nch) {
                uint4* nb = buf4[(ci + 1) & 1];
                int pb = (ci + 1) * SCHUNK;
                for (int i = t - 32; i < SCHUNK * 16; i += (SNT - 32)) {
                    int p = pb + (i >> 4);
                    nb[i] = (p < V) ? g_mask4[p * 16 + (i & 15)] : z4;
                }
            }
        } else {
            const unsigned* B = (const unsigned*)buf4[ci & 1];
            int pb = ci * SCHUNK;
            #pragma unroll
            for (int r = 0; r < 2; r++) {
                int rb = pb + r * 32;
                if (rb >= V) break;
                int w = rb >> 5;
                int lim = min(32, V - rb);
                unsigned dw = (w < 32) ? __shfl_sync(0xFFFFFFFFu, r0, w)
                                       : __shfl_sync(0xFFFFFFFFu, r1, w - 32);
                for (int jb = 0; jb < lim; jb += 8) {
                    unsigned qa[8], qb[8], qw[8];
                    #pragma unroll
                    for (int j = 0; j < 8; j++) {
                        int jj = r * 32 + jb + j;
                        bool ok = (jb + j) < lim;
                        qa[j] = ok ? B[jj*64 + t]      : 0u;
                        qb[j] = ok ? B[jj*64 + 32 + t] : 0u;
                        qw[j] = ok ? B[jj*64 + w]      : 0u;
                    }
                    #pragma unroll
                    for (int j = 0; j < 8; j++) {
                        int bb = jb + j;
                        unsigned m = ((dw >> bb) & 1u) - 1u;
                        dw |= qw[j] & m;
                        r0 |= qa[j] & m;
                        r1 |= qb[j] & m;
                    }
                }
                if (t == 0) {
                    unsigned vmask = (lim >= 32) ? 0xFFFFFFFFu : ((1u << lim) - 1u);
                    keepw[w] = (~dw) & vmask;
                }
            }
        }
        __syncthreads();
    }
    for (int i = t; i < NBOX * 4; i += SNT) out[i] = 0.f;
    __syncthreads();
    for (int p = t; p < NBOX; p += SNT) {
        if ((keepw[p >> 5] >> (p & 31)) & 1u) {
            int o = g_sidx[p];
            out[o*4+0] = g_sbox[p*4+0];
            out[o*4+1] = g_sbox[p*4+1];
            out[o*4+2] = g_sbox[p*4+2];
            out[o*4+3] = g_sbox[p*4+3];
        }
    }
}

extern "C" void kernel_launch(void* const* d_in, const int* in_sizes, int n_in,
                              void* d_out, int out_size) {
    (void)in_sizes; (void)n_in; (void)out_size;
    cudaFuncSetAttribute(onet_cnn, cudaFuncAttributeMaxDynamicSharedMemorySize, SMEM1_FLOATS * 4);
    onet_cnn<<<NBOX, TPB, SMEM1_FLOATS * 4>>>(
        (const float*)d_in[0],  (const float*)d_in[1],
        (const float*)d_in[2],  (const float*)d_in[3],  (const float*)d_in[4],
        (const float*)d_in[5],  (const float*)d_in[6],  (const float*)d_in[7],
        (const float*)d_in[8],  (const float*)d_in[9],  (const float*)d_in[10],
        (const float*)d_in[11], (const float*)d_in[12], (const float*)d_in[13],
        (const float*)d_in[14], (const float*)d_in[15], (const float*)d_in[16],
        (const float*)d_in[17], (const float*)d_in[18],
        (const float*)d_in[19], (const float*)d_in[20]);
    nms_sort<<<1, 1024>>>();
    nms_mask<<<dim3(64, 32), 64>>>();
    nms_scan<<<1, SNT>>>((float*)d_out);
}

// round 14
// speedup vs baseline: 2.2741x; 1.0374x over previous
#include <cuda_runtime.h>
#include <cuda_bf16.h>
#include <math.h>

#define NBOX 2048
#define TPB  256

// shared arena offsets (floats) — liveness: crop/P2 @0 (crop s1; P2 s3+),
// P1 @6912 live s1-s2 (dead s3+ -> P3/C4/F5/FC6/W34), small scratch @23840 always free.
#define OFF_CROP   0
#define OFF_P2     0
#define OFF_GAP    6400
#define OFF_P1     6912
#define OFF_P3     6912
#define OFF_C4     7936
#define OFF_F5     9088
#define OFF_FC6    9344
#define OFF_W34    9472     // stage3/4 ONLY (inside dead-P1 region)
#define OFF_W      23840    // stage1/2/3 small scratch (4312 floats)
#define SMEM1_FLOATS 28152  // 112,608 bytes -> 2 CTAs/SM

__device__ float    g_score[NBOX];
__device__ float    g_box[NBOX * 4];
__device__ float    g_skey[NBOX];
__device__ int      g_sidx[NBOX];
__device__ float    g_sbox[NBOX * 4];
__device__ uint4    g_mask4[NBOX * 16];

// packed dual fp32 FMA: c += a*b per lane (FFMA2)
__device__ __forceinline__ void dfma(float2& c, float2 a, float2 b) {
    asm("fma.rn.f32x2 %0, %1, %2, %0;"
        : "+l"(reinterpret_cast<unsigned long long&>(c))
        : "l"(reinterpret_cast<unsigned long long&>(a)),
          "l"(reinterpret_cast<unsigned long long&>(b)));
}
__device__ __forceinline__ float2 bcast2(float v) { return make_float2(v, v); }

__global__ __launch_bounds__(TPB, 2) void onet_cnn(
    const float* __restrict__ bboxes, const float* __restrict__ image,
    const float* __restrict__ c1w, const float* __restrict__ c1b, const float* __restrict__ p1a,
    const float* __restrict__ c2w, const float* __restrict__ c2b, const float* __restrict__ p2a,
    const float* __restrict__ c3w, const float* __restrict__ c3b, const float* __restrict__ p3a,
    const float* __restrict__ c4w, const float* __restrict__ c4b, const float* __restrict__ p4a,
    const float* __restrict__ f5w, const float* __restrict__ f5b, const float* __restrict__ p5a,
    const float* __restrict__ f6aw, const float* __restrict__ f6ab,
    const float* __restrict__ f6bw, const float* __restrict__ f6bb)
{
    extern __shared__ float sm[];
    const int t = threadIdx.x;
    const int b = blockIdx.x;

    float B0 = bboxes[b*4+0], B1 = bboxes[b*4+1], B2 = bboxes[b*4+2], B3 = bboxes[b*4+3];
    float bx1 = fmaxf(B0, 0.f), by1 = fmaxf(B1, 0.f);
    float bx2 = fminf(B2, 1024.f), by2 = fminf(B3, 1024.f);
    int ix1 = (int)bx1, iy1 = (int)by1, ix2 = (int)bx2, iy2 = (int)by2;
    int cw = max(ix2 - ix1, 1), ch = max(iy2 - iy1, 1);

    // ---- crop 48x48x3 HWC ----
    float* crop = sm + OFF_CROP;
    for (int i = t; i < 2304; i += TPB) {
        int x = i % 48; int y = i / 48;
        int gx = ix1 + (x * cw) / 48;
        int gy = iy1 + (y * ch) / 48;
        const float* src = image + (gy * 1024 + gx) * 3;
        float* dst = crop + i * 3;
        dst[0] = (__ldg(&src[0]) - 127.5f) * 0.0078125f;
        dst[1] = (__ldg(&src[1]) - 127.5f) * 0.0078125f;
        dst[2] = (__ldg(&src[2]) - 127.5f) * 0.0078125f;
    }
    __syncthreads();

    // ===== stage 1: conv1 3x3x3->32 + prelu + pool(3,2,pad1) -> P1 [32][23][23] =====
    float* temp1 = sm + OFF_W;                 // 4232 floats (float2-interleaved 46x46)
    float* P1 = sm + OFF_P1;
    for (int g = 0; g < 16; ++g) {
        float2 wr[27];
        #pragma unroll
        for (int k = 0; k < 27; k++) wr[k] = __ldg((const float2*)&c1w[k * 32 + 2*g]);
        float2 bias  = __ldg((const float2*)&c1b[2*g]);
        float2 alpha = __ldg((const float2*)&p1a[2*g]);
        for (int task = t; task < 552; task += TPB) {
            int xg = task % 12; int cy = task / 12;
            int x0 = xg * 4;
            float2 a0 = make_float2(0.f,0.f), a1v = a0, a2 = a0, a3 = a0;
            #pragma unroll
            for (int ky = 0; ky < 3; ky++) {
                const float* row = crop + (cy + ky) * 144;
                float in[18];
                #pragma unroll
                for (int j = 0; j < 6; j++) {
                    int col = x0 + j; if (col > 47) col = 47;
                    in[j*3+0] = row[col*3+0];
                    in[j*3+1] = row[col*3+1];
                    in[j*3+2] = row[col*3+2];
                }
                #pragma unroll
                for (int kx = 0; kx < 3; kx++)
                    #pragma unroll
                    for (int ic = 0; ic < 3; ic++) {
                        float2 w = wr[(ky*3+kx)*3+ic];
                        dfma(a0,  bcast2(in[(kx+0)*3+ic]), w);
                        dfma(a1v, bcast2(in[(kx+1)*3+ic]), w);
                        dfma(a2,  bcast2(in[(kx+2)*3+ic]), w);
                        dfma(a3,  bcast2(in[(kx+3)*3+ic]), w);
                    }
            }
            float2* tp = (float2*)temp1 + cy * 46;
            float2 o;
            o.x = a0.x + bias.x; o.y = a0.y + bias.y;
            o.x = o.x >= 0.f ? o.x : alpha.x * o.x; o.y = o.y >= 0.f ? o.y : alpha.y * o.y;
            tp[x0+0] = o;
            o.x = a1v.x + bias.x; o.y = a1v.y + bias.y;
            o.x = o.x >= 0.f ? o.x : alpha.x * o.x; o.y = o.y >= 0.f ? o.y : alpha.y * o.y;
            tp[x0+1] = o;
            if (x0+2 < 46) {
                o.x = a2.x + bias.x; o.y = a2.y + bias.y;
                o.x = o.x >= 0.f ? o.x : alpha.x * o.x; o.y = o.y >= 0.f ? o.y : alpha.y * o.y;
                tp[x0+2] = o;
            }
            if (x0+3 < 46) {
                o.x = a3.x + bias.x; o.y = a3.y + bias.y;
                o.x = o.x >= 0.f ? o.x : alpha.x * o.x; o.y = o.y >= 0.f ? o.y : alpha.y * o.y;
                tp[x0+3] = o;
            }
        }
        __syncthreads();
        for (int i = t; i < 1058; i += TPB) {
            int c = i & 1; int pos = i >> 1; int px = pos % 23; int py = pos / 23;
            float m = -3.4e38f;
            #pragma unroll
            for (int dy = 0; dy < 3; dy++) {
                int cy2 = 2*py - 1 + dy; if (cy2 < 0 || cy2 >= 46) continue;
                #pragma unroll
                for (int dx = 0; dx < 3; dx++) {
                    int cx2 = 2*px - 1 + dx; if (cx2 < 0 || cx2 >= 46) continue;
                    m = fmaxf(m, temp1[(cy2*46 + cx2)*2 + c]);
                }
            }
            P1[(g*2 + c) * 529 + py * 23 + px] = m;
        }
        __syncthreads();
    }

    // ===== stage 2: conv2 3x3x32->64 + prelu + pool(3,2) -> P2 [64][10][10] =====
    // Register-prefetched staging: rounds r = g*6 + ky*2 + ih (24 rounds of 768 floats).
    float* w2s = sm + OFF_W;
    float* temp2 = sm + OFF_W + 768;           // 8ch x 21x21 = 3528 (two halves)
    float* b2s = sm + OFF_GAP; float* a2s = b2s + 16;
    float* P2 = sm + OFF_P2;
    {
        const int sc = t & 15; const int srest = t >> 4;
        const int sicl = srest & 15;           // staging decode for i = t (+256,+512)
        float pre[3];
        // prefetch round 0 (g=0, ky=0, ih=0)
        #pragma unroll
        for (int r = 0; r < 3; r++) {
            int i = t + r*256;
            int c = i & 15; int rest = i >> 4; int icl = rest & 15; int kx = rest >> 4;
            pre[r] = __ldg(&c2w[(kx*32 + icl) * 64 + c]);
        }
        (void)sc; (void)sicl;
        for (int g = 0; g < 4; ++g) {
            if (t < 16) { b2s[t] = c2b[g*16 + t]; a2s[t] = p2a[g*16 + t]; }
            const int xg = t % 3; const int rem = t / 3;
            const int cq = rem & 3; const int cy = rem >> 2;
            const int x0 = xg * 7;
            float2 acc[2][7];
            #pragma unroll
            for (int p = 0; p < 2; p++)
                #pragma unroll
                for (int j = 0; j < 7; j++) acc[p][j] = make_float2(0.f, 0.f);
            for (int ky = 0; ky < 3; ky++) {
                for (int ih = 0; ih < 2; ih++) {
                    __syncthreads();
                    #pragma unroll
                    for (int r = 0; r < 3; r++) w2s[t + r*256] = pre[r];
                    __syncthreads();
                    // prefetch next round
                    int rr = g*6 + ky*2 + ih + 1;
                    if (rr < 24) {
                        int ng = rr / 6; int nrem = rr % 6; int nky = nrem >> 1; int nih = nrem & 1;
                        #pragma unroll
                        for (int r = 0; r < 3; r++) {
                            int i = t + r*256;
                            int c = i & 15; int rest = i >> 4; int icl = rest & 15; int kx = rest >> 4;
                            pre[r] = __ldg(&c2w[((nky*3 + kx)*32 + nih*16 + icl) * 64 + ng*16 + c]);
                        }
                    }
                    if (t < 252) {
                        const float* inb = P1 + (ih*16)*529 + (cy + ky) * 23 + x0;
                        const float* wb = w2s + 4*cq;
                        #pragma unroll
                        for (int icl = 0; icl < 16; icl++) {
                            const float* in = inb + icl * 529;
                            float2 p0 = bcast2(in[0]), p1 = bcast2(in[1]), p2 = bcast2(in[2]);
                            float2 p3 = bcast2(in[3]), p4 = bcast2(in[4]), p5 = bcast2(in[5]);
                            float2 p6 = bcast2(in[6]), p7 = bcast2(in[7]), p8 = bcast2(in[8]);
                            float2 wA0 = *(const float2*)&wb[(0*16+icl)*16];
                            float2 wB0 = *(const float2*)&wb[(0*16+icl)*16 + 2];
                            float2 wA1 = *(const float2*)&wb[(1*16+icl)*16];
                            float2 wB1 = *(const float2*)&wb[(1*16+icl)*16 + 2];
                            float2 wA2 = *(const float2*)&wb[(2*16+icl)*16];
                            float2 wB2 = *(const float2*)&wb[(2*16+icl)*16 + 2];
                            dfma(acc[0][0],p0,wA0); dfma(acc[0][1],p1,wA0); dfma(acc[0][2],p2,wA0);
                            dfma(acc[0][3],p3,wA0); dfma(acc[0][4],p4,wA0); dfma(acc[0][5],p5,wA0); dfma(acc[0][6],p6,wA0);
                            dfma(acc[1][0],p0,wB0); dfma(acc[1][1],p1,wB0); dfma(acc[1][2],p2,wB0);
                            dfma(acc[1][3],p3,wB0); dfma(acc[1][4],p4,wB0); dfma(acc[1][5],p5,wB0); dfma(acc[1][6],p6,wB0);
                            dfma(acc[0][0],p1,wA1); dfma(acc[0][1],p2,wA1); dfma(acc[0][2],p3,wA1);
                            dfma(acc[0][3],p4,wA1); dfma(acc[0][4],p5,wA1); dfma(acc[0][5],p6,wA1); dfma(acc[0][6],p7,wA1);
                            dfma(acc[1][0],p1,wB1); dfma(acc[1][1],p2,wB1); dfma(acc[1][2],p3,wB1);
                            dfma(acc[1][3],p4,wB1); dfma(acc[1][4],p5,wB1); dfma(acc[1][5],p6,wB1); dfma(acc[1][6],p7,wB1);
                            dfma(acc[0][0],p2,wA2); dfma(acc[0][1],p3,wA2); dfma(acc[0][2],p4,wA2);
                            dfma(acc[0][3],p5,wA2); dfma(acc[0][4],p6,wA2); dfma(acc[0][5],p7,wA2); dfma(acc[0][6],p8,wA2);
                            dfma(acc[1][0],p2,wB2); dfma(acc[1][1],p3,wB2); dfma(acc[1][2],p4,wB2);
                            dfma(acc[1][3],p5,wB2); dfma(acc[1][4],p6,wB2); dfma(acc[1][5],p7,wB2); dfma(acc[1][6],p8,wB2);
                        }
                    }
                }
            }
            float vb[4], va[4];
            if (t < 252) {
                #pragma unroll
                for (int k = 0; k < 4; k++) { vb[k] = b2s[4*cq + k]; va[k] = a2s[4*cq + k]; }
            }
            if (t < 252 && cq < 2) {
                #pragma unroll
                for (int p = 0; p < 2; p++) {
                    float* t0 = temp2 + (4*cq + 2*p)     * 441 + cy * 21 + x0;
                    float* t1 = temp2 + (4*cq + 2*p + 1) * 441 + cy * 21 + x0;
                    #pragma unroll
                    for (int j = 0; j < 7; j++) {
                        float v0 = acc[p][j].x + vb[2*p];
                        float v1 = acc[p][j].y + vb[2*p+1];
                        t0[j] = v0 >= 0.f ? v0 : va[2*p] * v0;
                        t1[j] = v1 >= 0.f ? v1 : va[2*p+1] * v1;
                    }
                }
            }
            __syncthreads();
            for (int i = t; i < 800; i += TPB) {
                int c = i & 7; int pos = i >> 3; int px = pos % 10; int py = pos / 10;
                const float* tp = temp2 + c * 441;
                float m = -3.4e38f;
                #pragma unroll
                for (int dy = 0; dy < 3; dy++)
                    #pragma unroll
                    for (int dx = 0; dx < 3; dx++)
                        m = fmaxf(m, tp[(2*py+dy)*21 + 2*px+dx]);
                P2[(g*16 + c) * 100 + py * 10 + px] = m;
            }
            __syncthreads();
            if (t < 252 && cq >= 2) {
                #pragma unroll
                for (int p = 0; p < 2; p++) {
                    float* t0 = temp2 + (4*(cq-2) + 2*p)     * 441 + cy * 21 + x0;
                    float* t1 = temp2 + (4*(cq-2) + 2*p + 1) * 441 + cy * 21 + x0;
                    #pragma unroll
                    for (int j = 0; j < 7; j++) {
                        float v0 = acc[p][j].x + vb[2*p];
                        float v1 = acc[p][j].y + vb[2*p+1];
                        t0[j] = v0 >= 0.f ? v0 : va[2*p] * v0;
                        t1[j] = v1 >= 0.f ? v1 : va[2*p+1] * v1;
                    }
                }
            }
            __syncthreads();
            for (int i = t; i < 800; i += TPB) {
                int c = i & 7; int pos = i >> 3; int px = pos % 10; int py = pos / 10;
                const float* tp = temp2 + c * 441;
                float m = -3.4e38f;
                #pragma unroll
                for (int dy = 0; dy < 3; dy++)
                    #pragma unroll
                    for (int dx = 0; dx < 3; dx++)
                        m = fmaxf(m, tp[(2*py+dy)*21 + 2*px+dx]);
                P2[(g*16 + 8 + c) * 100 + py * 10 + px] = m;
            }
            __syncthreads();
        }
    }

    // ===== stage 3: conv3 3x3x64->64 + prelu + pool(2,2) -> P3 [64][4][4] =====
    float* w3s = sm + OFF_W34; float* b3s = w3s + 9216; float* a3s = b3s + 64;
    float* temp3 = sm + OFF_W;                 // 32ch x 8x8 = 2048 (two halves)
    float* P3 = sm + OFF_P3;
    {
        if (t < 64) { b3s[t] = c3b[t]; a3s[t] = p3a[t]; }
        const int cq = t & 15; const int pos = t >> 4;
        const int xg = pos & 1; const int cy = pos >> 1;
        const int x0 = xg * 4;
        float2 acc[2][4];
        #pragma unroll
        for (int p = 0; p < 2; p++)
            #pragma unroll
            for (int j = 0; j < 4; j++) acc[p][j] = make_float2(0.f, 0.f);
        for (int q = 0; q < 4; q++) {
            __syncthreads();
            for (int i = t; i < 9216; i += TPB) {
                int c = i & 63; int kidx = i >> 6;
                int icl = kidx & 15; int kk = kidx >> 4;
                w3s[i] = c3w[(kk*64 + q*16 + icl) * 64 + c];
            }
            __syncthreads();
            #pragma unroll
            for (int ky = 0; ky < 3; ky++) {
                const float* inb = P2 + (q*16)*100 + (cy + ky) * 10 + x0;
                const float* wk = w3s + (ky*3)*1024 + 4*cq;
                #pragma unroll
                for (int icl = 0; icl < 16; icl++) {
                    const float* in = inb + icl * 100;
                    float2 p0 = bcast2(in[0]), p1 = bcast2(in[1]), p2 = bcast2(in[2]);
                    float2 p3 = bcast2(in[3]), p4 = bcast2(in[4]), p5 = bcast2(in[5]);
                    float2 wA0 = *(const float2*)&wk[(0*16+icl)*64];
                    float2 wB0 = *(const float2*)&wk[(0*16+icl)*64 + 2];
                    float2 wA1 = *(const float2*)&wk[(1*16+icl)*64];
                    float2 wB1 = *(const float2*)&wk[(1*16+icl)*64 + 2];
                    float2 wA2 = *(const float2*)&wk[(2*16+icl)*64];
                    float2 wB2 = *(const float2*)&wk[(2*16+icl)*64 + 2];
                    dfma(acc[0][0],p0,wA0); dfma(acc[0][1],p1,wA0); dfma(acc[0][2],p2,wA0); dfma(acc[0][3],p3,wA0);
                    dfma(acc[1][0],p0,wB0); dfma(acc[1][1],p1,wB0); dfma(acc[1][2],p2,wB0); dfma(acc[1][3],p3,wB0);
                    dfma(acc[0][0],p1,wA1); dfma(acc[0][1],p2,wA1); dfma(acc[0][2],p3,wA1); dfma(acc[0][3],p4,wA1);
                    dfma(acc[1][0],p1,wB1); dfma(acc[1][1],p2,wB1); dfma(acc[1][2],p3,wB1); dfma(acc[1][3],p4,wB1);
                    dfma(acc[0][0],p2,wA2); dfma(acc[0][1],p3,wA2); dfma(acc[0][2],p4,wA2); dfma(acc[0][3],p5,wA2);
                    dfma(acc[1][0],p2,wB2); dfma(acc[1][1],p3,wB2); dfma(acc[1][2],p4,wB2); dfma(acc[1][3],p5,wB2);
                }
            }
        }
        float vb[4], va[4];
        #pragma unroll
        for (int k = 0; k < 4; k++) { vb[k] = b3s[4*cq + k]; va[k] = a3s[4*cq + k]; }
        if (cq < 8) {
            #pragma unroll
            for (int p = 0; p < 2; p++) {
                float* t0 = temp3 + (4*cq + 2*p)     * 64 + cy * 8 + x0;
                float* t1 = temp3 + (4*cq + 2*p + 1) * 64 + cy * 8 + x0;
                #pragma unroll
                for (int j = 0; j < 4; j++) {
                    float v0 = acc[p][j].x + vb[2*p];
                    float v1 = acc[p][j].y + vb[2*p+1];
                    t0[j] = v0 >= 0.f ? v0 : va[2*p] * v0;
                    t1[j] = v1 >= 0.f ? v1 : va[2*p+1] * v1;
                }
            }
        }
        __syncthreads();
        for (int task = t; task < 512; task += TPB) {
            int c = task & 31; int pos2 = task >> 5; int px = pos2 & 3; int py = pos2 >> 2;
            const float* tp = temp3 + c * 64;
            float m = fmaxf(fmaxf(tp[(2*py)*8 + 2*px], tp[(2*py)*8 + 2*px + 1]),
                            fmaxf(tp[(2*py+1)*8 + 2*px], tp[(2*py+1)*8 + 2*px + 1]));
            P3[c * 16 + py * 4 + px] = m;
        }
        __syncthreads();
        if (cq >= 8) {
            #pragma unroll
            for (int p = 0; p < 2; p++) {
                float* t0 = temp3 + (4*(cq-8) + 2*p)     * 64 + cy * 8 + x0;
                float* t1 = temp3 + (4*(cq-8) + 2*p + 1) * 64 + cy * 8 + x0;
                #pragma unroll
                for (int j = 0; j < 4; j++) {
                    float v0 = acc[p][j].x + vb[2*p];
                    float v1 = acc[p][j].y + vb[2*p+1];
                    t0[j] = v0 >= 0.f ? v0 : va[2*p] * v0;
                    t1[j] = v1 >= 0.f ? v1 : va[2*p+1] * v1;
                }
            }
        }
        __syncthreads();
        for (int task = t; task < 512; task += TPB) {
            int c = task & 31; int pos2 = task >> 5; int px = pos2 & 3; int py = pos2 >> 2;
            const float* tp = temp3 + c * 64;
            float m = fmaxf(fmaxf(tp[(2*py)*8 + 2*px], tp[(2*py)*8 + 2*px + 1]),
                            fmaxf(tp[(2*py+1)*8 + 2*px], tp[(2*py+1)*8 + 2*px + 1]));
            P3[(32 + c) * 16 + py * 4 + px] = m;
        }
        __syncthreads();
    }

    // ===== stage 4: conv4 2x2x64->128 + prelu -> C4 flat (c*9 + y*3 + x) =====
    // Register-prefetched staging: rounds r = g*4 + k (8 rounds of 4096 floats).
    float* w4s = sm + OFF_W34; float* b4s = w4s + 4096; float* a4s = b4s + 64;
    float* C4 = sm + OFF_C4;
    {
        float pre4[16];
        #pragma unroll
        for (int r = 0; r < 16; r++) {
            int i = t + r*256;
            int c = i & 63; int ic = i >> 6;
            pre4[r] = __ldg(&c4w[ic*128 + c]);   // round 0: g=0,k=0
        }
        for (int g = 0; g < 2; ++g) {
            if (t < 64) { b4s[t] = c4b[g*64 + t]; a4s[t] = p4a[g*64 + t]; }
            const int cq = t & 15; const int pos = t >> 4;
            const int y = pos / 3, x = pos % 3;
            float2 accA = make_float2(0.f,0.f), accB = accA;
            for (int k = 0; k < 4; k++) {
                __syncthreads();
                #pragma unroll
                for (int r = 0; r < 16; r++) w4s[t + r*256] = pre4[r];
                __syncthreads();
                int rr = g*4 + k + 1;
                if (rr < 8) {
                    int ng = rr >> 2; int nk = rr & 3;
                    #pragma unroll
                    for (int r = 0; r < 16; r++) {
                        int i = t + r*256;
                        int c = i & 63; int ic = i >> 6;
                        pre4[r] = __ldg(&c4w[(nk*64 + ic)*128 + ng*64 + c]);
                    }
                }
                if (t < 144) {
                    int ky = k >> 1, kx = k & 1;
                    const float* inb = P3 + (y + ky) * 4 + (x + kx);
                    const float* wb  = w4s + 4*cq;
                    #pragma unroll
                    for (int ic = 0; ic < 64; ic++) {
                        float2 p = bcast2(inb[ic * 16]);
                        float2 wA = *(const float2*)&wb[ic * 64];
                        float2 wB = *(const float2*)&wb[ic * 64 + 2];
                        dfma(accA, p, wA); dfma(accB, p, wB);
                    }
                }
            }
            if (t < 144) {
                int c0 = g*64 + 4*cq;
                float v0 = accA.x + b4s[4*cq+0], v1 = accA.y + b4s[4*cq+1];
                float v2 = accB.x + b4s[4*cq+2], v3 = accB.y + b4s[4*cq+3];
                float l0 = a4s[4*cq+0], l1 = a4s[4*cq+1], l2 = a4s[4*cq+2], l3 = a4s[4*cq+3];
                C4[(c0+0)*9 + pos] = v0 >= 0.f ? v0 : l0 * v0;
                C4[(c0+1)*9 + pos] = v1 >= 0.f ? v1 : l1 * v1;
                C4[(c0+2)*9 + pos] = v2 >= 0.f ? v2 : l2 * v2;
                C4[(c0+3)*9 + pos] = v3 >= 0.f ? v3 : l3 * v3;
            }
            __syncthreads();
        }
    }

    // ===== fc5: 1152 -> 256 + prelu =====
    float* F5 = sm + OFF_F5;
    {
        int warp = t >> 5, lane = t & 31;
        for (int o = warp; o < 256; o += 8) {
            const float4* wrow = (const float4*)(f5w + o * 1152);
            float acc = 0.f;
            #pragma unroll
            for (int j = 0; j < 9; j++) {
                float4 cv = *(const float4*)&C4[j*128 + lane*4];
                float4 wv = __ldg(&wrow[j*32 + lane]);
                acc += cv.x*wv.x + cv.y*wv.y + cv.z*wv.z + cv.w*wv.w;
            }
            #pragma unroll
            for (int s = 16; s; s >>= 1) acc += __shfl_xor_sync(0xFFFFFFFFu, acc, s);
            if (lane == 0) {
                float v = acc + f5b[o];
                float al = p5a[o];
                F5[o] = v >= 0.f ? v : al * v;
            }
        }
    }
    __syncthreads();

    // ===== fc6a (2) + fc6b (4) =====
    float* FC6 = sm + OFF_FC6;
    if (t < 192) {
        int o = t >> 5, lane = t & 31;
        const float* wrow = (o < 2) ? (f6aw + o * 256) : (f6bw + (o - 2) * 256);
        float acc = 0.f;
        #pragma unroll
        for (int j = 0; j < 8; j++) { int k = lane + 32*j; acc += F5[k] * __ldg(&wrow[k]); }
        #pragma unroll
        for (int s = 16; s; s >>= 1) acc += __shfl_xor_sync(0xFFFFFFFFu, acc, s);
        if (lane == 0) FC6[o] = acc + ((o < 2) ? f6ab[o] : f6bb[o - 2]);
    }
    __syncthreads();

    if (t == 0) {
        float l0 = FC6[0], l1 = FC6[1];
        float m = fmaxf(l0, l1);
        float e0 = expf(l0 - m), e1 = expf(l1 - m);
        float score = e1 / (e0 + e1);
        float w = bx2 - bx1, h = by2 - by1;
        g_score[b] = score;
        g_box[b*4+0] = bx1 + FC6[2] * w;
        g_box[b*4+1] = by1 + FC6[3] * h;
        g_box[b*4+2] = bx2 + FC6[4] * w;
        g_box[b*4+3] = by2 + FC6[5] * h;
    }
}

// ---------- NMS: bitonic sort by (score desc, idx asc) ----------
__device__ __forceinline__ bool nms_before(float ka, int ia, float kb, int ib) {
    return (ka > kb) || (ka == kb && ia < ib);
}

__global__ __launch_bounds__(1024) void nms_sort() {
    __shared__ float kk[NBOX];
    __shared__ int   id[NBOX];
    int t = threadIdx.x;
    kk[t] = g_score[t];           id[t] = t;
    kk[t+1024] = g_score[t+1024]; id[t+1024] = t + 1024;
    for (int k = 2; k <= NBOX; k <<= 1) {
        for (int j = k >> 1; j > 0; j >>= 1) {
            __syncthreads();
            #pragma unroll 2
            for (int i = t; i < NBOX; i += 1024) {
                int ixj = i ^ j;
                if (ixj > i) {
                    float ka = kk[i], kb = kk[ixj];
                    int ia = id[i], ib = id[ixj];
                    bool up = ((i & k) == 0);
                    bool bad = up ? nms_before(kb, ib, ka, ia) : nms_before(ka, ia, kb, ib);
                    if (bad) { kk[i] = kb; kk[ixj] = ka; id[i] = ib; id[ixj] = ia; }
                }
            }
        }
    }
    __syncthreads();
    #pragma unroll 2
    for (int i = t; i < NBOX; i += 1024) {
        g_skey[i] = kk[i];
        int o = id[i];
        g_sidx[i] = o;
        g_sbox[i*4+0] = g_box[o*4+0];
        g_sbox[i*4+1] = g_box[o*4+1];
        g_sbox[i*4+2] = g_box[o*4+2];
        g_sbox[i*4+3] = g_box[o*4+3];
    }
}

// ---------- NMS: IOU bitmask ----------
__global__ __launch_bounds__(64) void nms_mask() {
    __shared__ float cb[32][4];
    int t = threadIdx.x;
    int j0 = blockIdx.x * 32;
    for (int i = t; i < 128; i += 64) cb[i >> 2][i & 3] = g_sbox[(j0 + (i >> 2)) * 4 + (i & 3)];
    __syncthreads();
    int i = blockIdx.y * 64 + t;
    float x1 = g_sbox[i*4+0], y1 = g_sbox[i*4+1], x2 = g_sbox[i*4+2], y2 = g_sbox[i*4+3];
    float area = (x2 - x1) * (y2 - y1);
    unsigned word = 0;
    #pragma unroll 8
    for (int jj = 0; jj < 32; jj++) {
        int j = j0 + jj;
        if (j > i) {
            float bx1v = cb[jj][0], by1v = cb[jj][1], bx2v = cb[jj][2], by2v = cb[jj][3];
            float xx1 = fmaxf(x1, bx1v), yy1 = fmaxf(y1, by1v);
            float xx2 = fminf(x2, bx2v), yy2 = fminf(y2, by2v);
            float inter = fmaxf(xx2 - xx1, 0.f) * fmaxf(yy2 - yy1, 0.f);
            float areab = (bx2v - bx1v) * (by2v - by1v);
            float iou = inter / (area + areab - inter + 1e-12f);
            if (iou > 0.5f) word |= (1u << jj);
        }
    }
    ((unsigned*)g_mask4)[i * 64 + blockIdx.x] = word;
}

// ---------- NMS: serial scan; uint4 streaming producers + register decision word ----------
#define SCHUNK 64
#define SNT    512
__global__ __launch_bounds__(SNT) void nms_scan(float* __restrict__ out) {
    __shared__ uint4 buf4[2][SCHUNK * 16];
    __shared__ unsigned keepw[64];
    __shared__ int sV;
    int t = threadIdx.x;
    if (t < 64) keepw[t] = 0u;
    if (t == 0) sV = 0;
    __syncthreads();
    for (int p = t; p < NBOX; p += SNT) {
        bool v = g_skey[p] >= 0.5f;
        unsigned bal = __ballot_sync(0xFFFFFFFFu, v);
        if ((t & 31) == 0) atomicAdd(&sV, __popc(bal));
    }
    __syncthreads();
    const int V = sV;
    const int nch = (V + SCHUNK - 1) / SCHUNK;
    const uint4 z4 = make_uint4(0u,0u,0u,0u);
    for (int i = t; i < SCHUNK * 16; i += SNT) {
        int p = i >> 4;
        buf4[0][i] = (p < V) ? g_mask4[i] : z4;
    }
    __syncthreads();
    unsigned r0 = 0u, r1 = 0u;
    for (int ci = 0; ci < nch; ci++) {
        if (t >= 32) {
            if (ci + 1 < nch) {
                uint4* nb = buf4[(ci + 1) & 1];
                int pb = (ci + 1) * SCHUNK;
                for (int i = t - 32; i < SCHUNK * 16; i += (SNT - 32)) {
                    int p = pb + (i >> 4);
                    nb[i] = (p < V) ? g_mask4[p * 16 + (i & 15)] : z4;
                }
            }
        } else {
            const unsigned* B = (const unsigned*)buf4[ci & 1];
            int pb = ci * SCHUNK;
            #pragma unroll
            for (int r = 0; r < 2; r++) {
                int rb = pb + r * 32;
                if (rb >= V) break;
                int w = rb >> 5;
                int lim = min(32, V - rb);
                unsigned dw = (w < 32) ? __shfl_sync(0xFFFFFFFFu, r0, w)
                                       : __shfl_sync(0xFFFFFFFFu, r1, w - 32);
                for (int jb = 0; jb < lim; jb += 8) {
                    unsigned qa[8], qb[8], qw[8];
                    #pragma unroll
                    for (int j = 0; j < 8; j++) {
                        int jj = r * 32 + jb + j;
                        bool ok = (jb + j) < lim;
                        qa[j] = ok ? B[jj*64 + t]      : 0u;
                        qb[j] = ok ? B[jj*64 + 32 + t] : 0u;
                        qw[j] = ok ? B[jj*64 + w]      : 0u;
                    }
                    #pragma unroll
                    for (int j = 0; j < 8; j++) {
                        int bb = jb + j;
                        unsigned m = ((dw >> bb) & 1u) - 1u;
                        dw |= qw[j] & m;
                        r0 |= qa[j] & m;
                        r1 |= qb[j] & m;
                    }
                }
                if (t == 0) {
                    unsigned vmask = (lim >= 32) ? 0xFFFFFFFFu : ((1u << lim) - 1u);
                    keepw[w] = (~dw) & vmask;
                }
            }
        }
        __syncthreads();
    }
    for (int i = t; i < NBOX * 4; i += SNT) out[i] = 0.f;
    __syncthreads();
    for (int p = t; p < NBOX; p += SNT) {
        if ((keepw[p >> 5] >> (p & 31)) & 1u) {
            int o = g_sidx[p];
            out[o*4+0] = g_sbox[p*4+0];
            out[o*4+1] = g_sbox[p*4+1];
            out[o*4+2] = g_sbox[p*4+2];
            out[o*4+3] = g_sbox[p*4+3];
        }
    }
}

extern "C" void kernel_launch(void* const* d_in, const int* in_sizes, int n_in,
                              void* d_out, int out_size) {
    (void)in_sizes; (void)n_in; (void)out_size;
    cudaFuncSetAttribute(onet_cnn, cudaFuncAttributeMaxDynamicSharedMemorySize, SMEM1_FLOATS * 4);
    onet_cnn<<<NBOX, TPB, SMEM1_FLOATS * 4>>>(
        (const float*)d_in[0],  (const float*)d_in[1],
        (const float*)d_in[2],  (const float*)d_in[3],  (const float*)d_in[4],
        (const float*)d_in[5],  (const float*)d_in[6],  (const float*)d_in[7],
        (const float*)d_in[8],  (const float*)d_in[9],  (const float*)d_in[10],
        (const float*)d_in[11], (const float*)d_in[12], (const float*)d_in[13],
        (const float*)d_in[14], (const float*)d_in[15], (const float*)d_in[16],
        (const float*)d_in[17], (const float*)d_in[18],
        (const float*)d_in[19], (const float*)d_in[20]);
    nms_sort<<<1, 1024>>>();
    nms_mask<<<dim3(64, 32), 64>>>();
    nms_scan<<<1, SNT>>>((float*)d_out);
}

// round 15
// speedup vs baseline: 2.3005x; 1.0116x over previous
#include <cuda_runtime.h>
#include <cuda_bf16.h>
#include <math.h>

#define NBOX 2048
#define TPB  256

// shared arena offsets (floats) — liveness: crop/P2 @0 (crop s1; P2 s3+),
// P1 @6912 live s1-s2 (dead s3+ -> P3/C4/F5/FC6/W34), small scratch @23840 always free.
#define OFF_CROP   0
#define OFF_P2     0
#define OFF_GAP    6400
#define OFF_P1     6912
#define OFF_P3     6912
#define OFF_C4     7936
#define OFF_F5     9088
#define OFF_FC6    9344
#define OFF_W34    9472     // stage3/4 ONLY (inside dead-P1 region)
#define OFF_W      23840    // stage1/2/3 small scratch (4312 floats)
#define SMEM1_FLOATS 28152  // 112,608 bytes -> 2 CTAs/SM

__device__ float    g_score[NBOX];
__device__ float    g_box[NBOX * 4];
__device__ float    g_skey[NBOX];
__device__ int      g_sidx[NBOX];
__device__ float    g_sbox[NBOX * 4];
__device__ uint4    g_mask4[NBOX * 16];

// packed dual fp32 FMA: c += a*b per lane (FFMA2)
__device__ __forceinline__ void dfma(float2& c, float2 a, float2 b) {
    asm("fma.rn.f32x2 %0, %1, %2, %0;"
        : "+l"(reinterpret_cast<unsigned long long&>(c))
        : "l"(reinterpret_cast<unsigned long long&>(a)),
          "l"(reinterpret_cast<unsigned long long&>(b)));
}
__device__ __forceinline__ float2 bcast2(float v) { return make_float2(v, v); }

__device__ __forceinline__ void cpasync8(float* dst, const float* src) {
    unsigned sa = (unsigned)__cvta_generic_to_shared(dst);
    asm volatile("cp.async.ca.shared.global [%0], [%1], 8;" :: "r"(sa), "l"(src));
}
#define CP_COMMIT() asm volatile("cp.async.commit_group;")
#define CP_WAIT0()  asm volatile("cp.async.wait_group 0;")

__global__ __launch_bounds__(TPB, 2) void onet_cnn(
    const float* __restrict__ bboxes, const float* __restrict__ image,
    const float* __restrict__ c1w, const float* __restrict__ c1b, const float* __restrict__ p1a,
    const float* __restrict__ c2w, const float* __restrict__ c2b, const float* __restrict__ p2a,
    const float* __restrict__ c3w, const float* __restrict__ c3b, const float* __restrict__ p3a,
    const float* __restrict__ c4w, const float* __restrict__ c4b, const float* __restrict__ p4a,
    const float* __restrict__ f5w, const float* __restrict__ f5b, const float* __restrict__ p5a,
    const float* __restrict__ f6aw, const float* __restrict__ f6ab,
    const float* __restrict__ f6bw, const float* __restrict__ f6bb)
{
    extern __shared__ float sm[];
    const int t = threadIdx.x;
    const int b = blockIdx.x;

    float B0 = bboxes[b*4+0], B1 = bboxes[b*4+1], B2 = bboxes[b*4+2], B3 = bboxes[b*4+3];
    float bx1 = fmaxf(B0, 0.f), by1 = fmaxf(B1, 0.f);
    float bx2 = fminf(B2, 1024.f), by2 = fminf(B3, 1024.f);
    int ix1 = (int)bx1, iy1 = (int)by1, ix2 = (int)bx2, iy2 = (int)by2;
    int cw = max(ix2 - ix1, 1), ch = max(iy2 - iy1, 1);

    // ---- crop 48x48x3 HWC ----
    float* crop = sm + OFF_CROP;
    for (int i = t; i < 2304; i += TPB) {
        int x = i % 48; int y = i / 48;
        int gx = ix1 + (x * cw) / 48;
        int gy = iy1 + (y * ch) / 48;
        const float* src = image + (gy * 1024 + gx) * 3;
        float* dst = crop + i * 3;
        dst[0] = (__ldg(&src[0]) - 127.5f) * 0.0078125f;
        dst[1] = (__ldg(&src[1]) - 127.5f) * 0.0078125f;
        dst[2] = (__ldg(&src[2]) - 127.5f) * 0.0078125f;
    }
    __syncthreads();

    // ===== stage 1: conv1 3x3x3->32 + prelu + pool(3,2,pad1) -> P1 [32][23][23] =====
    float* temp1 = sm + OFF_W;                 // 4232 floats (float2-interleaved 46x46)
    float* P1 = sm + OFF_P1;
    for (int g = 0; g < 16; ++g) {
        float2 wr[27];
        #pragma unroll
        for (int k = 0; k < 27; k++) wr[k] = __ldg((const float2*)&c1w[k * 32 + 2*g]);
        float2 bias  = __ldg((const float2*)&c1b[2*g]);
        float2 alpha = __ldg((const float2*)&p1a[2*g]);
        for (int task = t; task < 552; task += TPB) {
            int xg = task % 12; int cy = task / 12;
            int x0 = xg * 4;
            float2 a0 = make_float2(0.f,0.f), a1v = a0, a2 = a0, a3 = a0;
            #pragma unroll
            for (int ky = 0; ky < 3; ky++) {
                const float* row = crop + (cy + ky) * 144;
                float in[18];
                #pragma unroll
                for (int j = 0; j < 6; j++) {
                    int col = x0 + j; if (col > 47) col = 47;
                    in[j*3+0] = row[col*3+0];
                    in[j*3+1] = row[col*3+1];
                    in[j*3+2] = row[col*3+2];
                }
                #pragma unroll
                for (int kx = 0; kx < 3; kx++)
                    #pragma unroll
                    for (int ic = 0; ic < 3; ic++) {
                        float2 w = wr[(ky*3+kx)*3+ic];
                        dfma(a0,  bcast2(in[(kx+0)*3+ic]), w);
                        dfma(a1v, bcast2(in[(kx+1)*3+ic]), w);
                        dfma(a2,  bcast2(in[(kx+2)*3+ic]), w);
                        dfma(a3,  bcast2(in[(kx+3)*3+ic]), w);
                    }
            }
            float2* tp = (float2*)temp1 + cy * 46;
            float2 o;
            o.x = a0.x + bias.x; o.y = a0.y + bias.y;
            o.x = o.x >= 0.f ? o.x : alpha.x * o.x; o.y = o.y >= 0.f ? o.y : alpha.y * o.y;
            tp[x0+0] = o;
            o.x = a1v.x + bias.x; o.y = a1v.y + bias.y;
            o.x = o.x >= 0.f ? o.x : alpha.x * o.x; o.y = o.y >= 0.f ? o.y : alpha.y * o.y;
            tp[x0+1] = o;
            if (x0+2 < 46) {
                o.x = a2.x + bias.x; o.y = a2.y + bias.y;
                o.x = o.x >= 0.f ? o.x : alpha.x * o.x; o.y = o.y >= 0.f ? o.y : alpha.y * o.y;
                tp[x0+2] = o;
            }
            if (x0+3 < 46) {
                o.x = a3.x + bias.x; o.y = a3.y + bias.y;
                o.x = o.x >= 0.f ? o.x : alpha.x * o.x; o.y = o.y >= 0.f ? o.y : alpha.y * o.y;
                tp[x0+3] = o;
            }
        }
        __syncthreads();
        for (int i = t; i < 1058; i += TPB) {
            int c = i & 1; int pos = i >> 1; int px = pos % 23; int py = pos / 23;
            float m = -3.4e38f;
            #pragma unroll
            for (int dy = 0; dy < 3; dy++) {
                int cy2 = 2*py - 1 + dy; if (cy2 < 0 || cy2 >= 46) continue;
                #pragma unroll
                for (int dx = 0; dx < 3; dx++) {
                    int cx2 = 2*px - 1 + dx; if (cx2 < 0 || cx2 >= 46) continue;
                    m = fmaxf(m, temp1[(cy2*46 + cx2)*2 + c]);
                }
            }
            P1[(g*2 + c) * 529 + py * 23 + px] = m;
        }
        __syncthreads();
    }

    // ===== stage 2: conv2 3x3x32->64 + prelu + pool(3,2) -> P2 [64][10][10] =====
    // Register-prefetched staging: rounds r = g*6 + ky*2 + ih (24 rounds of 768 floats).
    float* w2s = sm + OFF_W;
    float* temp2 = sm + OFF_W + 768;           // 8ch x 21x21 = 3528 (two halves)
    float* b2s = sm + OFF_GAP; float* a2s = b2s + 16;
    float* P2 = sm + OFF_P2;
    {
        float pre[3];
        #pragma unroll
        for (int r = 0; r < 3; r++) {
            int i = t + r*256;
            int c = i & 15; int rest = i >> 4; int icl = rest & 15; int kx = rest >> 4;
            pre[r] = __ldg(&c2w[(kx*32 + icl) * 64 + c]);
        }
        for (int g = 0; g < 4; ++g) {
            if (t < 16) { b2s[t] = c2b[g*16 + t]; a2s[t] = p2a[g*16 + t]; }
            const int xg = t % 3; const int rem = t / 3;
            const int cq = rem & 3; const int cy = rem >> 2;
            const int x0 = xg * 7;
            float2 acc[2][7];
            #pragma unroll
            for (int p = 0; p < 2; p++)
                #pragma unroll
                for (int j = 0; j < 7; j++) acc[p][j] = make_float2(0.f, 0.f);
            for (int ky = 0; ky < 3; ky++) {
                for (int ih = 0; ih < 2; ih++) {
                    __syncthreads();
                    #pragma unroll
                    for (int r = 0; r < 3; r++) w2s[t + r*256] = pre[r];
                    __syncthreads();
                    int rr = g*6 + ky*2 + ih + 1;
                    if (rr < 24) {
                        int ng = rr / 6; int nrem = rr % 6; int nky = nrem >> 1; int nih = nrem & 1;
                        #pragma unroll
                        for (int r = 0; r < 3; r++) {
                            int i = t + r*256;
                            int c = i & 15; int rest = i >> 4; int icl = rest & 15; int kx = rest >> 4;
                            pre[r] = __ldg(&c2w[((nky*3 + kx)*32 + nih*16 + icl) * 64 + ng*16 + c]);
                        }
                    }
                    if (t < 252) {
                        const float* inb = P1 + (ih*16)*529 + (cy + ky) * 23 + x0;
                        const float* wb = w2s + 4*cq;
                        #pragma unroll
                        for (int icl = 0; icl < 16; icl++) {
                            const float* in = inb + icl * 529;
                            float2 p0 = bcast2(in[0]), p1 = bcast2(in[1]), p2 = bcast2(in[2]);
                            float2 p3 = bcast2(in[3]), p4 = bcast2(in[4]), p5 = bcast2(in[5]);
                            float2 p6 = bcast2(in[6]), p7 = bcast2(in[7]), p8 = bcast2(in[8]);
                            float2 wA0 = *(const float2*)&wb[(0*16+icl)*16];
                            float2 wB0 = *(const float2*)&wb[(0*16+icl)*16 + 2];
                            float2 wA1 = *(const float2*)&wb[(1*16+icl)*16];
                            float2 wB1 = *(const float2*)&wb[(1*16+icl)*16 + 2];
                            float2 wA2 = *(const float2*)&wb[(2*16+icl)*16];
                            float2 wB2 = *(const float2*)&wb[(2*16+icl)*16 + 2];
                            dfma(acc[0][0],p0,wA0); dfma(acc[0][1],p1,wA0); dfma(acc[0][2],p2,wA0);
                            dfma(acc[0][3],p3,wA0); dfma(acc[0][4],p4,wA0); dfma(acc[0][5],p5,wA0); dfma(acc[0][6],p6,wA0);
                            dfma(acc[1][0],p0,wB0); dfma(acc[1][1],p1,wB0); dfma(acc[1][2],p2,wB0);
                            dfma(acc[1][3],p3,wB0); dfma(acc[1][4],p4,wB0); dfma(acc[1][5],p5,wB0); dfma(acc[1][6],p6,wB0);
                            dfma(acc[0][0],p1,wA1); dfma(acc[0][1],p2,wA1); dfma(acc[0][2],p3,wA1);
                            dfma(acc[0][3],p4,wA1); dfma(acc[0][4],p5,wA1); dfma(acc[0][5],p6,wA1); dfma(acc[0][6],p7,wA1);
                            dfma(acc[1][0],p1,wB1); dfma(acc[1][1],p2,wB1); dfma(acc[1][2],p3,wB1);
                            dfma(acc[1][3],p4,wB1); dfma(acc[1][4],p5,wB1); dfma(acc[1][5],p6,wB1); dfma(acc[1][6],p7,wB1);
                            dfma(acc[0][0],p2,wA2); dfma(acc[0][1],p3,wA2); dfma(acc[0][2],p4,wA2);
                            dfma(acc[0][3],p5,wA2); dfma(acc[0][4],p6,wA2); dfma(acc[0][5],p7,wA2); dfma(acc[0][6],p8,wA2);
                            dfma(acc[1][0],p2,wB2); dfma(acc[1][1],p3,wB2); dfma(acc[1][2],p4,wB2);
                            dfma(acc[1][3],p5,wB2); dfma(acc[1][4],p6,wB2); dfma(acc[1][5],p7,wB2); dfma(acc[1][6],p8,wB2);
                        }
                    }
                }
            }
            float vb[4], va[4];
            if (t < 252) {
                #pragma unroll
                for (int k = 0; k < 4; k++) { vb[k] = b2s[4*cq + k]; va[k] = a2s[4*cq + k]; }
            }
            if (t < 252 && cq < 2) {
                #pragma unroll
                for (int p = 0; p < 2; p++) {
                    float* t0 = temp2 + (4*cq + 2*p)     * 441 + cy * 21 + x0;
                    float* t1 = temp2 + (4*cq + 2*p + 1) * 441 + cy * 21 + x0;
                    #pragma unroll
                    for (int j = 0; j < 7; j++) {
                        float v0 = acc[p][j].x + vb[2*p];
                        float v1 = acc[p][j].y + vb[2*p+1];
                        t0[j] = v0 >= 0.f ? v0 : va[2*p] * v0;
                        t1[j] = v1 >= 0.f ? v1 : va[2*p+1] * v1;
                    }
                }
            }
            __syncthreads();
            for (int i = t; i < 800; i += TPB) {
                int c = i & 7; int pos = i >> 3; int px = pos % 10; int py = pos / 10;
                const float* tp = temp2 + c * 441;
                float m = -3.4e38f;
                #pragma unroll
                for (int dy = 0; dy < 3; dy++)
                    #pragma unroll
                    for (int dx = 0; dx < 3; dx++)
                        m = fmaxf(m, tp[(2*py+dy)*21 + 2*px+dx]);
                P2[(g*16 + c) * 100 + py * 10 + px] = m;
            }
            __syncthreads();
            if (t < 252 && cq >= 2) {
                #pragma unroll
                for (int p = 0; p < 2; p++) {
                    float* t0 = temp2 + (4*(cq-2) + 2*p)     * 441 + cy * 21 + x0;
                    float* t1 = temp2 + (4*(cq-2) + 2*p + 1) * 441 + cy * 21 + x0;
                    #pragma unroll
                    for (int j = 0; j < 7; j++) {
                        float v0 = acc[p][j].x + vb[2*p];
                        float v1 = acc[p][j].y + vb[2*p+1];
                        t0[j] = v0 >= 0.f ? v0 : va[2*p] * v0;
                        t1[j] = v1 >= 0.f ? v1 : va[2*p+1] * v1;
                    }
                }
            }
            __syncthreads();
            for (int i = t; i < 800; i += TPB) {
                int c = i & 7; int pos = i >> 3; int px = pos % 10; int py = pos / 10;
                const float* tp = temp2 + c * 441;
                float m = -3.4e38f;
                #pragma unroll
                for (int dy = 0; dy < 3; dy++)
                    #pragma unroll
                    for (int dx = 0; dx < 3; dx++)
                        m = fmaxf(m, tp[(2*py+dy)*21 + 2*px+dx]);
                P2[(g*16 + 8 + c) * 100 + py * 10 + px] = m;
            }
            __syncthreads();
        }
    }

    // ===== stage 3: conv3 3x3x64->64 + prelu + pool(2,2) -> P3 [64][4][4] =====
    // cp.async double-buffered staging: 8 rounds of ic-octets (4608 floats each).
    // Buffers at W34: buf0 @0, buf1 @4608; b3s @9216, a3s @9280.
    float* w3buf = sm + OFF_W34;
    float* b3s = w3buf + 9216; float* a3s = b3s + 64;
    float* temp3 = sm + OFF_W;                 // 32ch x 8x8 = 2048 (two halves)
    float* P3 = sm + OFF_P3;
    {
        if (t < 64) { b3s[t] = c3b[t]; a3s[t] = p3a[t]; }
        const int cq = t & 15; const int pos = t >> 4;
        const int xg = pos & 1; const int cy = pos >> 1;
        const int x0 = xg * 4;
        float2 acc[2][4];
        #pragma unroll
        for (int p = 0; p < 2; p++)
            #pragma unroll
            for (int j = 0; j < 4; j++) acc[p][j] = make_float2(0.f, 0.f);
        // issue copy for round 0 into buf0
        {
            #pragma unroll
            for (int j = 0; j < 9; j++) {
                int d = t + j*256;               // float2 index in [0,2304)
                int i = 2*d;
                int c = i & 63; int kidx = i >> 6;  // kidx = kk*8+icl
                int icl = kidx & 7; int kk = kidx >> 3;
                cpasync8(&w3buf[i], &c3w[(kk*64 + icl) * 64 + c]);
            }
            CP_COMMIT();
        }
        for (int r = 0; r < 8; r++) {
            CP_WAIT0();
            __syncthreads();
            if (r + 1 < 8) {
                float* nb = w3buf + ((r+1) & 1) * 4608;
                int obase = (r+1) * 8;
                #pragma unroll
                for (int j = 0; j < 9; j++) {
                    int d = t + j*256;
                    int i = 2*d;
                    int c = i & 63; int kidx = i >> 6;
                    int icl = kidx & 7; int kk = kidx >> 3;
                    cpasync8(&nb[i], &c3w[(kk*64 + obase + icl) * 64 + c]);
                }
                CP_COMMIT();
            }
            const float* wbuf = w3buf + (r & 1) * 4608;
            #pragma unroll
            for (int ky = 0; ky < 3; ky++) {
                const float* inb = P2 + (r*8)*100 + (cy + ky) * 10 + x0;
                const float* wk = wbuf + (ky*3)*512 + 4*cq;
                #pragma unroll
                for (int icl = 0; icl < 8; icl++) {
                    const float* in = inb + icl * 100;
                    float2 p0 = bcast2(in[0]), p1 = bcast2(in[1]), p2 = bcast2(in[2]);
                    float2 p3 = bcast2(in[3]), p4 = bcast2(in[4]), p5 = bcast2(in[5]);
                    float2 wA0 = *(const float2*)&wk[(0*8+icl)*64];
                    float2 wB0 = *(const float2*)&wk[(0*8+icl)*64 + 2];
                    float2 wA1 = *(const float2*)&wk[(1*8+icl)*64];
                    float2 wB1 = *(const float2*)&wk[(1*8+icl)*64 + 2];
                    float2 wA2 = *(const float2*)&wk[(2*8+icl)*64];
                    float2 wB2 = *(const float2*)&wk[(2*8+icl)*64 + 2];
                    dfma(acc[0][0],p0,wA0); dfma(acc[0][1],p1,wA0); dfma(acc[0][2],p2,wA0); dfma(acc[0][3],p3,wA0);
                    dfma(acc[1][0],p0,wB0); dfma(acc[1][1],p1,wB0); dfma(acc[1][2],p2,wB0); dfma(acc[1][3],p3,wB0);
                    dfma(acc[0][0],p1,wA1); dfma(acc[0][1],p2,wA1); dfma(acc[0][2],p3,wA1); dfma(acc[0][3],p4,wA1);
                    dfma(acc[1][0],p1,wB1); dfma(acc[1][1],p2,wB1); dfma(acc[1][2],p3,wB1); dfma(acc[1][3],p4,wB1);
                    dfma(acc[0][0],p2,wA2); dfma(acc[0][1],p3,wA2); dfma(acc[0][2],p4,wA2); dfma(acc[0][3],p5,wA2);
                    dfma(acc[1][0],p2,wB2); dfma(acc[1][1],p3,wB2); dfma(acc[1][2],p4,wB2); dfma(acc[1][3],p5,wB2);
                }
            }
        }
        float vb[4], va[4];
        #pragma unroll
        for (int k = 0; k < 4; k++) { vb[k] = b3s[4*cq + k]; va[k] = a3s[4*cq + k]; }
        if (cq < 8) {
            #pragma unroll
            for (int p = 0; p < 2; p++) {
                float* t0 = temp3 + (4*cq + 2*p)     * 64 + cy * 8 + x0;
                float* t1 = temp3 + (4*cq + 2*p + 1) * 64 + cy * 8 + x0;
                #pragma unroll
                for (int j = 0; j < 4; j++) {
                    float v0 = acc[p][j].x + vb[2*p];
                    float v1 = acc[p][j].y + vb[2*p+1];
                    t0[j] = v0 >= 0.f ? v0 : va[2*p] * v0;
                    t1[j] = v1 >= 0.f ? v1 : va[2*p+1] * v1;
                }
            }
        }
        __syncthreads();
        for (int task = t; task < 512; task += TPB) {
            int c = task & 31; int pos2 = task >> 5; int px = pos2 & 3; int py = pos2 >> 2;
            const float* tp = temp3 + c * 64;
            float m = fmaxf(fmaxf(tp[(2*py)*8 + 2*px], tp[(2*py)*8 + 2*px + 1]),
                            fmaxf(tp[(2*py+1)*8 + 2*px], tp[(2*py+1)*8 + 2*px + 1]));
            P3[c * 16 + py * 4 + px] = m;
        }
        __syncthreads();
        if (cq >= 8) {
            #pragma unroll
            for (int p = 0; p < 2; p++) {
                float* t0 = temp3 + (4*(cq-8) + 2*p)     * 64 + cy * 8 + x0;
                float* t1 = temp3 + (4*(cq-8) + 2*p + 1) * 64 + cy * 8 + x0;
                #pragma unroll
                for (int j = 0; j < 4; j++) {
                    float v0 = acc[p][j].x + vb[2*p];
                    float v1 = acc[p][j].y + vb[2*p+1];
                    t0[j] = v0 >= 0.f ? v0 : va[2*p] * v0;
                    t1[j] = v1 >= 0.f ? v1 : va[2*p+1] * v1;
                }
            }
        }
        __syncthreads();
        for (int task = t; task < 512; task += TPB) {
            int c = task & 31; int pos2 = task >> 5; int px = pos2 & 3; int py = pos2 >> 2;
            const float* tp = temp3 + c * 64;
            float m = fmaxf(fmaxf(tp[(2*py)*8 + 2*px], tp[(2*py)*8 + 2*px + 1]),
                            fmaxf(tp[(2*py+1)*8 + 2*px], tp[(2*py+1)*8 + 2*px + 1]));
            P3[(32 + c) * 16 + py * 4 + px] = m;
        }
        __syncthreads();
    }

    // ===== stage 4: conv4 2x2x64->128 + prelu -> C4 flat (c*9 + y*3 + x) =====
    // Register-prefetched staging: rounds r = g*4 + k (8 rounds of 4096 floats).
    float* w4s = sm + OFF_W34; float* b4s = w4s + 4096; float* a4s = b4s + 64;
    float* C4 = sm + OFF_C4;
    {
        float pre4[16];
        #pragma unroll
        for (int r = 0; r < 16; r++) {
            int i = t + r*256;
            int c = i & 63; int ic = i >> 6;
            pre4[r] = __ldg(&c4w[ic*128 + c]);   // round 0: g=0,k=0
        }
        for (int g = 0; g < 2; ++g) {
            if (t < 64) { b4s[t] = c4b[g*64 + t]; a4s[t] = p4a[g*64 + t]; }
            const int cq = t & 15; const int pos = t >> 4;
            const int y = pos / 3, x = pos % 3;
            float2 accA = make_float2(0.f,0.f), accB = accA;
            for (int k = 0; k < 4; k++) {
                __syncthreads();
                #pragma unroll
                for (int r = 0; r < 16; r++) w4s[t + r*256] = pre4[r];
                __syncthreads();
                int rr = g*4 + k + 1;
                if (rr < 8) {
                    int ng = rr >> 2; int nk = rr & 3;
                    #pragma unroll
                    for (int r = 0; r < 16; r++) {
                        int i = t + r*256;
                        int c = i & 63; int ic = i >> 6;
                        pre4[r] = __ldg(&c4w[(nk*64 + ic)*128 + ng*64 + c]);
                    }
                }
                if (t < 144) {
                    int ky = k >> 1, kx = k & 1;
                    const float* inb = P3 + (y + ky) * 4 + (x + kx);
                    const float* wb  = w4s + 4*cq;
                    #pragma unroll
                    for (int ic = 0; ic < 64; ic++) {
                        float2 p = bcast2(inb[ic * 16]);
                        float2 wA = *(const float2*)&wb[ic * 64];
                        float2 wB = *(const float2*)&wb[ic * 64 + 2];
                        dfma(accA, p, wA); dfma(accB, p, wB);
                    }
                }
            }
            if (t < 144) {
                int c0 = g*64 + 4*cq;
                float v0 = accA.x + b4s[4*cq+0], v1 = accA.y + b4s[4*cq+1];
                float v2 = accB.x + b4s[4*cq+2], v3 = accB.y + b4s[4*cq+3];
                float l0 = a4s[4*cq+0], l1 = a4s[4*cq+1], l2 = a4s[4*cq+2], l3 = a4s[4*cq+3];
                C4[(c0+0)*9 + pos] = v0 >= 0.f ? v0 : l0 * v0;
                C4[(c0+1)*9 + pos] = v1 >= 0.f ? v1 : l1 * v1;
                C4[(c0+2)*9 + pos] = v2 >= 0.f ? v2 : l2 * v2;
                C4[(c0+3)*9 + pos] = v3 >= 0.f ? v3 : l3 * v3;
            }
            __syncthreads();
        }
    }

    // ===== fc5: 1152 -> 256 + prelu =====
    float* F5 = sm + OFF_F5;
    {
        int warp = t >> 5, lane = t & 31;
        for (int o = warp; o < 256; o += 8) {
            const float4* wrow = (const float4*)(f5w + o * 1152);
            float acc = 0.f;
            #pragma unroll
            for (int j = 0; j < 9; j++) {
                float4 cv = *(const float4*)&C4[j*128 + lane*4];
                float4 wv = __ldg(&wrow[j*32 + lane]);
                acc += cv.x*wv.x + cv.y*wv.y + cv.z*wv.z + cv.w*wv.w;
            }
            #pragma unroll
            for (int s = 16; s; s >>= 1) acc += __shfl_xor_sync(0xFFFFFFFFu, acc, s);
            if (lane == 0) {
                float v = acc + f5b[o];
                float al = p5a[o];
                F5[o] = v >= 0.f ? v : al * v;
            }
        }
    }
    __syncthreads();

    // ===== fc6a (2) + fc6b (4) =====
    float* FC6 = sm + OFF_FC6;
    if (t < 192) {
        int o = t >> 5, lane = t & 31;
        const float* wrow = (o < 2) ? (f6aw + o * 256) : (f6bw + (o - 2) * 256);
        float acc = 0.f;
        #pragma unroll
        for (int j = 0; j < 8; j++) { int k = lane + 32*j; acc += F5[k] * __ldg(&wrow[k]); }
        #pragma unroll
        for (int s = 16; s; s >>= 1) acc += __shfl_xor_sync(0xFFFFFFFFu, acc, s);
        if (lane == 0) FC6[o] = acc + ((o < 2) ? f6ab[o] : f6bb[o - 2]);
    }
    __syncthreads();

    if (t == 0) {
        float l0 = FC6[0], l1 = FC6[1];
        float m = fmaxf(l0, l1);
        float e0 = expf(l0 - m), e1 = expf(l1 - m);
        float score = e1 / (e0 + e1);
        float w = bx2 - bx1, h = by2 - by1;
        g_score[b] = score;
        g_box[b*4+0] = bx1 + FC6[2] * w;
        g_box[b*4+1] = by1 + FC6[3] * h;
        g_box[b*4+2] = bx2 + FC6[4] * w;
        g_box[b*4+3] = by2 + FC6[5] * h;
    }
}

// ---------- NMS: bitonic sort by (score desc, idx asc) ----------
__device__ __forceinline__ bool nms_before(float ka, int ia, float kb, int ib) {
    return (ka > kb) || (ka == kb && ia < ib);
}

__global__ __launch_bounds__(1024) void nms_sort() {
    __shared__ float kk[NBOX];
    __shared__ int   id[NBOX];
    int t = threadIdx.x;
    kk[t] = g_score[t];           id[t] = t;
    kk[t+1024] = g_score[t+1024]; id[t+1024] = t + 1024;
    for (int k = 2; k <= NBOX; k <<= 1) {
        for (int j = k >> 1; j > 0; j >>= 1) {
            __syncthreads();
            #pragma unroll 2
            for (int i = t; i < NBOX; i += 1024) {
                int ixj = i ^ j;
                if (ixj > i) {
                    float ka = kk[i], kb = kk[ixj];
                    int ia = id[i], ib = id[ixj];
                    bool up = ((i & k) == 0);
                    bool bad = up ? nms_before(kb, ib, ka, ia) : nms_before(ka, ia, kb, ib);
                    if (bad) { kk[i] = kb; kk[ixj] = ka; id[i] = ib; id[ixj] = ia; }
                }
            }
        }
    }
    __syncthreads();
    #pragma unroll 2
    for (int i = t; i < NBOX; i += 1024) {
        g_skey[i] = kk[i];
        int o = id[i];
        g_sidx[i] = o;
        g_sbox[i*4+0] = g_box[o*4+0];
        g_sbox[i*4+1] = g_box[o*4+1];
        g_sbox[i*4+2] = g_box[o*4+2];
        g_sbox[i*4+3] = g_box[o*4+3];
    }
}

// ---------- NMS: IOU bitmask ----------
__global__ __launch_bounds__(64) void nms_mask() {
    __shared__ float cb[32][4];
    int t = threadIdx.x;
    int j0 = blockIdx.x * 32;
    for (int i = t; i < 128; i += 64) cb[i >> 2][i & 3] = g_sbox[(j0 + (i >> 2)) * 4 + (i & 3)];
    __syncthreads();
    int i = blockIdx.y * 64 + t;
    float x1 = g_sbox[i*4+0], y1 = g_sbox[i*4+1], x2 = g_sbox[i*4+2], y2 = g_sbox[i*4+3];
    float area = (x2 - x1) * (y2 - y1);
    unsigned word = 0;
    #pragma unroll 8
    for (int jj = 0; jj < 32; jj++) {
        int j = j0 + jj;
        if (j > i) {
            float bx1v = cb[jj][0], by1v = cb[jj][1], bx2v = cb[jj][2], by2v = cb[jj][3];
            float xx1 = fmaxf(x1, bx1v), yy1 = fmaxf(y1, by1v);
            float xx2 = fminf(x2, bx2v), yy2 = fminf(y2, by2v);
            float inter = fmaxf(xx2 - xx1, 0.f) * fmaxf(yy2 - yy1, 0.f);
            float areab = (bx2v - bx1v) * (by2v - by1v);
            float iou = inter / (area + areab - inter + 1e-12f);
            if (iou > 0.5f) word |= (1u << jj);
        }
    }
    ((unsigned*)g_mask4)[i * 64 + blockIdx.x] = word;
}

// ---------- NMS: serial scan; uint4 streaming producers + register decision word ----------
#define SCHUNK 64
#define SNT    512
__global__ __launch_bounds__(SNT) void nms_scan(float* __restrict__ out) {
    __shared__ uint4 buf4[2][SCHUNK * 16];
    __shared__ unsigned keepw[64];
    __shared__ int sV;
    int t = threadIdx.x;
    if (t < 64) keepw[t] = 0u;
    if (t == 0) sV = 0;
    __syncthreads();
    for (int p = t; p < NBOX; p += SNT) {
        bool v = g_skey[p] >= 0.5f;
        unsigned bal = __ballot_sync(0xFFFFFFFFu, v);
        if ((t & 31) == 0) atomicAdd(&sV, __popc(bal));
    }
    __syncthreads();
    const int V = sV;
    const int nch = (V + SCHUNK - 1) / SCHUNK;
    const uint4 z4 = make_uint4(0u,0u,0u,0u);
    for (int i = t; i < SCHUNK * 16; i += SNT) {
        int p = i >> 4;
        buf4[0][i] = (p < V) ? g_mask4[i] : z4;
    }
    __syncthreads();
    unsigned r0 = 0u, r1 = 0u;
    for (int ci = 0; ci < nch; ci++) {
        if (t >= 32) {
            if (ci + 1 < nch) {
                uint4* nb = buf4[(ci + 1) & 1];
                int pb = (ci + 1) * SCHUNK;
                for (int i = t - 32; i < SCHUNK * 16; i += (SNT - 32)) {
                    int p = pb + (i >> 4);
                    nb[i] = (p < V) ? g_mask4[p * 16 + (i & 15)] : z4;
                }
            }
        } else {
            const unsigned* B = (const unsigned*)buf4[ci & 1];
            int pb = ci * SCHUNK;
            #pragma unroll
            for (int r = 0; r < 2; r++) {
                int rb = pb + r * 32;
                if (rb >= V) break;
                int w = rb >> 5;
                int lim = min(32, V - rb);
                unsigned dw = (w < 32) ? __shfl_sync(0xFFFFFFFFu, r0, w)
                                       : __shfl_sync(0xFFFFFFFFu, r1, w - 32);
                for (int jb = 0; jb < lim; jb += 8) {
                    unsigned qa[8], qb[8], qw[8];
                    #pragma unroll
                    for (int j = 0; j < 8; j++) {
                        int jj = r * 32 + jb + j;
                        bool ok = (jb + j) < lim;
                        qa[j] = ok ? B[jj*64 + t]      : 0u;
                        qb[j] = ok ? B[jj*64 + 32 + t] : 0u;
                        qw[j] = ok ? B[jj*64 + w]      : 0u;
                    }
                    #pragma unroll
                    for (int j = 0; j < 8; j++) {
                        int bb = jb + j;
                        unsigned m = ((dw >> bb) & 1u) - 1u;
                        dw |= qw[j] & m;
                        r0 |= qa[j] & m;
                        r1 |= qb[j] & m;
                    }
                }
                if (t == 0) {
                    unsigned vmask = (lim >= 32) ? 0xFFFFFFFFu : ((1u << lim) - 1u);
                    keepw[w] = (~dw) & vmask;
                }
            }
        }
        __syncthreads();
    }
    for (int i = t; i < NBOX * 4; i += SNT) out[i] = 0.f;
    __syncthreads();
    for (int p = t; p < NBOX; p += SNT) {
        if ((keepw[p >> 5] >> (p & 31)) & 1u) {
            int o = g_sidx[p];
            out[o*4+0] = g_sbox[p*4+0];
            out[o*4+1] = g_sbox[p*4+1];
            out[o*4+2] = g_sbox[p*4+2];
            out[o*4+3] = g_sbox[p*4+3];
        }
    }
}

extern "C" void kernel_launch(void* const* d_in, const int* in_sizes, int n_in,
                              void* d_out, int out_size) {
    (void)in_sizes; (void)n_in; (void)out_size;
    cudaFuncSetAttribute(onet_cnn, cudaFuncAttributeMaxDynamicSharedMemorySize, SMEM1_FLOATS * 4);
    onet_cnn<<<NBOX, TPB, SMEM1_FLOATS * 4>>>(
        (const float*)d_in[0],  (const float*)d_in[1],
        (const float*)d_in[2],  (const float*)d_in[3],  (const float*)d_in[4],
        (const float*)d_in[5],  (const float*)d_in[6],  (const float*)d_in[7],
        (const float*)d_in[8],  (const float*)d_in[9],  (const float*)d_in[10],
        (const float*)d_in[11], (const float*)d_in[12], (const float*)d_in[13],
        (const float*)d_in[14], (const float*)d_in[15], (const float*)d_in[16],
        (const float*)d_in[17], (const float*)d_in[18],
        (const float*)d_in[19], (const float*)d_in[20]);
    nms_sort<<<1, 1024>>>();
    nms_mask<<<dim3(64, 32), 64>>>();
    nms_scan<<<1, SNT>>>((float*)d_out);
}

// round 16
// speedup vs baseline: 2.3856x; 1.0370x over previous
#include <cuda_runtime.h>
#include <cuda_bf16.h>
#include <math.h>

#define NBOX 2048
#define TPB  256

// shared arena offsets (floats) — liveness: crop/P2 @0 (crop s1; P2 s3+),
// P1 @6912 live s1-s2 (dead s3+ -> P3/C4/F5/FC6/W34), small scratch @23840 always free.
#define OFF_CROP   0
#define OFF_P2     0
#define OFF_GAP    6400
#define OFF_P1     6912
#define OFF_P3     6912
#define OFF_C4     7936
#define OFF_F5     9088
#define OFF_FC6    9344
#define OFF_W34    9472     // stage3/4 ONLY (inside dead-P1 region)
#define OFF_W      23840    // stage1/2/3 small scratch + fc5 dual-box buffers (4312 floats)
#define SMEM1_FLOATS 28152  // 112,608 bytes -> 2 CTAs/SM

__device__ float    g_score[NBOX];
__device__ float    g_box[NBOX * 4];
__device__ float    g_skey[NBOX];
__device__ int      g_sidx[NBOX];
__device__ float    g_sbox[NBOX * 4];
__device__ uint4    g_mask4[NBOX * 16];
__device__ float    g_c4park[(NBOX/2) * 1152];

// packed dual fp32 FMA: c += a*b per lane (FFMA2)
__device__ __forceinline__ void dfma(float2& c, float2 a, float2 b) {
    asm("fma.rn.f32x2 %0, %1, %2, %0;"
        : "+l"(reinterpret_cast<unsigned long long&>(c))
        : "l"(reinterpret_cast<unsigned long long&>(a)),
          "l"(reinterpret_cast<unsigned long long&>(b)));
}
__device__ __forceinline__ float2 bcast2(float v) { return make_float2(v, v); }

__device__ __forceinline__ void cpasync8(float* dst, const float* src) {
    unsigned sa = (unsigned)__cvta_generic_to_shared(dst);
    asm volatile("cp.async.ca.shared.global [%0], [%1], 8;" :: "r"(sa), "l"(src));
}
#define CP_COMMIT() asm volatile("cp.async.commit_group;")
#define CP_WAIT0()  asm volatile("cp.async.wait_group 0;")

__global__ __launch_bounds__(TPB, 2) void onet_cnn(
    const float* __restrict__ bboxes, const float* __restrict__ image,
    const float* __restrict__ c1w, const float* __restrict__ c1b, const float* __restrict__ p1a,
    const float* __restrict__ c2w, const float* __restrict__ c2b, const float* __restrict__ p2a,
    const float* __restrict__ c3w, const float* __restrict__ c3b, const float* __restrict__ p3a,
    const float* __restrict__ c4w, const float* __restrict__ c4b, const float* __restrict__ p4a,
    const float* __restrict__ f5w, const float* __restrict__ f5b, const float* __restrict__ p5a,
    const float* __restrict__ f6aw, const float* __restrict__ f6ab,
    const float* __restrict__ f6bw, const float* __restrict__ f6bb)
{
    extern __shared__ float sm[];
    const int t = threadIdx.x;

    for (int bb = 0; bb < 2; bb++) {
        const int b = blockIdx.x * 2 + bb;
        float B0 = bboxes[b*4+0], B1 = bboxes[b*4+1], B2 = bboxes[b*4+2], B3 = bboxes[b*4+3];
        float bx1 = fmaxf(B0, 0.f), by1 = fmaxf(B1, 0.f);
        float bx2 = fminf(B2, 1024.f), by2 = fminf(B3, 1024.f);
        int ix1 = (int)bx1, iy1 = (int)by1, ix2 = (int)bx2, iy2 = (int)by2;
        int cw = max(ix2 - ix1, 1), ch = max(iy2 - iy1, 1);

        // ---- crop 48x48x3 HWC ----
        float* crop = sm + OFF_CROP;
        for (int i = t; i < 2304; i += TPB) {
            int x = i % 48; int y = i / 48;
            int gx = ix1 + (x * cw) / 48;
            int gy = iy1 + (y * ch) / 48;
            const float* src = image + (gy * 1024 + gx) * 3;
            float* dst = crop + i * 3;
            dst[0] = (__ldg(&src[0]) - 127.5f) * 0.0078125f;
            dst[1] = (__ldg(&src[1]) - 127.5f) * 0.0078125f;
            dst[2] = (__ldg(&src[2]) - 127.5f) * 0.0078125f;
        }
        __syncthreads();

        // ===== stage 1: conv1 3x3x3->32 + prelu + pool(3,2,pad1) -> P1 [32][23][23] =====
        float* temp1 = sm + OFF_W;
        float* P1 = sm + OFF_P1;
        for (int g = 0; g < 16; ++g) {
            float2 wr[27];
            #pragma unroll
            for (int k = 0; k < 27; k++) wr[k] = __ldg((const float2*)&c1w[k * 32 + 2*g]);
            float2 bias  = __ldg((const float2*)&c1b[2*g]);
            float2 alpha = __ldg((const float2*)&p1a[2*g]);
            for (int task = t; task < 552; task += TPB) {
                int xg = task % 12; int cy = task / 12;
                int x0 = xg * 4;
                float2 a0 = make_float2(0.f,0.f), a1v = a0, a2 = a0, a3 = a0;
                #pragma unroll
                for (int ky = 0; ky < 3; ky++) {
                    const float* row = crop + (cy + ky) * 144;
                    float in[18];
                    #pragma unroll
                    for (int j = 0; j < 6; j++) {
                        int col = x0 + j; if (col > 47) col = 47;
                        in[j*3+0] = row[col*3+0];
                        in[j*3+1] = row[col*3+1];
                        in[j*3+2] = row[col*3+2];
                    }
                    #pragma unroll
                    for (int kx = 0; kx < 3; kx++)
                        #pragma unroll
                        for (int ic = 0; ic < 3; ic++) {
                            float2 w = wr[(ky*3+kx)*3+ic];
                            dfma(a0,  bcast2(in[(kx+0)*3+ic]), w);
                            dfma(a1v, bcast2(in[(kx+1)*3+ic]), w);
                            dfma(a2,  bcast2(in[(kx+2)*3+ic]), w);
                            dfma(a3,  bcast2(in[(kx+3)*3+ic]), w);
                        }
                }
                float2* tp = (float2*)temp1 + cy * 46;
                float2 o;
                o.x = a0.x + bias.x; o.y = a0.y + bias.y;
                o.x = o.x >= 0.f ? o.x : alpha.x * o.x; o.y = o.y >= 0.f ? o.y : alpha.y * o.y;
                tp[x0+0] = o;
                o.x = a1v.x + bias.x; o.y = a1v.y + bias.y;
                o.x = o.x >= 0.f ? o.x : alpha.x * o.x; o.y = o.y >= 0.f ? o.y : alpha.y * o.y;
                tp[x0+1] = o;
                if (x0+2 < 46) {
                    o.x = a2.x + bias.x; o.y = a2.y + bias.y;
                    o.x = o.x >= 0.f ? o.x : alpha.x * o.x; o.y = o.y >= 0.f ? o.y : alpha.y * o.y;
                    tp[x0+2] = o;
                }
                if (x0+3 < 46) {
                    o.x = a3.x + bias.x; o.y = a3.y + bias.y;
                    o.x = o.x >= 0.f ? o.x : alpha.x * o.x; o.y = o.y >= 0.f ? o.y : alpha.y * o.y;
                    tp[x0+3] = o;
                }
            }
            __syncthreads();
            for (int i = t; i < 1058; i += TPB) {
                int c = i & 1; int pos = i >> 1; int px = pos % 23; int py = pos / 23;
                float m = -3.4e38f;
                #pragma unroll
                for (int dy = 0; dy < 3; dy++) {
                    int cy2 = 2*py - 1 + dy; if (cy2 < 0 || cy2 >= 46) continue;
                    #pragma unroll
                    for (int dx = 0; dx < 3; dx++) {
                        int cx2 = 2*px - 1 + dx; if (cx2 < 0 || cx2 >= 46) continue;
                        m = fmaxf(m, temp1[(cy2*46 + cx2)*2 + c]);
                    }
                }
                P1[(g*2 + c) * 529 + py * 23 + px] = m;
            }
            __syncthreads();
        }

        // ===== stage 2: conv2 3x3x32->64 + prelu + pool(3,2) -> P2 [64][10][10] =====
        float* w2s = sm + OFF_W;
        float* temp2 = sm + OFF_W + 768;
        float* b2s = sm + OFF_GAP; float* a2s = b2s + 16;
        float* P2 = sm + OFF_P2;
        {
            float pre[3];
            #pragma unroll
            for (int r = 0; r < 3; r++) {
                int i = t + r*256;
                int c = i & 15; int rest = i >> 4; int icl = rest & 15; int kx = rest >> 4;
                pre[r] = __ldg(&c2w[(kx*32 + icl) * 64 + c]);
            }
            for (int g = 0; g < 4; ++g) {
                if (t < 16) { b2s[t] = c2b[g*16 + t]; a2s[t] = p2a[g*16 + t]; }
                const int xg = t % 3; const int rem = t / 3;
                const int cq = rem & 3; const int cy = rem >> 2;
                const int x0 = xg * 7;
                float2 acc[2][7];
                #pragma unroll
                for (int p = 0; p < 2; p++)
                    #pragma unroll
                    for (int j = 0; j < 7; j++) acc[p][j] = make_float2(0.f, 0.f);
                for (int ky = 0; ky < 3; ky++) {
                    for (int ih = 0; ih < 2; ih++) {
                        __syncthreads();
                        #pragma unroll
                        for (int r = 0; r < 3; r++) w2s[t + r*256] = pre[r];
                        __syncthreads();
                        int rr = g*6 + ky*2 + ih + 1;
                        if (rr < 24) {
                            int ng = rr / 6; int nrem = rr % 6; int nky = nrem >> 1; int nih = nrem & 1;
                            #pragma unroll
                            for (int r = 0; r < 3; r++) {
                                int i = t + r*256;
                                int c = i & 15; int rest = i >> 4; int icl = rest & 15; int kx = rest >> 4;
                                pre[r] = __ldg(&c2w[((nky*3 + kx)*32 + nih*16 + icl) * 64 + ng*16 + c]);
                            }
                        }
                        if (t < 252) {
                            const float* inb = P1 + (ih*16)*529 + (cy + ky) * 23 + x0;
                            const float* wb = w2s + 4*cq;
                            #pragma unroll
                            for (int icl = 0; icl < 16; icl++) {
                                const float* in = inb + icl * 529;
                                float2 p0 = bcast2(in[0]), p1 = bcast2(in[1]), p2 = bcast2(in[2]);
                                float2 p3 = bcast2(in[3]), p4 = bcast2(in[4]), p5 = bcast2(in[5]);
                                float2 p6 = bcast2(in[6]), p7 = bcast2(in[7]), p8 = bcast2(in[8]);
                                float2 wA0 = *(const float2*)&wb[(0*16+icl)*16];
                                float2 wB0 = *(const float2*)&wb[(0*16+icl)*16 + 2];
                                float2 wA1 = *(const float2*)&wb[(1*16+icl)*16];
                                float2 wB1 = *(const float2*)&wb[(1*16+icl)*16 + 2];
                                float2 wA2 = *(const float2*)&wb[(2*16+icl)*16];
                                float2 wB2 = *(const float2*)&wb[(2*16+icl)*16 + 2];
                                dfma(acc[0][0],p0,wA0); dfma(acc[0][1],p1,wA0); dfma(acc[0][2],p2,wA0);
                                dfma(acc[0][3],p3,wA0); dfma(acc[0][4],p4,wA0); dfma(acc[0][5],p5,wA0); dfma(acc[0][6],p6,wA0);
                                dfma(acc[1][0],p0,wB0); dfma(acc[1][1],p1,wB0); dfma(acc[1][2],p2,wB0);
                                dfma(acc[1][3],p3,wB0); dfma(acc[1][4],p4,wB0); dfma(acc[1][5],p5,wB0); dfma(acc[1][6],p6,wB0);
                                dfma(acc[0][0],p1,wA1); dfma(acc[0][1],p2,wA1); dfma(acc[0][2],p3,wA1);
                                dfma(acc[0][3],p4,wA1); dfma(acc[0][4],p5,wA1); dfma(acc[0][5],p6,wA1); dfma(acc[0][6],p7,wA1);
                                dfma(acc[1][0],p1,wB1); dfma(acc[1][1],p2,wB1); dfma(acc[1][2],p3,wB1);
                                dfma(acc[1][3],p4,wB1); dfma(acc[1][4],p5,wB1); dfma(acc[1][5],p6,wB1); dfma(acc[1][6],p7,wB1);
                                dfma(acc[0][0],p2,wA2); dfma(acc[0][1],p3,wA2); dfma(acc[0][2],p4,wA2);
                                dfma(acc[0][3],p5,wA2); dfma(acc[0][4],p6,wA2); dfma(acc[0][5],p7,wA2); dfma(acc[0][6],p8,wA2);
                                dfma(acc[1][0],p2,wB2); dfma(acc[1][1],p3,wB2); dfma(acc[1][2],p4,wB2);
                                dfma(acc[1][3],p5,wB2); dfma(acc[1][4],p6,wB2); dfma(acc[1][5],p7,wB2); dfma(acc[1][6],p8,wB2);
                            }
                        }
                    }
                }
                float vb[4], va[4];
                if (t < 252) {
                    #pragma unroll
                    for (int k = 0; k < 4; k++) { vb[k] = b2s[4*cq + k]; va[k] = a2s[4*cq + k]; }
                }
                if (t < 252 && cq < 2) {
                    #pragma unroll
                    for (int p = 0; p < 2; p++) {
                        float* t0 = temp2 + (4*cq + 2*p)     * 441 + cy * 21 + x0;
                        float* t1 = temp2 + (4*cq + 2*p + 1) * 441 + cy * 21 + x0;
                        #pragma unroll
                        for (int j = 0; j < 7; j++) {
                            float v0 = acc[p][j].x + vb[2*p];
                            float v1 = acc[p][j].y + vb[2*p+1];
                            t0[j] = v0 >= 0.f ? v0 : va[2*p] * v0;
                            t1[j] = v1 >= 0.f ? v1 : va[2*p+1] * v1;
                        }
                    }
                }
                __syncthreads();
                for (int i = t; i < 800; i += TPB) {
                    int c = i & 7; int pos = i >> 3; int px = pos % 10; int py = pos / 10;
                    const float* tp = temp2 + c * 441;
                    float m = -3.4e38f;
                    #pragma unroll
                    for (int dy = 0; dy < 3; dy++)
                        #pragma unroll
                        for (int dx = 0; dx < 3; dx++)
                            m = fmaxf(m, tp[(2*py+dy)*21 + 2*px+dx]);
                    P2[(g*16 + c) * 100 + py * 10 + px] = m;
                }
                __syncthreads();
                if (t < 252 && cq >= 2) {
                    #pragma unroll
                    for (int p = 0; p < 2; p++) {
                        float* t0 = temp2 + (4*(cq-2) + 2*p)     * 441 + cy * 21 + x0;
                        float* t1 = temp2 + (4*(cq-2) + 2*p + 1) * 441 + cy * 21 + x0;
                        #pragma unroll
                        for (int j = 0; j < 7; j++) {
                            float v0 = acc[p][j].x + vb[2*p];
                            float v1 = acc[p][j].y + vb[2*p+1];
                            t0[j] = v0 >= 0.f ? v0 : va[2*p] * v0;
                            t1[j] = v1 >= 0.f ? v1 : va[2*p+1] * v1;
                        }
                    }
                }
                __syncthreads();
                for (int i = t; i < 800; i += TPB) {
                    int c = i & 7; int pos = i >> 3; int px = pos % 10; int py = pos / 10;
                    const float* tp = temp2 + c * 441;
                    float m = -3.4e38f;
                    #pragma unroll
                    for (int dy = 0; dy < 3; dy++)
                        #pragma unroll
                        for (int dx = 0; dx < 3; dx++)
                            m = fmaxf(m, tp[(2*py+dy)*21 + 2*px+dx]);
                    P2[(g*16 + 8 + c) * 100 + py * 10 + px] = m;
                }
                __syncthreads();
            }
        }

        // ===== stage 3: conv3 (cp.async double-buffered, 8 ic-octet rounds) =====
        float* w3buf = sm + OFF_W34;
        float* b3s = w3buf + 9216; float* a3s = b3s + 64;
        float* temp3 = sm + OFF_W;
        float* P3 = sm + OFF_P3;
        {
            if (t < 64) { b3s[t] = c3b[t]; a3s[t] = p3a[t]; }
            const int cq = t & 15; const int pos = t >> 4;
            const int xg = pos & 1; const int cy = pos >> 1;
            const int x0 = xg * 4;
            float2 acc[2][4];
            #pragma unroll
            for (int p = 0; p < 2; p++)
                #pragma unroll
                for (int j = 0; j < 4; j++) acc[p][j] = make_float2(0.f, 0.f);
            {
                #pragma unroll
                for (int j = 0; j < 9; j++) {
                    int d = t + j*256;
                    int i = 2*d;
                    int c = i & 63; int kidx = i >> 6;
                    int icl = kidx & 7; int kk = kidx >> 3;
                    cpasync8(&w3buf[i], &c3w[(kk*64 + icl) * 64 + c]);
                }
                CP_COMMIT();
            }
            for (int r = 0; r < 8; r++) {
                CP_WAIT0();
                __syncthreads();
                if (r + 1 < 8) {
                    float* nb = w3buf + ((r+1) & 1) * 4608;
                    int obase = (r+1) * 8;
                    #pragma unroll
                    for (int j = 0; j < 9; j++) {
                        int d = t + j*256;
                        int i = 2*d;
                        int c = i & 63; int kidx = i >> 6;
                        int icl = kidx & 7; int kk = kidx >> 3;
                        cpasync8(&nb[i], &c3w[(kk*64 + obase + icl) * 64 + c]);
                    }
                    CP_COMMIT();
                }
                const float* wbuf = w3buf + (r & 1) * 4608;
                #pragma unroll
                for (int ky = 0; ky < 3; ky++) {
                    const float* inb = P2 + (r*8)*100 + (cy + ky) * 10 + x0;
                    const float* wk = wbuf + (ky*3)*512 + 4*cq;
                    #pragma unroll
                    for (int icl = 0; icl < 8; icl++) {
                        const float* in = inb + icl * 100;
                        float2 p0 = bcast2(in[0]), p1 = bcast2(in[1]), p2 = bcast2(in[2]);
                        float2 p3 = bcast2(in[3]), p4 = bcast2(in[4]), p5 = bcast2(in[5]);
                        float2 wA0 = *(const float2*)&wk[(0*8+icl)*64];
                        float2 wB0 = *(const float2*)&wk[(0*8+icl)*64 + 2];
                        float2 wA1 = *(const float2*)&wk[(1*8+icl)*64];
                        float2 wB1 = *(const float2*)&wk[(1*8+icl)*64 + 2];
                        float2 wA2 = *(const float2*)&wk[(2*8+icl)*64];
                        float2 wB2 = *(const float2*)&wk[(2*8+icl)*64 + 2];
                        dfma(acc[0][0],p0,wA0); dfma(acc[0][1],p1,wA0); dfma(acc[0][2],p2,wA0); dfma(acc[0][3],p3,wA0);
                        dfma(acc[1][0],p0,wB0); dfma(acc[1][1],p1,wB0); dfma(acc[1][2],p2,wB0); dfma(acc[1][3],p3,wB0);
                        dfma(acc[0][0],p1,wA1); dfma(acc[0][1],p2,wA1); dfma(acc[0][2],p3,wA1); dfma(acc[0][3],p4,wA1);
                        dfma(acc[1][0],p1,wB1); dfma(acc[1][1],p2,wB1); dfma(acc[1][2],p3,wB1); dfma(acc[1][3],p4,wB1);
                        dfma(acc[0][0],p2,wA2); dfma(acc[0][1],p3,wA2); dfma(acc[0][2],p4,wA2); dfma(acc[0][3],p5,wA2);
                        dfma(acc[1][0],p2,wB2); dfma(acc[1][1],p3,wB2); dfma(acc[1][2],p4,wB2); dfma(acc[1][3],p5,wB2);
                    }
                }
            }
            float vb[4], va[4];
            #pragma unroll
            for (int k = 0; k < 4; k++) { vb[k] = b3s[4*cq + k]; va[k] = a3s[4*cq + k]; }
            if (cq < 8) {
                #pragma unroll
                for (int p = 0; p < 2; p++) {
                    float* t0 = temp3 + (4*cq + 2*p)     * 64 + cy * 8 + x0;
                    float* t1 = temp3 + (4*cq + 2*p + 1) * 64 + cy * 8 + x0;
                    #pragma unroll
                    for (int j = 0; j < 4; j++) {
                        float v0 = acc[p][j].x + vb[2*p];
                        float v1 = acc[p][j].y + vb[2*p+1];
                        t0[j] = v0 >= 0.f ? v0 : va[2*p] * v0;
                        t1[j] = v1 >= 0.f ? v1 : va[2*p+1] * v1;
                    }
                }
            }
            __syncthreads();
            for (int task = t; task < 512; task += TPB) {
                int c = task & 31; int pos2 = task >> 5; int px = pos2 & 3; int py = pos2 >> 2;
                const float* tp = temp3 + c * 64;
                float m = fmaxf(fmaxf(tp[(2*py)*8 + 2*px], tp[(2*py)*8 + 2*px + 1]),
                                fmaxf(tp[(2*py+1)*8 + 2*px], tp[(2*py+1)*8 + 2*px + 1]));
                P3[c * 16 + py * 4 + px] = m;
            }
            __syncthreads();
            if (cq >= 8) {
                #pragma unroll
                for (int p = 0; p < 2; p++) {
                    float* t0 = temp3 + (4*(cq-8) + 2*p)     * 64 + cy * 8 + x0;
                    float* t1 = temp3 + (4*(cq-8) + 2*p + 1) * 64 + cy * 8 + x0;
                    #pragma unroll
                    for (int j = 0; j < 4; j++) {
                        float v0 = acc[p][j].x + vb[2*p];
                        float v1 = acc[p][j].y + vb[2*p+1];
                        t0[j] = v0 >= 0.f ? v0 : va[2*p] * v0;
                        t1[j] = v1 >= 0.f ? v1 : va[2*p+1] * v1;
                    }
                }
            }
            __syncthreads();
            for (int task = t; task < 512; task += TPB) {
                int c = task & 31; int pos2 = task >> 5; int px = pos2 & 3; int py = pos2 >> 2;
                const float* tp = temp3 + c * 64;
                float m = fmaxf(fmaxf(tp[(2*py)*8 + 2*px], tp[(2*py)*8 + 2*px + 1]),
                                fmaxf(tp[(2*py+1)*8 + 2*px], tp[(2*py+1)*8 + 2*px + 1]));
                P3[(32 + c) * 16 + py * 4 + px] = m;
            }
            __syncthreads();
        }

        // ===== stage 4: conv4 2x2x64->128 + prelu -> C4 flat =====
        float* w4s = sm + OFF_W34; float* b4s = w4s + 4096; float* a4s = b4s + 64;
        float* C4 = sm + OFF_C4;
        {
            float pre4[16];
            #pragma unroll
            for (int r = 0; r < 16; r++) {
                int i = t + r*256;
                int c = i & 63; int ic = i >> 6;
                pre4[r] = __ldg(&c4w[ic*128 + c]);
            }
            for (int g = 0; g < 2; ++g) {
                if (t < 64) { b4s[t] = c4b[g*64 + t]; a4s[t] = p4a[g*64 + t]; }
                const int cq = t & 15; const int pos = t >> 4;
                const int y = pos / 3, x = pos % 3;
                float2 accA = make_float2(0.f,0.f), accB = accA;
                for (int k = 0; k < 4; k++) {
                    __syncthreads();
                    #pragma unroll
                    for (int r = 0; r < 16; r++) w4s[t + r*256] = pre4[r];
                    __syncthreads();
                    int rr = g*4 + k + 1;
                    if (rr < 8) {
                        int ng = rr >> 2; int nk = rr & 3;
                        #pragma unroll
                        for (int r = 0; r < 16; r++) {
                            int i = t + r*256;
                            int c = i & 63; int ic = i >> 6;
                            pre4[r] = __ldg(&c4w[(nk*64 + ic)*128 + ng*64 + c]);
                        }
                    }
                    if (t < 144) {
                        int ky = k >> 1, kx = k & 1;
                        const float* inb = P3 + (y + ky) * 4 + (x + kx);
                        const float* wb  = w4s + 4*cq;
                        #pragma unroll
                        for (int ic = 0; ic < 64; ic++) {
                            float2 p = bcast2(inb[ic * 16]);
                            float2 wA = *(const float2*)&wb[ic * 64];
                            float2 wB = *(const float2*)&wb[ic * 64 + 2];
                            dfma(accA, p, wA); dfma(accB, p, wB);
                        }
                    }
                }
                if (t < 144) {
                    int c0 = g*64 + 4*cq;
                    float v0 = accA.x + b4s[4*cq+0], v1 = accA.y + b4s[4*cq+1];
                    float v2 = accB.x + b4s[4*cq+2], v3 = accB.y + b4s[4*cq+3];
                    float l0 = a4s[4*cq+0], l1 = a4s[4*cq+1], l2 = a4s[4*cq+2], l3 = a4s[4*cq+3];
                    C4[(c0+0)*9 + pos] = v0 >= 0.f ? v0 : l0 * v0;
                    C4[(c0+1)*9 + pos] = v1 >= 0.f ? v1 : l1 * v1;
                    C4[(c0+2)*9 + pos] = v2 >= 0.f ? v2 : l2 * v2;
                    C4[(c0+3)*9 + pos] = v3 >= 0.f ? v3 : l3 * v3;
                }
                __syncthreads();
            }
        }

        // park box-0's C4 in gmem scratch (box-1's stays in smem)
        if (bb == 0) {
            float4* park = (float4*)(g_c4park + (size_t)blockIdx.x * 1152);
            const float4* src = (const float4*)(sm + OFF_C4);
            for (int i = t; i < 288; i += TPB) park[i] = src[i];
            __syncthreads();
        }
    }

    // ===== fc5 dual: 1152 -> 256 + prelu for BOTH boxes (weights read once) =====
    float* C40 = sm + OFF_W;            // 1152 (box 0, reloaded from park)
    float* F50 = sm + OFF_W + 1152;     // 256
    float* FC60 = sm + OFF_W + 1408;    // 8
    float* C41 = sm + OFF_C4;           // box 1 (in place)
    float* F51 = sm + OFF_F5;
    float* FC61 = sm + OFF_FC6;
    {
        float4* dst = (float4*)C40;
        const float4* park = (const float4*)(g_c4park + (size_t)blockIdx.x * 1152);
        for (int i = t; i < 288; i += TPB) dst[i] = park[i];
    }
    __syncthreads();
    {
        int warp = t >> 5, lane = t & 31;
        for (int o = warp; o < 256; o += 8) {
            const float4* wrow = (const float4*)(f5w + o * 1152);
            float acc0 = 0.f, acc1 = 0.f;
            #pragma unroll
            for (int j = 0; j < 9; j++) {
                float4 wv = __ldg(&wrow[j*32 + lane]);
                float4 c0 = *(const float4*)&C40[j*128 + lane*4];
                float4 c1 = *(const float4*)&C41[j*128 + lane*4];
                acc0 += c0.x*wv.x + c0.y*wv.y + c0.z*wv.z + c0.w*wv.w;
                acc1 += c1.x*wv.x + c1.y*wv.y + c1.z*wv.z + c1.w*wv.w;
            }
            #pragma unroll
            for (int s = 16; s; s >>= 1) {
                acc0 += __shfl_xor_sync(0xFFFFFFFFu, acc0, s);
                acc1 += __shfl_xor_sync(0xFFFFFFFFu, acc1, s);
            }
            if (lane == 0) {
                float bsv = f5b[o], al = p5a[o];
                float v0 = acc0 + bsv, v1 = acc1 + bsv;
                F50[o] = v0 >= 0.f ? v0 : al * v0;
                F51[o] = v1 >= 0.f ? v1 : al * v1;
            }
        }
    }
    __syncthreads();

    // ===== fc6 dual =====
    if (t < 192) {
        int o = t >> 5, lane = t & 31;
        const float* wrow = (o < 2) ? (f6aw + o * 256) : (f6bw + (o - 2) * 256);
        float acc0 = 0.f, acc1 = 0.f;
        #pragma unroll
        for (int j = 0; j < 8; j++) {
            int k = lane + 32*j;
            float w = __ldg(&wrow[k]);
            acc0 += F50[k] * w;
            acc1 += F51[k] * w;
        }
        #pragma unroll
        for (int s = 16; s; s >>= 1) {
            acc0 += __shfl_xor_sync(0xFFFFFFFFu, acc0, s);
            acc1 += __shfl_xor_sync(0xFFFFFFFFu, acc1, s);
        }
        if (lane == 0) {
            float bv = (o < 2) ? f6ab[o] : f6bb[o - 2];
            FC60[o] = acc0 + bv;
            FC61[o] = acc1 + bv;
        }
    }
    __syncthreads();

    if (t == 0) {
        #pragma unroll
        for (int bb = 0; bb < 2; bb++) {
            const int bidx = blockIdx.x * 2 + bb;
            const float* FC = bb ? FC61 : FC60;
            float B0 = bboxes[bidx*4+0], B1 = bboxes[bidx*4+1], B2 = bboxes[bidx*4+2], B3 = bboxes[bidx*4+3];
            float bx1 = fmaxf(B0, 0.f), by1 = fmaxf(B1, 0.f);
            float bx2 = fminf(B2, 1024.f), by2 = fminf(B3, 1024.f);
            float l0 = FC[0], l1 = FC[1];
            float m = fmaxf(l0, l1);
            float e0 = expf(l0 - m), e1 = expf(l1 - m);
            float score = e1 / (e0 + e1);
            float w = bx2 - bx1, h = by2 - by1;
            g_score[bidx] = score;
            g_box[bidx*4+0] = bx1 + FC[2] * w;
            g_box[bidx*4+1] = by1 + FC[3] * h;
            g_box[bidx*4+2] = bx2 + FC[4] * w;
            g_box[bidx*4+3] = by2 + FC[5] * h;
        }
    }
}

// ---------- NMS: bitonic sort by (score desc, idx asc) ----------
__device__ __forceinline__ bool nms_before(float ka, int ia, float kb, int ib) {
    return (ka > kb) || (ka == kb && ia < ib);
}

__global__ __launch_bounds__(1024) void nms_sort() {
    __shared__ float kk[NBOX];
    __shared__ int   id[NBOX];
    int t = threadIdx.x;
    kk[t] = g_score[t];           id[t] = t;
    kk[t+1024] = g_score[t+1024]; id[t+1024] = t + 1024;
    for (int k = 2; k <= NBOX; k <<= 1) {
        for (int j = k >> 1; j > 0; j >>= 1) {
            __syncthreads();
            #pragma unroll 2
            for (int i = t; i < NBOX; i += 1024) {
                int ixj = i ^ j;
                if (ixj > i) {
                    float ka = kk[i], kb = kk[ixj];
                    int ia = id[i], ib = id[ixj];
                    bool up = ((i & k) == 0);
                    bool bad = up ? nms_before(kb, ib, ka, ia) : nms_before(ka, ia, kb, ib);
                    if (bad) { kk[i] = kb; kk[ixj] = ka; id[i] = ib; id[ixj] = ia; }
                }
            }
        }
    }
    __syncthreads();
    #pragma unroll 2
    for (int i = t; i < NBOX; i += 1024) {
        g_skey[i] = kk[i];
        int o = id[i];
        g_sidx[i] = o;
        g_sbox[i*4+0] = g_box[o*4+0];
        g_sbox[i*4+1] = g_box[o*4+1];
        g_sbox[i*4+2] = g_box[o*4+2];
        g_sbox[i*4+3] = g_box[o*4+3];
    }
}

// ---------- NMS: IOU bitmask ----------
__global__ __launch_bounds__(64) void nms_mask() {
    __shared__ float cb[32][4];
    int t = threadIdx.x;
    int j0 = blockIdx.x * 32;
    for (int i = t; i < 128; i += 64) cb[i >> 2][i & 3] = g_sbox[(j0 + (i >> 2)) * 4 + (i & 3)];
    __syncthreads();
    int i = blockIdx.y * 64 + t;
    float x1 = g_sbox[i*4+0], y1 = g_sbox[i*4+1], x2 = g_sbox[i*4+2], y2 = g_sbox[i*4+3];
    float area = (x2 - x1) * (y2 - y1);
    unsigned word = 0;
    #pragma unroll 8
    for (int jj = 0; jj < 32; jj++) {
        int j = j0 + jj;
        if (j > i) {
            float bx1v = cb[jj][0], by1v = cb[jj][1], bx2v = cb[jj][2], by2v = cb[jj][3];
            float xx1 = fmaxf(x1, bx1v), yy1 = fmaxf(y1, by1v);
            float xx2 = fminf(x2, bx2v), yy2 = fminf(y2, by2v);
            float inter = fmaxf(xx2 - xx1, 0.f) * fmaxf(yy2 - yy1, 0.f);
            float areab = (bx2v - bx1v) * (by2v - by1v);
            float iou = inter / (area + areab - inter + 1e-12f);
            if (iou > 0.5f) word |= (1u << jj);
        }
    }
    ((unsigned*)g_mask4)[i * 64 + blockIdx.x] = word;
}

// ---------- NMS: serial scan; uint4 streaming producers + register decision word ----------
#define SCHUNK 64
#define SNT    512
__global__ __launch_bounds__(SNT) void nms_scan(float* __restrict__ out) {
    __shared__ uint4 buf4[2][SCHUNK * 16];
    __shared__ unsigned keepw[64];
    __shared__ int sV;
    int t = threadIdx.x;
    if (t < 64) keepw[t] = 0u;
    if (t == 0) sV = 0;
    __syncthreads();
    for (int p = t; p < NBOX; p += SNT) {
        bool v = g_skey[p] >= 0.5f;
        unsigned bal = __ballot_sync(0xFFFFFFFFu, v);
        if ((t & 31) == 0) atomicAdd(&sV, __popc(bal));
    }
    __syncthreads();
    const int V = sV;
    const int nch = (V + SCHUNK - 1) / SCHUNK;
    const uint4 z4 = make_uint4(0u,0u,0u,0u);
    for (int i = t; i < SCHUNK * 16; i += SNT) {
        int p = i >> 4;
        buf4[0][i] = (p < V) ? g_mask4[i] : z4;
    }
    __syncthreads();
    unsigned r0 = 0u, r1 = 0u;
    for (int ci = 0; ci < nch; ci++) {
        if (t >= 32) {
            if (ci + 1 < nch) {
                uint4* nb = buf4[(ci + 1) & 1];
                int pb = (ci + 1) * SCHUNK;
                for (int i = t - 32; i < SCHUNK * 16; i += (SNT - 32)) {
                    int p = pb + (i >> 4);
                    nb[i] = (p < V) ? g_mask4[p * 16 + (i & 15)] : z4;
                }
            }
        } else {
            const unsigned* B = (const unsigned*)buf4[ci & 1];
            int pb = ci * SCHUNK;
            #pragma unroll
            for (int r = 0; r < 2; r++) {
                int rb = pb + r * 32;
                if (rb >= V) break;
                int w = rb >> 5;
                int lim = min(32, V - rb);
                unsigned dw = (w < 32) ? __shfl_sync(0xFFFFFFFFu, r0, w)
                                       : __shfl_sync(0xFFFFFFFFu, r1, w - 32);
                for (int jb = 0; jb < lim; jb += 8) {
                    unsigned qa[8], qb[8], qw[8];
                    #pragma unroll
                    for (int j = 0; j < 8; j++) {
                        int jj = r * 32 + jb + j;
                        bool ok = (jb + j) < lim;
                        qa[j] = ok ? B[jj*64 + t]      : 0u;
                        qb[j] = ok ? B[jj*64 + 32 + t] : 0u;
                        qw[j] = ok ? B[jj*64 + w]      : 0u;
                    }
                    #pragma unroll
                    for (int j = 0; j < 8; j++) {
                        int bb = jb + j;
                        unsigned m = ((dw >> bb) & 1u) - 1u;
                        dw |= qw[j] & m;
                        r0 |= qa[j] & m;
                        r1 |= qb[j] & m;
                    }
                }
                if (t == 0) {
                    unsigned vmask = (lim >= 32) ? 0xFFFFFFFFu : ((1u << lim) - 1u);
                    keepw[w] = (~dw) & vmask;
                }
            }
        }
        __syncthreads();
    }
    for (int i = t; i < NBOX * 4; i += SNT) out[i] = 0.f;
    __syncthreads();
    for (int p = t; p < NBOX; p += SNT) {
        if ((keepw[p >> 5] >> (p & 31)) & 1u) {
            int o = g_sidx[p];
            out[o*4+0] = g_sbox[p*4+0];
            out[o*4+1] = g_sbox[p*4+1];
            out[o*4+2] = g_sbox[p*4+2];
            out[o*4+3] = g_sbox[p*4+3];
        }
    }
}

extern "C" void kernel_launch(void* const* d_in, const int* in_sizes, int n_in,
                              void* d_out, int out_size) {
    (void)in_sizes; (void)n_in; (void)out_size;
    cudaFuncSetAttribute(onet_cnn, cudaFuncAttributeMaxDynamicSharedMemorySize, SMEM1_FLOATS * 4);
    onet_cnn<<<NBOX/2, TPB, SMEM1_FLOATS * 4>>>(
        (const float*)d_in[0],  (const float*)d_in[1],
        (const float*)d_in[2],  (const float*)d_in[3],  (const float*)d_in[4],
        (const float*)d_in[5],  (const float*)d_in[6],  (const float*)d_in[7],
        (const float*)d_in[8],  (const float*)d_in[9],  (const float*)d_in[10],
        (const float*)d_in[11], (const float*)d_in[12], (const float*)d_in[13],
        (const float*)d_in[14], (const float*)d_in[15], (const float*)d_in[16],
        (const float*)d_in[17], (const float*)d_in[18],
        (const float*)d_in[19], (const float*)d_in[20]);
    nms_sort<<<1, 1024>>>();
    nms_mask<<<dim3(64, 32), 64>>>();
    nms_scan<<<1, SNT>>>((float*)d_out);
}

// round 17
// speedup vs baseline: 2.3888x; 1.0014x over previous
#include <cuda_runtime.h>
#include <cuda_bf16.h>
#include <math.h>

#define NBOX 2048
#define TPB  256

// shared arena offsets (floats) — liveness: crop/P2 @0 (crop s1; P2 s3+),
// P1 @6912 live s1-s2 (dead s3+ -> P3/C4/F5/FC6/W34), small scratch @23840 always free.
#define OFF_CROP   0
#define OFF_P2     0
#define OFF_GAP    6400
#define OFF_P1     6912
#define OFF_P3     6912
#define OFF_C4     7936
#define OFF_F5     9088
#define OFF_FC6    9344
#define OFF_W34    9472     // stage3/4 ONLY (inside dead-P1 region)
#define OFF_W      23840    // stage1/2/3 small scratch + fc dual-box buffers (4312 floats)
#define SMEM1_FLOATS 28152  // 112,608 bytes -> 2 CTAs/SM

__device__ float    g_score[NBOX];
__device__ float    g_box[NBOX * 4];
__device__ float    g_skey[NBOX];
__device__ int      g_sidx[NBOX];
__device__ float    g_sbox[NBOX * 4];
__device__ uint4    g_mask4[NBOX * 16];
__device__ float    g_c4park[(NBOX/2) * 1152];
__device__ int      g_V;

// packed dual fp32 FMA: c += a*b per lane (FFMA2)
__device__ __forceinline__ void dfma(float2& c, float2 a, float2 b) {
    asm("fma.rn.f32x2 %0, %1, %2, %0;"
        : "+l"(reinterpret_cast<unsigned long long&>(c))
        : "l"(reinterpret_cast<unsigned long long&>(a)),
          "l"(reinterpret_cast<unsigned long long&>(b)));
}
__device__ __forceinline__ float2 bcast2(float v) { return make_float2(v, v); }

__device__ __forceinline__ void cpasync8(float* dst, const float* src) {
    unsigned sa = (unsigned)__cvta_generic_to_shared(dst);
    asm volatile("cp.async.ca.shared.global [%0], [%1], 8;" :: "r"(sa), "l"(src));
}
__device__ __forceinline__ void cpasync16(float* dst, const float* src) {
    unsigned sa = (unsigned)__cvta_generic_to_shared(dst);
    asm volatile("cp.async.ca.shared.global [%0], [%1], 16;" :: "r"(sa), "l"(src));
}
#define CP_COMMIT() asm volatile("cp.async.commit_group;")
#define CP_WAIT0()  asm volatile("cp.async.wait_group 0;")

__global__ __launch_bounds__(TPB, 2) void onet_cnn(
    const float* __restrict__ bboxes, const float* __restrict__ image,
    const float* __restrict__ c1w, const float* __restrict__ c1b, const float* __restrict__ p1a,
    const float* __restrict__ c2w, const float* __restrict__ c2b, const float* __restrict__ p2a,
    const float* __restrict__ c3w, const float* __restrict__ c3b, const float* __restrict__ p3a,
    const float* __restrict__ c4w, const float* __restrict__ c4b, const float* __restrict__ p4a,
    const float* __restrict__ f5w, const float* __restrict__ f5b, const float* __restrict__ p5a,
    const float* __restrict__ f6aw, const float* __restrict__ f6ab,
    const float* __restrict__ f6bw, const float* __restrict__ f6bb)
{
    extern __shared__ float sm[];
    const int t = threadIdx.x;

    for (int bb = 0; bb < 2; bb++) {
        const int b = blockIdx.x * 2 + bb;
        float B0 = bboxes[b*4+0], B1 = bboxes[b*4+1], B2 = bboxes[b*4+2], B3 = bboxes[b*4+3];
        float bx1 = fmaxf(B0, 0.f), by1 = fmaxf(B1, 0.f);
        float bx2 = fminf(B2, 1024.f), by2 = fminf(B3, 1024.f);
        int ix1 = (int)bx1, iy1 = (int)by1, ix2 = (int)bx2, iy2 = (int)by2;
        int cw = max(ix2 - ix1, 1), ch = max(iy2 - iy1, 1);

        // ---- crop 48x48x3 HWC ----
        float* crop = sm + OFF_CROP;
        for (int i = t; i < 2304; i += TPB) {
            int x = i % 48; int y = i / 48;
            int gx = ix1 + (x * cw) / 48;
            int gy = iy1 + (y * ch) / 48;
            const float* src = image + (gy * 1024 + gx) * 3;
            float* dst = crop + i * 3;
            dst[0] = (__ldg(&src[0]) - 127.5f) * 0.0078125f;
            dst[1] = (__ldg(&src[1]) - 127.5f) * 0.0078125f;
            dst[2] = (__ldg(&src[2]) - 127.5f) * 0.0078125f;
        }
        __syncthreads();

        // ===== stage 1: conv1 3x3x3->32 + prelu + pool(3,2,pad1) -> P1 [32][23][23] =====
        float* temp1 = sm + OFF_W;
        float* P1 = sm + OFF_P1;
        for (int g = 0; g < 16; ++g) {
            float2 wr[27];
            #pragma unroll
            for (int k = 0; k < 27; k++) wr[k] = __ldg((const float2*)&c1w[k * 32 + 2*g]);
            float2 bias  = __ldg((const float2*)&c1b[2*g]);
            float2 alpha = __ldg((const float2*)&p1a[2*g]);
            for (int task = t; task < 552; task += TPB) {
                int xg = task % 12; int cy = task / 12;
                int x0 = xg * 4;
                float2 a0 = make_float2(0.f,0.f), a1v = a0, a2 = a0, a3 = a0;
                #pragma unroll
                for (int ky = 0; ky < 3; ky++) {
                    const float* row = crop + (cy + ky) * 144;
                    float in[18];
                    #pragma unroll
                    for (int j = 0; j < 6; j++) {
                        int col = x0 + j; if (col > 47) col = 47;
                        in[j*3+0] = row[col*3+0];
                        in[j*3+1] = row[col*3+1];
                        in[j*3+2] = row[col*3+2];
                    }
                    #pragma unroll
                    for (int kx = 0; kx < 3; kx++)
                        #pragma unroll
                        for (int ic = 0; ic < 3; ic++) {
                            float2 w = wr[(ky*3+kx)*3+ic];
                            dfma(a0,  bcast2(in[(kx+0)*3+ic]), w);
                            dfma(a1v, bcast2(in[(kx+1)*3+ic]), w);
                            dfma(a2,  bcast2(in[(kx+2)*3+ic]), w);
                            dfma(a3,  bcast2(in[(kx+3)*3+ic]), w);
                        }
                }
                float2* tp = (float2*)temp1 + cy * 46;
                float2 o;
                o.x = a0.x + bias.x; o.y = a0.y + bias.y;
                o.x = o.x >= 0.f ? o.x : alpha.x * o.x; o.y = o.y >= 0.f ? o.y : alpha.y * o.y;
                tp[x0+0] = o;
                o.x = a1v.x + bias.x; o.y = a1v.y + bias.y;
                o.x = o.x >= 0.f ? o.x : alpha.x * o.x; o.y = o.y >= 0.f ? o.y : alpha.y * o.y;
                tp[x0+1] = o;
                if (x0+2 < 46) {
                    o.x = a2.x + bias.x; o.y = a2.y + bias.y;
                    o.x = o.x >= 0.f ? o.x : alpha.x * o.x; o.y = o.y >= 0.f ? o.y : alpha.y * o.y;
                    tp[x0+2] = o;
                }
                if (x0+3 < 46) {
                    o.x = a3.x + bias.x; o.y = a3.y + bias.y;
                    o.x = o.x >= 0.f ? o.x : alpha.x * o.x; o.y = o.y >= 0.f ? o.y : alpha.y * o.y;
                    tp[x0+3] = o;
                }
            }
            __syncthreads();
            for (int i = t; i < 1058; i += TPB) {
                int c = i & 1; int pos = i >> 1; int px = pos % 23; int py = pos / 23;
                float m = -3.4e38f;
                #pragma unroll
                for (int dy = 0; dy < 3; dy++) {
                    int cy2 = 2*py - 1 + dy; if (cy2 < 0 || cy2 >= 46) continue;
                    #pragma unroll
                    for (int dx = 0; dx < 3; dx++) {
                        int cx2 = 2*px - 1 + dx; if (cx2 < 0 || cx2 >= 46) continue;
                        m = fmaxf(m, temp1[(cy2*46 + cx2)*2 + c]);
                    }
                }
                P1[(g*2 + c) * 529 + py * 23 + px] = m;
            }
            __syncthreads();
        }

        // ===== stage 2: conv2 3x3x32->64 + prelu + pool(3,2) -> P2 [64][10][10] =====
        float* w2s = sm + OFF_W;
        float* temp2 = sm + OFF_W + 768;
        float* b2s = sm + OFF_GAP; float* a2s = b2s + 16;
        float* P2 = sm + OFF_P2;
        {
            float pre[3];
            #pragma unroll
            for (int r = 0; r < 3; r++) {
                int i = t + r*256;
                int c = i & 15; int rest = i >> 4; int icl = rest & 15; int kx = rest >> 4;
                pre[r] = __ldg(&c2w[(kx*32 + icl) * 64 + c]);
            }
            for (int g = 0; g < 4; ++g) {
                if (t < 16) { b2s[t] = c2b[g*16 + t]; a2s[t] = p2a[g*16 + t]; }
                const int xg = t % 3; const int rem = t / 3;
                const int cq = rem & 3; const int cy = rem >> 2;
                const int x0 = xg * 7;
                float2 acc[2][7];
                #pragma unroll
                for (int p = 0; p < 2; p++)
                    #pragma unroll
                    for (int j = 0; j < 7; j++) acc[p][j] = make_float2(0.f, 0.f);
                for (int ky = 0; ky < 3; ky++) {
                    for (int ih = 0; ih < 2; ih++) {
                        __syncthreads();
                        #pragma unroll
                        for (int r = 0; r < 3; r++) w2s[t + r*256] = pre[r];
                        __syncthreads();
                        int rr = g*6 + ky*2 + ih + 1;
                        if (rr < 24) {
                            int ng = rr / 6; int nrem = rr % 6; int nky = nrem >> 1; int nih = nrem & 1;
                            #pragma unroll
                            for (int r = 0; r < 3; r++) {
                                int i = t + r*256;
                                int c = i & 15; int rest = i >> 4; int icl = rest & 15; int kx = rest >> 4;
                                pre[r] = __ldg(&c2w[((nky*3 + kx)*32 + nih*16 + icl) * 64 + ng*16 + c]);
                            }
                        }
                        if (t < 252) {
                            const float* inb = P1 + (ih*16)*529 + (cy + ky) * 23 + x0;
                            const float* wb = w2s + 4*cq;
                            #pragma unroll
                            for (int icl = 0; icl < 16; icl++) {
                                const float* in = inb + icl * 529;
                                float2 p0 = bcast2(in[0]), p1 = bcast2(in[1]), p2 = bcast2(in[2]);
                                float2 p3 = bcast2(in[3]), p4 = bcast2(in[4]), p5 = bcast2(in[5]);
                                float2 p6 = bcast2(in[6]), p7 = bcast2(in[7]), p8 = bcast2(in[8]);
                                float2 wA0 = *(const float2*)&wb[(0*16+icl)*16];
                                float2 wB0 = *(const float2*)&wb[(0*16+icl)*16 + 2];
                                float2 wA1 = *(const float2*)&wb[(1*16+icl)*16];
                                float2 wB1 = *(const float2*)&wb[(1*16+icl)*16 + 2];
                                float2 wA2 = *(const float2*)&wb[(2*16+icl)*16];
                                float2 wB2 = *(const float2*)&wb[(2*16+icl)*16 + 2];
                                dfma(acc[0][0],p0,wA0); dfma(acc[0][1],p1,wA0); dfma(acc[0][2],p2,wA0);
                                dfma(acc[0][3],p3,wA0); dfma(acc[0][4],p4,wA0); dfma(acc[0][5],p5,wA0); dfma(acc[0][6],p6,wA0);
                                dfma(acc[1][0],p0,wB0); dfma(acc[1][1],p1,wB0); dfma(acc[1][2],p2,wB0);
                                dfma(acc[1][3],p3,wB0); dfma(acc[1][4],p4,wB0); dfma(acc[1][5],p5,wB0); dfma(acc[1][6],p6,wB0);
                                dfma(acc[0][0],p1,wA1); dfma(acc[0][1],p2,wA1); dfma(acc[0][2],p3,wA1);
                                dfma(acc[0][3],p4,wA1); dfma(acc[0][4],p5,wA1); dfma(acc[0][5],p6,wA1); dfma(acc[0][6],p7,wA1);
                                dfma(acc[1][0],p1,wB1); dfma(acc[1][1],p2,wB1); dfma(acc[1][2],p3,wB1);
                                dfma(acc[1][3],p4,wB1); dfma(acc[1][4],p5,wB1); dfma(acc[1][5],p6,wB1); dfma(acc[1][6],p7,wB1);
                                dfma(acc[0][0],p2,wA2); dfma(acc[0][1],p3,wA2); dfma(acc[0][2],p4,wA2);
                                dfma(acc[0][3],p5,wA2); dfma(acc[0][4],p6,wA2); dfma(acc[0][5],p7,wA2); dfma(acc[0][6],p8,wA2);
                                dfma(acc[1][0],p2,wB2); dfma(acc[1][1],p3,wB2); dfma(acc[1][2],p4,wB2);
                                dfma(acc[1][3],p5,wB2); dfma(acc[1][4],p6,wB2); dfma(acc[1][5],p7,wB2); dfma(acc[1][6],p8,wB2);
                            }
                        }
                    }
                }
                float vb[4], va[4];
                if (t < 252) {
                    #pragma unroll
                    for (int k = 0; k < 4; k++) { vb[k] = b2s[4*cq + k]; va[k] = a2s[4*cq + k]; }
                }
                if (t < 252 && cq < 2) {
                    #pragma unroll
                    for (int p = 0; p < 2; p++) {
                        float* t0 = temp2 + (4*cq + 2*p)     * 441 + cy * 21 + x0;
                        float* t1 = temp2 + (4*cq + 2*p + 1) * 441 + cy * 21 + x0;
                        #pragma unroll
                        for (int j = 0; j < 7; j++) {
                            float v0 = acc[p][j].x + vb[2*p];
                            float v1 = acc[p][j].y + vb[2*p+1];
                            t0[j] = v0 >= 0.f ? v0 : va[2*p] * v0;
                            t1[j] = v1 >= 0.f ? v1 : va[2*p+1] * v1;
                        }
                    }
                }
                __syncthreads();
                for (int i = t; i < 800; i += TPB) {
                    int c = i & 7; int pos = i >> 3; int px = pos % 10; int py = pos / 10;
                    const float* tp = temp2 + c * 441;
                    float m = -3.4e38f;
                    #pragma unroll
                    for (int dy = 0; dy < 3; dy++)
                        #pragma unroll
                        for (int dx = 0; dx < 3; dx++)
                            m = fmaxf(m, tp[(2*py+dy)*21 + 2*px+dx]);
                    P2[(g*16 + c) * 100 + py * 10 + px] = m;
                }
                __syncthreads();
                if (t < 252 && cq >= 2) {
                    #pragma unroll
                    for (int p = 0; p < 2; p++) {
                        float* t0 = temp2 + (4*(cq-2) + 2*p)     * 441 + cy * 21 + x0;
                        float* t1 = temp2 + (4*(cq-2) + 2*p + 1) * 441 + cy * 21 + x0;
                        #pragma unroll
                        for (int j = 0; j < 7; j++) {
                            float v0 = acc[p][j].x + vb[2*p];
                            float v1 = acc[p][j].y + vb[2*p+1];
                            t0[j] = v0 >= 0.f ? v0 : va[2*p] * v0;
                            t1[j] = v1 >= 0.f ? v1 : va[2*p+1] * v1;
                        }
                    }
                }
                __syncthreads();
                for (int i = t; i < 800; i += TPB) {
                    int c = i & 7; int pos = i >> 3; int px = pos % 10; int py = pos / 10;
                    const float* tp = temp2 + c * 441;
                    float m = -3.4e38f;
                    #pragma unroll
                    for (int dy = 0; dy < 3; dy++)
                        #pragma unroll
                        for (int dx = 0; dx < 3; dx++)
                            m = fmaxf(m, tp[(2*py+dy)*21 + 2*px+dx]);
                    P2[(g*16 + 8 + c) * 100 + py * 10 + px] = m;
                }
                __syncthreads();
            }
        }

        // ===== stage 3: conv3 (cp.async double-buffered, 8 ic-octet rounds) =====
        float* w3buf = sm + OFF_W34;
        float* b3s = w3buf + 9216; float* a3s = b3s + 64;
        float* temp3 = sm + OFF_W;
        float* P3 = sm + OFF_P3;
        {
            if (t < 64) { b3s[t] = c3b[t]; a3s[t] = p3a[t]; }
            const int cq = t & 15; const int pos = t >> 4;
            const int xg = pos & 1; const int cy = pos >> 1;
            const int x0 = xg * 4;
            float2 acc[2][4];
            #pragma unroll
            for (int p = 0; p < 2; p++)
                #pragma unroll
                for (int j = 0; j < 4; j++) acc[p][j] = make_float2(0.f, 0.f);
            {
                #pragma unroll
                for (int j = 0; j < 9; j++) {
                    int d = t + j*256;
                    int i = 2*d;
                    int c = i & 63; int kidx = i >> 6;
                    int icl = kidx & 7; int kk = kidx >> 3;
                    cpasync8(&w3buf[i], &c3w[(kk*64 + icl) * 64 + c]);
                }
                CP_COMMIT();
            }
            for (int r = 0; r < 8; r++) {
                CP_WAIT0();
                __syncthreads();
                if (r + 1 < 8) {
                    float* nb = w3buf + ((r+1) & 1) * 4608;
                    int obase = (r+1) * 8;
                    #pragma unroll
                    for (int j = 0; j < 9; j++) {
                        int d = t + j*256;
                        int i = 2*d;
                        int c = i & 63; int kidx = i >> 6;
                        int icl = kidx & 7; int kk = kidx >> 3;
                        cpasync8(&nb[i], &c3w[(kk*64 + obase + icl) * 64 + c]);
                    }
                    CP_COMMIT();
                }
                const float* wbuf = w3buf + (r & 1) * 4608;
                #pragma unroll
                for (int ky = 0; ky < 3; ky++) {
                    const float* inb = P2 + (r*8)*100 + (cy + ky) * 10 + x0;
                    const float* wk = wbuf + (ky*3)*512 + 4*cq;
                    #pragma unroll
                    for (int icl = 0; icl < 8; icl++) {
                        const float* in = inb + icl * 100;
                        float2 p0 = bcast2(in[0]), p1 = bcast2(in[1]), p2 = bcast2(in[2]);
                        float2 p3 = bcast2(in[3]), p4 = bcast2(in[4]), p5 = bcast2(in[5]);
                        float2 wA0 = *(const float2*)&wk[(0*8+icl)*64];
                        float2 wB0 = *(const float2*)&wk[(0*8+icl)*64 + 2];
                        float2 wA1 = *(const float2*)&wk[(1*8+icl)*64];
                        float2 wB1 = *(const float2*)&wk[(1*8+icl)*64 + 2];
                        float2 wA2 = *(const float2*)&wk[(2*8+icl)*64];
                        float2 wB2 = *(const float2*)&wk[(2*8+icl)*64 + 2];
                        dfma(acc[0][0],p0,wA0); dfma(acc[0][1],p1,wA0); dfma(acc[0][2],p2,wA0); dfma(acc[0][3],p3,wA0);
                        dfma(acc[1][0],p0,wB0); dfma(acc[1][1],p1,wB0); dfma(acc[1][2],p2,wB0); dfma(acc[1][3],p3,wB0);
                        dfma(acc[0][0],p1,wA1); dfma(acc[0][1],p2,wA1); dfma(acc[0][2],p3,wA1); dfma(acc[0][3],p4,wA1);
                        dfma(acc[1][0],p1,wB1); dfma(acc[1][1],p2,wB1); dfma(acc[1][2],p3,wB1); dfma(acc[1][3],p4,wB1);
                        dfma(acc[0][0],p2,wA2); dfma(acc[0][1],p3,wA2); dfma(acc[0][2],p4,wA2); dfma(acc[0][3],p5,wA2);
                        dfma(acc[1][0],p2,wB2); dfma(acc[1][1],p3,wB2); dfma(acc[1][2],p4,wB2); dfma(acc[1][3],p5,wB2);
                    }
                }
            }
            float vb[4], va[4];
            #pragma unroll
            for (int k = 0; k < 4; k++) { vb[k] = b3s[4*cq + k]; va[k] = a3s[4*cq + k]; }
            if (cq < 8) {
                #pragma unroll
                for (int p = 0; p < 2; p++) {
                    float* t0 = temp3 + (4*cq + 2*p)     * 64 + cy * 8 + x0;
                    float* t1 = temp3 + (4*cq + 2*p + 1) * 64 + cy * 8 + x0;
                    #pragma unroll
                    for (int j = 0; j < 4; j++) {
                        float v0 = acc[p][j].x + vb[2*p];
                        float v1 = acc[p][j].y + vb[2*p+1];
                        t0[j] = v0 >= 0.f ? v0 : va[2*p] * v0;
                        t1[j] = v1 >= 0.f ? v1 : va[2*p+1] * v1;
                    }
                }
            }
            __syncthreads();
            for (int task = t; task < 512; task += TPB) {
                int c = task & 31; int pos2 = task >> 5; int px = pos2 & 3; int py = pos2 >> 2;
                const float* tp = temp3 + c * 64;
                float m = fmaxf(fmaxf(tp[(2*py)*8 + 2*px], tp[(2*py)*8 + 2*px + 1]),
                                fmaxf(tp[(2*py+1)*8 + 2*px], tp[(2*py+1)*8 + 2*px + 1]));
                P3[c * 16 + py * 4 + px] = m;
            }
            __syncthreads();
            if (cq >= 8) {
                #pragma unroll
                for (int p = 0; p < 2; p++) {
                    float* t0 = temp3 + (4*(cq-8) + 2*p)     * 64 + cy * 8 + x0;
                    float* t1 = temp3 + (4*(cq-8) + 2*p + 1) * 64 + cy * 8 + x0;
                    #pragma unroll
                    for (int j = 0; j < 4; j++) {
                        float v0 = acc[p][j].x + vb[2*p];
                        float v1 = acc[p][j].y + vb[2*p+1];
                        t0[j] = v0 >= 0.f ? v0 : va[2*p] * v0;
                        t1[j] = v1 >= 0.f ? v1 : va[2*p+1] * v1;
                    }
                }
            }
            __syncthreads();
            for (int task = t; task < 512; task += TPB) {
                int c = task & 31; int pos2 = task >> 5; int px = pos2 & 3; int py = pos2 >> 2;
                const float* tp = temp3 + c * 64;
                float m = fmaxf(fmaxf(tp[(2*py)*8 + 2*px], tp[(2*py)*8 + 2*px + 1]),
                                fmaxf(tp[(2*py+1)*8 + 2*px], tp[(2*py+1)*8 + 2*px + 1]));
                P3[(32 + c) * 16 + py * 4 + px] = m;
            }
            __syncthreads();
        }

        // ===== stage 4: conv4 2x2x64->128 + prelu -> C4 flat (cp.async double-buffered) =====
        float* w4a = sm + OFF_W34;            // 4096
        float* w4b = sm + OFF_W34 + 4096;     // 4096
        float* b4s = sm + OFF_W34 + 8192; float* a4s = b4s + 64;
        float* C4 = sm + OFF_C4;
        {
            // prologue: round 0 (g=0,k=0) into w4a
            #pragma unroll
            for (int j = 0; j < 4; j++) {
                int ic = (t >> 4) + j*16;
                int c0 = (t & 15) * 4;
                cpasync16(&w4a[ic*64 + c0], &c4w[ic*128 + c0]);
            }
            CP_COMMIT();
            for (int g = 0; g < 2; ++g) {
                if (t < 64) { b4s[t] = c4b[g*64 + t]; a4s[t] = p4a[g*64 + t]; }
                const int cq = t & 15; const int pos = t >> 4;
                const int y = pos / 3, x = pos % 3;
                float2 accA = make_float2(0.f,0.f), accB = accA;
                for (int k = 0; k < 4; k++) {
                    CP_WAIT0();
                    __syncthreads();
                    int rr = g*4 + k + 1;
                    if (rr < 8) {
                        int ng = rr >> 2; int nk = rr & 3;
                        float* nb = (rr & 1) ? w4b : w4a;
                        #pragma unroll
                        for (int j = 0; j < 4; j++) {
                            int ic = (t >> 4) + j*16;
                            int c0 = (t & 15) * 4;
                            cpasync16(&nb[ic*64 + c0], &c4w[(nk*64 + ic)*128 + ng*64 + c0]);
                        }
                        CP_COMMIT();
                    }
                    const float* wb4 = (((g*4 + k) & 1) ? w4b : w4a) + 4*cq;
                    if (t < 144) {
                        int ky = k >> 1, kx = k & 1;
                        const float* inb = P3 + (y + ky) * 4 + (x + kx);
                        #pragma unroll
                        for (int ic = 0; ic < 64; ic++) {
                            float2 p = bcast2(inb[ic * 16]);
                            float2 wA = *(const float2*)&wb4[ic * 64];
                            float2 wB = *(const float2*)&wb4[ic * 64 + 2];
                            dfma(accA, p, wA); dfma(accB, p, wB);
                        }
                    }
                }
                if (t < 144) {
                    int c0 = g*64 + 4*cq;
                    float v0 = accA.x + b4s[4*cq+0], v1 = accA.y + b4s[4*cq+1];
                    float v2 = accB.x + b4s[4*cq+2], v3 = accB.y + b4s[4*cq+3];
                    float l0 = a4s[4*cq+0], l1 = a4s[4*cq+1], l2 = a4s[4*cq+2], l3 = a4s[4*cq+3];
                    C4[(c0+0)*9 + pos] = v0 >= 0.f ? v0 : l0 * v0;
                    C4[(c0+1)*9 + pos] = v1 >= 0.f ? v1 : l1 * v1;
                    C4[(c0+2)*9 + pos] = v2 >= 0.f ? v2 : l2 * v2;
                    C4[(c0+3)*9 + pos] = v3 >= 0.f ? v3 : l3 * v3;
                }
                __syncthreads();
            }
        }

        // park box-0's C4 in gmem scratch (box-1's stays in smem)
        if (bb == 0) {
            float4* park = (float4*)(g_c4park + (size_t)blockIdx.x * 1152);
            const float4* src = (const float4*)(sm + OFF_C4);
            for (int i = t; i < 288; i += TPB) park[i] = src[i];
            __syncthreads();
        }
    }

    // ===== fc5 dual: 1152 -> 256 + prelu for BOTH boxes (weights read once) =====
    float* C40 = sm + OFF_W;
    float* F50 = sm + OFF_W + 1152;
    float* FC60 = sm + OFF_W + 1408;
    float* C41 = sm + OFF_C4;
    float* F51 = sm + OFF_F5;
    float* FC61 = sm + OFF_FC6;
    {
        float4* dst = (float4*)C40;
        const float4* park = (const float4*)(g_c4park + (size_t)blockIdx.x * 1152);
        for (int i = t; i < 288; i += TPB) dst[i] = park[i];
    }
    __syncthreads();
    {
        int warp = t >> 5, lane = t & 31;
        for (int o = warp; o < 256; o += 8) {
            const float4* wrow = (const float4*)(f5w + o * 1152);
            float acc0 = 0.f, acc1 = 0.f;
            #pragma unroll
            for (int j = 0; j < 9; j++) {
                float4 wv = __ldg(&wrow[j*32 + lane]);
                float4 c0 = *(const float4*)&C40[j*128 + lane*4];
                float4 c1 = *(const float4*)&C41[j*128 + lane*4];
                acc0 += c0.x*wv.x + c0.y*wv.y + c0.z*wv.z + c0.w*wv.w;
                acc1 += c1.x*wv.x + c1.y*wv.y + c1.z*wv.z + c1.w*wv.w;
            }
            #pragma unroll
            for (int s = 16; s; s >>= 1) {
                acc0 += __shfl_xor_sync(0xFFFFFFFFu, acc0, s);
                acc1 += __shfl_xor_sync(0xFFFFFFFFu, acc1, s);
            }
            if (lane == 0) {
                float bsv = f5b[o], al = p5a[o];
                float v0 = acc0 + bsv, v1 = acc1 + bsv;
                F50[o] = v0 >= 0.f ? v0 : al * v0;
                F51[o] = v1 >= 0.f ? v1 : al * v1;
            }
        }
    }
    __syncthreads();

    // ===== fc6 dual =====
    if (t < 192) {
        int o = t >> 5, lane = t & 31;
        const float* wrow = (o < 2) ? (f6aw + o * 256) : (f6bw + (o - 2) * 256);
        float acc0 = 0.f, acc1 = 0.f;
        #pragma unroll
        for (int j = 0; j < 8; j++) {
            int k = lane + 32*j;
            float w = __ldg(&wrow[k]);
            acc0 += F50[k] * w;
            acc1 += F51[k] * w;
        }
        #pragma unroll
        for (int s = 16; s; s >>= 1) {
            acc0 += __shfl_xor_sync(0xFFFFFFFFu, acc0, s);
            acc1 += __shfl_xor_sync(0xFFFFFFFFu, acc1, s);
        }
        if (lane == 0) {
            float bv = (o < 2) ? f6ab[o] : f6bb[o - 2];
            FC60[o] = acc0 + bv;
            FC61[o] = acc1 + bv;
        }
    }
    __syncthreads();

    if (t == 0) {
        #pragma unroll
        for (int bb = 0; bb < 2; bb++) {
            const int bidx = blockIdx.x * 2 + bb;
            const float* FC = bb ? FC61 : FC60;
            float B0 = bboxes[bidx*4+0], B1 = bboxes[bidx*4+1], B2 = bboxes[bidx*4+2], B3 = bboxes[bidx*4+3];
            float bx1 = fmaxf(B0, 0.f), by1 = fmaxf(B1, 0.f);
            float bx2 = fminf(B2, 1024.f), by2 = fminf(B3, 1024.f);
            float l0 = FC[0], l1 = FC[1];
            float m = fmaxf(l0, l1);
            float e0 = expf(l0 - m), e1 = expf(l1 - m);
            float score = e1 / (e0 + e1);
            float w = bx2 - bx1, h = by2 - by1;
            g_score[bidx] = score;
            g_box[bidx*4+0] = bx1 + FC[2] * w;
            g_box[bidx*4+1] = by1 + FC[3] * h;
            g_box[bidx*4+2] = bx2 + FC[4] * w;
            g_box[bidx*4+3] = by2 + FC[5] * h;
        }
    }
}

// ---------- NMS: bitonic sort by (score desc, idx asc); also computes V ----------
__device__ __forceinline__ bool nms_before(float ka, int ia, float kb, int ib) {
    return (ka > kb) || (ka == kb && ia < ib);
}

__global__ __launch_bounds__(1024) void nms_sort() {
    __shared__ float kk[NBOX];
    __shared__ int   id[NBOX];
    int t = threadIdx.x;
    kk[t] = g_score[t];           id[t] = t;
    kk[t+1024] = g_score[t+1024]; id[t+1024] = t + 1024;
    for (int k = 2; k <= NBOX; k <<= 1) {
        for (int j = k >> 1; j > 0; j >>= 1) {
            __syncthreads();
            #pragma unroll 2
            for (int i = t; i < NBOX; i += 1024) {
                int ixj = i ^ j;
                if (ixj > i) {
                    float ka = kk[i], kb = kk[ixj];
                    int ia = id[i], ib = id[ixj];
                    bool up = ((i & k) == 0);
                    bool bad = up ? nms_before(kb, ib, ka, ia) : nms_before(ka, ia, kb, ib);
                    if (bad) { kk[i] = kb; kk[ixj] = ka; id[i] = ib; id[ixj] = ia; }
                }
            }
        }
    }
    __syncthreads();
    #pragma unroll 2
    for (int i = t; i < NBOX; i += 1024) {
        g_skey[i] = kk[i];
        int o = id[i];
        g_sidx[i] = o;
        g_sbox[i*4+0] = g_box[o*4+0];
        g_sbox[i*4+1] = g_box[o*4+1];
        g_sbox[i*4+2] = g_box[o*4+2];
        g_sbox[i*4+3] = g_box[o*4+3];
        // valid prefix boundary (scores sorted desc)
        bool v = kk[i] >= 0.5f;
        bool nv = (i + 1 < NBOX) ? (kk[i+1] < 0.5f) : true;
        if (v && nv) g_V = i + 1;
    }
    if (t == 0 && kk[0] < 0.5f) g_V = 0;
}

// ---------- NMS: IOU bitmask (valid prefix only) ----------
__global__ __launch_bounds__(64) void nms_mask() {
    __shared__ float cb[32][4];
    int t = threadIdx.x;
    int j0 = blockIdx.x * 32;
    if (g_skey[j0] < 0.5f) return;           // all columns in this block >= V: words never consumed
    for (int i = t; i < 128; i += 64) cb[i >> 2][i & 3] = g_sbox[(j0 + (i >> 2)) * 4 + (i & 3)];
    __syncthreads();
    int i = blockIdx.y * 64 + t;
    if (g_skey[i] < 0.5f) return;            // row >= V: never read by scan
    float x1 = g_sbox[i*4+0], y1 = g_sbox[i*4+1], x2 = g_sbox[i*4+2], y2 = g_sbox[i*4+3];
    float area = (x2 - x1) * (y2 - y1);
    unsigned word = 0;
    #pragma unroll 8
    for (int jj = 0; jj < 32; jj++) {
        int j = j0 + jj;
        if (j > i) {
            float bx1v = cb[jj][0], by1v = cb[jj][1], bx2v = cb[jj][2], by2v = cb[jj][3];
            float xx1 = fmaxf(x1, bx1v), yy1 = fmaxf(y1, by1v);
            float xx2 = fminf(x2, bx2v), yy2 = fminf(y2, by2v);
            float inter = fmaxf(xx2 - xx1, 0.f) * fmaxf(yy2 - yy1, 0.f);
            float areab = (bx2v - bx1v) * (by2v - by1v);
            float iou = inter / (area + areab - inter + 1e-12f);
            if (iou > 0.5f) word |= (1u << jj);
        }
    }
    ((unsigned*)g_mask4)[i * 64 + blockIdx.x] = word;
}

// ---------- NMS: serial scan; uint4 streaming producers + register decision word ----------
#define SCHUNK 64
#define SNT    512
__global__ __launch_bounds__(SNT) void nms_scan(float* __restrict__ out) {
    __shared__ uint4 buf4[2][SCHUNK * 16];
    __shared__ unsigned keepw[64];
    int t = threadIdx.x;
    if (t < 64) keepw[t] = 0u;
    const int V = g_V;
    __syncthreads();
    const int nch = (V + SCHUNK - 1) / SCHUNK;
    const uint4 z4 = make_uint4(0u,0u,0u,0u);
    for (int i = t; i < SCHUNK * 16; i += SNT) {
        int p = i >> 4;
        buf4[0][i] = (p < V) ? g_mask4[i] : z4;
    }
    __syncthreads();
    unsigned r0 = 0u, r1 = 0u;
    for (int ci = 0; ci < nch; ci++) {
        if (t >= 32) {
            if (ci + 1 < nch) {
                uint4* nb = buf4[(ci + 1) & 1];
                int pb = (ci + 1) * SCHUNK;
                for (int i = t - 32; i < SCHUNK * 16; i += (SNT - 32)) {
                    int p = pb + (i >> 4);
                    nb[i] = (p < V) ? g_mask4[p * 16 + (i & 15)] : z4;
                }
            }
        } else {
            const unsigned* B = (const unsigned*)buf4[ci & 1];
            int pb = ci * SCHUNK;
            #pragma unroll
            for (int r = 0; r < 2; r++) {
                int rb = pb + r * 32;
                if (rb >= V) break;
                int w = rb >> 5;
                int lim = min(32, V - rb);
                unsigned dw = (w < 32) ? __shfl_sync(0xFFFFFFFFu, r0, w)
                                       : __shfl_sync(0xFFFFFFFFu, r1, w - 32);
                for (int jb = 0; jb < lim; jb += 8) {
                    unsigned qa[8], qb[8], qw[8];
                    #pragma unroll
                    for (int j = 0; j < 8; j++) {
                        int jj = r * 32 + jb + j;
                        bool ok = (jb + j) < lim;
                        qa[j] = ok ? B[jj*64 + t]      : 0u;
                        qb[j] = ok ? B[jj*64 + 32 + t] : 0u;
                        qw[j] = ok ? B[jj*64 + w]      : 0u;
                    }
                    #pragma unroll
                    for (int j = 0; j < 8; j++) {
                        int bb = jb + j;
                        unsigned m = ((dw >> bb) & 1u) - 1u;
                        dw |= qw[j] & m;
                        r0 |= qa[j] & m;
                        r1 |= qb[j] & m;
                    }
                }
                if (t == 0) {
                    unsigned vmask = (lim >= 32) ? 0xFFFFFFFFu : ((1u << lim) - 1u);
                    keepw[w] = (~dw) & vmask;
                }
            }
        }
        __syncthreads();
    }
    for (int i = t; i < NBOX * 4; i += SNT) out[i] = 0.f;
    __syncthreads();
    for (int p = t; p < NBOX; p += SNT) {
        if ((keepw[p >> 5] >> (p & 31)) & 1u) {
            int o = g_sidx[p];
            out[o*4+0] = g_sbox[p*4+0];
            out[o*4+1] = g_sbox[p*4+1];
            out[o*4+2] = g_sbox[p*4+2];
            out[o*4+3] = g_sbox[p*4+3];
        }
    }
}

extern "C" void kernel_launch(void* const* d_in, const int* in_sizes, int n_in,
                              void* d_out, int out_size) {
    (void)in_sizes; (void)n_in; (void)out_size;
    cudaFuncSetAttribute(onet_cnn, cudaFuncAttributeMaxDynamicSharedMemorySize, SMEM1_FLOATS * 4);
    onet_cnn<<<NBOX/2, TPB, SMEM1_FLOATS * 4>>>(
        (const float*)d_in[0],  (const float*)d_in[1],
        (const float*)d_in[2],  (const float*)d_in[3],  (const float*)d_in[4],
        (const float*)d_in[5],  (const float*)d_in[6],  (const float*)d_in[7],
        (const float*)d_in[8],  (const float*)d_in[9],  (const float*)d_in[10],
        (const float*)d_in[11], (const float*)d_in[12], (const float*)d_in[13],
        (const float*)d_in[14], (const float*)d_in[15], (const float*)d_in[16],
        (const float*)d_in[17], (const float*)d_in[18],
        (const float*)d_in[19], (const float*)d_in[20]);
    nms_sort<<<1, 1024>>>();
    nms_mask<<<dim3(64, 32), 64>>>();
    nms_scan<<<1, SNT>>>((float*)d_out);
}